// round 3
// baseline (speedup 1.0000x reference)
#include <cuda_runtime.h>
#include <math.h>

#define Bb 8
#define Np 4096
#define Gg 128
#define Kk 16
#define Vv 64
#define Mm 64
#define Dd 384
#define NHh 8
#define DHh 48
#define FFf 1536

__device__ float g_centers[2][Bb*Gg*3];
__device__ int   g_nidx[Bb*Gg*Kk];
__device__ int   g_nidxS[Bb*Gg*Kk];
__device__ float g_rel[Bb*Gg*Kk*3];
__device__ float g_f1[Bb*Gg*Kk*128];
__device__ float g_f2[Bb*Gg*Kk*256];
__device__ float g_gmax[Bb*Gg*256];
__device__ float g_cat[Bb*Gg*Kk*512];
__device__ float g_t1[Bb*Gg*Kk*512];
__device__ float g_t2[Bb*Gg*Kk*Dd];
__device__ float g_tokens[2][Bb*Gg*Dd];
__device__ float g_cpe[2][Bb*Gg*Dd];
__device__ float g_ppe[2][Bb*Np*Dd];
__device__ unsigned char g_mfull[2][Bb*Gg*Gg];
__device__ unsigned char g_mvis[2][Bb*Vv*Vv];
__device__ float g_vis3[Bb*Vv*3];
__device__ float g_visbuf[2][Bb*Vv*Dd];
__device__ float g_fullbuf[2][Bb*Gg*Dd];
__device__ float g_decx[2][Bb*(Mm+Vv)*Dd];
__device__ float g_mbuf[Bb*Gg*Dd];
__device__ float g_lnm[Bb*Gg*Dd];
__device__ float g_lnS[Bb*Gg*Dd];
__device__ float g_lnT[Bb*Gg*Dd];
__device__ float g_lnbig[Bb*Np*Dd];
__device__ float g_qbuf[Bb*Np*Dd];
__device__ float g_kbuf[Bb*Gg*Dd];
__device__ float g_vbuf[Bb*Gg*Dd];
__device__ float g_ctx[Bb*Np*Dd];
__device__ float g_hid[Bb*Np*FFf];
__device__ float g_upcat[Bb*Np*387];
__device__ int   g_nn3i[Bb*Np*3];
__device__ float g_nn3w[Bb*Np*3];
__device__ float g_lpart[2*64];

// C[rows,Nc] = act(A @ W + bias) (+= if accum). rows%128==0, Nc%128==0.
// 128x128 block tile, Ktile=8, 256 threads, 8x8 microtile (2x2 of 4x4).
__global__ __launch_bounds__(256, 2)
void gemm_kernel(const float* __restrict__ A, const float* __restrict__ W,
                 const float* __restrict__ bias, float* __restrict__ C,
                 int rows, int Kd, int Nc, int relu, int accum)
{
    __shared__ float As[8][128];
    __shared__ float Ws[8][128];
    int tid = threadIdx.x, tx = tid & 15, ty = tid >> 4;
    int row0 = blockIdx.y * 128, col0 = blockIdx.x * 128;
    float acc[8][8] = {};
    for (int k0 = 0; k0 < Kd; k0 += 8) {
        #pragma unroll
        for (int l = 0; l < 4; l++) {
            int i = tid + l*256;
            int m = i & 127, kk = i >> 7;
            bool ok = (k0 + kk < Kd);
            As[kk][m] = ok ? A[(size_t)(row0+m)*Kd + k0 + kk] : 0.f;
            Ws[kk][m] = ok ? W[(size_t)(k0+kk)*Nc + col0 + m] : 0.f;
        }
        __syncthreads();
        #pragma unroll
        for (int kk = 0; kk < 8; kk++) {
            float a[8], b[8];
            *(float4*)&a[0] = *(const float4*)&As[kk][ty*4];
            *(float4*)&a[4] = *(const float4*)&As[kk][ty*4 + 64];
            *(float4*)&b[0] = *(const float4*)&Ws[kk][tx*4];
            *(float4*)&b[4] = *(const float4*)&Ws[kk][tx*4 + 64];
            #pragma unroll
            for (int i = 0; i < 8; i++)
                #pragma unroll
                for (int j = 0; j < 8; j++)
                    acc[i][j] += a[i]*b[j];
        }
        __syncthreads();
    }
    #pragma unroll
    for (int i = 0; i < 8; i++) {
        int r = row0 + ((i < 4) ? (ty*4 + i) : (64 + ty*4 + i - 4));
        #pragma unroll
        for (int j = 0; j < 8; j++) {
            int c = col0 + ((j < 4) ? (tx*4 + j) : (64 + tx*4 + j - 4));
            float v = acc[i][j];
            if (bias) v += bias[c];
            if (relu) v = fmaxf(v, 0.f);
            size_t o = (size_t)r*Nc + c;
            if (accum) C[o] += v; else C[o] = v;
        }
    }
}

__global__ void ln_kernel(const float* __restrict__ x, float* __restrict__ y)
{
    int row = blockIdx.x, t = threadIdx.x;
    const float* xr = x + (size_t)row*Dd;
    __shared__ float red[128];
    float a = xr[t], b = xr[t+128], c = xr[t+256];
    red[t] = a + b + c; __syncthreads();
    for (int o = 64; o > 0; o >>= 1) { if (t < o) red[t] += red[t+o]; __syncthreads(); }
    float m = red[0] / (float)Dd; __syncthreads();
    float da=a-m, db=b-m, dc=c-m;
    red[t] = da*da + db*db + dc*dc; __syncthreads();
    for (int o = 64; o > 0; o >>= 1) { if (t < o) red[t] += red[t+o]; __syncthreads(); }
    float inv = rsqrtf(red[0] / (float)Dd + 1e-5f);
    float* yr = y + (size_t)row*Dd;
    yr[t]=da*inv; yr[t+128]=db*inv; yr[t+256]=dc*inv;
}

// one block per (q,h,b); Sk<=128
__global__ void attn_kernel(const float* __restrict__ q, const float* __restrict__ kmat,
                            const float* __restrict__ vmat, const unsigned char* __restrict__ mask,
                            float* __restrict__ ctx, int Sq, int Sk)
{
    int qi = blockIdx.x, h = blockIdx.y, b = blockIdx.z, t = threadIdx.x;
    __shared__ float shq[DHh], shp[128], red[128];
    const float* qr = q + ((size_t)(b*Sq + qi))*Dd + h*DHh;
    if (t < DHh) shq[t] = qr[t];
    __syncthreads();
    float val = -3e38f;
    if (t < Sk) {
        const float* kr = kmat + ((size_t)(b*Sk + t))*Dd + h*DHh;
        float s = 0.f;
        #pragma unroll
        for (int d = 0; d < DHh; d++) s += shq[d]*kr[d];
        s /= sqrtf((float)DHh);
        if (mask && !mask[((size_t)b*Sq + qi)*Sk + t]) s = -1e9f;
        val = s;
    }
    red[t] = val; __syncthreads();
    for (int o = 64; o > 0; o >>= 1) { if (t < o) red[t] = fmaxf(red[t], red[t+o]); __syncthreads(); }
    float mx = red[0]; __syncthreads();
    float e = (t < Sk) ? expf(val - mx) : 0.f;
    shp[t] = e; red[t] = e; __syncthreads();
    for (int o = 64; o > 0; o >>= 1) { if (t < o) red[t] += red[t+o]; __syncthreads(); }
    float inv = 1.f / red[0];
    if (t < DHh) {
        float acc = 0.f;
        const float* vb = vmat + ((size_t)(b*Sk))*Dd + h*DHh + t;
        for (int kk = 0; kk < Sk; kk++) acc += shp[kk]*vb[(size_t)kk*Dd];
        ctx[((size_t)(b*Sq + qi))*Dd + h*DHh + t] = acc*inv;
    }
}

__global__ void fps_kernel(const float* __restrict__ pos, float* __restrict__ centers)
{
    int b = blockIdx.x, t = threadIdx.x;
    __shared__ float mind[Np];
    __shared__ float rv[512]; __shared__ int ri[512]; __shared__ float curp[3];
    const float* P = pos + (size_t)b*Np*3;
    float* C = centers + (size_t)b*Gg*3;
    if (t == 0) { curp[0]=P[0]; curp[1]=P[1]; curp[2]=P[2]; C[0]=P[0]; C[1]=P[1]; C[2]=P[2]; }
    __syncthreads();
    for (int i = t; i < Np; i += 512) {
        float dx=P[3*i]-curp[0], dy=P[3*i+1]-curp[1], dz=P[3*i+2]-curp[2];
        mind[i] = dx*dx + dy*dy + dz*dz;
    }
    __syncthreads();
    for (int s = 1; s < Gg; s++) {
        float bv = -3e38f; int bi = 0x7fffffff;
        for (int i = t; i < Np; i += 512) { float v = mind[i]; if (v > bv) { bv = v; bi = i; } }
        rv[t] = bv; ri[t] = bi; __syncthreads();
        for (int o = 256; o > 0; o >>= 1) {
            if (t < o && (rv[t+o] > rv[t] || (rv[t+o] == rv[t] && ri[t+o] < ri[t]))) { rv[t]=rv[t+o]; ri[t]=ri[t+o]; }
            __syncthreads();
        }
        if (t == 0) {
            int nxt = ri[0];
            curp[0]=P[3*nxt]; curp[1]=P[3*nxt+1]; curp[2]=P[3*nxt+2];
            C[3*s]=curp[0]; C[3*s+1]=curp[1]; C[3*s+2]=curp[2];
        }
        __syncthreads();
        for (int i = t; i < Np; i += 512) {
            float dx=P[3*i]-curp[0], dy=P[3*i+1]-curp[1], dz=P[3*i+2]-curp[2];
            float d = dx*dx + dy*dy + dz*dz;
            if (d < mind[i]) mind[i] = d;
        }
        __syncthreads();
    }
}

__global__ void knn_big_kernel(const float* __restrict__ qpts, const float* __restrict__ rpts,
                               int* __restrict__ nidx)
{
    int blk = blockIdx.x, b = blk / Gg, qc = blk % Gg, t = threadIdx.x;
    __shared__ float dist[Np];
    __shared__ float rv[128]; __shared__ int ri[128];
    const float* Q = qpts + ((size_t)b*Gg + qc)*3;
    float qx=Q[0], qy=Q[1], qz=Q[2], qq = qx*qx+qy*qy+qz*qz;
    const float* R = rpts + (size_t)b*Np*3;
    for (int i = t; i < Np; i += 128) {
        float rx=R[3*i], ry=R[3*i+1], rz=R[3*i+2];
        dist[i] = qq + (rx*rx+ry*ry+rz*rz) - 2.f*(qx*rx+qy*ry+qz*rz);
    }
    __syncthreads();
    for (int kk = 0; kk < Kk; kk++) {
        float bv = 3e38f; int bi = 0x7fffffff;
        for (int i = t; i < Np; i += 128) { float v = dist[i]; if (v < bv) { bv = v; bi = i; } }
        rv[t] = bv; ri[t] = bi; __syncthreads();
        for (int o = 64; o > 0; o >>= 1) {
            if (t < o && (rv[t+o] < rv[t] || (rv[t+o] == rv[t] && ri[t+o] < ri[t]))) { rv[t]=rv[t+o]; ri[t]=ri[t+o]; }
            __syncthreads();
        }
        if (t == 0) { nidx[((size_t)b*Gg + qc)*Kk + kk] = ri[0]; dist[ri[0]] = 3e38f; }
        __syncthreads();
    }
}

__global__ void knn_small_kernel(const float* __restrict__ pts, int S, int* __restrict__ nidx)
{
    int blk = blockIdx.x, b = blk / S, qi = blk % S, t = threadIdx.x;
    __shared__ float dist[128]; __shared__ float rv[128]; __shared__ int ri[128];
    const float* Q = pts + ((size_t)b*S + qi)*3;
    float qx=Q[0], qy=Q[1], qz=Q[2], qq=qx*qx+qy*qy+qz*qz;
    if (t < S) {
        const float* R = pts + ((size_t)b*S + t)*3;
        dist[t] = qq + (R[0]*R[0]+R[1]*R[1]+R[2]*R[2]) - 2.f*(qx*R[0]+qy*R[1]+qz*R[2]);
    } else dist[t] = 3e38f;
    __syncthreads();
    for (int kk = 0; kk < Kk; kk++) {
        rv[t] = dist[t]; ri[t] = t; __syncthreads();
        for (int o = 64; o > 0; o >>= 1) {
            if (t < o && (rv[t+o] < rv[t] || (rv[t+o] == rv[t] && ri[t+o] < ri[t]))) { rv[t]=rv[t+o]; ri[t]=ri[t+o]; }
            __syncthreads();
        }
        if (t == 0) { nidx[((size_t)b*S + qi)*Kk + kk] = ri[0]; dist[ri[0]] = 3e38f; }
        __syncthreads();
    }
}

__global__ void zero_u8_kernel(unsigned char* m, int n)
{ int i = blockIdx.x*blockDim.x + threadIdx.x; if (i < n) m[i] = 0; }

__global__ void scatter_mask_kernel(const int* __restrict__ nidx, unsigned char* __restrict__ m, int S)
{
    int i = blockIdx.x*blockDim.x + threadIdx.x;
    if (i >= Bb*S*Kk) return;
    int b = i / (S*Kk), r = (i / Kk) % S;
    m[((size_t)b*S + r)*S + nidx[i]] = 1;
}

__global__ void group_rel_kernel(const float* __restrict__ pos, const float* __restrict__ centers,
                                 const int* __restrict__ nidx, float* __restrict__ rel)
{
    int i = blockIdx.x*blockDim.x + threadIdx.x;
    if (i >= Bb*Gg*Kk) return;
    int b = i / (Gg*Kk), g = (i / Kk) % Gg, src = nidx[i];
    const float* P = pos + ((size_t)b*Np + src)*3;
    const float* C = centers + ((size_t)b*Gg + g)*3;
    rel[3*i]=P[0]-C[0]; rel[3*i+1]=P[1]-C[1]; rel[3*i+2]=P[2]-C[2];
}

__global__ void gmax_kernel(const float* __restrict__ f, float* __restrict__ g, int C)
{
    int i = blockIdx.x*blockDim.x + threadIdx.x;
    if (i >= Bb*Gg*C) return;
    int bg = i / C, c = i % C;
    const float* fp = f + (size_t)bg*Kk*C + c;
    float m = fp[0];
    #pragma unroll
    for (int k = 1; k < Kk; k++) m = fmaxf(m, fp[(size_t)k*C]);
    g[i] = m;
}

__global__ void cat_kernel(const float* __restrict__ g, const float* __restrict__ f, float* __restrict__ cat)
{
    int i = blockIdx.x*blockDim.x + threadIdx.x;
    if (i >= Bb*Gg*Kk*512) return;
    int c = i % 512, r = i / 512, bg = r / Kk;
    cat[i] = (c < 256) ? g[(size_t)bg*256 + c] : f[(size_t)r*256 + (c - 256)];
}

__global__ void pe_kernel(const float* __restrict__ xyz, float* __restrict__ pe, int rows)
{
    int i = blockIdx.x*blockDim.x + threadIdx.x;
    if (i >= rows*Dd) return;
    int r = i / Dd, j = i % Dd, c = j / 128, jj = j % 128;
    float x = xyz[(size_t)r*3 + c];
    float dt = powf(10000.0f, (float)(2*(jj/2)) / 128.0f);
    float p = x / dt;
    pe[i] = (jj & 1) ? cosf(p) : sinf(p);
}

__global__ void gather_kernel(const float* __restrict__ src, const int* __restrict__ idx,
                              float* __restrict__ dst, int outR, int inR, int W)
{
    int row = blockIdx.x, b = row / outR, r = row % outR;
    int s = idx[(size_t)b*outR + r];
    const float* sp = src + ((size_t)b*inR + s)*W;
    float* dp = dst + (size_t)row*W;
    for (int w = threadIdx.x; w < W; w += blockDim.x) dp[w] = sp[w];
}

__global__ void decq_kernel(const float* __restrict__ visout, const float* __restrict__ cpe,
                            const float* __restrict__ mask_token, const int* __restrict__ mskidx,
                            const int* __restrict__ visidx, float* __restrict__ x)
{
    int i = blockIdx.x*blockDim.x + threadIdx.x;
    if (i >= Bb*(Mm+Vv)*Dd) return;
    int d = i % Dd, r = (i / Dd) % (Mm+Vv), b = i / (Dd*(Mm+Vv));
    float base; int pidx;
    if (r < Mm) { base = mask_token[d]; pidx = mskidx[(size_t)b*Mm + r]; }
    else { base = visout[((size_t)b*Vv + (r-Mm))*Dd + d]; pidx = visidx[(size_t)b*Vv + (r-Mm)]; }
    x[i] = base + cpe[((size_t)b*Gg + pidx)*Dd + d];
}

__global__ void add_kernel(const float* __restrict__ a, const float* __restrict__ b,
                           float* __restrict__ c, int n)
{ int i = blockIdx.x*blockDim.x + threadIdx.x; if (i < n) c[i] = a[i] + b[i]; }

__global__ void nn3_kernel(const float* __restrict__ pos, const float* __restrict__ centers,
                           int* __restrict__ oi, float* __restrict__ ow)
{
    int i = blockIdx.x*blockDim.x + threadIdx.x;
    if (i >= Bb*Np) return;
    int b = i / Np;
    const float* P = pos + (size_t)i*3;
    float px=P[0], py=P[1], pz=P[2], qq=px*px+py*py+pz*pz;
    float d0=3e38f, d1=3e38f, d2=3e38f; int i0=-1, i1=-1, i2=-1;
    const float* C = centers + (size_t)b*Gg*3;
    for (int g = 0; g < Gg; g++) {
        float cx=C[3*g], cy=C[3*g+1], cz=C[3*g+2];
        float d = qq + (cx*cx+cy*cy+cz*cz) - 2.f*(px*cx+py*cy+pz*cz);
        if (d < d0) { d2=d1;i2=i1; d1=d0;i1=i0; d0=d;i0=g; }
        else if (d < d1) { d2=d1;i2=i1; d1=d;i1=g; }
        else if (d < d2) { d2=d;i2=g; }
    }
    float w0=1.f/(fmaxf(d0,0.f)+1e-8f), w1=1.f/(fmaxf(d1,0.f)+1e-8f), w2=1.f/(fmaxf(d2,0.f)+1e-8f);
    float s = w0+w1+w2;
    ow[3*i]=w0/s; ow[3*i+1]=w1/s; ow[3*i+2]=w2/s;
    oi[3*i]=i0; oi[3*i+1]=i1; oi[3*i+2]=i2;
}

__global__ void upcat_kernel(const float* __restrict__ feats, const float* __restrict__ pos,
                             const int* __restrict__ oi, const float* __restrict__ ow,
                             float* __restrict__ cat)
{
    int row = blockIdx.x, b = row / Np, t = threadIdx.x;
    int i0=oi[3*row], i1=oi[3*row+1], i2=oi[3*row+2];
    float w0=ow[3*row], w1=ow[3*row+1], w2=ow[3*row+2];
    const float* F = feats + (size_t)b*Gg*Dd;
    float* cp = cat + (size_t)row*387;
    for (int d = t; d < Dd; d += 128)
        cp[d] = w0*F[(size_t)i0*Dd+d] + w1*F[(size_t)i1*Dd+d] + w2*F[(size_t)i2*Dd+d];
    if (t < 3) cp[Dd + t] = pos[(size_t)row*3 + t];
}

__global__ void loss_kernel(const float* __restrict__ fullout, const int* __restrict__ mskidx,
                            const float* __restrict__ decx, float* __restrict__ partial)
{
    __shared__ float red[256];
    int t = threadIdx.x;
    float acc = 0.f;
    for (int i = blockIdx.x*256 + t; i < Bb*Mm*Dd; i += 64*256) {
        int d = i % Dd, r = (i / Dd) % Mm, b = i / (Dd*Mm);
        int gi = mskidx[(size_t)b*Mm + r];
        float tv = fullout[((size_t)b*Gg + gi)*Dd + d];
        float pv = decx[((size_t)b*(Mm+Vv) + r)*Dd + d];
        float a = fabsf(pv - tv);
        acc += (a < 2.0f) ? 0.25f*a*a : a - 1.0f;
    }
    red[t] = acc; __syncthreads();
    for (int o = 128; o > 0; o >>= 1) { if (t < o) red[t] += red[t+o]; __syncthreads(); }
    if (t == 0) partial[blockIdx.x] = red[0];
}

__global__ void loss_final_kernel(const float* __restrict__ pa, const float* __restrict__ pb,
                                  float* __restrict__ out)
{
    float sa = 0.f, sb = 0.f;
    for (int i = 0; i < 64; i++) { sa += pa[i]; sb += pb[i]; }
    float cnt = (float)(Bb*Mm*Dd);
    out[0] = 0.5f*(sa/cnt) + 0.5f*(sb/cnt);
}

__global__ void copy_kernel(const float* __restrict__ a, float* __restrict__ b, int n)
{ int i = blockIdx.x*blockDim.x + threadIdx.x; if (i < n) b[i] = a[i]; }

static void gemm(const float* A, const float* W, const float* bias, float* C,
                 int rows, int Kd, int Nc, int relu, int accum)
{
    dim3 grid(Nc/128, rows/128);
    gemm_kernel<<<grid, 256>>>(A, W, bias, C, rows, Kd, Nc, relu, accum);
}

static void attn_block(const float* lnq, const float* lnkv, const float* w,
                       const unsigned char* mask, float* x, int Sq, int Sk,
                       float* qb, float* kb, float* vb, float* cb)
{
    gemm(lnq,  w,           nullptr, qb, Bb*Sq, Dd, Dd, 0, 0);
    gemm(lnkv, w + Dd*Dd,   nullptr, kb, Bb*Sk, Dd, Dd, 0, 0);
    gemm(lnkv, w + 2*Dd*Dd, nullptr, vb, Bb*Sk, Dd, Dd, 0, 0);
    dim3 g(Sq, NHh, Bb);
    attn_kernel<<<g, 128>>>(qb, kb, vb, mask, cb, Sq, Sk);
    gemm(cb, w + 3*Dd*Dd, nullptr, x, Bb*Sq, Dd, Dd, 0, 1);
}

static void encode_pair(float* Sb, float* Tb, const unsigned char* mS, const unsigned char* mT,
                        int S, const float* cxw, const float* ff1, const float* ff2,
                        float* lnS, float* lnT, float* qb, float* kb, float* vb, float* cb, float* hid)
{
    int rows = Bb*S;
    const float* sa = cxw;
    const float* ca = cxw + 4*Dd*Dd;
    ln_kernel<<<rows, 128>>>(Sb, lnS);
    attn_block(lnS, lnS, sa, mS, Sb, S, S, qb, kb, vb, cb);
    ln_kernel<<<rows, 128>>>(Tb, lnT);
    attn_block(lnT, lnT, sa, mT, Tb, S, S, qb, kb, vb, cb);
    ln_kernel<<<rows, 128>>>(Sb, lnS);
    ln_kernel<<<rows, 128>>>(Tb, lnT);
    attn_block(lnS, lnT, ca, nullptr, Sb, S, S, qb, kb, vb, cb);
    attn_block(lnT, lnS, ca, nullptr, Tb, S, S, qb, kb, vb, cb);
    ln_kernel<<<rows, 128>>>(Sb, lnS);
    gemm(lnS, ff1, nullptr, hid, rows, Dd, FFf, 1, 0);
    gemm(hid, ff2, nullptr, Sb, rows, FFf, Dd, 0, 1);
    ln_kernel<<<rows, 128>>>(Tb, lnT);
    gemm(lnT, ff1, nullptr, hid, rows, Dd, FFf, 1, 0);
    gemm(hid, ff2, nullptr, Tb, rows, FFf, Dd, 0, 1);
}

#define GETSYM(var, sym) do { void* _p; cudaGetSymbolAddress(&_p, sym); var = (decltype(var))_p; } while (0)

extern "C" void kernel_launch(void* const* d_in, const int* in_sizes, int n_in,
                              void* d_out_v, int out_size)
{
    (void)in_sizes; (void)n_in; (void)out_size;
    const float* pos[2]    = {(const float*)d_in[0], (const float*)d_in[1]};
    const int*   visidx[2] = {(const int*)d_in[2], (const int*)d_in[4]};
    const int*   mskidx[2] = {(const int*)d_in[3], (const int*)d_in[5]};
    const float* tok_w1 = (const float*)d_in[6];  const float* tok_b1 = (const float*)d_in[7];
    const float* tok_w2 = (const float*)d_in[8];  const float* tok_b2 = (const float*)d_in[9];
    const float* tok_w3 = (const float*)d_in[10]; const float* tok_b3 = (const float*)d_in[11];
    const float* tok_w4 = (const float*)d_in[12]; const float* tok_b4 = (const float*)d_in[13];
    const float* mask_token = (const float*)d_in[14];
    const float* cx_attn = (const float*)d_in[15];
    const float* cx_ff1  = (const float*)d_in[16]; const float* cx_ff2 = (const float*)d_in[17];
    const float* enc_sa  = (const float*)d_in[18]; const float* enc_ca = (const float*)d_in[19];
    const float* enc_ff1 = (const float*)d_in[20]; const float* enc_ff2 = (const float*)d_in[21];
    const float* dec_ca  = (const float*)d_in[22]; const float* dec_ff1 = (const float*)d_in[23];
    const float* dec_ff2 = (const float*)d_in[24];
    const float* up_w1 = (const float*)d_in[25]; const float* up_b1 = (const float*)d_in[26];
    const float* up_w2 = (const float*)d_in[27]; const float* up_b2 = (const float*)d_in[28];
    float* dout = (float*)d_out_v;

    float *centersB, *relB, *f1B, *f2B, *gmaxB, *catB, *t1B, *t2B, *tokensB;
    float *cpeB, *ppeB, *vis3B, *visB, *fullB, *decxB, *mbufB, *lnmB, *lnSB, *lnTB;
    float *lnbigB, *qB, *kB, *vB, *ctxB, *hidB, *upcatB, *nn3wB, *lpartB;
    int *nidxB, *nidxSB, *nn3iB;
    unsigned char *mfullB, *mvisB;
    GETSYM(centersB, g_centers); GETSYM(nidxB, g_nidx); GETSYM(nidxSB, g_nidxS);
    GETSYM(relB, g_rel); GETSYM(f1B, g_f1); GETSYM(f2B, g_f2); GETSYM(gmaxB, g_gmax);
    GETSYM(catB, g_cat); GETSYM(t1B, g_t1); GETSYM(t2B, g_t2); GETSYM(tokensB, g_tokens);
    GETSYM(cpeB, g_cpe); GETSYM(ppeB, g_ppe); GETSYM(mfullB, g_mfull); GETSYM(mvisB, g_mvis);
    GETSYM(vis3B, g_vis3); GETSYM(visB, g_visbuf); GETSYM(fullB, g_fullbuf); GETSYM(decxB, g_decx);
    GETSYM(mbufB, g_mbuf); GETSYM(lnmB, g_lnm); GETSYM(lnSB, g_lnS); GETSYM(lnTB, g_lnT);
    GETSYM(lnbigB, g_lnbig); GETSYM(qB, g_qbuf); GETSYM(kB, g_kbuf); GETSYM(vB, g_vbuf);
    GETSYM(ctxB, g_ctx); GETSYM(hidB, g_hid); GETSYM(upcatB, g_upcat);
    GETSYM(nn3iB, g_nn3i); GETSYM(nn3wB, g_nn3w); GETSYM(lpartB, g_lpart);

    float* centers[2] = {centersB, centersB + Bb*Gg*3};
    float* tokens[2]  = {tokensB,  tokensB  + Bb*Gg*Dd};
    float* cpe[2]     = {cpeB,     cpeB     + Bb*Gg*Dd};
    float* ppe[2]     = {ppeB,     ppeB     + Bb*Np*Dd};
    float* visb[2]    = {visB,     visB     + Bb*Vv*Dd};
    float* fullb[2]   = {fullB,    fullB    + Bb*Gg*Dd};
    float* decx[2]    = {decxB,    decxB    + Bb*(Mm+Vv)*Dd};
    unsigned char* mfull[2] = {mfullB, mfullB + Bb*Gg*Gg};
    unsigned char* mvis[2]  = {mvisB,  mvisB  + Bb*Vv*Vv};

    // Phase 1: tokenize + PE + masks
    for (int s = 0; s < 2; s++) {
        fps_kernel<<<Bb, 512>>>(pos[s], centers[s]);
        knn_big_kernel<<<Bb*Gg, 128>>>(centers[s], pos[s], nidxB);
        group_rel_kernel<<<(Bb*Gg*Kk + 255)/256, 256>>>(pos[s], centers[s], nidxB, relB);
        gemm(relB, tok_w1, tok_b1, f1B, Bb*Gg*Kk, 3, 128, 1, 0);
        gemm(f1B, tok_w2, tok_b2, f2B, Bb*Gg*Kk, 128, 256, 0, 0);
        gmax_kernel<<<(Bb*Gg*256 + 255)/256, 256>>>(f2B, gmaxB, 256);
        cat_kernel<<<(Bb*Gg*Kk*512 + 255)/256, 256>>>(gmaxB, f2B, catB);
        gemm(catB, tok_w3, tok_b3, t1B, Bb*Gg*Kk, 512, 512, 1, 0);
        gemm(t1B, tok_w4, tok_b4, t2B, Bb*Gg*Kk, 512, Dd, 0, 0);
        gmax_kernel<<<(Bb*Gg*Dd + 255)/256, 256>>>(t2B, tokens[s], Dd);
        pe_kernel<<<(Bb*Gg*Dd + 255)/256, 256>>>(centers[s], cpe[s], Bb*Gg);
        pe_kernel<<<(Bb*Np*Dd + 255)/256, 256>>>(pos[s], ppe[s], Bb*Np);
        knn_small_kernel<<<Bb*Gg, 128>>>(centers[s], Gg, nidxSB);
        zero_u8_kernel<<<(Bb*Gg*Gg + 255)/256, 256>>>(mfull[s], Bb*Gg*Gg);
        scatter_mask_kernel<<<(Bb*Gg*Kk + 255)/256, 256>>>(nidxSB, mfull[s], Gg);
        gather_kernel<<<Bb*Vv, 32>>>(centers[s], visidx[s], vis3B, Vv, Gg, 3);
        knn_small_kernel<<<Bb*Vv, 128>>>(vis3B, Vv, nidxSB);
        zero_u8_kernel<<<(Bb*Vv*Vv + 255)/256, 256>>>(mvis[s], Bb*Vv*Vv);
        scatter_mask_kernel<<<(Bb*Vv*Kk + 255)/256, 256>>>(nidxSB, mvis[s], Vv);
        gather_kernel<<<Bb*Vv, 128>>>(tokens[s], visidx[s], visb[s], Vv, Gg, Dd);
        copy_kernel<<<(Bb*Gg*Dd + 255)/256, 256>>>(tokens[s], fullb[s], Bb*Gg*Dd);
    }

    // Phase 2: cross encoders
    encode_pair(visb[0], visb[1], mvis[0], mvis[1], Vv, cx_attn, cx_ff1, cx_ff2,
                lnSB, lnTB, qB, kB, vB, ctxB, hidB);
    encode_pair(fullb[0], fullb[1], mfull[0], mfull[1], Gg, cx_attn, cx_ff1, cx_ff2,
                lnSB, lnTB, qB, kB, vB, ctxB, hidB);

    // Phase 3: MAE decoder + loss
    for (int s = 0; s < 2; s++) {
        int o = 1 - s;
        decq_kernel<<<(Bb*(Mm+Vv)*Dd + 255)/256, 256>>>(visb[s], cpe[s], mask_token,
                                                        mskidx[s], visidx[s], decx[s]);
        add_kernel<<<(Bb*Gg*Dd + 255)/256, 256>>>(fullb[o], cpe[o], mbufB, Bb*Gg*Dd);
        ln_kernel<<<Bb*Gg, 128>>>(mbufB, lnmB);
        for (int l = 0; l < 4; l++) {
            const float* sal = enc_sa + (size_t)l*4*Dd*Dd;
            const float* cal = enc_ca + (size_t)l*4*Dd*Dd;
            ln_kernel<<<Bb*(Mm+Vv), 128>>>(decx[s], lnSB);
            attn_block(lnSB, lnSB, sal, nullptr, decx[s], Mm+Vv, Mm+Vv, qB, kB, vB, ctxB);
            ln_kernel<<<Bb*(Mm+Vv), 128>>>(decx[s], lnSB);
            attn_block(lnSB, lnmB, cal, nullptr, decx[s], Mm+Vv, Gg, qB, kB, vB, ctxB);
            ln_kernel<<<Bb*(Mm+Vv), 128>>>(decx[s], lnSB);
            gemm(lnSB, enc_ff1 + (size_t)l*Dd*FFf, nullptr, hidB, Bb*(Mm+Vv), Dd, FFf, 1, 0);
            gemm(hidB, enc_ff2 + (size_t)l*FFf*Dd, nullptr, decx[s], Bb*(Mm+Vv), FFf, Dd, 0, 1);
        }
        loss_kernel<<<64, 256>>>(fullb[s], mskidx[s], decx[s], lpartB + s*64);
    }

    // Phase 4: upsample + dense decoder
    for (int s = 0; s < 2; s++) {
        float* X = dout + (size_t)s*Bb*Np*Dd;
        nn3_kernel<<<(Bb*Np + 255)/256, 256>>>(pos[s], centers[s], nn3iB, nn3wB);
        upcat_kernel<<<Bb*Np, 128>>>(fullb[s], pos[s], nn3iB, nn3wB, upcatB);
        gemm(upcatB, up_w1, up_b1, lnbigB, Bb*Np, 387, Dd, 1, 0);
        gemm(lnbigB, up_w2, up_b2, ctxB, Bb*Np, Dd, Dd, 1, 0);
        add_kernel<<<(Bb*Np*Dd + 255)/256, 256>>>(ctxB, ppe[s], X, Bb*Np*Dd);
        add_kernel<<<(Bb*Gg*Dd + 255)/256, 256>>>(fullb[s], cpe[s], mbufB, Bb*Gg*Dd);
        ln_kernel<<<Bb*Gg, 128>>>(mbufB, lnmB);
        for (int l = 0; l < 2; l++) {
            const float* cal = dec_ca + (size_t)l*4*Dd*Dd;
            ln_kernel<<<Bb*Np, 128>>>(X, lnbigB);
            attn_block(lnbigB, lnmB, cal, nullptr, X, Np, Gg, qB, kB, vB, ctxB);
            ln_kernel<<<Bb*Np, 128>>>(X, lnbigB);
            gemm(lnbigB, dec_ff1 + (size_t)l*Dd*FFf, nullptr, hidB, Bb*Np, Dd, FFf, 1, 0);
            gemm(hidB, dec_ff2 + (size_t)l*FFf*Dd, nullptr, X, Bb*Np, FFf, Dd, 0, 1);
        }
    }
    loss_final_kernel<<<1, 1>>>(lpartB, lpartB + 64, dout + (size_t)2*Bb*Np*Dd);
}

// round 5
// speedup vs baseline: 2.4658x; 2.4658x over previous
#include <cuda_runtime.h>
#include <math.h>

#define Bb 8
#define Np 4096
#define Gg 128
#define Kk 16
#define Vv 64
#define Mm 64
#define Dd 384
#define NHh 8
#define DHh 48
#define FFf 1536

__device__ float g_centers[2][Bb*Gg*3];
__device__ int   g_nidx[Bb*Gg*Kk];
__device__ int   g_nidxS[Bb*Gg*Kk];
__device__ float g_rel[Bb*Gg*Kk*3];
__device__ float g_f1[Bb*Gg*Kk*128];
__device__ float g_f2[Bb*Gg*Kk*256];
__device__ float g_gmax[Bb*Gg*256];
__device__ float g_cat[Bb*Gg*Kk*512];
__device__ float g_t1[Bb*Gg*Kk*512];
__device__ float g_t2[Bb*Gg*Kk*Dd];
__device__ float g_tokens[2][Bb*Gg*Dd];
__device__ float g_cpe[2][Bb*Gg*Dd];
__device__ float g_ppe[2][Bb*Np*Dd];
__device__ unsigned char g_mfull[2][Bb*Gg*Gg];
__device__ unsigned char g_mvis[2][Bb*Vv*Vv];
__device__ float g_vis3[Bb*Vv*3];
__device__ float g_visbuf[2][Bb*Vv*Dd];
__device__ float g_fullbuf[2][Bb*Gg*Dd];
__device__ float g_decx[2][Bb*(Mm+Vv)*Dd];
__device__ float g_mbuf[Bb*Gg*Dd];
__device__ float g_lnm[Bb*Gg*Dd];
__device__ float g_lnS[Bb*Gg*Dd];
__device__ float g_lnT[Bb*Gg*Dd];
__device__ float g_lnbig[Bb*Np*Dd];
__device__ float g_qbuf[Bb*Np*Dd];
__device__ float g_kbuf[Bb*Gg*Dd];
__device__ float g_vbuf[Bb*Gg*Dd];
__device__ float g_ctx[Bb*Np*Dd];
__device__ float g_hid[Bb*Np*FFf];
__device__ float g_upcat[Bb*Np*387];
__device__ int   g_nn3i[Bb*Np*3];
__device__ float g_nn3w[Bb*Np*3];
__device__ float g_lpart[2*64];

// ---- small/medium GEMM: 64x64 tile, 4x4 microtile (R1 proven) ----
__global__ void gemm64_kernel(const float* __restrict__ A, const float* __restrict__ W,
                              const float* __restrict__ bias, float* __restrict__ C,
                              int rows, int Kd, int Nc, int relu, int accum)
{
    __shared__ float As[16][64];
    __shared__ float Ws[16][64];
    int tid = threadIdx.x, tx = tid & 15, ty = tid >> 4;
    int row0 = blockIdx.y * 64, col0 = blockIdx.x * 64;
    float acc[4][4] = {};
    for (int k0 = 0; k0 < Kd; k0 += 16) {
        #pragma unroll
        for (int l = 0; l < 4; l++) {
            int idx = tid + l*256, m = idx >> 4, kk = idx & 15;
            As[kk][m] = (k0 + kk < Kd) ? A[(size_t)(row0+m)*Kd + k0 + kk] : 0.f;
        }
        #pragma unroll
        for (int l = 0; l < 4; l++) {
            int idx = tid + l*256, kk = idx >> 6, n = idx & 63;
            Ws[kk][n] = (k0 + kk < Kd) ? W[(size_t)(k0+kk)*Nc + col0 + n] : 0.f;
        }
        __syncthreads();
        #pragma unroll
        for (int kk = 0; kk < 16; kk++) {
            float a0=As[kk][ty*4],a1=As[kk][ty*4+1],a2=As[kk][ty*4+2],a3=As[kk][ty*4+3];
            float b0=Ws[kk][tx*4],b1=Ws[kk][tx*4+1],b2=Ws[kk][tx*4+2],b3=Ws[kk][tx*4+3];
            acc[0][0]+=a0*b0;acc[0][1]+=a0*b1;acc[0][2]+=a0*b2;acc[0][3]+=a0*b3;
            acc[1][0]+=a1*b0;acc[1][1]+=a1*b1;acc[1][2]+=a1*b2;acc[1][3]+=a1*b3;
            acc[2][0]+=a2*b0;acc[2][1]+=a2*b1;acc[2][2]+=a2*b2;acc[2][3]+=a2*b3;
            acc[3][0]+=a3*b0;acc[3][1]+=a3*b1;acc[3][2]+=a3*b2;acc[3][3]+=a3*b3;
        }
        __syncthreads();
    }
    #pragma unroll
    for (int i = 0; i < 4; i++) {
        int r = row0 + ty*4 + i;
        #pragma unroll
        for (int j = 0; j < 4; j++) {
            int c = col0 + tx*4 + j;
            float v = acc[i][j];
            if (bias) v += bias[c];
            if (relu) v = fmaxf(v, 0.f);
            size_t o = (size_t)r*Nc + c;
            if (accum) C[o] += v; else C[o] = v;
        }
    }
}

// ---- big GEMM: 128x128 tile, 8x8 microtile, coalesced loads, padded smem ----
__global__ __launch_bounds__(256)
void gemm128_kernel(const float* __restrict__ A, const float* __restrict__ W,
                    const float* __restrict__ bias, float* __restrict__ C,
                    int rows, int Kd, int Nc, int relu, int accum)
{
    __shared__ float As[8][132];
    __shared__ float Ws[8][132];
    int tid = threadIdx.x, tx = tid & 15, ty = tid >> 4;
    int row0 = blockIdx.y * 128, col0 = blockIdx.x * 128;
    float acc[8][8] = {};
    for (int k0 = 0; k0 < Kd; k0 += 8) {
        // A: 128 rows x 8 k, coalesced by k (8 consecutive floats per 8 threads)
        #pragma unroll
        for (int l = 0; l < 4; l++) {
            int i = tid + l*256;
            int kk = i & 7, m = i >> 3;
            As[kk][m] = (k0 + kk < Kd) ? A[(size_t)(row0+m)*Kd + k0 + kk] : 0.f;
        }
        // W: 8 k x 128 n, coalesced by n
        #pragma unroll
        for (int l = 0; l < 4; l++) {
            int i = tid + l*256;
            int n = i & 127, kk = i >> 7;
            Ws[kk][n] = (k0 + kk < Kd) ? W[(size_t)(k0+kk)*Nc + col0 + n] : 0.f;
        }
        __syncthreads();
        #pragma unroll
        for (int kk = 0; kk < 8; kk++) {
            float a[8], b[8];
            *(float4*)&a[0] = *(const float4*)&As[kk][ty*4];
            *(float4*)&a[4] = *(const float4*)&As[kk][ty*4 + 64];
            *(float4*)&b[0] = *(const float4*)&Ws[kk][tx*4];
            *(float4*)&b[4] = *(const float4*)&Ws[kk][tx*4 + 64];
            #pragma unroll
            for (int i = 0; i < 8; i++)
                #pragma unroll
                for (int j = 0; j < 8; j++)
                    acc[i][j] += a[i]*b[j];
        }
        __syncthreads();
    }
    #pragma unroll
    for (int i = 0; i < 8; i++) {
        int r = row0 + ((i < 4) ? (ty*4 + i) : (64 + ty*4 + i - 4));
        #pragma unroll
        for (int j = 0; j < 8; j++) {
            int c = col0 + ((j < 4) ? (tx*4 + j) : (64 + tx*4 + j - 4));
            float v = acc[i][j];
            if (bias) v += bias[c];
            if (relu) v = fmaxf(v, 0.f);
            size_t o = (size_t)r*Nc + c;
            if (accum) C[o] += v; else C[o] = v;
        }
    }
}

__global__ void ln_kernel(const float* __restrict__ x, float* __restrict__ y)
{
    int row = blockIdx.x, t = threadIdx.x;
    const float* xr = x + (size_t)row*Dd;
    __shared__ float red[128];
    float a = xr[t], b = xr[t+128], c = xr[t+256];
    red[t] = a + b + c; __syncthreads();
    for (int o = 64; o > 0; o >>= 1) { if (t < o) red[t] += red[t+o]; __syncthreads(); }
    float m = red[0] / (float)Dd; __syncthreads();
    float da=a-m, db=b-m, dc=c-m;
    red[t] = da*da + db*db + dc*dc; __syncthreads();
    for (int o = 64; o > 0; o >>= 1) { if (t < o) red[t] += red[t+o]; __syncthreads(); }
    float inv = rsqrtf(red[0] / (float)Dd + 1e-5f);
    float* yr = y + (size_t)row*Dd;
    yr[t]=da*inv; yr[t+128]=db*inv; yr[t+256]=dc*inv;
}

// small attention: one block per (q,h,b); Sk<=128
__global__ void attn_kernel(const float* __restrict__ q, const float* __restrict__ kmat,
                            const float* __restrict__ vmat, const unsigned char* __restrict__ mask,
                            float* __restrict__ ctx, int Sq, int Sk)
{
    int qi = blockIdx.x, h = blockIdx.y, b = blockIdx.z, t = threadIdx.x;
    __shared__ float shq[DHh], shp[128], red[128];
    const float* qr = q + ((size_t)(b*Sq + qi))*Dd + h*DHh;
    if (t < DHh) shq[t] = qr[t];
    __syncthreads();
    float val = -3e38f;
    if (t < Sk) {
        const float* kr = kmat + ((size_t)(b*Sk + t))*Dd + h*DHh;
        float s = 0.f;
        #pragma unroll
        for (int d = 0; d < DHh; d++) s += shq[d]*kr[d];
        s /= sqrtf((float)DHh);
        if (mask && !mask[((size_t)b*Sq + qi)*Sk + t]) s = -1e9f;
        val = s;
    }
    red[t] = val; __syncthreads();
    for (int o = 64; o > 0; o >>= 1) { if (t < o) red[t] = fmaxf(red[t], red[t+o]); __syncthreads(); }
    float mx = red[0]; __syncthreads();
    float e = (t < Sk) ? expf(val - mx) : 0.f;
    shp[t] = e; red[t] = e; __syncthreads();
    for (int o = 64; o > 0; o >>= 1) { if (t < o) red[t] += red[t+o]; __syncthreads(); }
    float inv = 1.f / red[0];
    if (t < DHh) {
        float acc = 0.f;
        const float* vb = vmat + ((size_t)(b*Sk))*Dd + h*DHh + t;
        for (int kk = 0; kk < Sk; kk++) acc += shp[kk]*vb[(size_t)kk*Dd];
        ctx[((size_t)(b*Sq + qi))*Dd + h*DHh + t] = acc*inv;
    }
}

// big attention: 16 queries per block, Sk==128, no mask. V + scores in smem, K row per thread.
#define QT 16
__global__ __launch_bounds__(128)
void attn_big_kernel(const float* __restrict__ q, const float* __restrict__ kmat,
                     const float* __restrict__ vmat, float* __restrict__ ctx, int Sq)
{
    int qt = blockIdx.x, h = blockIdx.y, b = blockIdx.z, t = threadIdx.x;
    __shared__ float shq[QT][DHh];
    __shared__ float sc[QT][129];
    __shared__ float Vs[128][DHh];
    for (int i = t; i < QT*DHh; i += 128) {
        int qi = i / DHh, d = i % DHh;
        shq[qi][d] = q[((size_t)(b*Sq + qt*QT + qi))*Dd + h*DHh + d];
    }
    for (int i = t; i < 128*DHh; i += 128) {
        int k = i / DHh, d = i % DHh;
        Vs[k][d] = vmat[((size_t)(b*128 + k))*Dd + h*DHh + d];
    }
    __syncthreads();
    float kr[DHh];
    {
        const float* kp = kmat + ((size_t)(b*128 + t))*Dd + h*DHh;
        #pragma unroll
        for (int d = 0; d < DHh; d++) kr[d] = kp[d];
    }
    float inv_s = sqrtf((float)DHh);
    #pragma unroll 1
    for (int qi = 0; qi < QT; qi++) {
        float s = 0.f;
        #pragma unroll
        for (int d = 0; d < DHh; d++) s += shq[qi][d]*kr[d];
        sc[qi][t] = s / inv_s;
    }
    __syncthreads();
    int w = t >> 5, lane = t & 31;
    for (int qi = w; qi < QT; qi += 4) {
        float v0 = sc[qi][lane], v1 = sc[qi][lane+32], v2 = sc[qi][lane+64], v3 = sc[qi][lane+96];
        float mx = fmaxf(fmaxf(v0,v1), fmaxf(v2,v3));
        #pragma unroll
        for (int o = 16; o > 0; o >>= 1) mx = fmaxf(mx, __shfl_xor_sync(0xffffffffu, mx, o));
        float e0=expf(v0-mx), e1=expf(v1-mx), e2=expf(v2-mx), e3=expf(v3-mx);
        float sum = e0+e1+e2+e3;
        #pragma unroll
        for (int o = 16; o > 0; o >>= 1) sum += __shfl_xor_sync(0xffffffffu, sum, o);
        float inv = 1.f / sum;
        sc[qi][lane]=e0*inv; sc[qi][lane+32]=e1*inv; sc[qi][lane+64]=e2*inv; sc[qi][lane+96]=e3*inv;
    }
    __syncthreads();
    for (int i = t; i < QT*DHh; i += 128) {
        int qi = i / DHh, d = i % DHh;
        float acc = 0.f;
        #pragma unroll 4
        for (int k = 0; k < 128; k++) acc += sc[qi][k] * Vs[k][d];
        ctx[((size_t)(b*Sq + qt*QT + qi))*Dd + h*DHh + d] = acc;
    }
}

__global__ void fps_kernel(const float* __restrict__ pos, float* __restrict__ centers)
{
    int b = blockIdx.x, t = threadIdx.x;
    __shared__ float mind[Np];
    __shared__ float rv[512]; __shared__ int ri[512]; __shared__ float curp[3];
    const float* P = pos + (size_t)b*Np*3;
    float* C = centers + (size_t)b*Gg*3;
    if (t == 0) { curp[0]=P[0]; curp[1]=P[1]; curp[2]=P[2]; C[0]=P[0]; C[1]=P[1]; C[2]=P[2]; }
    __syncthreads();
    for (int i = t; i < Np; i += 512) {
        float dx=P[3*i]-curp[0], dy=P[3*i+1]-curp[1], dz=P[3*i+2]-curp[2];
        mind[i] = dx*dx + dy*dy + dz*dz;
    }
    __syncthreads();
    for (int s = 1; s < Gg; s++) {
        float bv = -3e38f; int bi = 0x7fffffff;
        for (int i = t; i < Np; i += 512) { float v = mind[i]; if (v > bv) { bv = v; bi = i; } }
        rv[t] = bv; ri[t] = bi; __syncthreads();
        for (int o = 256; o > 0; o >>= 1) {
            if (t < o && (rv[t+o] > rv[t] || (rv[t+o] == rv[t] && ri[t+o] < ri[t]))) { rv[t]=rv[t+o]; ri[t]=ri[t+o]; }
            __syncthreads();
        }
        if (t == 0) {
            int nxt = ri[0];
            curp[0]=P[3*nxt]; curp[1]=P[3*nxt+1]; curp[2]=P[3*nxt+2];
            C[3*s]=curp[0]; C[3*s+1]=curp[1]; C[3*s+2]=curp[2];
        }
        __syncthreads();
        for (int i = t; i < Np; i += 512) {
            float dx=P[3*i]-curp[0], dy=P[3*i+1]-curp[1], dz=P[3*i+2]-curp[2];
            float d = dx*dx + dy*dy + dz*dz;
            if (d < mind[i]) mind[i] = d;
        }
        __syncthreads();
    }
}

__global__ void knn_big_kernel(const float* __restrict__ qpts, const float* __restrict__ rpts,
                               int* __restrict__ nidx)
{
    int blk = blockIdx.x, b = blk / Gg, qc = blk % Gg, t = threadIdx.x;
    __shared__ float dist[Np];
    __shared__ float rv[128]; __shared__ int ri[128];
    const float* Q = qpts + ((size_t)b*Gg + qc)*3;
    float qx=Q[0], qy=Q[1], qz=Q[2], qq = qx*qx+qy*qy+qz*qz;
    const float* R = rpts + (size_t)b*Np*3;
    for (int i = t; i < Np; i += 128) {
        float rx=R[3*i], ry=R[3*i+1], rz=R[3*i+2];
        dist[i] = qq + (rx*rx+ry*ry+rz*rz) - 2.f*(qx*rx+qy*ry+qz*rz);
    }
    __syncthreads();
    for (int kk = 0; kk < Kk; kk++) {
        float bv = 3e38f; int bi = 0x7fffffff;
        for (int i = t; i < Np; i += 128) { float v = dist[i]; if (v < bv) { bv = v; bi = i; } }
        rv[t] = bv; ri[t] = bi; __syncthreads();
        for (int o = 64; o > 0; o >>= 1) {
            if (t < o && (rv[t+o] < rv[t] || (rv[t+o] == rv[t] && ri[t+o] < ri[t]))) { rv[t]=rv[t+o]; ri[t]=ri[t+o]; }
            __syncthreads();
        }
        if (t == 0) { nidx[((size_t)b*Gg + qc)*Kk + kk] = ri[0]; dist[ri[0]] = 3e38f; }
        __syncthreads();
    }
}

__global__ void knn_small_kernel(const float* __restrict__ pts, int S, int* __restrict__ nidx)
{
    int blk = blockIdx.x, b = blk / S, qi = blk % S, t = threadIdx.x;
    __shared__ float dist[128]; __shared__ float rv[128]; __shared__ int ri[128];
    const float* Q = pts + ((size_t)b*S + qi)*3;
    float qx=Q[0], qy=Q[1], qz=Q[2], qq=qx*qx+qy*qy+qz*qz;
    if (t < S) {
        const float* R = pts + ((size_t)b*S + t)*3;
        dist[t] = qq + (R[0]*R[0]+R[1]*R[1]+R[2]*R[2]) - 2.f*(qx*R[0]+qy*R[1]+qz*R[2]);
    } else dist[t] = 3e38f;
    __syncthreads();
    for (int kk = 0; kk < Kk; kk++) {
        rv[t] = dist[t]; ri[t] = t; __syncthreads();
        for (int o = 64; o > 0; o >>= 1) {
            if (t < o && (rv[t+o] < rv[t] || (rv[t+o] == rv[t] && ri[t+o] < ri[t]))) { rv[t]=rv[t+o]; ri[t]=ri[t+o]; }
            __syncthreads();
        }
        if (t == 0) { nidx[((size_t)b*S + qi)*Kk + kk] = ri[0]; dist[ri[0]] = 3e38f; }
        __syncthreads();
    }
}

__global__ void zero_u8_kernel(unsigned char* m, int n)
{ int i = blockIdx.x*blockDim.x + threadIdx.x; if (i < n) m[i] = 0; }

__global__ void scatter_mask_kernel(const int* __restrict__ nidx, unsigned char* __restrict__ m, int S)
{
    int i = blockIdx.x*blockDim.x + threadIdx.x;
    if (i >= Bb*S*Kk) return;
    int b = i / (S*Kk), r = (i / Kk) % S;
    m[((size_t)b*S + r)*S + nidx[i]] = 1;
}

__global__ void group_rel_kernel(const float* __restrict__ pos, const float* __restrict__ centers,
                                 const int* __restrict__ nidx, float* __restrict__ rel)
{
    int i = blockIdx.x*blockDim.x + threadIdx.x;
    if (i >= Bb*Gg*Kk) return;
    int b = i / (Gg*Kk), g = (i / Kk) % Gg, src = nidx[i];
    const float* P = pos + ((size_t)b*Np + src)*3;
    const float* C = centers + ((size_t)b*Gg + g)*3;
    rel[3*i]=P[0]-C[0]; rel[3*i+1]=P[1]-C[1]; rel[3*i+2]=P[2]-C[2];
}

__global__ void gmax_kernel(const float* __restrict__ f, float* __restrict__ g, int C)
{
    int i = blockIdx.x*blockDim.x + threadIdx.x;
    if (i >= Bb*Gg*C) return;
    int bg = i / C, c = i % C;
    const float* fp = f + (size_t)bg*Kk*C + c;
    float m = fp[0];
    #pragma unroll
    for (int k = 1; k < Kk; k++) m = fmaxf(m, fp[(size_t)k*C]);
    g[i] = m;
}

__global__ void cat_kernel(const float* __restrict__ g, const float* __restrict__ f, float* __restrict__ cat)
{
    int i = blockIdx.x*blockDim.x + threadIdx.x;
    if (i >= Bb*Gg*Kk*512) return;
    int c = i % 512, r = i / 512, bg = r / Kk;
    cat[i] = (c < 256) ? g[(size_t)bg*256 + c] : f[(size_t)r*256 + (c - 256)];
}

__global__ void pe_kernel(const float* __restrict__ xyz, float* __restrict__ pe, int rows)
{
    int i = blockIdx.x*blockDim.x + threadIdx.x;
    if (i >= rows*Dd) return;
    int r = i / Dd, j = i % Dd, c = j / 128, jj = j % 128;
    float x = xyz[(size_t)r*3 + c];
    float dt = powf(10000.0f, (float)(2*(jj/2)) / 128.0f);
    float p = x / dt;
    pe[i] = (jj & 1) ? cosf(p) : sinf(p);
}

__global__ void gather_kernel(const float* __restrict__ src, const int* __restrict__ idx,
                              float* __restrict__ dst, int outR, int inR, int W)
{
    int row = blockIdx.x, b = row / outR, r = row % outR;
    int s = idx[(size_t)b*outR + r];
    const float* sp = src + ((size_t)b*inR + s)*W;
    float* dp = dst + (size_t)row*W;
    for (int w = threadIdx.x; w < W; w += blockDim.x) dp[w] = sp[w];
}

__global__ void decq_kernel(const float* __restrict__ visout, const float* __restrict__ cpe,
                            const float* __restrict__ mask_token, const int* __restrict__ mskidx,
                            const int* __restrict__ visidx, float* __restrict__ x)
{
    int i = blockIdx.x*blockDim.x + threadIdx.x;
    if (i >= Bb*(Mm+Vv)*Dd) return;
    int d = i % Dd, r = (i / Dd) % (Mm+Vv), b = i / (Dd*(Mm+Vv));
    float base; int pidx;
    if (r < Mm) { base = mask_token[d]; pidx = mskidx[(size_t)b*Mm + r]; }
    else { base = visout[((size_t)b*Vv + (r-Mm))*Dd + d]; pidx = visidx[(size_t)b*Vv + (r-Mm)]; }
    x[i] = base + cpe[((size_t)b*Gg + pidx)*Dd + d];
}

__global__ void add_kernel(const float* __restrict__ a, const float* __restrict__ b,
                           float* __restrict__ c, int n)
{ int i = blockIdx.x*blockDim.x + threadIdx.x; if (i < n) c[i] = a[i] + b[i]; }

__global__ void nn3_kernel(const float* __restrict__ pos, const float* __restrict__ centers,
                           int* __restrict__ oi, float* __restrict__ ow)
{
    int i = blockIdx.x*blockDim.x + threadIdx.x;
    if (i >= Bb*Np) return;
    int b = i / Np;
    const float* P = pos + (size_t)i*3;
    float px=P[0], py=P[1], pz=P[2], qq=px*px+py*py+pz*pz;
    float d0=3e38f, d1=3e38f, d2=3e38f; int i0=-1, i1=-1, i2=-1;
    const float* C = centers + (size_t)b*Gg*3;
    for (int g = 0; g < Gg; g++) {
        float cx=C[3*g], cy=C[3*g+1], cz=C[3*g+2];
        float d = qq + (cx*cx+cy*cy+cz*cz) - 2.f*(px*cx+py*cy+pz*cz);
        if (d < d0) { d2=d1;i2=i1; d1=d0;i1=i0; d0=d;i0=g; }
        else if (d < d1) { d2=d1;i2=i1; d1=d;i1=g; }
        else if (d < d2) { d2=d;i2=g; }
    }
    float w0=1.f/(fmaxf(d0,0.f)+1e-8f), w1=1.f/(fmaxf(d1,0.f)+1e-8f), w2=1.f/(fmaxf(d2,0.f)+1e-8f);
    float s = w0+w1+w2;
    ow[3*i]=w0/s; ow[3*i+1]=w1/s; ow[3*i+2]=w2/s;
    oi[3*i]=i0; oi[3*i+1]=i1; oi[3*i+2]=i2;
}

__global__ void upcat_kernel(const float* __restrict__ feats, const float* __restrict__ pos,
                             const int* __restrict__ oi, const float* __restrict__ ow,
                             float* __restrict__ cat)
{
    int row = blockIdx.x, b = row / Np, t = threadIdx.x;
    int i0=oi[3*row], i1=oi[3*row+1], i2=oi[3*row+2];
    float w0=ow[3*row], w1=ow[3*row+1], w2=ow[3*row+2];
    const float* F = feats + (size_t)b*Gg*Dd;
    float* cp = cat + (size_t)row*387;
    for (int d = t; d < Dd; d += 128)
        cp[d] = w0*F[(size_t)i0*Dd+d] + w1*F[(size_t)i1*Dd+d] + w2*F[(size_t)i2*Dd+d];
    if (t < 3) cp[Dd + t] = pos[(size_t)row*3 + t];
}

__global__ void loss_kernel(const float* __restrict__ fullout, const int* __restrict__ mskidx,
                            const float* __restrict__ decx, float* __restrict__ partial)
{
    __shared__ float red[256];
    int t = threadIdx.x;
    float acc = 0.f;
    for (int i = blockIdx.x*256 + t; i < Bb*Mm*Dd; i += 64*256) {
        int d = i % Dd, r = (i / Dd) % Mm, b = i / (Dd*Mm);
        int gi = mskidx[(size_t)b*Mm + r];
        float tv = fullout[((size_t)b*Gg + gi)*Dd + d];
        float pv = decx[((size_t)b*(Mm+Vv) + r)*Dd + d];
        float a = fabsf(pv - tv);
        acc += (a < 2.0f) ? 0.25f*a*a : a - 1.0f;
    }
    red[t] = acc; __syncthreads();
    for (int o = 128; o > 0; o >>= 1) { if (t < o) red[t] += red[t+o]; __syncthreads(); }
    if (t == 0) partial[blockIdx.x] = red[0];
}

__global__ void loss_final_kernel(const float* __restrict__ pa, const float* __restrict__ pb,
                                  float* __restrict__ out)
{
    float sa = 0.f, sb = 0.f;
    for (int i = 0; i < 64; i++) { sa += pa[i]; sb += pb[i]; }
    float cnt = (float)(Bb*Mm*Dd);
    out[0] = 0.5f*(sa/cnt) + 0.5f*(sb/cnt);
}

__global__ void copy_kernel(const float* __restrict__ a, float* __restrict__ b, int n)
{ int i = blockIdx.x*blockDim.x + threadIdx.x; if (i < n) b[i] = a[i]; }

static void gemm(const float* A, const float* W, const float* bias, float* C,
                 int rows, int Kd, int Nc, int relu, int accum)
{
    if (rows >= 16384) {
        dim3 grid(Nc/128, rows/128);
        gemm128_kernel<<<grid, 256>>>(A, W, bias, C, rows, Kd, Nc, relu, accum);
    } else {
        dim3 grid(Nc/64, rows/64);
        gemm64_kernel<<<grid, 256>>>(A, W, bias, C, rows, Kd, Nc, relu, accum);
    }
}

static void attn_block(const float* lnq, const float* lnkv, const float* w,
                       const unsigned char* mask, float* x, int Sq, int Sk,
                       float* qb, float* kb, float* vb, float* cb)
{
    gemm(lnq,  w,           nullptr, qb, Bb*Sq, Dd, Dd, 0, 0);
    gemm(lnkv, w + Dd*Dd,   nullptr, kb, Bb*Sk, Dd, Dd, 0, 0);
    gemm(lnkv, w + 2*Dd*Dd, nullptr, vb, Bb*Sk, Dd, Dd, 0, 0);
    if (Sq >= 1024 && mask == nullptr && Sk == 128) {
        dim3 g(Sq/QT, NHh, Bb);
        attn_big_kernel<<<g, 128>>>(qb, kb, vb, cb, Sq);
    } else {
        dim3 g(Sq, NHh, Bb);
        attn_kernel<<<g, 128>>>(qb, kb, vb, mask, cb, Sq, Sk);
    }
    gemm(cb, w + 3*Dd*Dd, nullptr, x, Bb*Sq, Dd, Dd, 0, 1);
}

static void encode_pair(float* Sb, float* Tb, const unsigned char* mS, const unsigned char* mT,
                        int S, const float* cxw, const float* ff1, const float* ff2,
                        float* lnS, float* lnT, float* qb, float* kb, float* vb, float* cb, float* hid)
{
    int rows = Bb*S;
    const float* sa = cxw;
    const float* ca = cxw + 4*Dd*Dd;
    ln_kernel<<<rows, 128>>>(Sb, lnS);
    attn_block(lnS, lnS, sa, mS, Sb, S, S, qb, kb, vb, cb);
    ln_kernel<<<rows, 128>>>(Tb, lnT);
    attn_block(lnT, lnT, sa, mT, Tb, S, S, qb, kb, vb, cb);
    ln_kernel<<<rows, 128>>>(Sb, lnS);
    ln_kernel<<<rows, 128>>>(Tb, lnT);
    attn_block(lnS, lnT, ca, nullptr, Sb, S, S, qb, kb, vb, cb);
    attn_block(lnT, lnS, ca, nullptr, Tb, S, S, qb, kb, vb, cb);
    ln_kernel<<<rows, 128>>>(Sb, lnS);
    gemm(lnS, ff1, nullptr, hid, rows, Dd, FFf, 1, 0);
    gemm(hid, ff2, nullptr, Sb, rows, FFf, Dd, 0, 1);
    ln_kernel<<<rows, 128>>>(Tb, lnT);
    gemm(lnT, ff1, nullptr, hid, rows, Dd, FFf, 1, 0);
    gemm(hid, ff2, nullptr, Tb, rows, FFf, Dd, 0, 1);
}

#define GETSYM(var, sym) do { void* _p; cudaGetSymbolAddress(&_p, sym); var = (decltype(var))_p; } while (0)

extern "C" void kernel_launch(void* const* d_in, const int* in_sizes, int n_in,
                              void* d_out_v, int out_size)
{
    (void)in_sizes; (void)n_in; (void)out_size;
    const float* pos[2]    = {(const float*)d_in[0], (const float*)d_in[1]};
    const int*   visidx[2] = {(const int*)d_in[2], (const int*)d_in[4]};
    const int*   mskidx[2] = {(const int*)d_in[3], (const int*)d_in[5]};
    const float* tok_w1 = (const float*)d_in[6];  const float* tok_b1 = (const float*)d_in[7];
    const float* tok_w2 = (const float*)d_in[8];  const float* tok_b2 = (const float*)d_in[9];
    const float* tok_w3 = (const float*)d_in[10]; const float* tok_b3 = (const float*)d_in[11];
    const float* tok_w4 = (const float*)d_in[12]; const float* tok_b4 = (const float*)d_in[13];
    const float* mask_token = (const float*)d_in[14];
    const float* cx_attn = (const float*)d_in[15];
    const float* cx_ff1  = (const float*)d_in[16]; const float* cx_ff2 = (const float*)d_in[17];
    const float* enc_sa  = (const float*)d_in[18]; const float* enc_ca = (const float*)d_in[19];
    const float* enc_ff1 = (const float*)d_in[20]; const float* enc_ff2 = (const float*)d_in[21];
    const float* dec_ca  = (const float*)d_in[22]; const float* dec_ff1 = (const float*)d_in[23];
    const float* dec_ff2 = (const float*)d_in[24];
    const float* up_w1 = (const float*)d_in[25]; const float* up_b1 = (const float*)d_in[26];
    const float* up_w2 = (const float*)d_in[27]; const float* up_b2 = (const float*)d_in[28];
    float* dout = (float*)d_out_v;

    float *centersB, *relB, *f1B, *f2B, *gmaxB, *catB, *t1B, *t2B, *tokensB;
    float *cpeB, *ppeB, *vis3B, *visB, *fullB, *decxB, *mbufB, *lnmB, *lnSB, *lnTB;
    float *lnbigB, *qB, *kB, *vB, *ctxB, *hidB, *upcatB, *nn3wB, *lpartB;
    int *nidxB, *nidxSB, *nn3iB;
    unsigned char *mfullB, *mvisB;
    GETSYM(centersB, g_centers); GETSYM(nidxB, g_nidx); GETSYM(nidxSB, g_nidxS);
    GETSYM(relB, g_rel); GETSYM(f1B, g_f1); GETSYM(f2B, g_f2); GETSYM(gmaxB, g_gmax);
    GETSYM(catB, g_cat); GETSYM(t1B, g_t1); GETSYM(t2B, g_t2); GETSYM(tokensB, g_tokens);
    GETSYM(cpeB, g_cpe); GETSYM(ppeB, g_ppe); GETSYM(mfullB, g_mfull); GETSYM(mvisB, g_mvis);
    GETSYM(vis3B, g_vis3); GETSYM(visB, g_visbuf); GETSYM(fullB, g_fullbuf); GETSYM(decxB, g_decx);
    GETSYM(mbufB, g_mbuf); GETSYM(lnmB, g_lnm); GETSYM(lnSB, g_lnS); GETSYM(lnTB, g_lnT);
    GETSYM(lnbigB, g_lnbig); GETSYM(qB, g_qbuf); GETSYM(kB, g_kbuf); GETSYM(vB, g_vbuf);
    GETSYM(ctxB, g_ctx); GETSYM(hidB, g_hid); GETSYM(upcatB, g_upcat);
    GETSYM(nn3iB, g_nn3i); GETSYM(nn3wB, g_nn3w); GETSYM(lpartB, g_lpart);

    float* centers[2] = {centersB, centersB + Bb*Gg*3};
    float* tokens[2]  = {tokensB,  tokensB  + Bb*Gg*Dd};
    float* cpe[2]     = {cpeB,     cpeB     + Bb*Gg*Dd};
    float* ppe[2]     = {ppeB,     ppeB     + Bb*Np*Dd};
    float* visb[2]    = {visB,     visB     + Bb*Vv*Dd};
    float* fullb[2]   = {fullB,    fullB    + Bb*Gg*Dd};
    float* decx[2]    = {decxB,    decxB    + Bb*(Mm+Vv)*Dd};
    unsigned char* mfull[2] = {mfullB, mfullB + Bb*Gg*Gg};
    unsigned char* mvis[2]  = {mvisB,  mvisB  + Bb*Vv*Vv};

    // Phase 1: tokenize + PE + masks
    for (int s = 0; s < 2; s++) {
        fps_kernel<<<Bb, 512>>>(pos[s], centers[s]);
        knn_big_kernel<<<Bb*Gg, 128>>>(centers[s], pos[s], nidxB);
        group_rel_kernel<<<(Bb*Gg*Kk + 255)/256, 256>>>(pos[s], centers[s], nidxB, relB);
        gemm(relB, tok_w1, tok_b1, f1B, Bb*Gg*Kk, 3, 128, 1, 0);
        gemm(f1B, tok_w2, tok_b2, f2B, Bb*Gg*Kk, 128, 256, 0, 0);
        gmax_kernel<<<(Bb*Gg*256 + 255)/256, 256>>>(f2B, gmaxB, 256);
        cat_kernel<<<(Bb*Gg*Kk*512 + 255)/256, 256>>>(gmaxB, f2B, catB);
        gemm(catB, tok_w3, tok_b3, t1B, Bb*Gg*Kk, 512, 512, 1, 0);
        gemm(t1B, tok_w4, tok_b4, t2B, Bb*Gg*Kk, 512, Dd, 0, 0);
        gmax_kernel<<<(Bb*Gg*Dd + 255)/256, 256>>>(t2B, tokens[s], Dd);
        pe_kernel<<<(Bb*Gg*Dd + 255)/256, 256>>>(centers[s], cpe[s], Bb*Gg);
        pe_kernel<<<(Bb*Np*Dd + 255)/256, 256>>>(pos[s], ppe[s], Bb*Np);
        knn_small_kernel<<<Bb*Gg, 128>>>(centers[s], Gg, nidxSB);
        zero_u8_kernel<<<(Bb*Gg*Gg + 255)/256, 256>>>(mfull[s], Bb*Gg*Gg);
        scatter_mask_kernel<<<(Bb*Gg*Kk + 255)/256, 256>>>(nidxSB, mfull[s], Gg);
        gather_kernel<<<Bb*Vv, 32>>>(centers[s], visidx[s], vis3B, Vv, Gg, 3);
        knn_small_kernel<<<Bb*Vv, 128>>>(vis3B, Vv, nidxSB);
        zero_u8_kernel<<<(Bb*Vv*Vv + 255)/256, 256>>>(mvis[s], Bb*Vv*Vv);
        scatter_mask_kernel<<<(Bb*Vv*Kk + 255)/256, 256>>>(nidxSB, mvis[s], Vv);
        gather_kernel<<<Bb*Vv, 128>>>(tokens[s], visidx[s], visb[s], Vv, Gg, Dd);
        copy_kernel<<<(Bb*Gg*Dd + 255)/256, 256>>>(tokens[s], fullb[s], Bb*Gg*Dd);
    }

    // Phase 2: cross encoders
    encode_pair(visb[0], visb[1], mvis[0], mvis[1], Vv, cx_attn, cx_ff1, cx_ff2,
                lnSB, lnTB, qB, kB, vB, ctxB, hidB);
    encode_pair(fullb[0], fullb[1], mfull[0], mfull[1], Gg, cx_attn, cx_ff1, cx_ff2,
                lnSB, lnTB, qB, kB, vB, ctxB, hidB);

    // Phase 3: MAE decoder + loss
    for (int s = 0; s < 2; s++) {
        int o = 1 - s;
        decq_kernel<<<(Bb*(Mm+Vv)*Dd + 255)/256, 256>>>(visb[s], cpe[s], mask_token,
                                                        mskidx[s], visidx[s], decx[s]);
        add_kernel<<<(Bb*Gg*Dd + 255)/256, 256>>>(fullb[o], cpe[o], mbufB, Bb*Gg*Dd);
        ln_kernel<<<Bb*Gg, 128>>>(mbufB, lnmB);
        for (int l = 0; l < 4; l++) {
            const float* sal = enc_sa + (size_t)l*4*Dd*Dd;
            const float* cal = enc_ca + (size_t)l*4*Dd*Dd;
            ln_kernel<<<Bb*(Mm+Vv), 128>>>(decx[s], lnSB);
            attn_block(lnSB, lnSB, sal, nullptr, decx[s], Mm+Vv, Mm+Vv, qB, kB, vB, ctxB);
            ln_kernel<<<Bb*(Mm+Vv), 128>>>(decx[s], lnSB);
            attn_block(lnSB, lnmB, cal, nullptr, decx[s], Mm+Vv, Gg, qB, kB, vB, ctxB);
            ln_kernel<<<Bb*(Mm+Vv), 128>>>(decx[s], lnSB);
            gemm(lnSB, enc_ff1 + (size_t)l*Dd*FFf, nullptr, hidB, Bb*(Mm+Vv), Dd, FFf, 1, 0);
            gemm(hidB, enc_ff2 + (size_t)l*FFf*Dd, nullptr, decx[s], Bb*(Mm+Vv), FFf, Dd, 0, 1);
        }
        loss_kernel<<<64, 256>>>(fullb[s], mskidx[s], decx[s], lpartB + s*64);
    }

    // Phase 4: upsample + dense decoder
    for (int s = 0; s < 2; s++) {
        float* X = dout + (size_t)s*Bb*Np*Dd;
        nn3_kernel<<<(Bb*Np + 255)/256, 256>>>(pos[s], centers[s], nn3iB, nn3wB);
        upcat_kernel<<<Bb*Np, 128>>>(fullb[s], pos[s], nn3iB, nn3wB, upcatB);
        gemm(upcatB, up_w1, up_b1, lnbigB, Bb*Np, 387, Dd, 1, 0);
        gemm(lnbigB, up_w2, up_b2, ctxB, Bb*Np, Dd, Dd, 1, 0);
        add_kernel<<<(Bb*Np*Dd + 255)/256, 256>>>(ctxB, ppe[s], X, Bb*Np*Dd);
        add_kernel<<<(Bb*Gg*Dd + 255)/256, 256>>>(fullb[s], cpe[s], mbufB, Bb*Gg*Dd);
        ln_kernel<<<Bb*Gg, 128>>>(mbufB, lnmB);
        for (int l = 0; l < 2; l++) {
            const float* cal = dec_ca + (size_t)l*4*Dd*Dd;
            ln_kernel<<<Bb*Np, 128>>>(X, lnbigB);
            attn_block(lnbigB, lnmB, cal, nullptr, X, Np, Gg, qB, kB, vB, ctxB);
            ln_kernel<<<Bb*Np, 128>>>(X, lnbigB);
            gemm(lnbigB, dec_ff1 + (size_t)l*Dd*FFf, nullptr, hidB, Bb*Np, Dd, FFf, 1, 0);
            gemm(hidB, dec_ff2 + (size_t)l*FFf*Dd, nullptr, X, Bb*Np, FFf, Dd, 0, 1);
        }
    }
    loss_final_kernel<<<1, 1>>>(lpartB, lpartB + 64, dout + (size_t)2*Bb*Np*Dd);
}

// round 6
// speedup vs baseline: 2.9142x; 1.1819x over previous
#include <cuda_runtime.h>
#include <math.h>
#include <stdint.h>

#define Bb 8
#define Np 4096
#define Gg 128
#define Kk 16
#define Vv 64
#define Mm 64
#define Dd 384
#define NHh 8
#define DHh 48
#define FFf 1536

__device__ float g_centers[2][Bb*Gg*3];
__device__ int   g_nidx[Bb*Gg*Kk];
__device__ int   g_nidxS[Bb*Gg*Kk];
__device__ float g_rel[Bb*Gg*Kk*3];
__device__ float g_f1[Bb*Gg*Kk*128];
__device__ float g_f2[Bb*Gg*Kk*256];
__device__ float g_gmax[Bb*Gg*256];
__device__ float g_cat[Bb*Gg*Kk*512];
__device__ float g_t1[Bb*Gg*Kk*512];
__device__ float g_t2[Bb*Gg*Kk*Dd];
__device__ float g_tokens[2][Bb*Gg*Dd];
__device__ float g_cpe[2][Bb*Gg*Dd];
__device__ float g_ppe[2][Bb*Np*Dd];
__device__ unsigned char g_mfull[2][Bb*Gg*Gg];
__device__ unsigned char g_mvis[2][Bb*Vv*Vv];
__device__ float g_vis3[Bb*Vv*3];
__device__ float g_visbuf[2][Bb*Vv*Dd];
__device__ float g_fullbuf[2][Bb*Gg*Dd];
__device__ float g_decx[2][Bb*(Mm+Vv)*Dd];
__device__ float g_mbuf[Bb*Gg*Dd];
__device__ float g_lnm[Bb*Gg*Dd];
__device__ float g_lnS[Bb*Gg*Dd];
__device__ float g_lnT[Bb*Gg*Dd];
__device__ float g_lnbig[Bb*Np*Dd];
__device__ float g_qbuf[Bb*Np*Dd];
__device__ float g_kbuf[Bb*Gg*Dd];
__device__ float g_vbuf[Bb*Gg*Dd];
__device__ float g_ctx[Bb*Np*Dd];
__device__ float g_hid[Bb*Np*FFf];
__device__ float g_upcat[Bb*Np*387];
__device__ int   g_nn3i[Bb*Np*3];
__device__ float g_nn3w[Bb*Np*3];
__device__ float g_lpart[2*64];

// ---- small/medium GEMM: 64x64 tile, 4x4 microtile ----
__global__ void gemm64_kernel(const float* __restrict__ A, const float* __restrict__ W,
                              const float* __restrict__ bias, float* __restrict__ C,
                              int rows, int Kd, int Nc, int relu, int accum)
{
    __shared__ float As[16][64];
    __shared__ float Ws[16][64];
    int tid = threadIdx.x, tx = tid & 15, ty = tid >> 4;
    int row0 = blockIdx.y * 64, col0 = blockIdx.x * 64;
    float acc[4][4] = {};
    for (int k0 = 0; k0 < Kd; k0 += 16) {
        #pragma unroll
        for (int l = 0; l < 4; l++) {
            int idx = tid + l*256, m = idx >> 4, kk = idx & 15;
            As[kk][m] = (k0 + kk < Kd) ? A[(size_t)(row0+m)*Kd + k0 + kk] : 0.f;
        }
        #pragma unroll
        for (int l = 0; l < 4; l++) {
            int idx = tid + l*256, kk = idx >> 6, n = idx & 63;
            Ws[kk][n] = (k0 + kk < Kd) ? W[(size_t)(k0+kk)*Nc + col0 + n] : 0.f;
        }
        __syncthreads();
        #pragma unroll
        for (int kk = 0; kk < 16; kk++) {
            float a0=As[kk][ty*4],a1=As[kk][ty*4+1],a2=As[kk][ty*4+2],a3=As[kk][ty*4+3];
            float b0=Ws[kk][tx*4],b1=Ws[kk][tx*4+1],b2=Ws[kk][tx*4+2],b3=Ws[kk][tx*4+3];
            acc[0][0]+=a0*b0;acc[0][1]+=a0*b1;acc[0][2]+=a0*b2;acc[0][3]+=a0*b3;
            acc[1][0]+=a1*b0;acc[1][1]+=a1*b1;acc[1][2]+=a1*b2;acc[1][3]+=a1*b3;
            acc[2][0]+=a2*b0;acc[2][1]+=a2*b1;acc[2][2]+=a2*b2;acc[2][3]+=a2*b3;
            acc[3][0]+=a3*b0;acc[3][1]+=a3*b1;acc[3][2]+=a3*b2;acc[3][3]+=a3*b3;
        }
        __syncthreads();
    }
    #pragma unroll
    for (int i = 0; i < 4; i++) {
        int r = row0 + ty*4 + i;
        #pragma unroll
        for (int j = 0; j < 4; j++) {
            int c = col0 + tx*4 + j;
            float v = acc[i][j];
            if (bias) v += bias[c];
            if (relu) v = fmaxf(v, 0.f);
            size_t o = (size_t)r*Nc + c;
            if (accum) C[o] += v; else C[o] = v;
        }
    }
}

// ---- big GEMM fp32 fallback (Kd not %8): 128x128 tile, 8x8 microtile ----
__global__ __launch_bounds__(256)
void gemm128_kernel(const float* __restrict__ A, const float* __restrict__ W,
                    const float* __restrict__ bias, float* __restrict__ C,
                    int rows, int Kd, int Nc, int relu, int accum)
{
    __shared__ float As[8][132];
    __shared__ float Ws[8][132];
    int tid = threadIdx.x, tx = tid & 15, ty = tid >> 4;
    int row0 = blockIdx.y * 128, col0 = blockIdx.x * 128;
    float acc[8][8] = {};
    for (int k0 = 0; k0 < Kd; k0 += 8) {
        #pragma unroll
        for (int l = 0; l < 4; l++) {
            int i = tid + l*256;
            int kk = i & 7, m = i >> 3;
            As[kk][m] = (k0 + kk < Kd) ? A[(size_t)(row0+m)*Kd + k0 + kk] : 0.f;
        }
        #pragma unroll
        for (int l = 0; l < 4; l++) {
            int i = tid + l*256;
            int n = i & 127, kk = i >> 7;
            Ws[kk][n] = (k0 + kk < Kd) ? W[(size_t)(k0+kk)*Nc + col0 + n] : 0.f;
        }
        __syncthreads();
        #pragma unroll
        for (int kk = 0; kk < 8; kk++) {
            float a[8], b[8];
            *(float4*)&a[0] = *(const float4*)&As[kk][ty*4];
            *(float4*)&a[4] = *(const float4*)&As[kk][ty*4 + 64];
            *(float4*)&b[0] = *(const float4*)&Ws[kk][tx*4];
            *(float4*)&b[4] = *(const float4*)&Ws[kk][tx*4 + 64];
            #pragma unroll
            for (int i = 0; i < 8; i++)
                #pragma unroll
                for (int j = 0; j < 8; j++)
                    acc[i][j] += a[i]*b[j];
        }
        __syncthreads();
    }
    #pragma unroll
    for (int i = 0; i < 8; i++) {
        int r = row0 + ((i < 4) ? (ty*4 + i) : (64 + ty*4 + i - 4));
        #pragma unroll
        for (int j = 0; j < 8; j++) {
            int c = col0 + ((j < 4) ? (tx*4 + j) : (64 + tx*4 + j - 4));
            float v = acc[i][j];
            if (bias) v += bias[c];
            if (relu) v = fmaxf(v, 0.f);
            size_t o = (size_t)r*Nc + c;
            if (accum) C[o] += v; else C[o] = v;
        }
    }
}

// ---- big GEMM tf32 tensor-core: 128x128 tile, mma.m16n8k8, fp32 accumulate ----
// Requires rows%128==0, Nc%128==0, Kd%8==0.
__global__ __launch_bounds__(256)
void gemm_tf32_kernel(const float* __restrict__ A, const float* __restrict__ W,
                      const float* __restrict__ bias, float* __restrict__ C,
                      int rows, int Kd, int Nc, int relu, int accum)
{
    __shared__ float As[8][132];
    __shared__ float Ws[8][132];
    int tid = threadIdx.x;
    int wid = tid >> 5, lane = tid & 31;
    int g = lane >> 2, tig = lane & 3;
    int wm = (wid >> 1) * 32;   // 4 warps along M
    int wn = (wid & 1) * 64;    // 2 warps along N
    int row0 = blockIdx.y * 128, col0 = blockIdx.x * 128;
    float c[2][8][4];
    #pragma unroll
    for (int mt = 0; mt < 2; mt++)
        #pragma unroll
        for (int nt = 0; nt < 8; nt++)
            #pragma unroll
            for (int r = 0; r < 4; r++) c[mt][nt][r] = 0.f;

    for (int k0 = 0; k0 < Kd; k0 += 8) {
        #pragma unroll
        for (int l = 0; l < 4; l++) {
            int i = tid + l*256;
            int kk = i & 7, m = i >> 3;
            float av = A[(size_t)(row0+m)*Kd + k0 + kk];
            uint32_t ab; asm("cvt.rna.tf32.f32 %0, %1;" : "=r"(ab) : "f"(av));
            As[kk][m] = __uint_as_float(ab);
        }
        #pragma unroll
        for (int l = 0; l < 4; l++) {
            int i = tid + l*256;
            int n = i & 127, kk = i >> 7;
            float wv = W[(size_t)(k0+kk)*Nc + col0 + n];
            uint32_t wb; asm("cvt.rna.tf32.f32 %0, %1;" : "=r"(wb) : "f"(wv));
            Ws[kk][n] = __uint_as_float(wb);
        }
        __syncthreads();
        uint32_t a[2][4], b[8][2];
        #pragma unroll
        for (int mt = 0; mt < 2; mt++) {
            int m0 = wm + mt*16;
            a[mt][0] = __float_as_uint(As[tig    ][m0 + g    ]);
            a[mt][1] = __float_as_uint(As[tig    ][m0 + g + 8]);
            a[mt][2] = __float_as_uint(As[tig + 4][m0 + g    ]);
            a[mt][3] = __float_as_uint(As[tig + 4][m0 + g + 8]);
        }
        #pragma unroll
        for (int nt = 0; nt < 8; nt++) {
            int n0 = wn + nt*8;
            b[nt][0] = __float_as_uint(Ws[tig    ][n0 + g]);
            b[nt][1] = __float_as_uint(Ws[tig + 4][n0 + g]);
        }
        #pragma unroll
        for (int mt = 0; mt < 2; mt++)
            #pragma unroll
            for (int nt = 0; nt < 8; nt++)
                asm volatile(
                    "mma.sync.aligned.m16n8k8.row.col.f32.tf32.tf32.f32 "
                    "{%0,%1,%2,%3}, {%4,%5,%6,%7}, {%8,%9}, {%0,%1,%2,%3};"
                    : "+f"(c[mt][nt][0]), "+f"(c[mt][nt][1]),
                      "+f"(c[mt][nt][2]), "+f"(c[mt][nt][3])
                    : "r"(a[mt][0]), "r"(a[mt][1]), "r"(a[mt][2]), "r"(a[mt][3]),
                      "r"(b[nt][0]), "r"(b[nt][1]));
        __syncthreads();
    }
    #pragma unroll
    for (int mt = 0; mt < 2; mt++) {
        #pragma unroll
        for (int nt = 0; nt < 8; nt++) {
            int r0 = row0 + wm + mt*16 + g;
            int cc = col0 + wn + nt*8 + 2*tig;
            float v0 = c[mt][nt][0], v1 = c[mt][nt][1];
            float v2 = c[mt][nt][2], v3 = c[mt][nt][3];
            if (bias) { float b0 = bias[cc], b1 = bias[cc+1]; v0 += b0; v1 += b1; v2 += b0; v3 += b1; }
            if (relu) { v0 = fmaxf(v0,0.f); v1 = fmaxf(v1,0.f); v2 = fmaxf(v2,0.f); v3 = fmaxf(v3,0.f); }
            size_t o0 = (size_t)r0*Nc + cc;
            size_t o1 = (size_t)(r0+8)*Nc + cc;
            if (accum) { C[o0] += v0; C[o0+1] += v1; C[o1] += v2; C[o1+1] += v3; }
            else       { C[o0]  = v0; C[o0+1]  = v1; C[o1]  = v2; C[o1+1]  = v3; }
        }
    }
}

__global__ void ln_kernel(const float* __restrict__ x, float* __restrict__ y)
{
    int row = blockIdx.x, t = threadIdx.x;
    const float* xr = x + (size_t)row*Dd;
    __shared__ float red[128];
    float a = xr[t], b = xr[t+128], c = xr[t+256];
    red[t] = a + b + c; __syncthreads();
    for (int o = 64; o > 0; o >>= 1) { if (t < o) red[t] += red[t+o]; __syncthreads(); }
    float m = red[0] / (float)Dd; __syncthreads();
    float da=a-m, db=b-m, dc=c-m;
    red[t] = da*da + db*db + dc*dc; __syncthreads();
    for (int o = 64; o > 0; o >>= 1) { if (t < o) red[t] += red[t+o]; __syncthreads(); }
    float inv = rsqrtf(red[0] / (float)Dd + 1e-5f);
    float* yr = y + (size_t)row*Dd;
    yr[t]=da*inv; yr[t+128]=db*inv; yr[t+256]=dc*inv;
}

// small attention: one block per (q,h,b); Sk<=128
__global__ void attn_kernel(const float* __restrict__ q, const float* __restrict__ kmat,
                            const float* __restrict__ vmat, const unsigned char* __restrict__ mask,
                            float* __restrict__ ctx, int Sq, int Sk)
{
    int qi = blockIdx.x, h = blockIdx.y, b = blockIdx.z, t = threadIdx.x;
    __shared__ float shq[DHh], shp[128], red[128];
    const float* qr = q + ((size_t)(b*Sq + qi))*Dd + h*DHh;
    if (t < DHh) shq[t] = qr[t];
    __syncthreads();
    float val = -3e38f;
    if (t < Sk) {
        const float* kr = kmat + ((size_t)(b*Sk + t))*Dd + h*DHh;
        float s = 0.f;
        #pragma unroll
        for (int d = 0; d < DHh; d++) s += shq[d]*kr[d];
        s /= sqrtf((float)DHh);
        if (mask && !mask[((size_t)b*Sq + qi)*Sk + t]) s = -1e9f;
        val = s;
    }
    red[t] = val; __syncthreads();
    for (int o = 64; o > 0; o >>= 1) { if (t < o) red[t] = fmaxf(red[t], red[t+o]); __syncthreads(); }
    float mx = red[0]; __syncthreads();
    float e = (t < Sk) ? expf(val - mx) : 0.f;
    shp[t] = e; red[t] = e; __syncthreads();
    for (int o = 64; o > 0; o >>= 1) { if (t < o) red[t] += red[t+o]; __syncthreads(); }
    float inv = 1.f / red[0];
    if (t < DHh) {
        float acc = 0.f;
        const float* vb = vmat + ((size_t)(b*Sk))*Dd + h*DHh + t;
        for (int kk = 0; kk < Sk; kk++) acc += shp[kk]*vb[(size_t)kk*Dd];
        ctx[((size_t)(b*Sq + qi))*Dd + h*DHh + t] = acc*inv;
    }
}

// big attention: 16 queries per block, Sk==128, no mask
#define QT 16
__global__ __launch_bounds__(128)
void attn_big_kernel(const float* __restrict__ q, const float* __restrict__ kmat,
                     const float* __restrict__ vmat, float* __restrict__ ctx, int Sq)
{
    int qt = blockIdx.x, h = blockIdx.y, b = blockIdx.z, t = threadIdx.x;
    __shared__ float shq[QT][DHh];
    __shared__ float sc[QT][129];
    __shared__ float Vs[128][DHh];
    for (int i = t; i < QT*DHh; i += 128) {
        int qi = i / DHh, d = i % DHh;
        shq[qi][d] = q[((size_t)(b*Sq + qt*QT + qi))*Dd + h*DHh + d];
    }
    for (int i = t; i < 128*DHh; i += 128) {
        int k = i / DHh, d = i % DHh;
        Vs[k][d] = vmat[((size_t)(b*128 + k))*Dd + h*DHh + d];
    }
    __syncthreads();
    float kr[DHh];
    {
        const float* kp = kmat + ((size_t)(b*128 + t))*Dd + h*DHh;
        #pragma unroll
        for (int d = 0; d < DHh; d++) kr[d] = kp[d];
    }
    float inv_s = sqrtf((float)DHh);
    #pragma unroll 1
    for (int qi = 0; qi < QT; qi++) {
        float s = 0.f;
        #pragma unroll
        for (int d = 0; d < DHh; d++) s += shq[qi][d]*kr[d];
        sc[qi][t] = s / inv_s;
    }
    __syncthreads();
    int w = t >> 5, lane = t & 31;
    for (int qi = w; qi < QT; qi += 4) {
        float v0 = sc[qi][lane], v1 = sc[qi][lane+32], v2 = sc[qi][lane+64], v3 = sc[qi][lane+96];
        float mx = fmaxf(fmaxf(v0,v1), fmaxf(v2,v3));
        #pragma unroll
        for (int o = 16; o > 0; o >>= 1) mx = fmaxf(mx, __shfl_xor_sync(0xffffffffu, mx, o));
        float e0=expf(v0-mx), e1=expf(v1-mx), e2=expf(v2-mx), e3=expf(v3-mx);
        float sum = e0+e1+e2+e3;
        #pragma unroll
        for (int o = 16; o > 0; o >>= 1) sum += __shfl_xor_sync(0xffffffffu, sum, o);
        float inv = 1.f / sum;
        sc[qi][lane]=e0*inv; sc[qi][lane+32]=e1*inv; sc[qi][lane+64]=e2*inv; sc[qi][lane+96]=e3*inv;
    }
    __syncthreads();
    for (int i = t; i < QT*DHh; i += 128) {
        int qi = i / DHh, d = i % DHh;
        float acc = 0.f;
        #pragma unroll 4
        for (int k = 0; k < 128; k++) acc += sc[qi][k] * Vs[k][d];
        ctx[((size_t)(b*Sq + qt*QT + qi))*Dd + h*DHh + d] = acc;
    }
}

__global__ void fps_kernel(const float* __restrict__ pos, float* __restrict__ centers)
{
    int b = blockIdx.x, t = threadIdx.x;
    __shared__ float mind[Np];
    __shared__ float rv[512]; __shared__ int ri[512]; __shared__ float curp[3];
    const float* P = pos + (size_t)b*Np*3;
    float* C = centers + (size_t)b*Gg*3;
    if (t == 0) { curp[0]=P[0]; curp[1]=P[1]; curp[2]=P[2]; C[0]=P[0]; C[1]=P[1]; C[2]=P[2]; }
    __syncthreads();
    for (int i = t; i < Np; i += 512) {
        float dx=P[3*i]-curp[0], dy=P[3*i+1]-curp[1], dz=P[3*i+2]-curp[2];
        mind[i] = dx*dx + dy*dy + dz*dz;
    }
    __syncthreads();
    for (int s = 1; s < Gg; s++) {
        float bv = -3e38f; int bi = 0x7fffffff;
        for (int i = t; i < Np; i += 512) { float v = mind[i]; if (v > bv) { bv = v; bi = i; } }
        rv[t] = bv; ri[t] = bi; __syncthreads();
        for (int o = 256; o > 0; o >>= 1) {
            if (t < o && (rv[t+o] > rv[t] || (rv[t+o] == rv[t] && ri[t+o] < ri[t]))) { rv[t]=rv[t+o]; ri[t]=ri[t+o]; }
            __syncthreads();
        }
        if (t == 0) {
            int nxt = ri[0];
            curp[0]=P[3*nxt]; curp[1]=P[3*nxt+1]; curp[2]=P[3*nxt+2];
            C[3*s]=curp[0]; C[3*s+1]=curp[1]; C[3*s+2]=curp[2];
        }
        __syncthreads();
        for (int i = t; i < Np; i += 512) {
            float dx=P[3*i]-curp[0], dy=P[3*i+1]-curp[1], dz=P[3*i+2]-curp[2];
            float d = dx*dx + dy*dy + dz*dz;
            if (d < mind[i]) mind[i] = d;
        }
        __syncthreads();
    }
}

__global__ void knn_big_kernel(const float* __restrict__ qpts, const float* __restrict__ rpts,
                               int* __restrict__ nidx)
{
    int blk = blockIdx.x, b = blk / Gg, qc = blk % Gg, t = threadIdx.x;
    __shared__ float dist[Np];
    __shared__ float rv[128]; __shared__ int ri[128];
    const float* Q = qpts + ((size_t)b*Gg + qc)*3;
    float qx=Q[0], qy=Q[1], qz=Q[2], qq = qx*qx+qy*qy+qz*qz;
    const float* R = rpts + (size_t)b*Np*3;
    for (int i = t; i < Np; i += 128) {
        float rx=R[3*i], ry=R[3*i+1], rz=R[3*i+2];
        dist[i] = qq + (rx*rx+ry*ry+rz*rz) - 2.f*(qx*rx+qy*ry+qz*rz);
    }
    __syncthreads();
    for (int kk = 0; kk < Kk; kk++) {
        float bv = 3e38f; int bi = 0x7fffffff;
        for (int i = t; i < Np; i += 128) { float v = dist[i]; if (v < bv) { bv = v; bi = i; } }
        rv[t] = bv; ri[t] = bi; __syncthreads();
        for (int o = 64; o > 0; o >>= 1) {
            if (t < o && (rv[t+o] < rv[t] || (rv[t+o] == rv[t] && ri[t+o] < ri[t]))) { rv[t]=rv[t+o]; ri[t]=ri[t+o]; }
            __syncthreads();
        }
        if (t == 0) { nidx[((size_t)b*Gg + qc)*Kk + kk] = ri[0]; dist[ri[0]] = 3e38f; }
        __syncthreads();
    }
}

__global__ void knn_small_kernel(const float* __restrict__ pts, int S, int* __restrict__ nidx)
{
    int blk = blockIdx.x, b = blk / S, qi = blk % S, t = threadIdx.x;
    __shared__ float dist[128]; __shared__ float rv[128]; __shared__ int ri[128];
    const float* Q = pts + ((size_t)b*S + qi)*3;
    float qx=Q[0], qy=Q[1], qz=Q[2], qq=qx*qx+qy*qy+qz*qz;
    if (t < S) {
        const float* R = pts + ((size_t)b*S + t)*3;
        dist[t] = qq + (R[0]*R[0]+R[1]*R[1]+R[2]*R[2]) - 2.f*(qx*R[0]+qy*R[1]+qz*R[2]);
    } else dist[t] = 3e38f;
    __syncthreads();
    for (int kk = 0; kk < Kk; kk++) {
        rv[t] = dist[t]; ri[t] = t; __syncthreads();
        for (int o = 64; o > 0; o >>= 1) {
            if (t < o && (rv[t+o] < rv[t] || (rv[t+o] == rv[t] && ri[t+o] < ri[t]))) { rv[t]=rv[t+o]; ri[t]=ri[t+o]; }
            __syncthreads();
        }
        if (t == 0) { nidx[((size_t)b*S + qi)*Kk + kk] = ri[0]; dist[ri[0]] = 3e38f; }
        __syncthreads();
    }
}

__global__ void zero_u8_kernel(unsigned char* m, int n)
{ int i = blockIdx.x*blockDim.x + threadIdx.x; if (i < n) m[i] = 0; }

__global__ void scatter_mask_kernel(const int* __restrict__ nidx, unsigned char* __restrict__ m, int S)
{
    int i = blockIdx.x*blockDim.x + threadIdx.x;
    if (i >= Bb*S*Kk) return;
    int b = i / (S*Kk), r = (i / Kk) % S;
    m[((size_t)b*S + r)*S + nidx[i]] = 1;
}

__global__ void group_rel_kernel(const float* __restrict__ pos, const float* __restrict__ centers,
                                 const int* __restrict__ nidx, float* __restrict__ rel)
{
    int i = blockIdx.x*blockDim.x + threadIdx.x;
    if (i >= Bb*Gg*Kk) return;
    int b = i / (Gg*Kk), g = (i / Kk) % Gg, src = nidx[i];
    const float* P = pos + ((size_t)b*Np + src)*3;
    const float* C = centers + ((size_t)b*Gg + g)*3;
    rel[3*i]=P[0]-C[0]; rel[3*i+1]=P[1]-C[1]; rel[3*i+2]=P[2]-C[2];
}

__global__ void gmax_kernel(const float* __restrict__ f, float* __restrict__ g, int C)
{
    int i = blockIdx.x*blockDim.x + threadIdx.x;
    if (i >= Bb*Gg*C) return;
    int bg = i / C, c = i % C;
    const float* fp = f + (size_t)bg*Kk*C + c;
    float m = fp[0];
    #pragma unroll
    for (int k = 1; k < Kk; k++) m = fmaxf(m, fp[(size_t)k*C]);
    g[i] = m;
}

__global__ void cat_kernel(const float* __restrict__ g, const float* __restrict__ f, float* __restrict__ cat)
{
    int i = blockIdx.x*blockDim.x + threadIdx.x;
    if (i >= Bb*Gg*Kk*512) return;
    int c = i % 512, r = i / 512, bg = r / Kk;
    cat[i] = (c < 256) ? g[(size_t)bg*256 + c] : f[(size_t)r*256 + (c - 256)];
}

__global__ void pe_kernel(const float* __restrict__ xyz, float* __restrict__ pe, int rows)
{
    int i = blockIdx.x*blockDim.x + threadIdx.x;
    if (i >= rows*Dd) return;
    int r = i / Dd, j = i % Dd, c = j / 128, jj = j % 128;
    float x = xyz[(size_t)r*3 + c];
    float dt = powf(10000.0f, (float)(2*(jj/2)) / 128.0f);
    float p = x / dt;
    pe[i] = (jj & 1) ? cosf(p) : sinf(p);
}

__global__ void gather_kernel(const float* __restrict__ src, const int* __restrict__ idx,
                              float* __restrict__ dst, int outR, int inR, int W)
{
    int row = blockIdx.x, b = row / outR, r = row % outR;
    int s = idx[(size_t)b*outR + r];
    const float* sp = src + ((size_t)b*inR + s)*W;
    float* dp = dst + (size_t)row*W;
    for (int w = threadIdx.x; w < W; w += blockDim.x) dp[w] = sp[w];
}

__global__ void decq_kernel(const float* __restrict__ visout, const float* __restrict__ cpe,
                            const float* __restrict__ mask_token, const int* __restrict__ mskidx,
                            const int* __restrict__ visidx, float* __restrict__ x)
{
    int i = blockIdx.x*blockDim.x + threadIdx.x;
    if (i >= Bb*(Mm+Vv)*Dd) return;
    int d = i % Dd, r = (i / Dd) % (Mm+Vv), b = i / (Dd*(Mm+Vv));
    float base; int pidx;
    if (r < Mm) { base = mask_token[d]; pidx = mskidx[(size_t)b*Mm + r]; }
    else { base = visout[((size_t)b*Vv + (r-Mm))*Dd + d]; pidx = visidx[(size_t)b*Vv + (r-Mm)]; }
    x[i] = base + cpe[((size_t)b*Gg + pidx)*Dd + d];
}

__global__ void add_kernel(const float* __restrict__ a, const float* __restrict__ b,
                           float* __restrict__ c, int n)
{ int i = blockIdx.x*blockDim.x + threadIdx.x; if (i < n) c[i] = a[i] + b[i]; }

__global__ void nn3_kernel(const float* __restrict__ pos, const float* __restrict__ centers,
                           int* __restrict__ oi, float* __restrict__ ow)
{
    int i = blockIdx.x*blockDim.x + threadIdx.x;
    if (i >= Bb*Np) return;
    int b = i / Np;
    const float* P = pos + (size_t)i*3;
    float px=P[0], py=P[1], pz=P[2], qq=px*px+py*py+pz*pz;
    float d0=3e38f, d1=3e38f, d2=3e38f; int i0=-1, i1=-1, i2=-1;
    const float* C = centers + (size_t)b*Gg*3;
    for (int g = 0; g < Gg; g++) {
        float cx=C[3*g], cy=C[3*g+1], cz=C[3*g+2];
        float d = qq + (cx*cx+cy*cy+cz*cz) - 2.f*(px*cx+py*cy+pz*cz);
        if (d < d0) { d2=d1;i2=i1; d1=d0;i1=i0; d0=d;i0=g; }
        else if (d < d1) { d2=d1;i2=i1; d1=d;i1=g; }
        else if (d < d2) { d2=d;i2=g; }
    }
    float w0=1.f/(fmaxf(d0,0.f)+1e-8f), w1=1.f/(fmaxf(d1,0.f)+1e-8f), w2=1.f/(fmaxf(d2,0.f)+1e-8f);
    float s = w0+w1+w2;
    ow[3*i]=w0/s; ow[3*i+1]=w1/s; ow[3*i+2]=w2/s;
    oi[3*i]=i0; oi[3*i+1]=i1; oi[3*i+2]=i2;
}

__global__ void upcat_kernel(const float* __restrict__ feats, const float* __restrict__ pos,
                             const int* __restrict__ oi, const float* __restrict__ ow,
                             float* __restrict__ cat)
{
    int row = blockIdx.x, b = row / Np, t = threadIdx.x;
    int i0=oi[3*row], i1=oi[3*row+1], i2=oi[3*row+2];
    float w0=ow[3*row], w1=ow[3*row+1], w2=ow[3*row+2];
    const float* F = feats + (size_t)b*Gg*Dd;
    float* cp = cat + (size_t)row*387;
    for (int d = t; d < Dd; d += 128)
        cp[d] = w0*F[(size_t)i0*Dd+d] + w1*F[(size_t)i1*Dd+d] + w2*F[(size_t)i2*Dd+d];
    if (t < 3) cp[Dd + t] = pos[(size_t)row*3 + t];
}

__global__ void loss_kernel(const float* __restrict__ fullout, const int* __restrict__ mskidx,
                            const float* __restrict__ decx, float* __restrict__ partial)
{
    __shared__ float red[256];
    int t = threadIdx.x;
    float acc = 0.f;
    for (int i = blockIdx.x*256 + t; i < Bb*Mm*Dd; i += 64*256) {
        int d = i % Dd, r = (i / Dd) % Mm, b = i / (Dd*Mm);
        int gi = mskidx[(size_t)b*Mm + r];
        float tv = fullout[((size_t)b*Gg + gi)*Dd + d];
        float pv = decx[((size_t)b*(Mm+Vv) + r)*Dd + d];
        float a = fabsf(pv - tv);
        acc += (a < 2.0f) ? 0.25f*a*a : a - 1.0f;
    }
    red[t] = acc; __syncthreads();
    for (int o = 128; o > 0; o >>= 1) { if (t < o) red[t] += red[t+o]; __syncthreads(); }
    if (t == 0) partial[blockIdx.x] = red[0];
}

__global__ void loss_final_kernel(const float* __restrict__ pa, const float* __restrict__ pb,
                                  float* __restrict__ out)
{
    float sa = 0.f, sb = 0.f;
    for (int i = 0; i < 64; i++) { sa += pa[i]; sb += pb[i]; }
    float cnt = (float)(Bb*Mm*Dd);
    out[0] = 0.5f*(sa/cnt) + 0.5f*(sb/cnt);
}

__global__ void copy_kernel(const float* __restrict__ a, float* __restrict__ b, int n)
{ int i = blockIdx.x*blockDim.x + threadIdx.x; if (i < n) b[i] = a[i]; }

static void gemm(const float* A, const float* W, const float* bias, float* C,
                 int rows, int Kd, int Nc, int relu, int accum)
{
    if (rows >= 16384 && (Kd % 8) == 0 && (Nc % 128) == 0) {
        dim3 grid(Nc/128, rows/128);
        gemm_tf32_kernel<<<grid, 256>>>(A, W, bias, C, rows, Kd, Nc, relu, accum);
    } else if (rows >= 16384 && (Nc % 128) == 0) {
        dim3 grid(Nc/128, rows/128);
        gemm128_kernel<<<grid, 256>>>(A, W, bias, C, rows, Kd, Nc, relu, accum);
    } else {
        dim3 grid(Nc/64, rows/64);
        gemm64_kernel<<<grid, 256>>>(A, W, bias, C, rows, Kd, Nc, relu, accum);
    }
}

static void attn_block(const float* lnq, const float* lnkv, const float* w,
                       const unsigned char* mask, float* x, int Sq, int Sk,
                       float* qb, float* kb, float* vb, float* cb)
{
    gemm(lnq,  w,           nullptr, qb, Bb*Sq, Dd, Dd, 0, 0);
    gemm(lnkv, w + Dd*Dd,   nullptr, kb, Bb*Sk, Dd, Dd, 0, 0);
    gemm(lnkv, w + 2*Dd*Dd, nullptr, vb, Bb*Sk, Dd, Dd, 0, 0);
    if (Sq >= 1024 && mask == nullptr && Sk == 128) {
        dim3 g(Sq/QT, NHh, Bb);
        attn_big_kernel<<<g, 128>>>(qb, kb, vb, cb, Sq);
    } else {
        dim3 g(Sq, NHh, Bb);
        attn_kernel<<<g, 128>>>(qb, kb, vb, mask, cb, Sq, Sk);
    }
    gemm(cb, w + 3*Dd*Dd, nullptr, x, Bb*Sq, Dd, Dd, 0, 1);
}

static void encode_pair(float* Sb, float* Tb, const unsigned char* mS, const unsigned char* mT,
                        int S, const float* cxw, const float* ff1, const float* ff2,
                        float* lnS, float* lnT, float* qb, float* kb, float* vb, float* cb, float* hid)
{
    int rows = Bb*S;
    const float* sa = cxw;
    const float* ca = cxw + 4*Dd*Dd;
    ln_kernel<<<rows, 128>>>(Sb, lnS);
    attn_block(lnS, lnS, sa, mS, Sb, S, S, qb, kb, vb, cb);
    ln_kernel<<<rows, 128>>>(Tb, lnT);
    attn_block(lnT, lnT, sa, mT, Tb, S, S, qb, kb, vb, cb);
    ln_kernel<<<rows, 128>>>(Sb, lnS);
    ln_kernel<<<rows, 128>>>(Tb, lnT);
    attn_block(lnS, lnT, ca, nullptr, Sb, S, S, qb, kb, vb, cb);
    attn_block(lnT, lnS, ca, nullptr, Tb, S, S, qb, kb, vb, cb);
    ln_kernel<<<rows, 128>>>(Sb, lnS);
    gemm(lnS, ff1, nullptr, hid, rows, Dd, FFf, 1, 0);
    gemm(hid, ff2, nullptr, Sb, rows, FFf, Dd, 0, 1);
    ln_kernel<<<rows, 128>>>(Tb, lnT);
    gemm(lnT, ff1, nullptr, hid, rows, Dd, FFf, 1, 0);
    gemm(hid, ff2, nullptr, Tb, rows, FFf, Dd, 0, 1);
}

#define GETSYM(var, sym) do { void* _p; cudaGetSymbolAddress(&_p, sym); var = (decltype(var))_p; } while (0)

extern "C" void kernel_launch(void* const* d_in, const int* in_sizes, int n_in,
                              void* d_out_v, int out_size)
{
    (void)in_sizes; (void)n_in; (void)out_size;
    const float* pos[2]    = {(const float*)d_in[0], (const float*)d_in[1]};
    const int*   visidx[2] = {(const int*)d_in[2], (const int*)d_in[4]};
    const int*   mskidx[2] = {(const int*)d_in[3], (const int*)d_in[5]};
    const float* tok_w1 = (const float*)d_in[6];  const float* tok_b1 = (const float*)d_in[7];
    const float* tok_w2 = (const float*)d_in[8];  const float* tok_b2 = (const float*)d_in[9];
    const float* tok_w3 = (const float*)d_in[10]; const float* tok_b3 = (const float*)d_in[11];
    const float* tok_w4 = (const float*)d_in[12]; const float* tok_b4 = (const float*)d_in[13];
    const float* mask_token = (const float*)d_in[14];
    const float* cx_attn = (const float*)d_in[15];
    const float* cx_ff1  = (const float*)d_in[16]; const float* cx_ff2 = (const float*)d_in[17];
    const float* enc_sa  = (const float*)d_in[18]; const float* enc_ca = (const float*)d_in[19];
    const float* enc_ff1 = (const float*)d_in[20]; const float* enc_ff2 = (const float*)d_in[21];
    const float* dec_ca  = (const float*)d_in[22]; const float* dec_ff1 = (const float*)d_in[23];
    const float* dec_ff2 = (const float*)d_in[24];
    const float* up_w1 = (const float*)d_in[25]; const float* up_b1 = (const float*)d_in[26];
    const float* up_w2 = (const float*)d_in[27]; const float* up_b2 = (const float*)d_in[28];
    float* dout = (float*)d_out_v;

    float *centersB, *relB, *f1B, *f2B, *gmaxB, *catB, *t1B, *t2B, *tokensB;
    float *cpeB, *ppeB, *vis3B, *visB, *fullB, *decxB, *mbufB, *lnmB, *lnSB, *lnTB;
    float *lnbigB, *qB, *kB, *vB, *ctxB, *hidB, *upcatB, *nn3wB, *lpartB;
    int *nidxB, *nidxSB, *nn3iB;
    unsigned char *mfullB, *mvisB;
    GETSYM(centersB, g_centers); GETSYM(nidxB, g_nidx); GETSYM(nidxSB, g_nidxS);
    GETSYM(relB, g_rel); GETSYM(f1B, g_f1); GETSYM(f2B, g_f2); GETSYM(gmaxB, g_gmax);
    GETSYM(catB, g_cat); GETSYM(t1B, g_t1); GETSYM(t2B, g_t2); GETSYM(tokensB, g_tokens);
    GETSYM(cpeB, g_cpe); GETSYM(ppeB, g_ppe); GETSYM(mfullB, g_mfull); GETSYM(mvisB, g_mvis);
    GETSYM(vis3B, g_vis3); GETSYM(visB, g_visbuf); GETSYM(fullB, g_fullbuf); GETSYM(decxB, g_decx);
    GETSYM(mbufB, g_mbuf); GETSYM(lnmB, g_lnm); GETSYM(lnSB, g_lnS); GETSYM(lnTB, g_lnT);
    GETSYM(lnbigB, g_lnbig); GETSYM(qB, g_qbuf); GETSYM(kB, g_kbuf); GETSYM(vB, g_vbuf);
    GETSYM(ctxB, g_ctx); GETSYM(hidB, g_hid); GETSYM(upcatB, g_upcat);
    GETSYM(nn3iB, g_nn3i); GETSYM(nn3wB, g_nn3w); GETSYM(lpartB, g_lpart);

    float* centers[2] = {centersB, centersB + Bb*Gg*3};
    float* tokens[2]  = {tokensB,  tokensB  + Bb*Gg*Dd};
    float* cpe[2]     = {cpeB,     cpeB     + Bb*Gg*Dd};
    float* ppe[2]     = {ppeB,     ppeB     + Bb*Np*Dd};
    float* visb[2]    = {visB,     visB     + Bb*Vv*Dd};
    float* fullb[2]   = {fullB,    fullB    + Bb*Gg*Dd};
    float* decx[2]    = {decxB,    decxB    + Bb*(Mm+Vv)*Dd};
    unsigned char* mfull[2] = {mfullB, mfullB + Bb*Gg*Gg};
    unsigned char* mvis[2]  = {mvisB,  mvisB  + Bb*Vv*Vv};

    // Phase 1: tokenize + PE + masks
    for (int s = 0; s < 2; s++) {
        fps_kernel<<<Bb, 512>>>(pos[s], centers[s]);
        knn_big_kernel<<<Bb*Gg, 128>>>(centers[s], pos[s], nidxB);
        group_rel_kernel<<<(Bb*Gg*Kk + 255)/256, 256>>>(pos[s], centers[s], nidxB, relB);
        gemm(relB, tok_w1, tok_b1, f1B, Bb*Gg*Kk, 3, 128, 1, 0);
        gemm(f1B, tok_w2, tok_b2, f2B, Bb*Gg*Kk, 128, 256, 0, 0);
        gmax_kernel<<<(Bb*Gg*256 + 255)/256, 256>>>(f2B, gmaxB, 256);
        cat_kernel<<<(Bb*Gg*Kk*512 + 255)/256, 256>>>(gmaxB, f2B, catB);
        gemm(catB, tok_w3, tok_b3, t1B, Bb*Gg*Kk, 512, 512, 1, 0);
        gemm(t1B, tok_w4, tok_b4, t2B, Bb*Gg*Kk, 512, Dd, 0, 0);
        gmax_kernel<<<(Bb*Gg*Dd + 255)/256, 256>>>(t2B, tokens[s], Dd);
        pe_kernel<<<(Bb*Gg*Dd + 255)/256, 256>>>(centers[s], cpe[s], Bb*Gg);
        pe_kernel<<<(Bb*Np*Dd + 255)/256, 256>>>(pos[s], ppe[s], Bb*Np);
        knn_small_kernel<<<Bb*Gg, 128>>>(centers[s], Gg, nidxSB);
        zero_u8_kernel<<<(Bb*Gg*Gg + 255)/256, 256>>>(mfull[s], Bb*Gg*Gg);
        scatter_mask_kernel<<<(Bb*Gg*Kk + 255)/256, 256>>>(nidxSB, mfull[s], Gg);
        gather_kernel<<<Bb*Vv, 32>>>(centers[s], visidx[s], vis3B, Vv, Gg, 3);
        knn_small_kernel<<<Bb*Vv, 128>>>(vis3B, Vv, nidxSB);
        zero_u8_kernel<<<(Bb*Vv*Vv + 255)/256, 256>>>(mvis[s], Bb*Vv*Vv);
        scatter_mask_kernel<<<(Bb*Vv*Kk + 255)/256, 256>>>(nidxSB, mvis[s], Vv);
        gather_kernel<<<Bb*Vv, 128>>>(tokens[s], visidx[s], visb[s], Vv, Gg, Dd);
        copy_kernel<<<(Bb*Gg*Dd + 255)/256, 256>>>(tokens[s], fullb[s], Bb*Gg*Dd);
    }

    // Phase 2: cross encoders
    encode_pair(visb[0], visb[1], mvis[0], mvis[1], Vv, cx_attn, cx_ff1, cx_ff2,
                lnSB, lnTB, qB, kB, vB, ctxB, hidB);
    encode_pair(fullb[0], fullb[1], mfull[0], mfull[1], Gg, cx_attn, cx_ff1, cx_ff2,
                lnSB, lnTB, qB, kB, vB, ctxB, hidB);

    // Phase 3: MAE decoder + loss
    for (int s = 0; s < 2; s++) {
        int o = 1 - s;
        decq_kernel<<<(Bb*(Mm+Vv)*Dd + 255)/256, 256>>>(visb[s], cpe[s], mask_token,
                                                        mskidx[s], visidx[s], decx[s]);
        add_kernel<<<(Bb*Gg*Dd + 255)/256, 256>>>(fullb[o], cpe[o], mbufB, Bb*Gg*Dd);
        ln_kernel<<<Bb*Gg, 128>>>(mbufB, lnmB);
        for (int l = 0; l < 4; l++) {
            const float* sal = enc_sa + (size_t)l*4*Dd*Dd;
            const float* cal = enc_ca + (size_t)l*4*Dd*Dd;
            ln_kernel<<<Bb*(Mm+Vv), 128>>>(decx[s], lnSB);
            attn_block(lnSB, lnSB, sal, nullptr, decx[s], Mm+Vv, Mm+Vv, qB, kB, vB, ctxB);
            ln_kernel<<<Bb*(Mm+Vv), 128>>>(decx[s], lnSB);
            attn_block(lnSB, lnmB, cal, nullptr, decx[s], Mm+Vv, Gg, qB, kB, vB, ctxB);
            ln_kernel<<<Bb*(Mm+Vv), 128>>>(decx[s], lnSB);
            gemm(lnSB, enc_ff1 + (size_t)l*Dd*FFf, nullptr, hidB, Bb*(Mm+Vv), Dd, FFf, 1, 0);
            gemm(hidB, enc_ff2 + (size_t)l*FFf*Dd, nullptr, decx[s], Bb*(Mm+Vv), FFf, Dd, 0, 1);
        }
        loss_kernel<<<64, 256>>>(fullb[s], mskidx[s], decx[s], lpartB + s*64);
    }

    // Phase 4: upsample + dense decoder
    for (int s = 0; s < 2; s++) {
        float* X = dout + (size_t)s*Bb*Np*Dd;
        nn3_kernel<<<(Bb*Np + 255)/256, 256>>>(pos[s], centers[s], nn3iB, nn3wB);
        upcat_kernel<<<Bb*Np, 128>>>(fullb[s], pos[s], nn3iB, nn3wB, upcatB);
        gemm(upcatB, up_w1, up_b1, lnbigB, Bb*Np, 387, Dd, 1, 0);
        gemm(lnbigB, up_w2, up_b2, ctxB, Bb*Np, Dd, Dd, 1, 0);
        add_kernel<<<(Bb*Np*Dd + 255)/256, 256>>>(ctxB, ppe[s], X, Bb*Np*Dd);
        add_kernel<<<(Bb*Gg*Dd + 255)/256, 256>>>(fullb[s], cpe[s], mbufB, Bb*Gg*Dd);
        ln_kernel<<<Bb*Gg, 128>>>(mbufB, lnmB);
        for (int l = 0; l < 2; l++) {
            const float* cal = dec_ca + (size_t)l*4*Dd*Dd;
            ln_kernel<<<Bb*Np, 128>>>(X, lnbigB);
            attn_block(lnbigB, lnmB, cal, nullptr, X, Np, Gg, qB, kB, vB, ctxB);
            ln_kernel<<<Bb*Np, 128>>>(X, lnbigB);
            gemm(lnbigB, dec_ff1 + (size_t)l*Dd*FFf, nullptr, hidB, Bb*Np, Dd, FFf, 1, 0);
            gemm(hidB, dec_ff2 + (size_t)l*FFf*Dd, nullptr, X, Bb*Np, FFf, Dd, 0, 1);
        }
    }
    loss_final_kernel<<<1, 1>>>(lpartB, lpartB + 64, dout + (size_t)2*Bb*Np*Dd);
}

// round 7
// speedup vs baseline: 3.7893x; 1.3003x over previous
#include <cuda_runtime.h>
#include <math.h>
#include <stdint.h>

#define Bb 8
#define Np 4096
#define Gg 128
#define Kk 16
#define Vv 64
#define Mm 64
#define Dd 384
#define NHh 8
#define DHh 48
#define FFf 1536
#define UPK 400

__device__ float g_centers[2][Bb*Gg*3];
__device__ int   g_nidx[Bb*Gg*Kk];
__device__ int   g_nidxS[Bb*Gg*Kk];
__device__ float g_rel[Bb*Gg*Kk*3];
__device__ float g_f1[Bb*Gg*Kk*128];
__device__ float g_f2[Bb*Gg*Kk*256];
__device__ float g_gmax[Bb*Gg*256];
__device__ float g_cat[Bb*Gg*Kk*512];
__device__ float g_t1[Bb*Gg*Kk*512];
__device__ float g_t2[Bb*Gg*Kk*Dd];
__device__ float g_tokens[2][Bb*Gg*Dd];
__device__ float g_cpe[2][Bb*Gg*Dd];
__device__ float g_ppe[2][Bb*Np*Dd];
__device__ unsigned char g_mfull[2][Bb*Gg*Gg];
__device__ unsigned char g_mvis[2][Bb*Vv*Vv];
__device__ float g_vis3[Bb*Vv*3];
__device__ float g_visbuf[2][Bb*Vv*Dd];
__device__ float g_fullbuf[2][Bb*Gg*Dd];
__device__ float g_decx[2][Bb*(Mm+Vv)*Dd];
__device__ float g_mbuf[Bb*Gg*Dd];
__device__ float g_lnm[Bb*Gg*Dd];
__device__ float g_lnS[Bb*Gg*Dd];
__device__ float g_lnT[Bb*Gg*Dd];
__device__ float g_lnbig[Bb*Np*Dd];
__device__ float g_qbuf[Bb*Np*Dd];
__device__ float g_kbuf[Bb*Gg*Dd];
__device__ float g_vbuf[Bb*Gg*Dd];
__device__ float g_ctx[Bb*Np*Dd];
__device__ float g_hid[Bb*Np*FFf];
__device__ float g_upcat[Bb*Np*UPK];
__device__ float g_upw1p[UPK*Dd];
__device__ int   g_nn3i[Bb*Np*3];
__device__ float g_nn3w[Bb*Np*3];
__device__ float g_lpart[2*64];

// ---- small/medium GEMM fallback: 64x64 tile, 4x4 microtile ----
__global__ void gemm64_kernel(const float* __restrict__ A, const float* __restrict__ W,
                              const float* __restrict__ bias, float* __restrict__ C,
                              int rows, int Kd, int Nc, int relu, int accum)
{
    __shared__ float As[16][64];
    __shared__ float Ws[16][64];
    int tid = threadIdx.x, tx = tid & 15, ty = tid >> 4;
    int row0 = blockIdx.y * 64, col0 = blockIdx.x * 64;
    float acc[4][4] = {};
    for (int k0 = 0; k0 < Kd; k0 += 16) {
        #pragma unroll
        for (int l = 0; l < 4; l++) {
            int idx = tid + l*256, m = idx >> 4, kk = idx & 15;
            As[kk][m] = (k0 + kk < Kd) ? A[(size_t)(row0+m)*Kd + k0 + kk] : 0.f;
        }
        #pragma unroll
        for (int l = 0; l < 4; l++) {
            int idx = tid + l*256, kk = idx >> 6, n = idx & 63;
            Ws[kk][n] = (k0 + kk < Kd) ? W[(size_t)(k0+kk)*Nc + col0 + n] : 0.f;
        }
        __syncthreads();
        #pragma unroll
        for (int kk = 0; kk < 16; kk++) {
            float a0=As[kk][ty*4],a1=As[kk][ty*4+1],a2=As[kk][ty*4+2],a3=As[kk][ty*4+3];
            float b0=Ws[kk][tx*4],b1=Ws[kk][tx*4+1],b2=Ws[kk][tx*4+2],b3=Ws[kk][tx*4+3];
            acc[0][0]+=a0*b0;acc[0][1]+=a0*b1;acc[0][2]+=a0*b2;acc[0][3]+=a0*b3;
            acc[1][0]+=a1*b0;acc[1][1]+=a1*b1;acc[1][2]+=a1*b2;acc[1][3]+=a1*b3;
            acc[2][0]+=a2*b0;acc[2][1]+=a2*b1;acc[2][2]+=a2*b2;acc[2][3]+=a2*b3;
            acc[3][0]+=a3*b0;acc[3][1]+=a3*b1;acc[3][2]+=a3*b2;acc[3][3]+=a3*b3;
        }
        __syncthreads();
    }
    #pragma unroll
    for (int i = 0; i < 4; i++) {
        int r = row0 + ty*4 + i;
        #pragma unroll
        for (int j = 0; j < 4; j++) {
            int c = col0 + tx*4 + j;
            float v = acc[i][j];
            if (bias) v += bias[c];
            if (relu) v = fmaxf(v, 0.f);
            size_t o = (size_t)r*Nc + c;
            if (accum) C[o] += v; else C[o] = v;
        }
    }
}

// ---- big GEMM fp32 fallback (K not %16): 128x128 tile, 8x8 microtile ----
__global__ __launch_bounds__(256)
void gemm128_kernel(const float* __restrict__ A, const float* __restrict__ W,
                    const float* __restrict__ bias, float* __restrict__ C,
                    int rows, int Kd, int Nc, int relu, int accum)
{
    __shared__ float As[8][132];
    __shared__ float Ws[8][132];
    int tid = threadIdx.x, tx = tid & 15, ty = tid >> 4;
    int row0 = blockIdx.y * 128, col0 = blockIdx.x * 128;
    float acc[8][8] = {};
    for (int k0 = 0; k0 < Kd; k0 += 8) {
        #pragma unroll
        for (int l = 0; l < 4; l++) {
            int i = tid + l*256;
            int kk = i & 7, m = i >> 3;
            As[kk][m] = (k0 + kk < Kd) ? A[(size_t)(row0+m)*Kd + k0 + kk] : 0.f;
        }
        #pragma unroll
        for (int l = 0; l < 4; l++) {
            int i = tid + l*256;
            int n = i & 127, kk = i >> 7;
            Ws[kk][n] = (k0 + kk < Kd) ? W[(size_t)(k0+kk)*Nc + col0 + n] : 0.f;
        }
        __syncthreads();
        #pragma unroll
        for (int kk = 0; kk < 8; kk++) {
            float a[8], b[8];
            *(float4*)&a[0] = *(const float4*)&As[kk][ty*4];
            *(float4*)&a[4] = *(const float4*)&As[kk][ty*4 + 64];
            *(float4*)&b[0] = *(const float4*)&Ws[kk][tx*4];
            *(float4*)&b[4] = *(const float4*)&Ws[kk][tx*4 + 64];
            #pragma unroll
            for (int i = 0; i < 8; i++)
                #pragma unroll
                for (int j = 0; j < 8; j++)
                    acc[i][j] += a[i]*b[j];
        }
        __syncthreads();
    }
    #pragma unroll
    for (int i = 0; i < 8; i++) {
        int r = row0 + ((i < 4) ? (ty*4 + i) : (64 + ty*4 + i - 4));
        #pragma unroll
        for (int j = 0; j < 8; j++) {
            int c = col0 + ((j < 4) ? (tx*4 + j) : (64 + tx*4 + j - 4));
            float v = acc[i][j];
            if (bias) v += bias[c];
            if (relu) v = fmaxf(v, 0.f);
            size_t o = (size_t)r*Nc + c;
            if (accum) C[o] += v; else C[o] = v;
        }
    }
}

// ---- tf32 tensor-core GEMM: 128x128 tile, KT=16, cp.async double buffered ----
// Requires rows%128==0, Nc%128==0, Kd%16==0.
#define TFKT 16
__global__ __launch_bounds__(256)
void gemm_tf32_kernel(const float* __restrict__ A, const float* __restrict__ W,
                      const float* __restrict__ bias, float* __restrict__ C,
                      int rows, int Kd, int Nc, int relu, int accum)
{
    __shared__ float As[2][128][20];
    __shared__ float Ws[2][16][136];
    int tid = threadIdx.x;
    int wid = tid >> 5, lane = tid & 31;
    int g = lane >> 2, tig = lane & 3;
    int wm = (wid >> 1) * 32;
    int wn = (wid & 1) * 64;
    int row0 = blockIdx.y * 128, col0 = blockIdx.x * 128;
    float c[2][8][4] = {};

    int nIter = Kd / TFKT;
    // prologue: stage 0
    #pragma unroll
    for (int l = 0; l < 2; l++) {
        int idx = tid + l*256;
        int m = idx >> 2, f4 = idx & 3;
        const float* gp = A + (size_t)(row0+m)*Kd + f4*4;
        uint32_t sp = (uint32_t)__cvta_generic_to_shared(&As[0][m][f4*4]);
        asm volatile("cp.async.cg.shared.global [%0], [%1], 16;" :: "r"(sp), "l"(gp));
    }
    #pragma unroll
    for (int l = 0; l < 2; l++) {
        int idx = tid + l*256;
        int kk = idx >> 5, f4 = idx & 31;
        const float* gp = W + (size_t)kk*Nc + col0 + f4*4;
        uint32_t sp = (uint32_t)__cvta_generic_to_shared(&Ws[0][kk][f4*4]);
        asm volatile("cp.async.cg.shared.global [%0], [%1], 16;" :: "r"(sp), "l"(gp));
    }
    asm volatile("cp.async.commit_group;");

    for (int it = 0; it < nIter; it++) {
        int cur = it & 1;
        if (it + 1 < nIter) {
            int k0 = (it+1)*TFKT;
            #pragma unroll
            for (int l = 0; l < 2; l++) {
                int idx = tid + l*256;
                int m = idx >> 2, f4 = idx & 3;
                const float* gp = A + (size_t)(row0+m)*Kd + k0 + f4*4;
                uint32_t sp = (uint32_t)__cvta_generic_to_shared(&As[cur^1][m][f4*4]);
                asm volatile("cp.async.cg.shared.global [%0], [%1], 16;" :: "r"(sp), "l"(gp));
            }
            #pragma unroll
            for (int l = 0; l < 2; l++) {
                int idx = tid + l*256;
                int kk = idx >> 5, f4 = idx & 31;
                const float* gp = W + (size_t)(k0+kk)*Nc + col0 + f4*4;
                uint32_t sp = (uint32_t)__cvta_generic_to_shared(&Ws[cur^1][kk][f4*4]);
                asm volatile("cp.async.cg.shared.global [%0], [%1], 16;" :: "r"(sp), "l"(gp));
            }
            asm volatile("cp.async.commit_group;");
            asm volatile("cp.async.wait_group 1;");
        } else {
            asm volatile("cp.async.wait_group 0;");
        }
        __syncthreads();
        #pragma unroll
        for (int s8 = 0; s8 < 2; s8++) {
            int kb = s8*8;
            uint32_t a[2][4], b[8][2];
            #pragma unroll
            for (int mt = 0; mt < 2; mt++) {
                int m0 = wm + mt*16;
                float a0 = As[cur][m0+g  ][kb+tig  ];
                float a1 = As[cur][m0+g+8][kb+tig  ];
                float a2 = As[cur][m0+g  ][kb+tig+4];
                float a3 = As[cur][m0+g+8][kb+tig+4];
                asm("cvt.rna.tf32.f32 %0, %1;" : "=r"(a[mt][0]) : "f"(a0));
                asm("cvt.rna.tf32.f32 %0, %1;" : "=r"(a[mt][1]) : "f"(a1));
                asm("cvt.rna.tf32.f32 %0, %1;" : "=r"(a[mt][2]) : "f"(a2));
                asm("cvt.rna.tf32.f32 %0, %1;" : "=r"(a[mt][3]) : "f"(a3));
            }
            #pragma unroll
            for (int nt = 0; nt < 8; nt++) {
                int n0 = wn + nt*8;
                float b0 = Ws[cur][kb+tig  ][n0+g];
                float b1 = Ws[cur][kb+tig+4][n0+g];
                asm("cvt.rna.tf32.f32 %0, %1;" : "=r"(b[nt][0]) : "f"(b0));
                asm("cvt.rna.tf32.f32 %0, %1;" : "=r"(b[nt][1]) : "f"(b1));
            }
            #pragma unroll
            for (int mt = 0; mt < 2; mt++)
                #pragma unroll
                for (int nt = 0; nt < 8; nt++)
                    asm volatile(
                        "mma.sync.aligned.m16n8k8.row.col.f32.tf32.tf32.f32 "
                        "{%0,%1,%2,%3}, {%4,%5,%6,%7}, {%8,%9}, {%0,%1,%2,%3};"
                        : "+f"(c[mt][nt][0]), "+f"(c[mt][nt][1]),
                          "+f"(c[mt][nt][2]), "+f"(c[mt][nt][3])
                        : "r"(a[mt][0]), "r"(a[mt][1]), "r"(a[mt][2]), "r"(a[mt][3]),
                          "r"(b[nt][0]), "r"(b[nt][1]));
        }
        __syncthreads();
    }
    #pragma unroll
    for (int mt = 0; mt < 2; mt++) {
        #pragma unroll
        for (int nt = 0; nt < 8; nt++) {
            int r0 = row0 + wm + mt*16 + g;
            int cc = col0 + wn + nt*8 + 2*tig;
            float v0 = c[mt][nt][0], v1 = c[mt][nt][1];
            float v2 = c[mt][nt][2], v3 = c[mt][nt][3];
            if (bias) { float b0 = bias[cc], b1 = bias[cc+1]; v0 += b0; v1 += b1; v2 += b0; v3 += b1; }
            if (relu) { v0 = fmaxf(v0,0.f); v1 = fmaxf(v1,0.f); v2 = fmaxf(v2,0.f); v3 = fmaxf(v3,0.f); }
            size_t o0 = (size_t)r0*Nc + cc;
            size_t o1 = (size_t)(r0+8)*Nc + cc;
            if (accum) { C[o0] += v0; C[o0+1] += v1; C[o1] += v2; C[o1+1] += v3; }
            else       { C[o0]  = v0; C[o0+1]  = v1; C[o1]  = v2; C[o1+1]  = v3; }
        }
    }
}

__global__ void ln_kernel(const float* __restrict__ x, float* __restrict__ y)
{
    int row = blockIdx.x, t = threadIdx.x;
    const float* xr = x + (size_t)row*Dd;
    __shared__ float red[128];
    float a = xr[t], b = xr[t+128], c = xr[t+256];
    red[t] = a + b + c; __syncthreads();
    for (int o = 64; o > 0; o >>= 1) { if (t < o) red[t] += red[t+o]; __syncthreads(); }
    float m = red[0] / (float)Dd; __syncthreads();
    float da=a-m, db=b-m, dc=c-m;
    red[t] = da*da + db*db + dc*dc; __syncthreads();
    for (int o = 64; o > 0; o >>= 1) { if (t < o) red[t] += red[t+o]; __syncthreads(); }
    float inv = rsqrtf(red[0] / (float)Dd + 1e-5f);
    float* yr = y + (size_t)row*Dd;
    yr[t]=da*inv; yr[t+128]=db*inv; yr[t+256]=dc*inv;
}

// small attention: one block per (q,h,b); Sk<=128
__global__ void attn_kernel(const float* __restrict__ q, const float* __restrict__ kmat,
                            const float* __restrict__ vmat, const unsigned char* __restrict__ mask,
                            float* __restrict__ ctx, int Sq, int Sk)
{
    int qi = blockIdx.x, h = blockIdx.y, b = blockIdx.z, t = threadIdx.x;
    __shared__ float shq[DHh], shp[128], red[128];
    const float* qr = q + ((size_t)(b*Sq + qi))*Dd + h*DHh;
    if (t < DHh) shq[t] = qr[t];
    __syncthreads();
    float val = -3e38f;
    if (t < Sk) {
        const float* kr = kmat + ((size_t)(b*Sk + t))*Dd + h*DHh;
        float s = 0.f;
        #pragma unroll
        for (int d = 0; d < DHh; d++) s += shq[d]*kr[d];
        s /= sqrtf((float)DHh);
        if (mask && !mask[((size_t)b*Sq + qi)*Sk + t]) s = -1e9f;
        val = s;
    }
    red[t] = val; __syncthreads();
    for (int o = 64; o > 0; o >>= 1) { if (t < o) red[t] = fmaxf(red[t], red[t+o]); __syncthreads(); }
    float mx = red[0]; __syncthreads();
    float e = (t < Sk) ? expf(val - mx) : 0.f;
    shp[t] = e; red[t] = e; __syncthreads();
    for (int o = 64; o > 0; o >>= 1) { if (t < o) red[t] += red[t+o]; __syncthreads(); }
    float inv = 1.f / red[0];
    if (t < DHh) {
        float acc = 0.f;
        const float* vb = vmat + ((size_t)(b*Sk))*Dd + h*DHh + t;
        for (int kk = 0; kk < Sk; kk++) acc += shp[kk]*vb[(size_t)kk*Dd];
        ctx[((size_t)(b*Sq + qi))*Dd + h*DHh + t] = acc*inv;
    }
}

// big attention: 16 queries per block, Sk==128, no mask
#define QT 16
__global__ __launch_bounds__(128)
void attn_big_kernel(const float* __restrict__ q, const float* __restrict__ kmat,
                     const float* __restrict__ vmat, float* __restrict__ ctx, int Sq)
{
    int qt = blockIdx.x, h = blockIdx.y, b = blockIdx.z, t = threadIdx.x;
    __shared__ float shq[QT][DHh];
    __shared__ float sc[QT][129];
    __shared__ float Vs[128][DHh];
    for (int i = t; i < QT*DHh; i += 128) {
        int qi = i / DHh, d = i % DHh;
        shq[qi][d] = q[((size_t)(b*Sq + qt*QT + qi))*Dd + h*DHh + d];
    }
    for (int i = t; i < 128*DHh; i += 128) {
        int k = i / DHh, d = i % DHh;
        Vs[k][d] = vmat[((size_t)(b*128 + k))*Dd + h*DHh + d];
    }
    __syncthreads();
    float kr[DHh];
    {
        const float* kp = kmat + ((size_t)(b*128 + t))*Dd + h*DHh;
        #pragma unroll
        for (int d = 0; d < DHh; d++) kr[d] = kp[d];
    }
    float inv_s = sqrtf((float)DHh);
    #pragma unroll 1
    for (int qi = 0; qi < QT; qi++) {
        float s = 0.f;
        #pragma unroll
        for (int d = 0; d < DHh; d++) s += shq[qi][d]*kr[d];
        sc[qi][t] = s / inv_s;
    }
    __syncthreads();
    int w = t >> 5, lane = t & 31;
    for (int qi = w; qi < QT; qi += 4) {
        float v0 = sc[qi][lane], v1 = sc[qi][lane+32], v2 = sc[qi][lane+64], v3 = sc[qi][lane+96];
        float mx = fmaxf(fmaxf(v0,v1), fmaxf(v2,v3));
        #pragma unroll
        for (int o = 16; o > 0; o >>= 1) mx = fmaxf(mx, __shfl_xor_sync(0xffffffffu, mx, o));
        float e0=expf(v0-mx), e1=expf(v1-mx), e2=expf(v2-mx), e3=expf(v3-mx);
        float sum = e0+e1+e2+e3;
        #pragma unroll
        for (int o = 16; o > 0; o >>= 1) sum += __shfl_xor_sync(0xffffffffu, sum, o);
        float inv = 1.f / sum;
        sc[qi][lane]=e0*inv; sc[qi][lane+32]=e1*inv; sc[qi][lane+64]=e2*inv; sc[qi][lane+96]=e3*inv;
    }
    __syncthreads();
    for (int i = t; i < QT*DHh; i += 128) {
        int qi = i / DHh, d = i % DHh;
        float acc = 0.f;
        #pragma unroll 4
        for (int k = 0; k < 128; k++) acc += sc[qi][k] * Vs[k][d];
        ctx[((size_t)(b*Sq + qt*QT + qi))*Dd + h*DHh + d] = acc;
    }
}

__global__ void fps_kernel(const float* __restrict__ pos, float* __restrict__ centers)
{
    int b = blockIdx.x, t = threadIdx.x;
    __shared__ float mind[Np];
    __shared__ float rv[512]; __shared__ int ri[512]; __shared__ float curp[3];
    const float* P = pos + (size_t)b*Np*3;
    float* C = centers + (size_t)b*Gg*3;
    if (t == 0) { curp[0]=P[0]; curp[1]=P[1]; curp[2]=P[2]; C[0]=P[0]; C[1]=P[1]; C[2]=P[2]; }
    __syncthreads();
    for (int i = t; i < Np; i += 512) {
        float dx=P[3*i]-curp[0], dy=P[3*i+1]-curp[1], dz=P[3*i+2]-curp[2];
        mind[i] = dx*dx + dy*dy + dz*dz;
    }
    __syncthreads();
    for (int s = 1; s < Gg; s++) {
        float bv = -3e38f; int bi = 0x7fffffff;
        for (int i = t; i < Np; i += 512) { float v = mind[i]; if (v > bv) { bv = v; bi = i; } }
        rv[t] = bv; ri[t] = bi; __syncthreads();
        for (int o = 256; o > 0; o >>= 1) {
            if (t < o && (rv[t+o] > rv[t] || (rv[t+o] == rv[t] && ri[t+o] < ri[t]))) { rv[t]=rv[t+o]; ri[t]=ri[t+o]; }
            __syncthreads();
        }
        if (t == 0) {
            int nxt = ri[0];
            curp[0]=P[3*nxt]; curp[1]=P[3*nxt+1]; curp[2]=P[3*nxt+2];
            C[3*s]=curp[0]; C[3*s+1]=curp[1]; C[3*s+2]=curp[2];
        }
        __syncthreads();
        for (int i = t; i < Np; i += 512) {
            float dx=P[3*i]-curp[0], dy=P[3*i+1]-curp[1], dz=P[3*i+2]-curp[2];
            float d = dx*dx + dy*dy + dz*dz;
            if (d < mind[i]) mind[i] = d;
        }
        __syncthreads();
    }
}

__global__ void knn_big_kernel(const float* __restrict__ qpts, const float* __restrict__ rpts,
                               int* __restrict__ nidx)
{
    int blk = blockIdx.x, b = blk / Gg, qc = blk % Gg, t = threadIdx.x;
    __shared__ float dist[Np];
    __shared__ float rv[128]; __shared__ int ri[128];
    const float* Q = qpts + ((size_t)b*Gg + qc)*3;
    float qx=Q[0], qy=Q[1], qz=Q[2], qq = qx*qx+qy*qy+qz*qz;
    const float* R = rpts + (size_t)b*Np*3;
    for (int i = t; i < Np; i += 128) {
        float rx=R[3*i], ry=R[3*i+1], rz=R[3*i+2];
        dist[i] = qq + (rx*rx+ry*ry+rz*rz) - 2.f*(qx*rx+qy*ry+qz*rz);
    }
    __syncthreads();
    for (int kk = 0; kk < Kk; kk++) {
        float bv = 3e38f; int bi = 0x7fffffff;
        for (int i = t; i < Np; i += 128) { float v = dist[i]; if (v < bv) { bv = v; bi = i; } }
        rv[t] = bv; ri[t] = bi; __syncthreads();
        for (int o = 64; o > 0; o >>= 1) {
            if (t < o && (rv[t+o] < rv[t] || (rv[t+o] == rv[t] && ri[t+o] < ri[t]))) { rv[t]=rv[t+o]; ri[t]=ri[t+o]; }
            __syncthreads();
        }
        if (t == 0) { nidx[((size_t)b*Gg + qc)*Kk + kk] = ri[0]; dist[ri[0]] = 3e38f; }
        __syncthreads();
    }
}

__global__ void knn_small_kernel(const float* __restrict__ pts, int S, int* __restrict__ nidx)
{
    int blk = blockIdx.x, b = blk / S, qi = blk % S, t = threadIdx.x;
    __shared__ float dist[128]; __shared__ float rv[128]; __shared__ int ri[128];
    const float* Q = pts + ((size_t)b*S + qi)*3;
    float qx=Q[0], qy=Q[1], qz=Q[2], qq=qx*qx+qy*qy+qz*qz;
    if (t < S) {
        const float* R = pts + ((size_t)b*S + t)*3;
        dist[t] = qq + (R[0]*R[0]+R[1]*R[1]+R[2]*R[2]) - 2.f*(qx*R[0]+qy*R[1]+qz*R[2]);
    } else dist[t] = 3e38f;
    __syncthreads();
    for (int kk = 0; kk < Kk; kk++) {
        rv[t] = dist[t]; ri[t] = t; __syncthreads();
        for (int o = 64; o > 0; o >>= 1) {
            if (t < o && (rv[t+o] < rv[t] || (rv[t+o] == rv[t] && ri[t+o] < ri[t]))) { rv[t]=rv[t+o]; ri[t]=ri[t+o]; }
            __syncthreads();
        }
        if (t == 0) { nidx[((size_t)b*S + qi)*Kk + kk] = ri[0]; dist[ri[0]] = 3e38f; }
        __syncthreads();
    }
}

__global__ void zero_u8_kernel(unsigned char* m, int n)
{ int i = blockIdx.x*blockDim.x + threadIdx.x; if (i < n) m[i] = 0; }

__global__ void scatter_mask_kernel(const int* __restrict__ nidx, unsigned char* __restrict__ m, int S)
{
    int i = blockIdx.x*blockDim.x + threadIdx.x;
    if (i >= Bb*S*Kk) return;
    int b = i / (S*Kk), r = (i / Kk) % S;
    m[((size_t)b*S + r)*S + nidx[i]] = 1;
}

__global__ void group_rel_kernel(const float* __restrict__ pos, const float* __restrict__ centers,
                                 const int* __restrict__ nidx, float* __restrict__ rel)
{
    int i = blockIdx.x*blockDim.x + threadIdx.x;
    if (i >= Bb*Gg*Kk) return;
    int b = i / (Gg*Kk), g = (i / Kk) % Gg, src = nidx[i];
    const float* P = pos + ((size_t)b*Np + src)*3;
    const float* C = centers + ((size_t)b*Gg + g)*3;
    rel[3*i]=P[0]-C[0]; rel[3*i+1]=P[1]-C[1]; rel[3*i+2]=P[2]-C[2];
}

__global__ void gmax_kernel(const float* __restrict__ f, float* __restrict__ g, int C)
{
    int i = blockIdx.x*blockDim.x + threadIdx.x;
    if (i >= Bb*Gg*C) return;
    int bg = i / C, c = i % C;
    const float* fp = f + (size_t)bg*Kk*C + c;
    float m = fp[0];
    #pragma unroll
    for (int k = 1; k < Kk; k++) m = fmaxf(m, fp[(size_t)k*C]);
    g[i] = m;
}

__global__ void cat_kernel(const float* __restrict__ g, const float* __restrict__ f, float* __restrict__ cat)
{
    int i = blockIdx.x*blockDim.x + threadIdx.x;
    if (i >= Bb*Gg*Kk*512) return;
    int c = i % 512, r = i / 512, bg = r / Kk;
    cat[i] = (c < 256) ? g[(size_t)bg*256 + c] : f[(size_t)r*256 + (c - 256)];
}

__global__ void pe_kernel(const float* __restrict__ xyz, float* __restrict__ pe, int rows)
{
    int i = blockIdx.x*blockDim.x + threadIdx.x;
    if (i >= rows*Dd) return;
    int r = i / Dd, j = i % Dd, c = j / 128, jj = j % 128;
    float x = xyz[(size_t)r*3 + c];
    float dt = powf(10000.0f, (float)(2*(jj/2)) / 128.0f);
    float p = x / dt;
    pe[i] = (jj & 1) ? cosf(p) : sinf(p);
}

__global__ void gather_kernel(const float* __restrict__ src, const int* __restrict__ idx,
                              float* __restrict__ dst, int outR, int inR, int W)
{
    int row = blockIdx.x, b = row / outR, r = row % outR;
    int s = idx[(size_t)b*outR + r];
    const float* sp = src + ((size_t)b*inR + s)*W;
    float* dp = dst + (size_t)row*W;
    for (int w = threadIdx.x; w < W; w += blockDim.x) dp[w] = sp[w];
}

__global__ void decq_kernel(const float* __restrict__ visout, const float* __restrict__ cpe,
                            const float* __restrict__ mask_token, const int* __restrict__ mskidx,
                            const int* __restrict__ visidx, float* __restrict__ x)
{
    int i = blockIdx.x*blockDim.x + threadIdx.x;
    if (i >= Bb*(Mm+Vv)*Dd) return;
    int d = i % Dd, r = (i / Dd) % (Mm+Vv), b = i / (Dd*(Mm+Vv));
    float base; int pidx;
    if (r < Mm) { base = mask_token[d]; pidx = mskidx[(size_t)b*Mm + r]; }
    else { base = visout[((size_t)b*Vv + (r-Mm))*Dd + d]; pidx = visidx[(size_t)b*Vv + (r-Mm)]; }
    x[i] = base + cpe[((size_t)b*Gg + pidx)*Dd + d];
}

__global__ void add_kernel(const float* __restrict__ a, const float* __restrict__ b,
                           float* __restrict__ c, int n)
{ int i = blockIdx.x*blockDim.x + threadIdx.x; if (i < n) c[i] = a[i] + b[i]; }

__global__ void nn3_kernel(const float* __restrict__ pos, const float* __restrict__ centers,
                           int* __restrict__ oi, float* __restrict__ ow)
{
    int i = blockIdx.x*blockDim.x + threadIdx.x;
    if (i >= Bb*Np) return;
    int b = i / Np;
    const float* P = pos + (size_t)i*3;
    float px=P[0], py=P[1], pz=P[2], qq=px*px+py*py+pz*pz;
    float d0=3e38f, d1=3e38f, d2=3e38f; int i0=-1, i1=-1, i2=-1;
    const float* C = centers + (size_t)b*Gg*3;
    for (int g = 0; g < Gg; g++) {
        float cx=C[3*g], cy=C[3*g+1], cz=C[3*g+2];
        float d = qq + (cx*cx+cy*cy+cz*cz) - 2.f*(px*cx+py*cy+pz*cz);
        if (d < d0) { d2=d1;i2=i1; d1=d0;i1=i0; d0=d;i0=g; }
        else if (d < d1) { d2=d1;i2=i1; d1=d;i1=g; }
        else if (d < d2) { d2=d;i2=g; }
    }
    float w0=1.f/(fmaxf(d0,0.f)+1e-8f), w1=1.f/(fmaxf(d1,0.f)+1e-8f), w2=1.f/(fmaxf(d2,0.f)+1e-8f);
    float s = w0+w1+w2;
    ow[3*i]=w0/s; ow[3*i+1]=w1/s; ow[3*i+2]=w2/s;
    oi[3*i]=i0; oi[3*i+1]=i1; oi[3*i+2]=i2;
}

__global__ void upcat_kernel(const float* __restrict__ feats, const float* __restrict__ pos,
                             const int* __restrict__ oi, const float* __restrict__ ow,
                             float* __restrict__ cat)
{
    int row = blockIdx.x, b = row / Np, t = threadIdx.x;
    int i0=oi[3*row], i1=oi[3*row+1], i2=oi[3*row+2];
    float w0=ow[3*row], w1=ow[3*row+1], w2=ow[3*row+2];
    const float* F = feats + (size_t)b*Gg*Dd;
    float* cp = cat + (size_t)row*UPK;
    for (int d = t; d < Dd; d += 128)
        cp[d] = w0*F[(size_t)i0*Dd+d] + w1*F[(size_t)i1*Dd+d] + w2*F[(size_t)i2*Dd+d];
    if (t < 3) cp[Dd + t] = pos[(size_t)row*3 + t];
    else if (t < 16) cp[Dd + t] = 0.f;
}

__global__ void padw_kernel(const float* __restrict__ w, float* __restrict__ wp)
{
    int i = blockIdx.x*blockDim.x + threadIdx.x;
    if (i >= UPK*Dd) return;
    int r = i / Dd;
    wp[i] = (r < Dd + 3) ? w[i] : 0.f;
}

__global__ void loss_kernel(const float* __restrict__ fullout, const int* __restrict__ mskidx,
                            const float* __restrict__ decx, float* __restrict__ partial)
{
    __shared__ float red[256];
    int t = threadIdx.x;
    float acc = 0.f;
    for (int i = blockIdx.x*256 + t; i < Bb*Mm*Dd; i += 64*256) {
        int d = i % Dd, r = (i / Dd) % Mm, b = i / (Dd*Mm);
        int gi = mskidx[(size_t)b*Mm + r];
        float tv = fullout[((size_t)b*Gg + gi)*Dd + d];
        float pv = decx[((size_t)b*(Mm+Vv) + r)*Dd + d];
        float a = fabsf(pv - tv);
        acc += (a < 2.0f) ? 0.25f*a*a : a - 1.0f;
    }
    red[t] = acc; __syncthreads();
    for (int o = 128; o > 0; o >>= 1) { if (t < o) red[t] += red[t+o]; __syncthreads(); }
    if (t == 0) partial[blockIdx.x] = red[0];
}

__global__ void loss_final_kernel(const float* __restrict__ pa, const float* __restrict__ pb,
                                  float* __restrict__ out)
{
    float sa = 0.f, sb = 0.f;
    for (int i = 0; i < 64; i++) { sa += pa[i]; sb += pb[i]; }
    float cnt = (float)(Bb*Mm*Dd);
    out[0] = 0.5f*(sa/cnt) + 0.5f*(sb/cnt);
}

__global__ void copy_kernel(const float* __restrict__ a, float* __restrict__ b, int n)
{ int i = blockIdx.x*blockDim.x + threadIdx.x; if (i < n) b[i] = a[i]; }

static void gemm(const float* A, const float* W, const float* bias, float* C,
                 int rows, int Kd, int Nc, int relu, int accum)
{
    if ((rows % 128) == 0 && (Kd % 16) == 0 && (Nc % 128) == 0) {
        dim3 grid(Nc/128, rows/128);
        gemm_tf32_kernel<<<grid, 256>>>(A, W, bias, C, rows, Kd, Nc, relu, accum);
    } else if (rows >= 16384 && (Nc % 128) == 0) {
        dim3 grid(Nc/128, rows/128);
        gemm128_kernel<<<grid, 256>>>(A, W, bias, C, rows, Kd, Nc, relu, accum);
    } else {
        dim3 grid(Nc/64, rows/64);
        gemm64_kernel<<<grid, 256>>>(A, W, bias, C, rows, Kd, Nc, relu, accum);
    }
}

static void attn_block(const float* lnq, const float* lnkv, const float* w,
                       const unsigned char* mask, float* x, int Sq, int Sk,
                       float* qb, float* kb, float* vb, float* cb)
{
    gemm(lnq,  w,           nullptr, qb, Bb*Sq, Dd, Dd, 0, 0);
    gemm(lnkv, w + Dd*Dd,   nullptr, kb, Bb*Sk, Dd, Dd, 0, 0);
    gemm(lnkv, w + 2*Dd*Dd, nullptr, vb, Bb*Sk, Dd, Dd, 0, 0);
    if (Sq >= 1024 && mask == nullptr && Sk == 128) {
        dim3 g(Sq/QT, NHh, Bb);
        attn_big_kernel<<<g, 128>>>(qb, kb, vb, cb, Sq);
    } else {
        dim3 g(Sq, NHh, Bb);
        attn_kernel<<<g, 128>>>(qb, kb, vb, mask, cb, Sq, Sk);
    }
    gemm(cb, w + 3*Dd*Dd, nullptr, x, Bb*Sq, Dd, Dd, 0, 1);
}

static void encode_pair(float* Sb, float* Tb, const unsigned char* mS, const unsigned char* mT,
                        int S, const float* cxw, const float* ff1, const float* ff2,
                        float* lnS, float* lnT, float* qb, float* kb, float* vb, float* cb, float* hid)
{
    int rows = Bb*S;
    const float* sa = cxw;
    const float* ca = cxw + 4*Dd*Dd;
    ln_kernel<<<rows, 128>>>(Sb, lnS);
    attn_block(lnS, lnS, sa, mS, Sb, S, S, qb, kb, vb, cb);
    ln_kernel<<<rows, 128>>>(Tb, lnT);
    attn_block(lnT, lnT, sa, mT, Tb, S, S, qb, kb, vb, cb);
    ln_kernel<<<rows, 128>>>(Sb, lnS);
    ln_kernel<<<rows, 128>>>(Tb, lnT);
    attn_block(lnS, lnT, ca, nullptr, Sb, S, S, qb, kb, vb, cb);
    attn_block(lnT, lnS, ca, nullptr, Tb, S, S, qb, kb, vb, cb);
    ln_kernel<<<rows, 128>>>(Sb, lnS);
    gemm(lnS, ff1, nullptr, hid, rows, Dd, FFf, 1, 0);
    gemm(hid, ff2, nullptr, Sb, rows, FFf, Dd, 0, 1);
    ln_kernel<<<rows, 128>>>(Tb, lnT);
    gemm(lnT, ff1, nullptr, hid, rows, Dd, FFf, 1, 0);
    gemm(hid, ff2, nullptr, Tb, rows, FFf, Dd, 0, 1);
}

#define GETSYM(var, sym) do { void* _p; cudaGetSymbolAddress(&_p, sym); var = (decltype(var))_p; } while (0)

extern "C" void kernel_launch(void* const* d_in, const int* in_sizes, int n_in,
                              void* d_out_v, int out_size)
{
    (void)in_sizes; (void)n_in; (void)out_size;
    const float* pos[2]    = {(const float*)d_in[0], (const float*)d_in[1]};
    const int*   visidx[2] = {(const int*)d_in[2], (const int*)d_in[4]};
    const int*   mskidx[2] = {(const int*)d_in[3], (const int*)d_in[5]};
    const float* tok_w1 = (const float*)d_in[6];  const float* tok_b1 = (const float*)d_in[7];
    const float* tok_w2 = (const float*)d_in[8];  const float* tok_b2 = (const float*)d_in[9];
    const float* tok_w3 = (const float*)d_in[10]; const float* tok_b3 = (const float*)d_in[11];
    const float* tok_w4 = (const float*)d_in[12]; const float* tok_b4 = (const float*)d_in[13];
    const float* mask_token = (const float*)d_in[14];
    const float* cx_attn = (const float*)d_in[15];
    const float* cx_ff1  = (const float*)d_in[16]; const float* cx_ff2 = (const float*)d_in[17];
    const float* enc_sa  = (const float*)d_in[18]; const float* enc_ca = (const float*)d_in[19];
    const float* enc_ff1 = (const float*)d_in[20]; const float* enc_ff2 = (const float*)d_in[21];
    const float* dec_ca  = (const float*)d_in[22]; const float* dec_ff1 = (const float*)d_in[23];
    const float* dec_ff2 = (const float*)d_in[24];
    const float* up_w1 = (const float*)d_in[25]; const float* up_b1 = (const float*)d_in[26];
    const float* up_w2 = (const float*)d_in[27]; const float* up_b2 = (const float*)d_in[28];
    float* dout = (float*)d_out_v;

    float *centersB, *relB, *f1B, *f2B, *gmaxB, *catB, *t1B, *t2B, *tokensB;
    float *cpeB, *ppeB, *vis3B, *visB, *fullB, *decxB, *mbufB, *lnmB, *lnSB, *lnTB;
    float *lnbigB, *qB, *kB, *vB, *ctxB, *hidB, *upcatB, *upw1pB, *nn3wB, *lpartB;
    int *nidxB, *nidxSB, *nn3iB;
    unsigned char *mfullB, *mvisB;
    GETSYM(centersB, g_centers); GETSYM(nidxB, g_nidx); GETSYM(nidxSB, g_nidxS);
    GETSYM(relB, g_rel); GETSYM(f1B, g_f1); GETSYM(f2B, g_f2); GETSYM(gmaxB, g_gmax);
    GETSYM(catB, g_cat); GETSYM(t1B, g_t1); GETSYM(t2B, g_t2); GETSYM(tokensB, g_tokens);
    GETSYM(cpeB, g_cpe); GETSYM(ppeB, g_ppe); GETSYM(mfullB, g_mfull); GETSYM(mvisB, g_mvis);
    GETSYM(vis3B, g_vis3); GETSYM(visB, g_visbuf); GETSYM(fullB, g_fullbuf); GETSYM(decxB, g_decx);
    GETSYM(mbufB, g_mbuf); GETSYM(lnmB, g_lnm); GETSYM(lnSB, g_lnS); GETSYM(lnTB, g_lnT);
    GETSYM(lnbigB, g_lnbig); GETSYM(qB, g_qbuf); GETSYM(kB, g_kbuf); GETSYM(vB, g_vbuf);
    GETSYM(ctxB, g_ctx); GETSYM(hidB, g_hid); GETSYM(upcatB, g_upcat); GETSYM(upw1pB, g_upw1p);
    GETSYM(nn3iB, g_nn3i); GETSYM(nn3wB, g_nn3w); GETSYM(lpartB, g_lpart);

    float* centers[2] = {centersB, centersB + Bb*Gg*3};
    float* tokens[2]  = {tokensB,  tokensB  + Bb*Gg*Dd};
    float* cpe[2]     = {cpeB,     cpeB     + Bb*Gg*Dd};
    float* ppe[2]     = {ppeB,     ppeB     + Bb*Np*Dd};
    float* visb[2]    = {visB,     visB     + Bb*Vv*Dd};
    float* fullb[2]   = {fullB,    fullB    + Bb*Gg*Dd};
    float* decx[2]    = {decxB,    decxB    + Bb*(Mm+Vv)*Dd};
    unsigned char* mfull[2] = {mfullB, mfullB + Bb*Gg*Gg};
    unsigned char* mvis[2]  = {mvisB,  mvisB  + Bb*Vv*Vv};

    // Phase 1: tokenize + PE + masks
    for (int s = 0; s < 2; s++) {
        fps_kernel<<<Bb, 512>>>(pos[s], centers[s]);
        knn_big_kernel<<<Bb*Gg, 128>>>(centers[s], pos[s], nidxB);
        group_rel_kernel<<<(Bb*Gg*Kk + 255)/256, 256>>>(pos[s], centers[s], nidxB, relB);
        gemm(relB, tok_w1, tok_b1, f1B, Bb*Gg*Kk, 3, 128, 1, 0);
        gemm(f1B, tok_w2, tok_b2, f2B, Bb*Gg*Kk, 128, 256, 0, 0);
        gmax_kernel<<<(Bb*Gg*256 + 255)/256, 256>>>(f2B, gmaxB, 256);
        cat_kernel<<<(Bb*Gg*Kk*512 + 255)/256, 256>>>(gmaxB, f2B, catB);
        gemm(catB, tok_w3, tok_b3, t1B, Bb*Gg*Kk, 512, 512, 1, 0);
        gemm(t1B, tok_w4, tok_b4, t2B, Bb*Gg*Kk, 512, Dd, 0, 0);
        gmax_kernel<<<(Bb*Gg*Dd + 255)/256, 256>>>(t2B, tokens[s], Dd);
        pe_kernel<<<(Bb*Gg*Dd + 255)/256, 256>>>(centers[s], cpe[s], Bb*Gg);
        pe_kernel<<<(Bb*Np*Dd + 255)/256, 256>>>(pos[s], ppe[s], Bb*Np);
        knn_small_kernel<<<Bb*Gg, 128>>>(centers[s], Gg, nidxSB);
        zero_u8_kernel<<<(Bb*Gg*Gg + 255)/256, 256>>>(mfull[s], Bb*Gg*Gg);
        scatter_mask_kernel<<<(Bb*Gg*Kk + 255)/256, 256>>>(nidxSB, mfull[s], Gg);
        gather_kernel<<<Bb*Vv, 32>>>(centers[s], visidx[s], vis3B, Vv, Gg, 3);
        knn_small_kernel<<<Bb*Vv, 128>>>(vis3B, Vv, nidxSB);
        zero_u8_kernel<<<(Bb*Vv*Vv + 255)/256, 256>>>(mvis[s], Bb*Vv*Vv);
        scatter_mask_kernel<<<(Bb*Vv*Kk + 255)/256, 256>>>(nidxSB, mvis[s], Vv);
        gather_kernel<<<Bb*Vv, 128>>>(tokens[s], visidx[s], visb[s], Vv, Gg, Dd);
        copy_kernel<<<(Bb*Gg*Dd + 255)/256, 256>>>(tokens[s], fullb[s], Bb*Gg*Dd);
    }

    // Phase 2: cross encoders
    encode_pair(visb[0], visb[1], mvis[0], mvis[1], Vv, cx_attn, cx_ff1, cx_ff2,
                lnSB, lnTB, qB, kB, vB, ctxB, hidB);
    encode_pair(fullb[0], fullb[1], mfull[0], mfull[1], Gg, cx_attn, cx_ff1, cx_ff2,
                lnSB, lnTB, qB, kB, vB, ctxB, hidB);

    // Phase 3: MAE decoder + loss
    for (int s = 0; s < 2; s++) {
        int o = 1 - s;
        decq_kernel<<<(Bb*(Mm+Vv)*Dd + 255)/256, 256>>>(visb[s], cpe[s], mask_token,
                                                        mskidx[s], visidx[s], decx[s]);
        add_kernel<<<(Bb*Gg*Dd + 255)/256, 256>>>(fullb[o], cpe[o], mbufB, Bb*Gg*Dd);
        ln_kernel<<<Bb*Gg, 128>>>(mbufB, lnmB);
        for (int l = 0; l < 4; l++) {
            const float* sal = enc_sa + (size_t)l*4*Dd*Dd;
            const float* cal = enc_ca + (size_t)l*4*Dd*Dd;
            ln_kernel<<<Bb*(Mm+Vv), 128>>>(decx[s], lnSB);
            attn_block(lnSB, lnSB, sal, nullptr, decx[s], Mm+Vv, Mm+Vv, qB, kB, vB, ctxB);
            ln_kernel<<<Bb*(Mm+Vv), 128>>>(decx[s], lnSB);
            attn_block(lnSB, lnmB, cal, nullptr, decx[s], Mm+Vv, Gg, qB, kB, vB, ctxB);
            ln_kernel<<<Bb*(Mm+Vv), 128>>>(decx[s], lnSB);
            gemm(lnSB, enc_ff1 + (size_t)l*Dd*FFf, nullptr, hidB, Bb*(Mm+Vv), Dd, FFf, 1, 0);
            gemm(hidB, enc_ff2 + (size_t)l*FFf*Dd, nullptr, decx[s], Bb*(Mm+Vv), FFf, Dd, 0, 1);
        }
        loss_kernel<<<64, 256>>>(fullb[s], mskidx[s], decx[s], lpartB + s*64);
    }

    // Phase 4: upsample + dense decoder
    padw_kernel<<<(UPK*Dd + 255)/256, 256>>>(up_w1, upw1pB);
    for (int s = 0; s < 2; s++) {
        float* X = dout + (size_t)s*Bb*Np*Dd;
        nn3_kernel<<<(Bb*Np + 255)/256, 256>>>(pos[s], centers[s], nn3iB, nn3wB);
        upcat_kernel<<<Bb*Np, 128>>>(fullb[s], pos[s], nn3iB, nn3wB, upcatB);
        gemm(upcatB, upw1pB, up_b1, lnbigB, Bb*Np, UPK, Dd, 1, 0);
        gemm(lnbigB, up_w2, up_b2, ctxB, Bb*Np, Dd, Dd, 1, 0);
        add_kernel<<<(Bb*Np*Dd + 255)/256, 256>>>(ctxB, ppe[s], X, Bb*Np*Dd);
        add_kernel<<<(Bb*Gg*Dd + 255)/256, 256>>>(fullb[s], cpe[s], mbufB, Bb*Gg*Dd);
        ln_kernel<<<Bb*Gg, 128>>>(mbufB, lnmB);
        for (int l = 0; l < 2; l++) {
            const float* cal = dec_ca + (size_t)l*4*Dd*Dd;
            ln_kernel<<<Bb*Np, 128>>>(X, lnbigB);
            attn_block(lnbigB, lnmB, cal, nullptr, X, Np, Gg, qB, kB, vB, ctxB);
            ln_kernel<<<Bb*Np, 128>>>(X, lnbigB);
            gemm(lnbigB, dec_ff1 + (size_t)l*Dd*FFf, nullptr, hidB, Bb*Np, Dd, FFf, 1, 0);
            gemm(hidB, dec_ff2 + (size_t)l*FFf*Dd, nullptr, X, Bb*Np, FFf, Dd, 0, 1);
        }
    }
    loss_final_kernel<<<1, 1>>>(lpartB, lpartB + 64, dout + (size_t)2*Bb*Np*Dd);
}

// round 8
// speedup vs baseline: 4.3647x; 1.1519x over previous
#include <cuda_runtime.h>
#include <cuda_fp16.h>
#include <math.h>
#include <stdint.h>

#define Bb 8
#define Np 4096
#define Gg 128
#define Kk 16
#define Vv 64
#define Mm 64
#define Dd 384
#define NHh 8
#define DHh 48
#define FFf 1536
#define UPK 416

// fp32 buffers
__device__ float g_centers[2][Bb*Gg*3];
__device__ int   g_nidx[Bb*Gg*Kk];
__device__ int   g_nidxS[Bb*Gg*Kk];
__device__ float g_t2[Bb*Gg*Kk*Dd];
__device__ float g_tokens[2][Bb*Gg*Dd];
__device__ float g_cpe[2][Bb*Gg*Dd];
__device__ float g_ppe[2][Bb*Np*Dd];
__device__ unsigned char g_mfull[2][Bb*Gg*Gg];
__device__ unsigned char g_mvis[2][Bb*Vv*Vv];
__device__ float g_vis3[Bb*Vv*3];
__device__ float g_visbuf[2][Bb*Vv*Dd];
__device__ float g_fullbuf[2][Bb*Gg*Dd];
__device__ float g_decx[2][Bb*(Mm+Vv)*Dd];
__device__ float g_mbuf[Bb*Gg*Dd];
__device__ float g_qbuf[Bb*Np*Dd];
__device__ float g_kbuf[Bb*Gg*Dd];
__device__ float g_vbuf[Bb*Gg*Dd];
__device__ int   g_nn3i[Bb*Np*3];
__device__ float g_nn3w[Bb*Np*3];
__device__ float g_lpart[2*64];

// half buffers (16B aligned for cp.async)
__device__ __align__(16) __half g_relh[16384*32];
__device__ __align__(16) __half g_f1h[16384*128];
__device__ __align__(16) __half g_f2h[16384*256];
__device__ __align__(16) __half g_gmaxh[Bb*Gg*256];
__device__ __align__(16) __half g_cath[16384*512];
__device__ __align__(16) __half g_t1h[16384*512];
__device__ __align__(16) __half g_lnSh[Bb*Gg*Dd];
__device__ __align__(16) __half g_lnTh[Bb*Gg*Dd];
__device__ __align__(16) __half g_lnmh[Bb*Gg*Dd];
__device__ __align__(16) __half g_lnbigh[Bb*Np*Dd];
__device__ __align__(16) __half g_hidh[Bb*Np*FFf];
__device__ __align__(16) __half g_ctxh[Bb*Np*Dd];
__device__ __align__(16) __half g_upcath[Bb*Np*UPK];

// transposed+padded fp16 weights: each mat stored [Nc][KdPad]
#define MSZ 147456
#define OFF_W1    0
#define OFF_W2    (OFF_W1 + 32*128)
#define OFF_W3    (OFF_W2 + 128*256)
#define OFF_W4    (OFF_W3 + 512*512)
#define OFF_CX    (OFF_W4 + 512*384)
#define OFF_ENCSA (OFF_CX + 8*MSZ)
#define OFF_ENCCA (OFF_ENCSA + 16*MSZ)
#define OFF_DECCA (OFF_ENCCA + 16*MSZ)
#define OFF_CXFF1 (OFF_DECCA + 8*MSZ)
#define OFF_CXFF2 (OFF_CXFF1 + 384*1536)
#define OFF_EFF1  (OFF_CXFF2 + 1536*384)
#define OFF_EFF2  (OFF_EFF1 + 4*384*1536)
#define OFF_DFF1  (OFF_EFF2 + 4*1536*384)
#define OFF_DFF2  (OFF_DFF1 + 2*384*1536)
#define OFF_UP1   (OFF_DFF2 + 2*1536*384)
#define OFF_UP2   (OFF_UP1 + 416*384)
#define WTH_TOT   (OFF_UP2 + 384*384)
__device__ __align__(16) __half g_wth[WTH_TOT];

// weight convert: src [cnt][Kd][Nc] fp32 -> dst [cnt][Nc][KdPad] fp16 (zero-pad K)
__global__ void wtconv_kernel(const float* __restrict__ src, __half* __restrict__ dst,
                              int Kd, int KdPad, int Nc, int cnt)
{
    long i = (long)blockIdx.x*256 + threadIdx.x;
    long tot = (long)cnt*Nc*KdPad;
    if (i >= tot) return;
    int per = Nc*KdPad;
    int mt = (int)(i/per), r = (int)(i%per);
    int n = r/KdPad, k = r%KdPad;
    float v = (k < Kd) ? src[(size_t)mt*Kd*Nc + (size_t)k*Nc + n] : 0.f;
    dst[i] = __float2half(v);
}

// unified fp16 tensor-core GEMM: 128x128 tile, KT=32, m16n8k16, cp.async double buffered
// rows%128==0, Nc%128==0, Kd%32==0. Output fp32 (Cf) or fp16 (Ch).
__global__ __launch_bounds__(256)
void gemm_h_kernel(const __half* __restrict__ A, const __half* __restrict__ Wt,
                   const float* __restrict__ bias, float* __restrict__ Cf,
                   __half* __restrict__ Ch, int rows, int Kd, int Nc, int relu, int accum)
{
    __shared__ __half Ah[2][128][40];
    __shared__ __half Wh[2][128][40];
    int tid = threadIdx.x, wid = tid>>5, lane = tid&31;
    int g = lane>>2, tig = lane&3;
    int wm = (wid>>1)*32, wn = (wid&1)*64;
    int row0 = blockIdx.y*128, col0 = blockIdx.x*128;
    float c[2][8][4] = {};
    int nIter = Kd/32;

    #pragma unroll
    for (int l = 0; l < 2; l++) {
        int ci = tid + l*256;
        int m = ci>>2, f = ci&3;
        const __half* ga = A + (size_t)(row0+m)*Kd + f*8;
        uint32_t sa = (uint32_t)__cvta_generic_to_shared(&Ah[0][m][f*8]);
        asm volatile("cp.async.cg.shared.global [%0], [%1], 16;" :: "r"(sa), "l"(ga));
        const __half* gw = Wt + (size_t)(col0+m)*Kd + f*8;
        uint32_t sw = (uint32_t)__cvta_generic_to_shared(&Wh[0][m][f*8]);
        asm volatile("cp.async.cg.shared.global [%0], [%1], 16;" :: "r"(sw), "l"(gw));
    }
    asm volatile("cp.async.commit_group;");

    for (int it = 0; it < nIter; it++) {
        int cur = it & 1;
        if (it + 1 < nIter) {
            int k0 = (it+1)*32;
            #pragma unroll
            for (int l = 0; l < 2; l++) {
                int ci = tid + l*256;
                int m = ci>>2, f = ci&3;
                const __half* ga = A + (size_t)(row0+m)*Kd + k0 + f*8;
                uint32_t sa = (uint32_t)__cvta_generic_to_shared(&Ah[cur^1][m][f*8]);
                asm volatile("cp.async.cg.shared.global [%0], [%1], 16;" :: "r"(sa), "l"(ga));
                const __half* gw = Wt + (size_t)(col0+m)*Kd + k0 + f*8;
                uint32_t sw = (uint32_t)__cvta_generic_to_shared(&Wh[cur^1][m][f*8]);
                asm volatile("cp.async.cg.shared.global [%0], [%1], 16;" :: "r"(sw), "l"(gw));
            }
            asm volatile("cp.async.commit_group;");
            asm volatile("cp.async.wait_group 1;");
        } else {
            asm volatile("cp.async.wait_group 0;");
        }
        __syncthreads();
        #pragma unroll
        for (int st = 0; st < 2; st++) {
            int kb = st*16;
            uint32_t a[2][4], b[8][2];
            #pragma unroll
            for (int mt = 0; mt < 2; mt++) {
                int m0 = wm + mt*16;
                a[mt][0] = *(const uint32_t*)&Ah[cur][m0+g  ][kb+2*tig];
                a[mt][1] = *(const uint32_t*)&Ah[cur][m0+g+8][kb+2*tig];
                a[mt][2] = *(const uint32_t*)&Ah[cur][m0+g  ][kb+2*tig+8];
                a[mt][3] = *(const uint32_t*)&Ah[cur][m0+g+8][kb+2*tig+8];
            }
            #pragma unroll
            for (int nt = 0; nt < 8; nt++) {
                int n0 = wn + nt*8;
                b[nt][0] = *(const uint32_t*)&Wh[cur][n0+g][kb+2*tig];
                b[nt][1] = *(const uint32_t*)&Wh[cur][n0+g][kb+2*tig+8];
            }
            #pragma unroll
            for (int mt = 0; mt < 2; mt++)
                #pragma unroll
                for (int nt = 0; nt < 8; nt++)
                    asm volatile(
                        "mma.sync.aligned.m16n8k16.row.col.f32.f16.f16.f32 "
                        "{%0,%1,%2,%3}, {%4,%5,%6,%7}, {%8,%9}, {%0,%1,%2,%3};"
                        : "+f"(c[mt][nt][0]), "+f"(c[mt][nt][1]),
                          "+f"(c[mt][nt][2]), "+f"(c[mt][nt][3])
                        : "r"(a[mt][0]), "r"(a[mt][1]), "r"(a[mt][2]), "r"(a[mt][3]),
                          "r"(b[nt][0]), "r"(b[nt][1]));
        }
        __syncthreads();
    }
    #pragma unroll
    for (int mt = 0; mt < 2; mt++) {
        #pragma unroll
        for (int nt = 0; nt < 8; nt++) {
            int r0 = row0 + wm + mt*16 + g;
            int cc = col0 + wn + nt*8 + 2*tig;
            float v0 = c[mt][nt][0], v1 = c[mt][nt][1];
            float v2 = c[mt][nt][2], v3 = c[mt][nt][3];
            if (bias) { float b0 = bias[cc], b1 = bias[cc+1]; v0 += b0; v1 += b1; v2 += b0; v3 += b1; }
            if (relu) { v0 = fmaxf(v0,0.f); v1 = fmaxf(v1,0.f); v2 = fmaxf(v2,0.f); v3 = fmaxf(v3,0.f); }
            size_t o0 = (size_t)r0*Nc + cc;
            size_t o1 = (size_t)(r0+8)*Nc + cc;
            if (Ch) {
                Ch[o0] = __float2half(v0); Ch[o0+1] = __float2half(v1);
                Ch[o1] = __float2half(v2); Ch[o1+1] = __float2half(v3);
            } else if (accum) {
                Cf[o0] += v0; Cf[o0+1] += v1; Cf[o1] += v2; Cf[o1+1] += v3;
            } else {
                Cf[o0] = v0; Cf[o0+1] = v1; Cf[o1] = v2; Cf[o1+1] = v3;
            }
        }
    }
}

// LayerNorm fp32 -> fp16
__global__ void ln_kernel(const float* __restrict__ x, __half* __restrict__ y)
{
    int row = blockIdx.x, t = threadIdx.x;
    const float* xr = x + (size_t)row*Dd;
    __shared__ float red[128];
    float a = xr[t], b = xr[t+128], c = xr[t+256];
    red[t] = a + b + c; __syncthreads();
    for (int o = 64; o > 0; o >>= 1) { if (t < o) red[t] += red[t+o]; __syncthreads(); }
    float m = red[0] / (float)Dd; __syncthreads();
    float da=a-m, db=b-m, dc=c-m;
    red[t] = da*da + db*db + dc*dc; __syncthreads();
    for (int o = 64; o > 0; o >>= 1) { if (t < o) red[t] += red[t+o]; __syncthreads(); }
    float inv = rsqrtf(red[0] / (float)Dd + 1e-5f);
    __half* yr = y + (size_t)row*Dd;
    yr[t]=__float2half(da*inv); yr[t+128]=__float2half(db*inv); yr[t+256]=__float2half(dc*inv);
}

// small attention: one block per (q,h,b); Sk<=128; ctx out fp16
__global__ void attn_kernel(const float* __restrict__ q, const float* __restrict__ kmat,
                            const float* __restrict__ vmat, const unsigned char* __restrict__ mask,
                            __half* __restrict__ ctx, int Sq, int Sk)
{
    int qi = blockIdx.x, h = blockIdx.y, b = blockIdx.z, t = threadIdx.x;
    __shared__ float shq[DHh], shp[128], red[128];
    const float* qr = q + ((size_t)(b*Sq + qi))*Dd + h*DHh;
    if (t < DHh) shq[t] = qr[t];
    __syncthreads();
    float val = -3e38f;
    if (t < Sk) {
        const float* kr = kmat + ((size_t)(b*Sk + t))*Dd + h*DHh;
        float s = 0.f;
        #pragma unroll
        for (int d = 0; d < DHh; d++) s += shq[d]*kr[d];
        s /= sqrtf((float)DHh);
        if (mask && !mask[((size_t)b*Sq + qi)*Sk + t]) s = -1e9f;
        val = s;
    }
    red[t] = val; __syncthreads();
    for (int o = 64; o > 0; o >>= 1) { if (t < o) red[t] = fmaxf(red[t], red[t+o]); __syncthreads(); }
    float mx = red[0]; __syncthreads();
    float e = (t < Sk) ? expf(val - mx) : 0.f;
    shp[t] = e; red[t] = e; __syncthreads();
    for (int o = 64; o > 0; o >>= 1) { if (t < o) red[t] += red[t+o]; __syncthreads(); }
    float inv = 1.f / red[0];
    if (t < DHh) {
        float acc = 0.f;
        const float* vb = vmat + ((size_t)(b*Sk))*Dd + h*DHh + t;
        for (int kk = 0; kk < Sk; kk++) acc += shp[kk]*vb[(size_t)kk*Dd];
        ctx[((size_t)(b*Sq + qi))*Dd + h*DHh + t] = __float2half(acc*inv);
    }
}

// big attention: 16 queries/block, Sk==128, no mask; ctx out fp16
#define QT 16
__global__ __launch_bounds__(128)
void attn_big_kernel(const float* __restrict__ q, const float* __restrict__ kmat,
                     const float* __restrict__ vmat, __half* __restrict__ ctx, int Sq)
{
    int qt = blockIdx.x, h = blockIdx.y, b = blockIdx.z, t = threadIdx.x;
    __shared__ float shq[QT][DHh];
    __shared__ float sc[QT][129];
    __shared__ float Vs[128][DHh];
    for (int i = t; i < QT*DHh; i += 128) {
        int qi = i / DHh, d = i % DHh;
        shq[qi][d] = q[((size_t)(b*Sq + qt*QT + qi))*Dd + h*DHh + d];
    }
    for (int i = t; i < 128*DHh; i += 128) {
        int k = i / DHh, d = i % DHh;
        Vs[k][d] = vmat[((size_t)(b*128 + k))*Dd + h*DHh + d];
    }
    __syncthreads();
    float kr[DHh];
    {
        const float* kp = kmat + ((size_t)(b*128 + t))*Dd + h*DHh;
        #pragma unroll
        for (int d = 0; d < DHh; d++) kr[d] = kp[d];
    }
    float inv_s = sqrtf((float)DHh);
    #pragma unroll 1
    for (int qi = 0; qi < QT; qi++) {
        float s = 0.f;
        #pragma unroll
        for (int d = 0; d < DHh; d++) s += shq[qi][d]*kr[d];
        sc[qi][t] = s / inv_s;
    }
    __syncthreads();
    int w = t >> 5, lane = t & 31;
    for (int qi = w; qi < QT; qi += 4) {
        float v0 = sc[qi][lane], v1 = sc[qi][lane+32], v2 = sc[qi][lane+64], v3 = sc[qi][lane+96];
        float mx = fmaxf(fmaxf(v0,v1), fmaxf(v2,v3));
        #pragma unroll
        for (int o = 16; o > 0; o >>= 1) mx = fmaxf(mx, __shfl_xor_sync(0xffffffffu, mx, o));
        float e0=expf(v0-mx), e1=expf(v1-mx), e2=expf(v2-mx), e3=expf(v3-mx);
        float sum = e0+e1+e2+e3;
        #pragma unroll
        for (int o = 16; o > 0; o >>= 1) sum += __shfl_xor_sync(0xffffffffu, sum, o);
        float inv = 1.f / sum;
        sc[qi][lane]=e0*inv; sc[qi][lane+32]=e1*inv; sc[qi][lane+64]=e2*inv; sc[qi][lane+96]=e3*inv;
    }
    __syncthreads();
    for (int i = t; i < QT*DHh; i += 128) {
        int qi = i / DHh, d = i % DHh;
        float acc = 0.f;
        #pragma unroll 4
        for (int k = 0; k < 128; k++) acc += sc[qi][k] * Vs[k][d];
        ctx[((size_t)(b*Sq + qt*QT + qi))*Dd + h*DHh + d] = __float2half(acc);
    }
}

__global__ void fps_kernel(const float* __restrict__ pos, float* __restrict__ centers)
{
    int b = blockIdx.x, t = threadIdx.x;
    __shared__ float mind[Np];
    __shared__ float rv[512]; __shared__ int ri[512]; __shared__ float curp[3];
    const float* P = pos + (size_t)b*Np*3;
    float* C = centers + (size_t)b*Gg*3;
    if (t == 0) { curp[0]=P[0]; curp[1]=P[1]; curp[2]=P[2]; C[0]=P[0]; C[1]=P[1]; C[2]=P[2]; }
    __syncthreads();
    for (int i = t; i < Np; i += 512) {
        float dx=P[3*i]-curp[0], dy=P[3*i+1]-curp[1], dz=P[3*i+2]-curp[2];
        mind[i] = dx*dx + dy*dy + dz*dz;
    }
    __syncthreads();
    for (int s = 1; s < Gg; s++) {
        float bv = -3e38f; int bi = 0x7fffffff;
        for (int i = t; i < Np; i += 512) { float v = mind[i]; if (v > bv) { bv = v; bi = i; } }
        rv[t] = bv; ri[t] = bi; __syncthreads();
        for (int o = 256; o > 0; o >>= 1) {
            if (t < o && (rv[t+o] > rv[t] || (rv[t+o] == rv[t] && ri[t+o] < ri[t]))) { rv[t]=rv[t+o]; ri[t]=ri[t+o]; }
            __syncthreads();
        }
        if (t == 0) {
            int nxt = ri[0];
            curp[0]=P[3*nxt]; curp[1]=P[3*nxt+1]; curp[2]=P[3*nxt+2];
            C[3*s]=curp[0]; C[3*s+1]=curp[1]; C[3*s+2]=curp[2];
        }
        __syncthreads();
        for (int i = t; i < Np; i += 512) {
            float dx=P[3*i]-curp[0], dy=P[3*i+1]-curp[1], dz=P[3*i+2]-curp[2];
            float d = dx*dx + dy*dy + dz*dz;
            if (d < mind[i]) mind[i] = d;
        }
        __syncthreads();
    }
}

__global__ void knn_big_kernel(const float* __restrict__ qpts, const float* __restrict__ rpts,
                               int* __restrict__ nidx)
{
    int blk = blockIdx.x, b = blk / Gg, qc = blk % Gg, t = threadIdx.x;
    __shared__ float dist[Np];
    __shared__ float rv[128]; __shared__ int ri[128];
    const float* Q = qpts + ((size_t)b*Gg + qc)*3;
    float qx=Q[0], qy=Q[1], qz=Q[2], qq = qx*qx+qy*qy+qz*qz;
    const float* R = rpts + (size_t)b*Np*3;
    for (int i = t; i < Np; i += 128) {
        float rx=R[3*i], ry=R[3*i+1], rz=R[3*i+2];
        dist[i] = qq + (rx*rx+ry*ry+rz*rz) - 2.f*(qx*rx+qy*ry+qz*rz);
    }
    __syncthreads();
    for (int kk = 0; kk < Kk; kk++) {
        float bv = 3e38f; int bi = 0x7fffffff;
        for (int i = t; i < Np; i += 128) { float v = dist[i]; if (v < bv) { bv = v; bi = i; } }
        rv[t] = bv; ri[t] = bi; __syncthreads();
        for (int o = 64; o > 0; o >>= 1) {
            if (t < o && (rv[t+o] < rv[t] || (rv[t+o] == rv[t] && ri[t+o] < ri[t]))) { rv[t]=rv[t+o]; ri[t]=ri[t+o]; }
            __syncthreads();
        }
        if (t == 0) { nidx[((size_t)b*Gg + qc)*Kk + kk] = ri[0]; dist[ri[0]] = 3e38f; }
        __syncthreads();
    }
}

__global__ void knn_small_kernel(const float* __restrict__ pts, int S, int* __restrict__ nidx)
{
    int blk = blockIdx.x, b = blk / S, qi = blk % S, t = threadIdx.x;
    __shared__ float dist[128]; __shared__ float rv[128]; __shared__ int ri[128];
    const float* Q = pts + ((size_t)b*S + qi)*3;
    float qx=Q[0], qy=Q[1], qz=Q[2], qq=qx*qx+qy*qy+qz*qz;
    if (t < S) {
        const float* R = pts + ((size_t)b*S + t)*3;
        dist[t] = qq + (R[0]*R[0]+R[1]*R[1]+R[2]*R[2]) - 2.f*(qx*R[0]+qy*R[1]+qz*R[2]);
    } else dist[t] = 3e38f;
    __syncthreads();
    for (int kk = 0; kk < Kk; kk++) {
        rv[t] = dist[t]; ri[t] = t; __syncthreads();
        for (int o = 64; o > 0; o >>= 1) {
            if (t < o && (rv[t+o] < rv[t] || (rv[t+o] == rv[t] && ri[t+o] < ri[t]))) { rv[t]=rv[t+o]; ri[t]=ri[t+o]; }
            __syncthreads();
        }
        if (t == 0) { nidx[((size_t)b*S + qi)*Kk + kk] = ri[0]; dist[ri[0]] = 3e38f; }
        __syncthreads();
    }
}

__global__ void zero_u8_kernel(unsigned char* m, int n)
{ int i = blockIdx.x*blockDim.x + threadIdx.x; if (i < n) m[i] = 0; }

__global__ void scatter_mask_kernel(const int* __restrict__ nidx, unsigned char* __restrict__ m, int S)
{
    int i = blockIdx.x*blockDim.x + threadIdx.x;
    if (i >= Bb*S*Kk) return;
    int b = i / (S*Kk), r = (i / Kk) % S;
    m[((size_t)b*S + r)*S + nidx[i]] = 1;
}

// rel -> half, padded rows of 32
__global__ void group_rel_kernel(const float* __restrict__ pos, const float* __restrict__ centers,
                                 const int* __restrict__ nidx, __half* __restrict__ rel)
{
    int i = blockIdx.x*blockDim.x + threadIdx.x;
    if (i >= Bb*Gg*Kk) return;
    int b = i / (Gg*Kk), g = (i / Kk) % Gg, src = nidx[i];
    const float* P = pos + ((size_t)b*Np + src)*3;
    const float* C = centers + ((size_t)b*Gg + g)*3;
    __half* rp = rel + (size_t)i*32;
    rp[0] = __float2half(P[0]-C[0]);
    rp[1] = __float2half(P[1]-C[1]);
    rp[2] = __float2half(P[2]-C[2]);
    for (int j = 3; j < 32; j++) rp[j] = __float2half(0.f);
}

__global__ void gmax_h_kernel(const __half* __restrict__ f, __half* __restrict__ g, int C)
{
    int i = blockIdx.x*blockDim.x + threadIdx.x;
    if (i >= Bb*Gg*C) return;
    int bg = i / C, c = i % C;
    const __half* fp = f + (size_t)bg*Kk*C + c;
    float m = __half2float(fp[0]);
    #pragma unroll
    for (int k = 1; k < Kk; k++) m = fmaxf(m, __half2float(fp[(size_t)k*C]));
    g[i] = __float2half(m);
}

__global__ void gmax_f_kernel(const float* __restrict__ f, float* __restrict__ g, int C)
{
    int i = blockIdx.x*blockDim.x + threadIdx.x;
    if (i >= Bb*Gg*C) return;
    int bg = i / C, c = i % C;
    const float* fp = f + (size_t)bg*Kk*C + c;
    float m = fp[0];
    #pragma unroll
    for (int k = 1; k < Kk; k++) m = fmaxf(m, fp[(size_t)k*C]);
    g[i] = m;
}

__global__ void cat_kernel(const __half* __restrict__ g, const __half* __restrict__ f, __half* __restrict__ cat)
{
    int i = blockIdx.x*blockDim.x + threadIdx.x;
    if (i >= Bb*Gg*Kk*512) return;
    int c = i % 512, r = i / 512, bg = r / Kk;
    cat[i] = (c < 256) ? g[(size_t)bg*256 + c] : f[(size_t)r*256 + (c - 256)];
}

__global__ void pe_kernel(const float* __restrict__ xyz, float* __restrict__ pe, int rows)
{
    int i = blockIdx.x*blockDim.x + threadIdx.x;
    if (i >= rows*Dd) return;
    int r = i / Dd, j = i % Dd, c = j / 128, jj = j % 128;
    float x = xyz[(size_t)r*3 + c];
    float dt = powf(10000.0f, (float)(2*(jj/2)) / 128.0f);
    float p = x / dt;
    pe[i] = (jj & 1) ? cosf(p) : sinf(p);
}

__global__ void gather_kernel(const float* __restrict__ src, const int* __restrict__ idx,
                              float* __restrict__ dst, int outR, int inR, int W)
{
    int row = blockIdx.x, b = row / outR, r = row % outR;
    int s = idx[(size_t)b*outR + r];
    const float* sp = src + ((size_t)b*inR + s)*W;
    float* dp = dst + (size_t)row*W;
    for (int w = threadIdx.x; w < W; w += blockDim.x) dp[w] = sp[w];
}

__global__ void decq_kernel(const float* __restrict__ visout, const float* __restrict__ cpe,
                            const float* __restrict__ mask_token, const int* __restrict__ mskidx,
                            const int* __restrict__ visidx, float* __restrict__ x)
{
    int i = blockIdx.x*blockDim.x + threadIdx.x;
    if (i >= Bb*(Mm+Vv)*Dd) return;
    int d = i % Dd, r = (i / Dd) % (Mm+Vv), b = i / (Dd*(Mm+Vv));
    float base; int pidx;
    if (r < Mm) { base = mask_token[d]; pidx = mskidx[(size_t)b*Mm + r]; }
    else { base = visout[((size_t)b*Vv + (r-Mm))*Dd + d]; pidx = visidx[(size_t)b*Vv + (r-Mm)]; }
    x[i] = base + cpe[((size_t)b*Gg + pidx)*Dd + d];
}

__global__ void add_kernel(const float* __restrict__ a, const float* __restrict__ b,
                           float* __restrict__ c, int n)
{ int i = blockIdx.x*blockDim.x + threadIdx.x; if (i < n) c[i] = a[i] + b[i]; }

__global__ void nn3_kernel(const float* __restrict__ pos, const float* __restrict__ centers,
                           int* __restrict__ oi, float* __restrict__ ow)
{
    int i = blockIdx.x*blockDim.x + threadIdx.x;
    if (i >= Bb*Np) return;
    int b = i / Np;
    const float* P = pos + (size_t)i*3;
    float px=P[0], py=P[1], pz=P[2], qq=px*px+py*py+pz*pz;
    float d0=3e38f, d1=3e38f, d2=3e38f; int i0=-1, i1=-1, i2=-1;
    const float* C = centers + (size_t)b*Gg*3;
    for (int g = 0; g < Gg; g++) {
        float cx=C[3*g], cy=C[3*g+1], cz=C[3*g+2];
        float d = qq + (cx*cx+cy*cy+cz*cz) - 2.f*(px*cx+py*cy+pz*cz);
        if (d < d0) { d2=d1;i2=i1; d1=d0;i1=i0; d0=d;i0=g; }
        else if (d < d1) { d2=d1;i2=i1; d1=d;i1=g; }
        else if (d < d2) { d2=d;i2=g; }
    }
    float w0=1.f/(fmaxf(d0,0.f)+1e-8f), w1=1.f/(fmaxf(d1,0.f)+1e-8f), w2=1.f/(fmaxf(d2,0.f)+1e-8f);
    float s = w0+w1+w2;
    ow[3*i]=w0/s; ow[3*i+1]=w1/s; ow[3*i+2]=w2/s;
    oi[3*i]=i0; oi[3*i+1]=i1; oi[3*i+2]=i2;
}

// upsample concat -> half, rows of UPK (pad zeros)
__global__ void upcat_kernel(const float* __restrict__ feats, const float* __restrict__ pos,
                             const int* __restrict__ oi, const float* __restrict__ ow,
                             __half* __restrict__ cat)
{
    int row = blockIdx.x, b = row / Np, t = threadIdx.x;
    int i0=oi[3*row], i1=oi[3*row+1], i2=oi[3*row+2];
    float w0=ow[3*row], w1=ow[3*row+1], w2=ow[3*row+2];
    const float* F = feats + (size_t)b*Gg*Dd;
    __half* cp = cat + (size_t)row*UPK;
    for (int d = t; d < Dd; d += 128)
        cp[d] = __float2half(w0*F[(size_t)i0*Dd+d] + w1*F[(size_t)i1*Dd+d] + w2*F[(size_t)i2*Dd+d]);
    if (t < 32) cp[Dd + t] = __float2half((t < 3) ? pos[(size_t)row*3 + t] : 0.f);
}

__global__ void loss_kernel(const float* __restrict__ fullout, const int* __restrict__ mskidx,
                            const float* __restrict__ decx, float* __restrict__ partial)
{
    __shared__ float red[256];
    int t = threadIdx.x;
    float acc = 0.f;
    for (int i = blockIdx.x*256 + t; i < Bb*Mm*Dd; i += 64*256) {
        int d = i % Dd, r = (i / Dd) % Mm, b = i / (Dd*Mm);
        int gi = mskidx[(size_t)b*Mm + r];
        float tv = fullout[((size_t)b*Gg + gi)*Dd + d];
        float pv = decx[((size_t)b*(Mm+Vv) + r)*Dd + d];
        float a = fabsf(pv - tv);
        acc += (a < 2.0f) ? 0.25f*a*a : a - 1.0f;
    }
    red[t] = acc; __syncthreads();
    for (int o = 128; o > 0; o >>= 1) { if (t < o) red[t] += red[t+o]; __syncthreads(); }
    if (t == 0) partial[blockIdx.x] = red[0];
}

__global__ void loss_final_kernel(const float* __restrict__ pa, const float* __restrict__ pb,
                                  float* __restrict__ out)
{
    float sa = 0.f, sb = 0.f;
    for (int i = 0; i < 64; i++) { sa += pa[i]; sb += pb[i]; }
    float cnt = (float)(Bb*Mm*Dd);
    out[0] = 0.5f*(sa/cnt) + 0.5f*(sb/cnt);
}

__global__ void copy_kernel(const float* __restrict__ a, float* __restrict__ b, int n)
{ int i = blockIdx.x*blockDim.x + threadIdx.x; if (i < n) b[i] = a[i]; }

// ------------------------------ host side --------------------------------

static void gemm_h(const __half* A, const __half* Wt, const float* bias,
                   float* Cf, __half* Ch, int rows, int Kd, int Nc, int relu, int accum)
{
    dim3 grid(Nc/128, rows/128);
    gemm_h_kernel<<<grid, 256>>>(A, Wt, bias, Cf, Ch, rows, Kd, Nc, relu, accum);
}

static __half* WTH;
static float *QB, *KB, *VB;
static __half *CTXH;

static void attn_block(const __half* lnq, const __half* lnkv, long woff,
                       const unsigned char* mask, float* x, int Sq, int Sk)
{
    gemm_h(lnq,  WTH + woff,           nullptr, QB, nullptr, Bb*Sq, Dd, Dd, 0, 0);
    gemm_h(lnkv, WTH + woff + MSZ,     nullptr, KB, nullptr, Bb*Sk, Dd, Dd, 0, 0);
    gemm_h(lnkv, WTH + woff + 2*MSZ,   nullptr, VB, nullptr, Bb*Sk, Dd, Dd, 0, 0);
    if (Sq >= 1024 && mask == nullptr && Sk == 128) {
        dim3 g(Sq/QT, NHh, Bb);
        attn_big_kernel<<<g, 128>>>(QB, KB, VB, CTXH, Sq);
    } else {
        dim3 g(Sq, NHh, Bb);
        attn_kernel<<<g, 128>>>(QB, KB, VB, mask, CTXH, Sq, Sk);
    }
    gemm_h(CTXH, WTH + woff + 3*MSZ, nullptr, x, nullptr, Bb*Sq, Dd, Dd, 0, 1);
}

static void encode_pair(float* Sb, float* Tb, const unsigned char* mS, const unsigned char* mT,
                        int S, __half* lnS, __half* lnT, __half* hid)
{
    int rows = Bb*S;
    ln_kernel<<<rows, 128>>>(Sb, lnS);
    attn_block(lnS, lnS, OFF_CX, mS, Sb, S, S);
    ln_kernel<<<rows, 128>>>(Tb, lnT);
    attn_block(lnT, lnT, OFF_CX, mT, Tb, S, S);
    ln_kernel<<<rows, 128>>>(Sb, lnS);
    ln_kernel<<<rows, 128>>>(Tb, lnT);
    attn_block(lnS, lnT, OFF_CX + 4*MSZ, nullptr, Sb, S, S);
    attn_block(lnT, lnS, OFF_CX + 4*MSZ, nullptr, Tb, S, S);
    ln_kernel<<<rows, 128>>>(Sb, lnS);
    gemm_h(lnS, WTH + OFF_CXFF1, nullptr, nullptr, hid, rows, Dd, FFf, 1, 0);
    gemm_h(hid, WTH + OFF_CXFF2, nullptr, Sb, nullptr, rows, FFf, Dd, 0, 1);
    ln_kernel<<<rows, 128>>>(Tb, lnT);
    gemm_h(lnT, WTH + OFF_CXFF1, nullptr, nullptr, hid, rows, Dd, FFf, 1, 0);
    gemm_h(hid, WTH + OFF_CXFF2, nullptr, Tb, nullptr, rows, FFf, Dd, 0, 1);
}

static void wc(const float* src, long off, int Kd, int KdPad, int Nc, int cnt)
{
    long tot = (long)cnt*Nc*KdPad;
    wtconv_kernel<<<(int)((tot + 255)/256), 256>>>(src, WTH + off, Kd, KdPad, Nc, cnt);
}

#define GETSYM(var, sym) do { void* _p; cudaGetSymbolAddress(&_p, sym); var = (decltype(var))_p; } while (0)

extern "C" void kernel_launch(void* const* d_in, const int* in_sizes, int n_in,
                              void* d_out_v, int out_size)
{
    (void)in_sizes; (void)n_in; (void)out_size;
    const float* pos[2]    = {(const float*)d_in[0], (const float*)d_in[1]};
    const int*   visidx[2] = {(const int*)d_in[2], (const int*)d_in[4]};
    const int*   mskidx[2] = {(const int*)d_in[3], (const int*)d_in[5]};
    const float* tok_w1 = (const float*)d_in[6];  const float* tok_b1 = (const float*)d_in[7];
    const float* tok_w2 = (const float*)d_in[8];  const float* tok_b2 = (const float*)d_in[9];
    const float* tok_w3 = (const float*)d_in[10]; const float* tok_b3 = (const float*)d_in[11];
    const float* tok_w4 = (const float*)d_in[12]; const float* tok_b4 = (const float*)d_in[13];
    const float* mask_token = (const float*)d_in[14];
    const float* cx_attn = (const float*)d_in[15];
    const float* cx_ff1  = (const float*)d_in[16]; const float* cx_ff2 = (const float*)d_in[17];
    const float* enc_sa  = (const float*)d_in[18]; const float* enc_ca = (const float*)d_in[19];
    const float* enc_ff1 = (const float*)d_in[20]; const float* enc_ff2 = (const float*)d_in[21];
    const float* dec_ca  = (const float*)d_in[22]; const float* dec_ff1 = (const float*)d_in[23];
    const float* dec_ff2 = (const float*)d_in[24];
    const float* up_w1 = (const float*)d_in[25]; const float* up_b1 = (const float*)d_in[26];
    const float* up_w2 = (const float*)d_in[27]; const float* up_b2 = (const float*)d_in[28];
    float* dout = (float*)d_out_v;

    float *centersB, *t2B, *tokensB, *cpeB, *ppeB, *vis3B, *visB, *fullB, *decxB, *mbufB, *nn3wB, *lpartB;
    int *nidxB, *nidxSB, *nn3iB;
    unsigned char *mfullB, *mvisB;
    __half *relH, *f1H, *f2H, *gmaxH, *catH, *t1H, *lnSH, *lnTH, *lnmH, *lnbigH, *hidH, *upcatH;
    GETSYM(centersB, g_centers); GETSYM(nidxB, g_nidx); GETSYM(nidxSB, g_nidxS);
    GETSYM(t2B, g_t2); GETSYM(tokensB, g_tokens);
    GETSYM(cpeB, g_cpe); GETSYM(ppeB, g_ppe); GETSYM(mfullB, g_mfull); GETSYM(mvisB, g_mvis);
    GETSYM(vis3B, g_vis3); GETSYM(visB, g_visbuf); GETSYM(fullB, g_fullbuf); GETSYM(decxB, g_decx);
    GETSYM(mbufB, g_mbuf); GETSYM(QB, g_qbuf); GETSYM(KB, g_kbuf); GETSYM(VB, g_vbuf);
    GETSYM(nn3iB, g_nn3i); GETSYM(nn3wB, g_nn3w); GETSYM(lpartB, g_lpart);
    GETSYM(relH, g_relh); GETSYM(f1H, g_f1h); GETSYM(f2H, g_f2h); GETSYM(gmaxH, g_gmaxh);
    GETSYM(catH, g_cath); GETSYM(t1H, g_t1h); GETSYM(lnSH, g_lnSh); GETSYM(lnTH, g_lnTh);
    GETSYM(lnmH, g_lnmh); GETSYM(lnbigH, g_lnbigh); GETSYM(hidH, g_hidh);
    GETSYM(CTXH, g_ctxh); GETSYM(upcatH, g_upcath); GETSYM(WTH, g_wth);

    float* centers[2] = {centersB, centersB + Bb*Gg*3};
    float* tokens[2]  = {tokensB,  tokensB  + Bb*Gg*Dd};
    float* cpe[2]     = {cpeB,     cpeB     + Bb*Gg*Dd};
    float* ppe[2]     = {ppeB,     ppeB     + Bb*Np*Dd};
    float* visb[2]    = {visB,     visB     + Bb*Vv*Dd};
    float* fullb[2]   = {fullB,    fullB    + Bb*Gg*Dd};
    float* decx[2]    = {decxB,    decxB    + Bb*(Mm+Vv)*Dd};
    unsigned char* mfull[2] = {mfullB, mfullB + Bb*Gg*Gg};
    unsigned char* mvis[2]  = {mvisB,  mvisB  + Bb*Vv*Vv};

    // Phase 0: weight conversion (transpose + pad + fp16)
    wc(tok_w1, OFF_W1, 3, 32, 128, 1);
    wc(tok_w2, OFF_W2, 128, 128, 256, 1);
    wc(tok_w3, OFF_W3, 512, 512, 512, 1);
    wc(tok_w4, OFF_W4, 512, 512, Dd, 1);
    wc(cx_attn, OFF_CX, Dd, Dd, Dd, 8);
    wc(enc_sa, OFF_ENCSA, Dd, Dd, Dd, 16);
    wc(enc_ca, OFF_ENCCA, Dd, Dd, Dd, 16);
    wc(dec_ca, OFF_DECCA, Dd, Dd, Dd, 8);
    wc(cx_ff1, OFF_CXFF1, Dd, Dd, FFf, 1);
    wc(cx_ff2, OFF_CXFF2, FFf, FFf, Dd, 1);
    wc(enc_ff1, OFF_EFF1, Dd, Dd, FFf, 4);
    wc(enc_ff2, OFF_EFF2, FFf, FFf, Dd, 4);
    wc(dec_ff1, OFF_DFF1, Dd, Dd, FFf, 2);
    wc(dec_ff2, OFF_DFF2, FFf, FFf, Dd, 2);
    wc(up_w1, OFF_UP1, Dd + 3, UPK, Dd, 1);
    wc(up_w2, OFF_UP2, Dd, Dd, Dd, 1);

    // Phase 1: tokenize + PE + masks
    for (int s = 0; s < 2; s++) {
        fps_kernel<<<Bb, 512>>>(pos[s], centers[s]);
        knn_big_kernel<<<Bb*Gg, 128>>>(centers[s], pos[s], nidxB);
        group_rel_kernel<<<(Bb*Gg*Kk + 255)/256, 256>>>(pos[s], centers[s], nidxB, relH);
        gemm_h(relH, WTH + OFF_W1, tok_b1, nullptr, f1H, 16384, 32, 128, 1, 0);
        gemm_h(f1H, WTH + OFF_W2, tok_b2, nullptr, f2H, 16384, 128, 256, 0, 0);
        gmax_h_kernel<<<(Bb*Gg*256 + 255)/256, 256>>>(f2H, gmaxH, 256);
        cat_kernel<<<(Bb*Gg*Kk*512 + 255)/256, 256>>>(gmaxH, f2H, catH);
        gemm_h(catH, WTH + OFF_W3, tok_b3, nullptr, t1H, 16384, 512, 512, 1, 0);
        gemm_h(t1H, WTH + OFF_W4, tok_b4, t2B, nullptr, 16384, 512, Dd, 0, 0);
        gmax_f_kernel<<<(Bb*Gg*Dd + 255)/256, 256>>>(t2B, tokens[s], Dd);
        pe_kernel<<<(Bb*Gg*Dd + 255)/256, 256>>>(centers[s], cpe[s], Bb*Gg);
        pe_kernel<<<(Bb*Np*Dd + 255)/256, 256>>>(pos[s], ppe[s], Bb*Np);
        knn_small_kernel<<<Bb*Gg, 128>>>(centers[s], Gg, nidxSB);
        zero_u8_kernel<<<(Bb*Gg*Gg + 255)/256, 256>>>(mfull[s], Bb*Gg*Gg);
        scatter_mask_kernel<<<(Bb*Gg*Kk + 255)/256, 256>>>(nidxSB, mfull[s], Gg);
        gather_kernel<<<Bb*Vv, 32>>>(centers[s], visidx[s], vis3B, Vv, Gg, 3);
        knn_small_kernel<<<Bb*Vv, 128>>>(vis3B, Vv, nidxSB);
        zero_u8_kernel<<<(Bb*Vv*Vv + 255)/256, 256>>>(mvis[s], Bb*Vv*Vv);
        scatter_mask_kernel<<<(Bb*Vv*Kk + 255)/256, 256>>>(nidxSB, mvis[s], Vv);
        gather_kernel<<<Bb*Vv, 128>>>(tokens[s], visidx[s], visb[s], Vv, Gg, Dd);
        copy_kernel<<<(Bb*Gg*Dd + 255)/256, 256>>>(tokens[s], fullb[s], Bb*Gg*Dd);
    }

    // Phase 2: cross encoders
    encode_pair(visb[0], visb[1], mvis[0], mvis[1], Vv, lnSH, lnTH, hidH);
    encode_pair(fullb[0], fullb[1], mfull[0], mfull[1], Gg, lnSH, lnTH, hidH);

    // Phase 3: MAE decoder + loss
    for (int s = 0; s < 2; s++) {
        int o = 1 - s;
        decq_kernel<<<(Bb*(Mm+Vv)*Dd + 255)/256, 256>>>(visb[s], cpe[s], mask_token,
                                                        mskidx[s], visidx[s], decx[s]);
        add_kernel<<<(Bb*Gg*Dd + 255)/256, 256>>>(fullb[o], cpe[o], mbufB, Bb*Gg*Dd);
        ln_kernel<<<Bb*Gg, 128>>>(mbufB, lnmH);
        for (int l = 0; l < 4; l++) {
            ln_kernel<<<Bb*(Mm+Vv), 128>>>(decx[s], lnSH);
            attn_block(lnSH, lnSH, OFF_ENCSA + (long)l*4*MSZ, nullptr, decx[s], Mm+Vv, Mm+Vv);
            ln_kernel<<<Bb*(Mm+Vv), 128>>>(decx[s], lnSH);
            attn_block(lnSH, lnmH, OFF_ENCCA + (long)l*4*MSZ, nullptr, decx[s], Mm+Vv, Gg);
            ln_kernel<<<Bb*(Mm+Vv), 128>>>(decx[s], lnSH);
            gemm_h(lnSH, WTH + OFF_EFF1 + (long)l*Dd*FFf, nullptr, nullptr, hidH, Bb*(Mm+Vv), Dd, FFf, 1, 0);
            gemm_h(hidH, WTH + OFF_EFF2 + (long)l*FFf*Dd, nullptr, decx[s], nullptr, Bb*(Mm+Vv), FFf, Dd, 0, 1);
        }
        loss_kernel<<<64, 256>>>(fullb[s], mskidx[s], decx[s], lpartB + s*64);
    }

    // Phase 4: upsample + dense decoder
    for (int s = 0; s < 2; s++) {
        float* X = dout + (size_t)s*Bb*Np*Dd;
        nn3_kernel<<<(Bb*Np + 255)/256, 256>>>(pos[s], centers[s], nn3iB, nn3wB);
        upcat_kernel<<<Bb*Np, 128>>>(fullb[s], pos[s], nn3iB, nn3wB, upcatH);
        gemm_h(upcatH, WTH + OFF_UP1, up_b1, nullptr, hidH, Bb*Np, UPK, Dd, 1, 0);
        gemm_h(hidH, WTH + OFF_UP2, up_b2, QB, nullptr, Bb*Np, Dd, Dd, 1, 0);
        add_kernel<<<(Bb*Np*Dd + 255)/256, 256>>>(QB, ppe[s], X, Bb*Np*Dd);
        add_kernel<<<(Bb*Gg*Dd + 255)/256, 256>>>(fullb[s], cpe[s], mbufB, Bb*Gg*Dd);
        ln_kernel<<<Bb*Gg, 128>>>(mbufB, lnmH);
        for (int l = 0; l < 2; l++) {
            ln_kernel<<<Bb*Np, 128>>>(X, lnbigH);
            attn_block(lnbigH, lnmH, OFF_DECCA + (long)l*4*MSZ, nullptr, X, Np, Gg);
            ln_kernel<<<Bb*Np, 128>>>(X, lnbigH);
            gemm_h(lnbigH, WTH + OFF_DFF1 + (long)l*Dd*FFf, nullptr, nullptr, hidH, Bb*Np, Dd, FFf, 1, 0);
            gemm_h(hidH, WTH + OFF_DFF2 + (long)l*FFf*Dd, nullptr, X, nullptr, Bb*Np, FFf, Dd, 0, 1);
        }
    }
    loss_final_kernel<<<1, 1>>>(lpartB, lpartB + 64, dout + (size_t)2*Bb*Np*Dd);
}

// round 9
// speedup vs baseline: 4.4528x; 1.0202x over previous
#include <cuda_runtime.h>
#include <cuda_fp16.h>
#include <math.h>
#include <stdint.h>

#define Bb 8
#define Np 4096
#define Gg 128
#define Kk 16
#define Vv 64
#define Mm 64
#define Dd 384
#define NHh 8
#define DHh 48
#define FFf 1536
#define UPK 416

// fp32 buffers
__device__ float g_centers[2][Bb*Gg*3];
__device__ int   g_nidx[Bb*Gg*Kk];
__device__ int   g_nidxS[Bb*Gg*Kk];
__device__ float g_t2[Bb*Gg*Kk*Dd];
__device__ float g_tokens[2][Bb*Gg*Dd];
__device__ float g_cpe[2][Bb*Gg*Dd];
__device__ float g_ppe[2][Bb*Np*Dd];
__device__ unsigned char g_mfull[2][Bb*Gg*Gg];
__device__ unsigned char g_mvis[2][Bb*Vv*Vv];
__device__ float g_vis3[Bb*Vv*3];
__device__ float g_visbuf[2][Bb*Vv*Dd];
__device__ float g_fullbuf[2][Bb*Gg*Dd];
__device__ float g_decx[2][Bb*(Mm+Vv)*Dd];
__device__ float g_mbuf[Bb*Gg*Dd];
__device__ float g_qbuf[Bb*Np*Dd];
__device__ float g_kbuf[Bb*Gg*Dd];
__device__ float g_vbuf[Bb*Gg*Dd];
__device__ int   g_nn3i[Bb*Np*3];
__device__ float g_nn3w[Bb*Np*3];
__device__ float g_lpart[2*64];

// half buffers (16B aligned for cp.async)
__device__ __align__(16) __half g_relh[16384*32];
__device__ __align__(16) __half g_f1h[16384*128];
__device__ __align__(16) __half g_f2h[16384*256];
__device__ __align__(16) __half g_gmaxh[Bb*Gg*256];
__device__ __align__(16) __half g_cath[16384*512];
__device__ __align__(16) __half g_t1h[16384*512];
__device__ __align__(16) __half g_lnSh[Bb*Gg*Dd];
__device__ __align__(16) __half g_lnTh[Bb*Gg*Dd];
__device__ __align__(16) __half g_lnmh[Bb*Gg*Dd];
__device__ __align__(16) __half g_lnbigh[Bb*Np*Dd];
__device__ __align__(16) __half g_hidh[Bb*Np*FFf];
__device__ __align__(16) __half g_ctxh[Bb*Np*Dd];
__device__ __align__(16) __half g_upcath[Bb*Np*UPK];

// transposed+padded fp16 weights: each mat stored [Nc][KdPad]
#define MSZ 147456
#define OFF_W1    0
#define OFF_W2    (OFF_W1 + 32*128)
#define OFF_W3    (OFF_W2 + 128*256)
#define OFF_W4    (OFF_W3 + 512*512)
#define OFF_CX    (OFF_W4 + 512*384)
#define OFF_ENCSA (OFF_CX + 8*MSZ)
#define OFF_ENCCA (OFF_ENCSA + 16*MSZ)
#define OFF_DECCA (OFF_ENCCA + 16*MSZ)
#define OFF_CXFF1 (OFF_DECCA + 8*MSZ)
#define OFF_CXFF2 (OFF_CXFF1 + 384*1536)
#define OFF_EFF1  (OFF_CXFF2 + 1536*384)
#define OFF_EFF2  (OFF_EFF1 + 4*384*1536)
#define OFF_DFF1  (OFF_EFF2 + 4*1536*384)
#define OFF_DFF2  (OFF_DFF1 + 2*384*1536)
#define OFF_UP1   (OFF_DFF2 + 2*1536*384)
#define OFF_UP2   (OFF_UP1 + 416*384)
#define WTH_TOT   (OFF_UP2 + 384*384)
__device__ __align__(16) __half g_wth[WTH_TOT];

// ---- fused weight conversion: all 16 matrices in one launch ----
struct WConvArgs {
    const float* src[16];
    long start[17];
    int Kd[16], KdPad[16], Nc[16];
};

__global__ void wtconv_all_kernel(WConvArgs A, __half* __restrict__ dst)
{
    long i = (long)blockIdx.x*256 + threadIdx.x;
    if (i >= A.start[16]) return;
    int s = 0;
    while (s < 15 && i >= A.start[s+1]) s++;
    long li = i - A.start[s];
    int Kd = A.Kd[s], Kp = A.KdPad[s], Nc = A.Nc[s];
    long per = (long)Nc*Kp;
    int mt = (int)(li/per);
    long r = li % per;
    int n = (int)(r/Kp), k = (int)(r%Kp);
    float v = (k < Kd) ? A.src[s][(size_t)mt*Kd*Nc + (size_t)k*Nc + n] : 0.f;
    dst[i] = __float2half(v);
}

// unified fp16 tensor-core GEMM: 128x128 tile, KT=32, m16n8k16, ldmatrix frags,
// cp.async double buffered. rows%128==0, Nc%128==0, Kd%32==0. Out fp32 or fp16.
__global__ __launch_bounds__(256)
void gemm_h_kernel(const __half* __restrict__ A, const __half* __restrict__ Wt,
                   const float* __restrict__ bias, float* __restrict__ Cf,
                   __half* __restrict__ Ch, int rows, int Kd, int Nc, int relu, int accum)
{
    __shared__ __half Ah[2][128][40];
    __shared__ __half Wh[2][128][40];
    int tid = threadIdx.x, wid = tid>>5, lane = tid&31;
    int g = lane>>2, tig = lane&3;
    int wm = (wid>>1)*32, wn = (wid&1)*64;
    int row0 = blockIdx.y*128, col0 = blockIdx.x*128;
    float c[2][8][4] = {};
    int nIter = Kd/32;

    // per-lane ldmatrix addresses (byte offsets into stage 0)
    int lr = lane & 7, lj = lane >> 3;
    uint32_t ah0 = (uint32_t)__cvta_generic_to_shared(&Ah[0][0][0]);
    uint32_t wh0 = (uint32_t)__cvta_generic_to_shared(&Wh[0][0][0]);
    uint32_t aAddr[2], wAddr[4];
    #pragma unroll
    for (int mt = 0; mt < 2; mt++)
        aAddr[mt] = ah0 + (uint32_t)((wm + mt*16 + lr + (lj&1)*8)*80 + ((lj>>1)*8)*2);
    #pragma unroll
    for (int p = 0; p < 4; p++)
        wAddr[p] = wh0 + (uint32_t)((wn + p*16 + lr + ((lj>>1)&1)*8)*80 + ((lj&1)*8)*2);

    #pragma unroll
    for (int l = 0; l < 2; l++) {
        int ci = tid + l*256;
        int m = ci>>2, f = ci&3;
        const __half* ga = A + (size_t)(row0+m)*Kd + f*8;
        uint32_t sa = (uint32_t)__cvta_generic_to_shared(&Ah[0][m][f*8]);
        asm volatile("cp.async.cg.shared.global [%0], [%1], 16;" :: "r"(sa), "l"(ga));
        const __half* gw = Wt + (size_t)(col0+m)*Kd + f*8;
        uint32_t sw = (uint32_t)__cvta_generic_to_shared(&Wh[0][m][f*8]);
        asm volatile("cp.async.cg.shared.global [%0], [%1], 16;" :: "r"(sw), "l"(gw));
    }
    asm volatile("cp.async.commit_group;");

    for (int it = 0; it < nIter; it++) {
        int cur = it & 1;
        if (it + 1 < nIter) {
            int k0 = (it+1)*32;
            #pragma unroll
            for (int l = 0; l < 2; l++) {
                int ci = tid + l*256;
                int m = ci>>2, f = ci&3;
                const __half* ga = A + (size_t)(row0+m)*Kd + k0 + f*8;
                uint32_t sa = (uint32_t)__cvta_generic_to_shared(&Ah[cur^1][m][f*8]);
                asm volatile("cp.async.cg.shared.global [%0], [%1], 16;" :: "r"(sa), "l"(ga));
                const __half* gw = Wt + (size_t)(col0+m)*Kd + k0 + f*8;
                uint32_t sw = (uint32_t)__cvta_generic_to_shared(&Wh[cur^1][m][f*8]);
                asm volatile("cp.async.cg.shared.global [%0], [%1], 16;" :: "r"(sw), "l"(gw));
            }
            asm volatile("cp.async.commit_group;");
            asm volatile("cp.async.wait_group 1;");
        } else {
            asm volatile("cp.async.wait_group 0;");
        }
        __syncthreads();
        #pragma unroll
        for (int st = 0; st < 2; st++) {
            uint32_t kOff = (uint32_t)(cur*10240 + st*32);
            uint32_t a[2][4], b[8][2];
            #pragma unroll
            for (int mt = 0; mt < 2; mt++)
                asm volatile("ldmatrix.sync.aligned.m8n8.x4.shared.b16 {%0,%1,%2,%3}, [%4];"
                    : "=r"(a[mt][0]), "=r"(a[mt][1]), "=r"(a[mt][2]), "=r"(a[mt][3])
                    : "r"(aAddr[mt] + kOff));
            #pragma unroll
            for (int p = 0; p < 4; p++) {
                uint32_t d0, d1, d2, d3;
                asm volatile("ldmatrix.sync.aligned.m8n8.x4.shared.b16 {%0,%1,%2,%3}, [%4];"
                    : "=r"(d0), "=r"(d1), "=r"(d2), "=r"(d3)
                    : "r"(wAddr[p] + kOff));
                b[2*p][0] = d0; b[2*p][1] = d1; b[2*p+1][0] = d2; b[2*p+1][1] = d3;
            }
            #pragma unroll
            for (int mt = 0; mt < 2; mt++)
                #pragma unroll
                for (int nt = 0; nt < 8; nt++)
                    asm volatile(
                        "mma.sync.aligned.m16n8k16.row.col.f32.f16.f16.f32 "
                        "{%0,%1,%2,%3}, {%4,%5,%6,%7}, {%8,%9}, {%0,%1,%2,%3};"
                        : "+f"(c[mt][nt][0]), "+f"(c[mt][nt][1]),
                          "+f"(c[mt][nt][2]), "+f"(c[mt][nt][3])
                        : "r"(a[mt][0]), "r"(a[mt][1]), "r"(a[mt][2]), "r"(a[mt][3]),
                          "r"(b[nt][0]), "r"(b[nt][1]));
        }
        __syncthreads();
    }
    #pragma unroll
    for (int mt = 0; mt < 2; mt++) {
        #pragma unroll
        for (int nt = 0; nt < 8; nt++) {
            int r0 = row0 + wm + mt*16 + g;
            int cc = col0 + wn + nt*8 + 2*tig;
            float v0 = c[mt][nt][0], v1 = c[mt][nt][1];
            float v2 = c[mt][nt][2], v3 = c[mt][nt][3];
            if (bias) { float b0 = bias[cc], b1 = bias[cc+1]; v0 += b0; v1 += b1; v2 += b0; v3 += b1; }
            if (relu) { v0 = fmaxf(v0,0.f); v1 = fmaxf(v1,0.f); v2 = fmaxf(v2,0.f); v3 = fmaxf(v3,0.f); }
            size_t o0 = (size_t)r0*Nc + cc;
            size_t o1 = (size_t)(r0+8)*Nc + cc;
            if (Ch) {
                Ch[o0] = __float2half(v0); Ch[o0+1] = __float2half(v1);
                Ch[o1] = __float2half(v2); Ch[o1+1] = __float2half(v3);
            } else if (accum) {
                Cf[o0] += v0; Cf[o0+1] += v1; Cf[o1] += v2; Cf[o1+1] += v3;
            } else {
                Cf[o0] = v0; Cf[o0+1] = v1; Cf[o1] = v2; Cf[o1+1] = v3;
            }
        }
    }
}

// LayerNorm fp32 -> fp16
__global__ void ln_kernel(const float* __restrict__ x, __half* __restrict__ y)
{
    int row = blockIdx.x, t = threadIdx.x;
    const float* xr = x + (size_t)row*Dd;
    __shared__ float red[128];
    float a = xr[t], b = xr[t+128], c = xr[t+256];
    red[t] = a + b + c; __syncthreads();
    for (int o = 64; o > 0; o >>= 1) { if (t < o) red[t] += red[t+o]; __syncthreads(); }
    float m = red[0] / (float)Dd; __syncthreads();
    float da=a-m, db=b-m, dc=c-m;
    red[t] = da*da + db*db + dc*dc; __syncthreads();
    for (int o = 64; o > 0; o >>= 1) { if (t < o) red[t] += red[t+o]; __syncthreads(); }
    float inv = rsqrtf(red[0] / (float)Dd + 1e-5f);
    __half* yr = y + (size_t)row*Dd;
    yr[t]=__float2half(da*inv); yr[t+128]=__float2half(db*inv); yr[t+256]=__float2half(dc*inv);
}

// small attention: one block per (q,h,b); Sk<=128; ctx out fp16
__global__ void attn_kernel(const float* __restrict__ q, const float* __restrict__ kmat,
                            const float* __restrict__ vmat, const unsigned char* __restrict__ mask,
                            __half* __restrict__ ctx, int Sq, int Sk)
{
    int qi = blockIdx.x, h = blockIdx.y, b = blockIdx.z, t = threadIdx.x;
    __shared__ float shq[DHh], shp[128], red[128];
    const float* qr = q + ((size_t)(b*Sq + qi))*Dd + h*DHh;
    if (t < DHh) shq[t] = qr[t];
    __syncthreads();
    float val = -3e38f;
    if (t < Sk) {
        const float* kr = kmat + ((size_t)(b*Sk + t))*Dd + h*DHh;
        float s = 0.f;
        #pragma unroll
        for (int d = 0; d < DHh; d++) s += shq[d]*kr[d];
        s /= sqrtf((float)DHh);
        if (mask && !mask[((size_t)b*Sq + qi)*Sk + t]) s = -1e9f;
        val = s;
    }
    red[t] = val; __syncthreads();
    for (int o = 64; o > 0; o >>= 1) { if (t < o) red[t] = fmaxf(red[t], red[t+o]); __syncthreads(); }
    float mx = red[0]; __syncthreads();
    float e = (t < Sk) ? expf(val - mx) : 0.f;
    shp[t] = e; red[t] = e; __syncthreads();
    for (int o = 64; o > 0; o >>= 1) { if (t < o) red[t] += red[t+o]; __syncthreads(); }
    float inv = 1.f / red[0];
    if (t < DHh) {
        float acc = 0.f;
        const float* vb = vmat + ((size_t)(b*Sk))*Dd + h*DHh + t;
        for (int kk = 0; kk < Sk; kk++) acc += shp[kk]*vb[(size_t)kk*Dd];
        ctx[((size_t)(b*Sq + qi))*Dd + h*DHh + t] = __float2half(acc*inv);
    }
}

// big attention: 16 queries/block, Sk==128, no mask; ctx out fp16
#define QT 16
__global__ __launch_bounds__(128)
void attn_big_kernel(const float* __restrict__ q, const float* __restrict__ kmat,
                     const float* __restrict__ vmat, __half* __restrict__ ctx, int Sq)
{
    int qt = blockIdx.x, h = blockIdx.y, b = blockIdx.z, t = threadIdx.x;
    __shared__ float shq[QT][DHh];
    __shared__ float sc[QT][129];
    __shared__ float Vs[128][DHh];
    for (int i = t; i < QT*DHh; i += 128) {
        int qi = i / DHh, d = i % DHh;
        shq[qi][d] = q[((size_t)(b*Sq + qt*QT + qi))*Dd + h*DHh + d];
    }
    for (int i = t; i < 128*DHh; i += 128) {
        int k = i / DHh, d = i % DHh;
        Vs[k][d] = vmat[((size_t)(b*128 + k))*Dd + h*DHh + d];
    }
    __syncthreads();
    float kr[DHh];
    {
        const float* kp = kmat + ((size_t)(b*128 + t))*Dd + h*DHh;
        #pragma unroll
        for (int d = 0; d < DHh; d++) kr[d] = kp[d];
    }
    float inv_s = sqrtf((float)DHh);
    #pragma unroll 1
    for (int qi = 0; qi < QT; qi++) {
        float s = 0.f;
        #pragma unroll
        for (int d = 0; d < DHh; d++) s += shq[qi][d]*kr[d];
        sc[qi][t] = s / inv_s;
    }
    __syncthreads();
    int w = t >> 5, lane = t & 31;
    for (int qi = w; qi < QT; qi += 4) {
        float v0 = sc[qi][lane], v1 = sc[qi][lane+32], v2 = sc[qi][lane+64], v3 = sc[qi][lane+96];
        float mx = fmaxf(fmaxf(v0,v1), fmaxf(v2,v3));
        #pragma unroll
        for (int o = 16; o > 0; o >>= 1) mx = fmaxf(mx, __shfl_xor_sync(0xffffffffu, mx, o));
        float e0=expf(v0-mx), e1=expf(v1-mx), e2=expf(v2-mx), e3=expf(v3-mx);
        float sum = e0+e1+e2+e3;
        #pragma unroll
        for (int o = 16; o > 0; o >>= 1) sum += __shfl_xor_sync(0xffffffffu, sum, o);
        float inv = 1.f / sum;
        sc[qi][lane]=e0*inv; sc[qi][lane+32]=e1*inv; sc[qi][lane+64]=e2*inv; sc[qi][lane+96]=e3*inv;
    }
    __syncthreads();
    for (int i = t; i < QT*DHh; i += 128) {
        int qi = i / DHh, d = i % DHh;
        float acc = 0.f;
        #pragma unroll 4
        for (int k = 0; k < 128; k++) acc += sc[qi][k] * Vs[k][d];
        ctx[((size_t)(b*Sq + qt*QT + qi))*Dd + h*DHh + d] = __float2half(acc);
    }
}

__global__ void fps_kernel(const float* __restrict__ pos, float* __restrict__ centers)
{
    int b = blockIdx.x, t = threadIdx.x;
    __shared__ float mind[Np];
    __shared__ float rv[512]; __shared__ int ri[512]; __shared__ float curp[3];
    const float* P = pos + (size_t)b*Np*3;
    float* C = centers + (size_t)b*Gg*3;
    if (t == 0) { curp[0]=P[0]; curp[1]=P[1]; curp[2]=P[2]; C[0]=P[0]; C[1]=P[1]; C[2]=P[2]; }
    __syncthreads();
    for (int i = t; i < Np; i += 512) {
        float dx=P[3*i]-curp[0], dy=P[3*i+1]-curp[1], dz=P[3*i+2]-curp[2];
        mind[i] = dx*dx + dy*dy + dz*dz;
    }
    __syncthreads();
    for (int s = 1; s < Gg; s++) {
        float bv = -3e38f; int bi = 0x7fffffff;
        for (int i = t; i < Np; i += 512) { float v = mind[i]; if (v > bv) { bv = v; bi = i; } }
        rv[t] = bv; ri[t] = bi; __syncthreads();
        for (int o = 256; o > 0; o >>= 1) {
            if (t < o && (rv[t+o] > rv[t] || (rv[t+o] == rv[t] && ri[t+o] < ri[t]))) { rv[t]=rv[t+o]; ri[t]=ri[t+o]; }
            __syncthreads();
        }
        if (t == 0) {
            int nxt = ri[0];
            curp[0]=P[3*nxt]; curp[1]=P[3*nxt+1]; curp[2]=P[3*nxt+2];
            C[3*s]=curp[0]; C[3*s+1]=curp[1]; C[3*s+2]=curp[2];
        }
        __syncthreads();
        for (int i = t; i < Np; i += 512) {
            float dx=P[3*i]-curp[0], dy=P[3*i+1]-curp[1], dz=P[3*i+2]-curp[2];
            float d = dx*dx + dy*dy + dz*dz;
            if (d < mind[i]) mind[i] = d;
        }
        __syncthreads();
    }
}

__global__ void knn_big_kernel(const float* __restrict__ qpts, const float* __restrict__ rpts,
                               int* __restrict__ nidx)
{
    int blk = blockIdx.x, b = blk / Gg, qc = blk % Gg, t = threadIdx.x;
    __shared__ float dist[Np];
    __shared__ float rv[128]; __shared__ int ri[128];
    const float* Q = qpts + ((size_t)b*Gg + qc)*3;
    float qx=Q[0], qy=Q[1], qz=Q[2], qq = qx*qx+qy*qy+qz*qz;
    const float* R = rpts + (size_t)b*Np*3;
    for (int i = t; i < Np; i += 128) {
        float rx=R[3*i], ry=R[3*i+1], rz=R[3*i+2];
        dist[i] = qq + (rx*rx+ry*ry+rz*rz) - 2.f*(qx*rx+qy*ry+qz*rz);
    }
    __syncthreads();
    for (int kk = 0; kk < Kk; kk++) {
        float bv = 3e38f; int bi = 0x7fffffff;
        for (int i = t; i < Np; i += 128) { float v = dist[i]; if (v < bv) { bv = v; bi = i; } }
        rv[t] = bv; ri[t] = bi; __syncthreads();
        for (int o = 64; o > 0; o >>= 1) {
            if (t < o && (rv[t+o] < rv[t] || (rv[t+o] == rv[t] && ri[t+o] < ri[t]))) { rv[t]=rv[t+o]; ri[t]=ri[t+o]; }
            __syncthreads();
        }
        if (t == 0) { nidx[((size_t)b*Gg + qc)*Kk + kk] = ri[0]; dist[ri[0]] = 3e38f; }
        __syncthreads();
    }
}

__global__ void knn_small_kernel(const float* __restrict__ pts, int S, int* __restrict__ nidx)
{
    int blk = blockIdx.x, b = blk / S, qi = blk % S, t = threadIdx.x;
    __shared__ float dist[128]; __shared__ float rv[128]; __shared__ int ri[128];
    const float* Q = pts + ((size_t)b*S + qi)*3;
    float qx=Q[0], qy=Q[1], qz=Q[2], qq=qx*qx+qy*qy+qz*qz;
    if (t < S) {
        const float* R = pts + ((size_t)b*S + t)*3;
        dist[t] = qq + (R[0]*R[0]+R[1]*R[1]+R[2]*R[2]) - 2.f*(qx*R[0]+qy*R[1]+qz*R[2]);
    } else dist[t] = 3e38f;
    __syncthreads();
    for (int kk = 0; kk < Kk; kk++) {
        rv[t] = dist[t]; ri[t] = t; __syncthreads();
        for (int o = 64; o > 0; o >>= 1) {
            if (t < o && (rv[t+o] < rv[t] || (rv[t+o] == rv[t] && ri[t+o] < ri[t]))) { rv[t]=rv[t+o]; ri[t]=ri[t+o]; }
            __syncthreads();
        }
        if (t == 0) { nidx[((size_t)b*S + qi)*Kk + kk] = ri[0]; dist[ri[0]] = 3e38f; }
        __syncthreads();
    }
}

__global__ void zero_u8_kernel(unsigned char* m, int n)
{ int i = blockIdx.x*blockDim.x + threadIdx.x; if (i < n) m[i] = 0; }

__global__ void scatter_mask_kernel(const int* __restrict__ nidx, unsigned char* __restrict__ m, int S)
{
    int i = blockIdx.x*blockDim.x + threadIdx.x;
    if (i >= Bb*S*Kk) return;
    int b = i / (S*Kk), r = (i / Kk) % S;
    m[((size_t)b*S + r)*S + nidx[i]] = 1;
}

// rel -> half, padded rows of 32
__global__ void group_rel_kernel(const float* __restrict__ pos, const float* __restrict__ centers,
                                 const int* __restrict__ nidx, __half* __restrict__ rel)
{
    int i = blockIdx.x*blockDim.x + threadIdx.x;
    if (i >= Bb*Gg*Kk) return;
    int b = i / (Gg*Kk), g = (i / Kk) % Gg, src = nidx[i];
    const float* P = pos + ((size_t)b*Np + src)*3;
    const float* C = centers + ((size_t)b*Gg + g)*3;
    __half* rp = rel + (size_t)i*32;
    rp[0] = __float2half(P[0]-C[0]);
    rp[1] = __float2half(P[1]-C[1]);
    rp[2] = __float2half(P[2]-C[2]);
    for (int j = 3; j < 32; j++) rp[j] = __float2half(0.f);
}

__global__ void gmax_h_kernel(const __half* __restrict__ f, __half* __restrict__ g, int C)
{
    int i = blockIdx.x*blockDim.x + threadIdx.x;
    if (i >= Bb*Gg*C) return;
    int bg = i / C, c = i % C;
    const __half* fp = f + (size_t)bg*Kk*C + c;
    float m = __half2float(fp[0]);
    #pragma unroll
    for (int k = 1; k < Kk; k++) m = fmaxf(m, __half2float(fp[(size_t)k*C]));
    g[i] = __float2half(m);
}

__global__ void gmax_f_kernel(const float* __restrict__ f, float* __restrict__ g, int C)
{
    int i = blockIdx.x*blockDim.x + threadIdx.x;
    if (i >= Bb*Gg*C) return;
    int bg = i / C, c = i % C;
    const float* fp = f + (size_t)bg*Kk*C + c;
    float m = fp[0];
    #pragma unroll
    for (int k = 1; k < Kk; k++) m = fmaxf(m, fp[(size_t)k*C]);
    g[i] = m;
}

__global__ void cat_kernel(const __half* __restrict__ g, const __half* __restrict__ f, __half* __restrict__ cat)
{
    int i = blockIdx.x*blockDim.x + threadIdx.x;
    if (i >= Bb*Gg*Kk*512) return;
    int c = i % 512, r = i / 512, bg = r / Kk;
    cat[i] = (c < 256) ? g[(size_t)bg*256 + c] : f[(size_t)r*256 + (c - 256)];
}

__global__ void pe_kernel(const float* __restrict__ xyz, float* __restrict__ pe, int rows)
{
    int i = blockIdx.x*blockDim.x + threadIdx.x;
    if (i >= rows*Dd) return;
    int r = i / Dd, j = i % Dd, c = j / 128, jj = j % 128;
    float x = xyz[(size_t)r*3 + c];
    float dt = powf(10000.0f, (float)(2*(jj/2)) / 128.0f);
    float p = x / dt;
    pe[i] = (jj & 1) ? cosf(p) : sinf(p);
}

__global__ void gather_kernel(const float* __restrict__ src, const int* __restrict__ idx,
                              float* __restrict__ dst, int outR, int inR, int W)
{
    int row = blockIdx.x, b = row / outR, r = row % outR;
    int s = idx[(size_t)b*outR + r];
    const float* sp = src + ((size_t)b*inR + s)*W;
    float* dp = dst + (size_t)row*W;
    for (int w = threadIdx.x; w < W; w += blockDim.x) dp[w] = sp[w];
}

__global__ void decq_kernel(const float* __restrict__ visout, const float* __restrict__ cpe,
                            const float* __restrict__ mask_token, const int* __restrict__ mskidx,
                            const int* __restrict__ visidx, float* __restrict__ x)
{
    int i = blockIdx.x*blockDim.x + threadIdx.x;
    if (i >= Bb*(Mm+Vv)*Dd) return;
    int d = i % Dd, r = (i / Dd) % (Mm+Vv), b = i / (Dd*(Mm+Vv));
    float base; int pidx;
    if (r < Mm) { base = mask_token[d]; pidx = mskidx[(size_t)b*Mm + r]; }
    else { base = visout[((size_t)b*Vv + (r-Mm))*Dd + d]; pidx = visidx[(size_t)b*Vv + (r-Mm)]; }
    x[i] = base + cpe[((size_t)b*Gg + pidx)*Dd + d];
}

__global__ void add_kernel(const float* __restrict__ a, const float* __restrict__ b,
                           float* __restrict__ c, int n)
{ int i = blockIdx.x*blockDim.x + threadIdx.x; if (i < n) c[i] = a[i] + b[i]; }

__global__ void nn3_kernel(const float* __restrict__ pos, const float* __restrict__ centers,
                           int* __restrict__ oi, float* __restrict__ ow)
{
    int i = blockIdx.x*blockDim.x + threadIdx.x;
    if (i >= Bb*Np) return;
    int b = i / Np;
    const float* P = pos + (size_t)i*3;
    float px=P[0], py=P[1], pz=P[2], qq=px*px+py*py+pz*pz;
    float d0=3e38f, d1=3e38f, d2=3e38f; int i0=-1, i1=-1, i2=-1;
    const float* C = centers + (size_t)b*Gg*3;
    for (int g = 0; g < Gg; g++) {
        float cx=C[3*g], cy=C[3*g+1], cz=C[3*g+2];
        float d = qq + (cx*cx+cy*cy+cz*cz) - 2.f*(px*cx+py*cy+pz*cz);
        if (d < d0) { d2=d1;i2=i1; d1=d0;i1=i0; d0=d;i0=g; }
        else if (d < d1) { d2=d1;i2=i1; d1=d;i1=g; }
        else if (d < d2) { d2=d;i2=g; }
    }
    float w0=1.f/(fmaxf(d0,0.f)+1e-8f), w1=1.f/(fmaxf(d1,0.f)+1e-8f), w2=1.f/(fmaxf(d2,0.f)+1e-8f);
    float s = w0+w1+w2;
    ow[3*i]=w0/s; ow[3*i+1]=w1/s; ow[3*i+2]=w2/s;
    oi[3*i]=i0; oi[3*i+1]=i1; oi[3*i+2]=i2;
}

// upsample concat -> half, rows of UPK (pad zeros)
__global__ void upcat_kernel(const float* __restrict__ feats, const float* __restrict__ pos,
                             const int* __restrict__ oi, const float* __restrict__ ow,
                             __half* __restrict__ cat)
{
    int row = blockIdx.x, b = row / Np, t = threadIdx.x;
    int i0=oi[3*row], i1=oi[3*row+1], i2=oi[3*row+2];
    float w0=ow[3*row], w1=ow[3*row+1], w2=ow[3*row+2];
    const float* F = feats + (size_t)b*Gg*Dd;
    __half* cp = cat + (size_t)row*UPK;
    for (int d = t; d < Dd; d += 128)
        cp[d] = __float2half(w0*F[(size_t)i0*Dd+d] + w1*F[(size_t)i1*Dd+d] + w2*F[(size_t)i2*Dd+d]);
    if (t < 32) cp[Dd + t] = __float2half((t < 3) ? pos[(size_t)row*3 + t] : 0.f);
}

__global__ void loss_kernel(const float* __restrict__ fullout, const int* __restrict__ mskidx,
                            const float* __restrict__ decx, float* __restrict__ partial)
{
    __shared__ float red[256];
    int t = threadIdx.x;
    float acc = 0.f;
    for (int i = blockIdx.x*256 + t; i < Bb*Mm*Dd; i += 64*256) {
        int d = i % Dd, r = (i / Dd) % Mm, b = i / (Dd*Mm);
        int gi = mskidx[(size_t)b*Mm + r];
        float tv = fullout[((size_t)b*Gg + gi)*Dd + d];
        float pv = decx[((size_t)b*(Mm+Vv) + r)*Dd + d];
        float a = fabsf(pv - tv);
        acc += (a < 2.0f) ? 0.25f*a*a : a - 1.0f;
    }
    red[t] = acc; __syncthreads();
    for (int o = 128; o > 0; o >>= 1) { if (t < o) red[t] += red[t+o]; __syncthreads(); }
    if (t == 0) partial[blockIdx.x] = red[0];
}

__global__ void loss_final_kernel(const float* __restrict__ pa, const float* __restrict__ pb,
                                  float* __restrict__ out)
{
    float sa = 0.f, sb = 0.f;
    for (int i = 0; i < 64; i++) { sa += pa[i]; sb += pb[i]; }
    float cnt = (float)(Bb*Mm*Dd);
    out[0] = 0.5f*(sa/cnt) + 0.5f*(sb/cnt);
}

__global__ void copy_kernel(const float* __restrict__ a, float* __restrict__ b, int n)
{ int i = blockIdx.x*blockDim.x + threadIdx.x; if (i < n) b[i] = a[i]; }

// ------------------------------ host side --------------------------------

static void gemm_h(const __half* A, const __half* Wt, const float* bias,
                   float* Cf, __half* Ch, int rows, int Kd, int Nc, int relu, int accum)
{
    dim3 grid(Nc/128, rows/128);
    gemm_h_kernel<<<grid, 256>>>(A, Wt, bias, Cf, Ch, rows, Kd, Nc, relu, accum);
}

static __half* WTH;
static float *QB, *KB, *VB;
static __half *CTXH;

static void attn_block(const __half* lnq, const __half* lnkv, long woff,
                       const unsigned char* mask, float* x, int Sq, int Sk)
{
    gemm_h(lnq,  WTH + woff,           nullptr, QB, nullptr, Bb*Sq, Dd, Dd, 0, 0);
    gemm_h(lnkv, WTH + woff + MSZ,     nullptr, KB, nullptr, Bb*Sk, Dd, Dd, 0, 0);
    gemm_h(lnkv, WTH + woff + 2*MSZ,   nullptr, VB, nullptr, Bb*Sk, Dd, Dd, 0, 0);
    if (Sq >= 1024 && mask == nullptr && Sk == 128) {
        dim3 g(Sq/QT, NHh, Bb);
        attn_big_kernel<<<g, 128>>>(QB, KB, VB, CTXH, Sq);
    } else {
        dim3 g(Sq, NHh, Bb);
        attn_kernel<<<g, 128>>>(QB, KB, VB, mask, CTXH, Sq, Sk);
    }
    gemm_h(CTXH, WTH + woff + 3*MSZ, nullptr, x, nullptr, Bb*Sq, Dd, Dd, 0, 1);
}

static void encode_pair(float* Sb, float* Tb, const unsigned char* mS, const unsigned char* mT,
                        int S, __half* lnS, __half* lnT, __half* hid)
{
    int rows = Bb*S;
    ln_kernel<<<rows, 128>>>(Sb, lnS);
    attn_block(lnS, lnS, OFF_CX, mS, Sb, S, S);
    ln_kernel<<<rows, 128>>>(Tb, lnT);
    attn_block(lnT, lnT, OFF_CX, mT, Tb, S, S);
    ln_kernel<<<rows, 128>>>(Sb, lnS);
    ln_kernel<<<rows, 128>>>(Tb, lnT);
    attn_block(lnS, lnT, OFF_CX + 4*MSZ, nullptr, Sb, S, S);
    attn_block(lnT, lnS, OFF_CX + 4*MSZ, nullptr, Tb, S, S);
    ln_kernel<<<rows, 128>>>(Sb, lnS);
    gemm_h(lnS, WTH + OFF_CXFF1, nullptr, nullptr, hid, rows, Dd, FFf, 1, 0);
    gemm_h(hid, WTH + OFF_CXFF2, nullptr, Sb, nullptr, rows, FFf, Dd, 0, 1);
    ln_kernel<<<rows, 128>>>(Tb, lnT);
    gemm_h(lnT, WTH + OFF_CXFF1, nullptr, nullptr, hid, rows, Dd, FFf, 1, 0);
    gemm_h(hid, WTH + OFF_CXFF2, nullptr, Tb, nullptr, rows, FFf, Dd, 0, 1);
}

#define GETSYM(var, sym) do { void* _p; cudaGetSymbolAddress(&_p, sym); var = (decltype(var))_p; } while (0)

extern "C" void kernel_launch(void* const* d_in, const int* in_sizes, int n_in,
                              void* d_out_v, int out_size)
{
    (void)in_sizes; (void)n_in; (void)out_size;
    const float* pos[2]    = {(const float*)d_in[0], (const float*)d_in[1]};
    const int*   visidx[2] = {(const int*)d_in[2], (const int*)d_in[4]};
    const int*   mskidx[2] = {(const int*)d_in[3], (const int*)d_in[5]};
    const float* tok_w1 = (const float*)d_in[6];  const float* tok_b1 = (const float*)d_in[7];
    const float* tok_w2 = (const float*)d_in[8];  const float* tok_b2 = (const float*)d_in[9];
    const float* tok_w3 = (const float*)d_in[10]; const float* tok_b3 = (const float*)d_in[11];
    const float* tok_w4 = (const float*)d_in[12]; const float* tok_b4 = (const float*)d_in[13];
    const float* mask_token = (const float*)d_in[14];
    const float* cx_attn = (const float*)d_in[15];
    const float* cx_ff1  = (const float*)d_in[16]; const float* cx_ff2 = (const float*)d_in[17];
    const float* enc_sa  = (const float*)d_in[18]; const float* enc_ca = (const float*)d_in[19];
    const float* enc_ff1 = (const float*)d_in[20]; const float* enc_ff2 = (const float*)d_in[21];
    const float* dec_ca  = (const float*)d_in[22]; const float* dec_ff1 = (const float*)d_in[23];
    const float* dec_ff2 = (const float*)d_in[24];
    const float* up_w1 = (const float*)d_in[25]; const float* up_b1 = (const float*)d_in[26];
    const float* up_w2 = (const float*)d_in[27]; const float* up_b2 = (const float*)d_in[28];
    float* dout = (float*)d_out_v;

    float *centersB, *t2B, *tokensB, *cpeB, *ppeB, *vis3B, *visB, *fullB, *decxB, *mbufB, *nn3wB, *lpartB;
    int *nidxB, *nidxSB, *nn3iB;
    unsigned char *mfullB, *mvisB;
    __half *relH, *f1H, *f2H, *gmaxH, *catH, *t1H, *lnSH, *lnTH, *lnmH, *lnbigH, *hidH, *upcatH;
    GETSYM(centersB, g_centers); GETSYM(nidxB, g_nidx); GETSYM(nidxSB, g_nidxS);
    GETSYM(t2B, g_t2); GETSYM(tokensB, g_tokens);
    GETSYM(cpeB, g_cpe); GETSYM(ppeB, g_ppe); GETSYM(mfullB, g_mfull); GETSYM(mvisB, g_mvis);
    GETSYM(vis3B, g_vis3); GETSYM(visB, g_visbuf); GETSYM(fullB, g_fullbuf); GETSYM(decxB, g_decx);
    GETSYM(mbufB, g_mbuf); GETSYM(QB, g_qbuf); GETSYM(KB, g_kbuf); GETSYM(VB, g_vbuf);
    GETSYM(nn3iB, g_nn3i); GETSYM(nn3wB, g_nn3w); GETSYM(lpartB, g_lpart);
    GETSYM(relH, g_relh); GETSYM(f1H, g_f1h); GETSYM(f2H, g_f2h); GETSYM(gmaxH, g_gmaxh);
    GETSYM(catH, g_cath); GETSYM(t1H, g_t1h); GETSYM(lnSH, g_lnSh); GETSYM(lnTH, g_lnTh);
    GETSYM(lnmH, g_lnmh); GETSYM(lnbigH, g_lnbigh); GETSYM(hidH, g_hidh);
    GETSYM(CTXH, g_ctxh); GETSYM(upcatH, g_upcath); GETSYM(WTH, g_wth);

    float* centers[2] = {centersB, centersB + Bb*Gg*3};
    float* tokens[2]  = {tokensB,  tokensB  + Bb*Gg*Dd};
    float* cpe[2]     = {cpeB,     cpeB     + Bb*Gg*Dd};
    float* ppe[2]     = {ppeB,     ppeB     + Bb*Np*Dd};
    float* visb[2]    = {visB,     visB     + Bb*Vv*Dd};
    float* fullb[2]   = {fullB,    fullB    + Bb*Gg*Dd};
    float* decx[2]    = {decxB,    decxB    + Bb*(Mm+Vv)*Dd};
    unsigned char* mfull[2] = {mfullB, mfullB + Bb*Gg*Gg};
    unsigned char* mvis[2]  = {mvisB,  mvisB  + Bb*Vv*Vv};

    // Phase 0: single fused weight conversion
    {
        WConvArgs wa;
        const float* srcs[16] = {tok_w1, tok_w2, tok_w3, tok_w4, cx_attn, enc_sa, enc_ca,
                                 dec_ca, cx_ff1, cx_ff2, enc_ff1, enc_ff2, dec_ff1, dec_ff2,
                                 up_w1, up_w2};
        long starts[17] = {OFF_W1, OFF_W2, OFF_W3, OFF_W4, OFF_CX, OFF_ENCSA, OFF_ENCCA,
                           OFF_DECCA, OFF_CXFF1, OFF_CXFF2, OFF_EFF1, OFF_EFF2, OFF_DFF1,
                           OFF_DFF2, OFF_UP1, OFF_UP2, WTH_TOT};
        int kds[16]  = {3, 128, 512, 512, Dd, Dd, Dd, Dd, Dd, FFf, Dd, FFf, Dd, FFf, Dd+3, Dd};
        int kps[16]  = {32, 128, 512, 512, Dd, Dd, Dd, Dd, Dd, FFf, Dd, FFf, Dd, FFf, UPK, Dd};
        int ncs[16]  = {128, 256, 512, Dd, Dd, Dd, Dd, Dd, FFf, Dd, FFf, Dd, FFf, Dd, Dd, Dd};
        for (int i = 0; i < 16; i++) { wa.src[i]=srcs[i]; wa.start[i]=starts[i]; wa.Kd[i]=kds[i]; wa.KdPad[i]=kps[i]; wa.Nc[i]=ncs[i]; }
        wa.start[16] = starts[16];
        long tot = WTH_TOT;
        wtconv_all_kernel<<<(int)((tot + 255)/256), 256>>>(wa, WTH);
    }

    // Phase 1: tokenize + PE + masks
    for (int s = 0; s < 2; s++) {
        fps_kernel<<<Bb, 512>>>(pos[s], centers[s]);
        knn_big_kernel<<<Bb*Gg, 128>>>(centers[s], pos[s], nidxB);
        group_rel_kernel<<<(Bb*Gg*Kk + 255)/256, 256>>>(pos[s], centers[s], nidxB, relH);
        gemm_h(relH, WTH + OFF_W1, tok_b1, nullptr, f1H, 16384, 32, 128, 1, 0);
        gemm_h(f1H, WTH + OFF_W2, tok_b2, nullptr, f2H, 16384, 128, 256, 0, 0);
        gmax_h_kernel<<<(Bb*Gg*256 + 255)/256, 256>>>(f2H, gmaxH, 256);
        cat_kernel<<<(Bb*Gg*Kk*512 + 255)/256, 256>>>(gmaxH, f2H, catH);
        gemm_h(catH, WTH + OFF_W3, tok_b3, nullptr, t1H, 16384, 512, 512, 1, 0);
        gemm_h(t1H, WTH + OFF_W4, tok_b4, t2B, nullptr, 16384, 512, Dd, 0, 0);
        gmax_f_kernel<<<(Bb*Gg*Dd + 255)/256, 256>>>(t2B, tokens[s], Dd);
        pe_kernel<<<(Bb*Gg*Dd + 255)/256, 256>>>(centers[s], cpe[s], Bb*Gg);
        pe_kernel<<<(Bb*Np*Dd + 255)/256, 256>>>(pos[s], ppe[s], Bb*Np);
        knn_small_kernel<<<Bb*Gg, 128>>>(centers[s], Gg, nidxSB);
        zero_u8_kernel<<<(Bb*Gg*Gg + 255)/256, 256>>>(mfull[s], Bb*Gg*Gg);
        scatter_mask_kernel<<<(Bb*Gg*Kk + 255)/256, 256>>>(nidxSB, mfull[s], Gg);
        gather_kernel<<<Bb*Vv, 32>>>(centers[s], visidx[s], vis3B, Vv, Gg, 3);
        knn_small_kernel<<<Bb*Vv, 128>>>(vis3B, Vv, nidxSB);
        zero_u8_kernel<<<(Bb*Vv*Vv + 255)/256, 256>>>(mvis[s], Bb*Vv*Vv);
        scatter_mask_kernel<<<(Bb*Vv*Kk + 255)/256, 256>>>(nidxSB, mvis[s], Vv);
        gather_kernel<<<Bb*Vv, 128>>>(tokens[s], visidx[s], visb[s], Vv, Gg, Dd);
        copy_kernel<<<(Bb*Gg*Dd + 255)/256, 256>>>(tokens[s], fullb[s], Bb*Gg*Dd);
    }

    // Phase 2: cross encoders
    encode_pair(visb[0], visb[1], mvis[0], mvis[1], Vv, lnSH, lnTH, hidH);
    encode_pair(fullb[0], fullb[1], mfull[0], mfull[1], Gg, lnSH, lnTH, hidH);

    // Phase 3: MAE decoder + loss
    for (int s = 0; s < 2; s++) {
        int o = 1 - s;
        decq_kernel<<<(Bb*(Mm+Vv)*Dd + 255)/256, 256>>>(visb[s], cpe[s], mask_token,
                                                        mskidx[s], visidx[s], decx[s]);
        add_kernel<<<(Bb*Gg*Dd + 255)/256, 256>>>(fullb[o], cpe[o], mbufB, Bb*Gg*Dd);
        ln_kernel<<<Bb*Gg, 128>>>(mbufB, lnmH);
        for (int l = 0; l < 4; l++) {
            ln_kernel<<<Bb*(Mm+Vv), 128>>>(decx[s], lnSH);
            attn_block(lnSH, lnSH, OFF_ENCSA + (long)l*4*MSZ, nullptr, decx[s], Mm+Vv, Mm+Vv);
            ln_kernel<<<Bb*(Mm+Vv), 128>>>(decx[s], lnSH);
            attn_block(lnSH, lnmH, OFF_ENCCA + (long)l*4*MSZ, nullptr, decx[s], Mm+Vv, Gg);
            ln_kernel<<<Bb*(Mm+Vv), 128>>>(decx[s], lnSH);
            gemm_h(lnSH, WTH + OFF_EFF1 + (long)l*Dd*FFf, nullptr, nullptr, hidH, Bb*(Mm+Vv), Dd, FFf, 1, 0);
            gemm_h(hidH, WTH + OFF_EFF2 + (long)l*FFf*Dd, nullptr, decx[s], nullptr, Bb*(Mm+Vv), FFf, Dd, 0, 1);
        }
        loss_kernel<<<64, 256>>>(fullb[s], mskidx[s], decx[s], lpartB + s*64);
    }

    // Phase 4: upsample + dense decoder
    for (int s = 0; s < 2; s++) {
        float* X = dout + (size_t)s*Bb*Np*Dd;
        nn3_kernel<<<(Bb*Np + 255)/256, 256>>>(pos[s], centers[s], nn3iB, nn3wB);
        upcat_kernel<<<Bb*Np, 128>>>(fullb[s], pos[s], nn3iB, nn3wB, upcatH);
        gemm_h(upcatH, WTH + OFF_UP1, up_b1, nullptr, hidH, Bb*Np, UPK, Dd, 1, 0);
        gemm_h(hidH, WTH + OFF_UP2, up_b2, QB, nullptr, Bb*Np, Dd, Dd, 1, 0);
        add_kernel<<<(Bb*Np*Dd + 255)/256, 256>>>(QB, ppe[s], X, Bb*Np*Dd);
        add_kernel<<<(Bb*Gg*Dd + 255)/256, 256>>>(fullb[s], cpe[s], mbufB, Bb*Gg*Dd);
        ln_kernel<<<Bb*Gg, 128>>>(mbufB, lnmH);
        for (int l = 0; l < 2; l++) {
            ln_kernel<<<Bb*Np, 128>>>(X, lnbigH);
            attn_block(lnbigH, lnmH, OFF_DECCA + (long)l*4*MSZ, nullptr, X, Np, Gg);
            ln_kernel<<<Bb*Np, 128>>>(X, lnbigH);
            gemm_h(lnbigH, WTH + OFF_DFF1 + (long)l*Dd*FFf, nullptr, nullptr, hidH, Bb*Np, Dd, FFf, 1, 0);
            gemm_h(hidH, WTH + OFF_DFF2 + (long)l*FFf*Dd, nullptr, X, nullptr, Bb*Np, FFf, Dd, 0, 1);
        }
    }
    loss_final_kernel<<<1, 1>>>(lpartB, lpartB + 64, dout + (size_t)2*Bb*Np*Dd);
}

// round 10
// speedup vs baseline: 4.9987x; 1.1226x over previous
#include <cuda_runtime.h>
#include <cuda_fp16.h>
#include <math.h>
#include <stdint.h>

#define Bb 8
#define Np 4096
#define Gg 128
#define Kk 16
#define Vv 64
#define Mm 64
#define Dd 384
#define NHh 8
#define DHh 48
#define FFf 1536
#define UPK 416

// fp32 buffers
__device__ float g_centers[2*Bb*Gg*3];
__device__ int   g_nidx[2*Bb*Gg*Kk];
__device__ int   g_nidxS[Bb*Gg*Kk];
__device__ float g_t2[2*16384*Dd];
__device__ float g_tokens[2*Bb*Gg*Dd];
__device__ float g_cpe[2*Bb*Gg*Dd];
__device__ float g_ppe[2*Bb*Np*Dd];
__device__ unsigned char g_mfull[2*Bb*Gg*Gg];
__device__ unsigned char g_mvis[2*Bb*Vv*Vv];
__device__ float g_vis3[Bb*Vv*3];
__device__ float g_visbuf[2*Bb*Vv*Dd];
__device__ float g_fullbuf[2*Bb*Gg*Dd];
__device__ float g_decx[2*Bb*(Mm+Vv)*Dd];
__device__ float g_mbuf[2*Bb*Gg*Dd];
__device__ float g_qbuf[2*Bb*Np*Dd];
__device__ float g_skv[2048*1152];
__device__ int   g_nn3i[Bb*Np*3];
__device__ float g_nn3w[Bb*Np*3];
__device__ float g_lpart[2*64];

// half buffers
__device__ __align__(16) __half g_relh[32768*32];
__device__ __align__(16) __half g_f1h[32768*128];
__device__ __align__(16) __half g_f2h[32768*256];
__device__ __align__(16) __half g_gmaxh[2*Bb*Gg*256];
__device__ __align__(16) __half g_cath[32768*512];
__device__ __align__(16) __half g_t1h[32768*512];
__device__ __align__(16) __half g_lnSh[2*Bb*Gg*Dd];
__device__ __align__(16) __half g_lnmh[2*Bb*Gg*Dd];
__device__ __align__(16) __half g_lnbigh[2*Bb*Np*Dd];
__device__ __align__(16) __half g_hidh[(size_t)2*Bb*Np*FFf];
__device__ __align__(16) __half g_ctxh[2*Bb*Np*Dd];
__device__ __align__(16) __half g_upcath[2*Bb*Np*UPK];

// transposed+padded fp16 weights: each mat stored [Nc][KdPad]
#define MSZ 147456
#define OFF_W1    0
#define OFF_W2    (OFF_W1 + 32*128)
#define OFF_W3    (OFF_W2 + 128*256)
#define OFF_W4    (OFF_W3 + 512*512)
#define OFF_CX    (OFF_W4 + 512*384)
#define OFF_ENCSA (OFF_CX + 8*MSZ)
#define OFF_ENCCA (OFF_ENCSA + 16*MSZ)
#define OFF_DECCA (OFF_ENCCA + 16*MSZ)
#define OFF_CXFF1 (OFF_DECCA + 8*MSZ)
#define OFF_CXFF2 (OFF_CXFF1 + 384*1536)
#define OFF_EFF1  (OFF_CXFF2 + 1536*384)
#define OFF_EFF2  (OFF_EFF1 + 4*384*1536)
#define OFF_DFF1  (OFF_EFF2 + 4*1536*384)
#define OFF_DFF2  (OFF_DFF1 + 2*384*1536)
#define OFF_UP1   (OFF_DFF2 + 2*1536*384)
#define OFF_UP2   (OFF_UP1 + 416*384)
#define WTH_TOT   (OFF_UP2 + 384*384)
__device__ __align__(16) __half g_wth[WTH_TOT];

struct WConvArgs {
    const float* src[16];
    long start[17];
    int Kd[16], KdPad[16], Nc[16];
};

__global__ void wtconv_all_kernel(WConvArgs A, __half* __restrict__ dst)
{
    long i = (long)blockIdx.x*256 + threadIdx.x;
    if (i >= A.start[16]) return;
    int s = 0;
    while (s < 15 && i >= A.start[s+1]) s++;
    long li = i - A.start[s];
    int Kd = A.Kd[s], Kp = A.KdPad[s], Nc = A.Nc[s];
    long per = (long)Nc*Kp;
    int mt = (int)(li/per);
    long r = li % per;
    int n = (int)(r/Kp), k = (int)(r%Kp);
    float v = (k < Kd) ? A.src[s][(size_t)mt*Kd*Nc + (size_t)k*Nc + n] : 0.f;
    dst[i] = __float2half(v);
}

// fp16 tensor-core GEMM: 128x128 tile, KT=32, m16n8k16, ldmatrix, cp.async x2
__global__ __launch_bounds__(256)
void gemm_h_kernel(const __half* __restrict__ A, const __half* __restrict__ Wt,
                   const float* __restrict__ bias, float* __restrict__ Cf,
                   __half* __restrict__ Ch, int rows, int Kd, int Nc, int relu, int accum)
{
    __shared__ __half Ah[2][128][40];
    __shared__ __half Wh[2][128][40];
    int tid = threadIdx.x, wid = tid>>5, lane = tid&31;
    int g = lane>>2, tig = lane&3;
    int wm = (wid>>1)*32, wn = (wid&1)*64;
    int row0 = blockIdx.y*128, col0 = blockIdx.x*128;
    float c[2][8][4] = {};
    int nIter = Kd/32;

    int lr = lane & 7, lj = lane >> 3;
    uint32_t ah0 = (uint32_t)__cvta_generic_to_shared(&Ah[0][0][0]);
    uint32_t wh0 = (uint32_t)__cvta_generic_to_shared(&Wh[0][0][0]);
    uint32_t aAddr[2], wAddr[4];
    #pragma unroll
    for (int mt = 0; mt < 2; mt++)
        aAddr[mt] = ah0 + (uint32_t)((wm + mt*16 + lr + (lj&1)*8)*80 + ((lj>>1)*8)*2);
    #pragma unroll
    for (int p = 0; p < 4; p++)
        wAddr[p] = wh0 + (uint32_t)((wn + p*16 + lr + ((lj>>1)&1)*8)*80 + ((lj&1)*8)*2);

    #pragma unroll
    for (int l = 0; l < 2; l++) {
        int ci = tid + l*256;
        int m = ci>>2, f = ci&3;
        const __half* ga = A + (size_t)(row0+m)*Kd + f*8;
        uint32_t sa = (uint32_t)__cvta_generic_to_shared(&Ah[0][m][f*8]);
        asm volatile("cp.async.cg.shared.global [%0], [%1], 16;" :: "r"(sa), "l"(ga));
        const __half* gw = Wt + (size_t)(col0+m)*Kd + f*8;
        uint32_t sw = (uint32_t)__cvta_generic_to_shared(&Wh[0][m][f*8]);
        asm volatile("cp.async.cg.shared.global [%0], [%1], 16;" :: "r"(sw), "l"(gw));
    }
    asm volatile("cp.async.commit_group;");

    for (int it = 0; it < nIter; it++) {
        int cur = it & 1;
        if (it + 1 < nIter) {
            int k0 = (it+1)*32;
            #pragma unroll
            for (int l = 0; l < 2; l++) {
                int ci = tid + l*256;
                int m = ci>>2, f = ci&3;
                const __half* ga = A + (size_t)(row0+m)*Kd + k0 + f*8;
                uint32_t sa = (uint32_t)__cvta_generic_to_shared(&Ah[cur^1][m][f*8]);
                asm volatile("cp.async.cg.shared.global [%0], [%1], 16;" :: "r"(sa), "l"(ga));
                const __half* gw = Wt + (size_t)(col0+m)*Kd + k0 + f*8;
                uint32_t sw = (uint32_t)__cvta_generic_to_shared(&Wh[cur^1][m][f*8]);
                asm volatile("cp.async.cg.shared.global [%0], [%1], 16;" :: "r"(sw), "l"(gw));
            }
            asm volatile("cp.async.commit_group;");
            asm volatile("cp.async.wait_group 1;");
        } else {
            asm volatile("cp.async.wait_group 0;");
        }
        __syncthreads();
        #pragma unroll
        for (int st = 0; st < 2; st++) {
            uint32_t kOff = (uint32_t)(cur*10240 + st*32);
            uint32_t a[2][4], b[8][2];
            #pragma unroll
            for (int mt = 0; mt < 2; mt++)
                asm volatile("ldmatrix.sync.aligned.m8n8.x4.shared.b16 {%0,%1,%2,%3}, [%4];"
                    : "=r"(a[mt][0]), "=r"(a[mt][1]), "=r"(a[mt][2]), "=r"(a[mt][3])
                    : "r"(aAddr[mt] + kOff));
            #pragma unroll
            for (int p = 0; p < 4; p++) {
                uint32_t d0, d1, d2, d3;
                asm volatile("ldmatrix.sync.aligned.m8n8.x4.shared.b16 {%0,%1,%2,%3}, [%4];"
                    : "=r"(d0), "=r"(d1), "=r"(d2), "=r"(d3)
                    : "r"(wAddr[p] + kOff));
                b[2*p][0] = d0; b[2*p][1] = d1; b[2*p+1][0] = d2; b[2*p+1][1] = d3;
            }
            #pragma unroll
            for (int mt = 0; mt < 2; mt++)
                #pragma unroll
                for (int nt = 0; nt < 8; nt++)
                    asm volatile(
                        "mma.sync.aligned.m16n8k16.row.col.f32.f16.f16.f32 "
                        "{%0,%1,%2,%3}, {%4,%5,%6,%7}, {%8,%9}, {%0,%1,%2,%3};"
                        : "+f"(c[mt][nt][0]), "+f"(c[mt][nt][1]),
                          "+f"(c[mt][nt][2]), "+f"(c[mt][nt][3])
                        : "r"(a[mt][0]), "r"(a[mt][1]), "r"(a[mt][2]), "r"(a[mt][3]),
                          "r"(b[nt][0]), "r"(b[nt][1]));
        }
        __syncthreads();
    }
    #pragma unroll
    for (int mt = 0; mt < 2; mt++) {
        #pragma unroll
        for (int nt = 0; nt < 8; nt++) {
            int r0 = row0 + wm + mt*16 + g;
            int cc = col0 + wn + nt*8 + 2*tig;
            float v0 = c[mt][nt][0], v1 = c[mt][nt][1];
            float v2 = c[mt][nt][2], v3 = c[mt][nt][3];
            if (bias) { float b0 = bias[cc], b1 = bias[cc+1]; v0 += b0; v1 += b1; v2 += b0; v3 += b1; }
            if (relu) { v0 = fmaxf(v0,0.f); v1 = fmaxf(v1,0.f); v2 = fmaxf(v2,0.f); v3 = fmaxf(v3,0.f); }
            size_t o0 = (size_t)r0*Nc + cc;
            size_t o1 = (size_t)(r0+8)*Nc + cc;
            if (Ch) {
                Ch[o0] = __float2half(v0); Ch[o0+1] = __float2half(v1);
                Ch[o1] = __float2half(v2); Ch[o1+1] = __float2half(v3);
            } else if (accum) {
                Cf[o0] += v0; Cf[o0+1] += v1; Cf[o1] += v2; Cf[o1+1] += v3;
            } else {
                Cf[o0] = v0; Cf[o0+1] = v1; Cf[o1] = v2; Cf[o1+1] = v3;
            }
        }
    }
}

__global__ void ln_kernel(const float* __restrict__ x, __half* __restrict__ y)
{
    int row = blockIdx.x, t = threadIdx.x;
    const float* xr = x + (size_t)row*Dd;
    __shared__ float red[128];
    float a = xr[t], b = xr[t+128], c = xr[t+256];
    red[t] = a + b + c; __syncthreads();
    for (int o = 64; o > 0; o >>= 1) { if (t < o) red[t] += red[t+o]; __syncthreads(); }
    float m = red[0] / (float)Dd; __syncthreads();
    float da=a-m, db=b-m, dc=c-m;
    red[t] = da*da + db*db + dc*dc; __syncthreads();
    for (int o = 64; o > 0; o >>= 1) { if (t < o) red[t] += red[t+o]; __syncthreads(); }
    float inv = rsqrtf(red[0] / (float)Dd + 1e-5f);
    __half* yr = y + (size_t)row*Dd;
    yr[t]=__float2half(da*inv); yr[t+128]=__float2half(db*inv); yr[t+256]=__float2half(dc*inv);
}

// small attention: one block per (q,h,b); Sk<=128; strided q/k/v; kvxor batch map
__global__ void attn_kernel(const float* __restrict__ q, int qs,
                            const float* __restrict__ kmat, const float* __restrict__ vmat, int kvs,
                            const unsigned char* __restrict__ mask,
                            __half* __restrict__ ctx, int Sq, int Sk, int kvxor)
{
    int qi = blockIdx.x, h = blockIdx.y, b = blockIdx.z, t = threadIdx.x;
    int bk = b ^ kvxor;
    __shared__ float shq[DHh], shp[128], red[128];
    const float* qr = q + (size_t)(b*Sq + qi)*qs + h*DHh;
    if (t < DHh) shq[t] = qr[t];
    __syncthreads();
    float val = -3e38f;
    if (t < Sk) {
        const float* kr = kmat + (size_t)(bk*Sk + t)*kvs + h*DHh;
        float s = 0.f;
        #pragma unroll
        for (int d = 0; d < DHh; d++) s += shq[d]*kr[d];
        s /= sqrtf((float)DHh);
        if (mask && !mask[((size_t)b*Sq + qi)*Sk + t]) s = -1e9f;
        val = s;
    }
    red[t] = val; __syncthreads();
    for (int o = 64; o > 0; o >>= 1) { if (t < o) red[t] = fmaxf(red[t], red[t+o]); __syncthreads(); }
    float mx = red[0]; __syncthreads();
    float e = (t < Sk) ? expf(val - mx) : 0.f;
    shp[t] = e; red[t] = e; __syncthreads();
    for (int o = 64; o > 0; o >>= 1) { if (t < o) red[t] += red[t+o]; __syncthreads(); }
    float inv = 1.f / red[0];
    if (t < DHh) {
        float acc = 0.f;
        const float* vb = vmat + (size_t)(bk*Sk)*kvs + h*DHh + t;
        for (int kk = 0; kk < Sk; kk++) acc += shp[kk]*vb[(size_t)kk*kvs];
        ctx[((size_t)(b*Sq + qi))*Dd + h*DHh + t] = __float2half(acc*inv);
    }
}

// big attention: 16 queries/block, Sk==128, no mask, strided q/kv
#define QT 16
__global__ __launch_bounds__(128)
void attn_big_kernel(const float* __restrict__ q, int qs,
                     const float* __restrict__ kmat, const float* __restrict__ vmat, int kvs,
                     __half* __restrict__ ctx, int Sq)
{
    int qt = blockIdx.x, h = blockIdx.y, b = blockIdx.z, t = threadIdx.x;
    __shared__ float shq[QT][DHh];
    __shared__ float sc[QT][129];
    __shared__ float Vs[128][DHh];
    for (int i = t; i < QT*DHh; i += 128) {
        int qi = i / DHh, d = i % DHh;
        shq[qi][d] = q[(size_t)(b*Sq + qt*QT + qi)*qs + h*DHh + d];
    }
    for (int i = t; i < 128*DHh; i += 128) {
        int k = i / DHh, d = i % DHh;
        Vs[k][d] = vmat[(size_t)(b*128 + k)*kvs + h*DHh + d];
    }
    __syncthreads();
    float kr[DHh];
    {
        const float* kp = kmat + (size_t)(b*128 + t)*kvs + h*DHh;
        #pragma unroll
        for (int d = 0; d < DHh; d++) kr[d] = kp[d];
    }
    float inv_s = sqrtf((float)DHh);
    #pragma unroll 1
    for (int qi = 0; qi < QT; qi++) {
        float s = 0.f;
        #pragma unroll
        for (int d = 0; d < DHh; d++) s += shq[qi][d]*kr[d];
        sc[qi][t] = s / inv_s;
    }
    __syncthreads();
    int w = t >> 5, lane = t & 31;
    for (int qi = w; qi < QT; qi += 4) {
        float v0 = sc[qi][lane], v1 = sc[qi][lane+32], v2 = sc[qi][lane+64], v3 = sc[qi][lane+96];
        float mx = fmaxf(fmaxf(v0,v1), fmaxf(v2,v3));
        #pragma unroll
        for (int o = 16; o > 0; o >>= 1) mx = fmaxf(mx, __shfl_xor_sync(0xffffffffu, mx, o));
        float e0=expf(v0-mx), e1=expf(v1-mx), e2=expf(v2-mx), e3=expf(v3-mx);
        float sum = e0+e1+e2+e3;
        #pragma unroll
        for (int o = 16; o > 0; o >>= 1) sum += __shfl_xor_sync(0xffffffffu, sum, o);
        float inv = 1.f / sum;
        sc[qi][lane]=e0*inv; sc[qi][lane+32]=e1*inv; sc[qi][lane+64]=e2*inv; sc[qi][lane+96]=e3*inv;
    }
    __syncthreads();
    for (int i = t; i < QT*DHh; i += 128) {
        int qi = i / DHh, d = i % DHh;
        float acc = 0.f;
        #pragma unroll 4
        for (int k = 0; k < 128; k++) acc += sc[qi][k] * Vs[k][d];
        ctx[((size_t)(b*Sq + qt*QT + qi))*Dd + h*DHh + d] = __float2half(acc);
    }
}

__global__ void fps_kernel(const float* __restrict__ pos, float* __restrict__ centers)
{
    int b = blockIdx.x, t = threadIdx.x;
    __shared__ float mind[Np];
    __shared__ float rv[512]; __shared__ int ri[512]; __shared__ float curp[3];
    const float* P = pos + (size_t)b*Np*3;
    float* C = centers + (size_t)b*Gg*3;
    if (t == 0) { curp[0]=P[0]; curp[1]=P[1]; curp[2]=P[2]; C[0]=P[0]; C[1]=P[1]; C[2]=P[2]; }
    __syncthreads();
    for (int i = t; i < Np; i += 512) {
        float dx=P[3*i]-curp[0], dy=P[3*i+1]-curp[1], dz=P[3*i+2]-curp[2];
        mind[i] = dx*dx + dy*dy + dz*dz;
    }
    __syncthreads();
    for (int s = 1; s < Gg; s++) {
        float bv = -3e38f; int bi = 0x7fffffff;
        for (int i = t; i < Np; i += 512) { float v = mind[i]; if (v > bv) { bv = v; bi = i; } }
        rv[t] = bv; ri[t] = bi; __syncthreads();
        for (int o = 256; o > 0; o >>= 1) {
            if (t < o && (rv[t+o] > rv[t] || (rv[t+o] == rv[t] && ri[t+o] < ri[t]))) { rv[t]=rv[t+o]; ri[t]=ri[t+o]; }
            __syncthreads();
        }
        if (t == 0) {
            int nxt = ri[0];
            curp[0]=P[3*nxt]; curp[1]=P[3*nxt+1]; curp[2]=P[3*nxt+2];
            C[3*s]=curp[0]; C[3*s+1]=curp[1]; C[3*s+2]=curp[2];
        }
        __syncthreads();
        for (int i = t; i < Np; i += 512) {
            float dx=P[3*i]-curp[0], dy=P[3*i+1]-curp[1], dz=P[3*i+2]-curp[2];
            float d = dx*dx + dy*dy + dz*dz;
            if (d < mind[i]) mind[i] = d;
        }
        __syncthreads();
    }
}

__global__ void knn_big_kernel(const float* __restrict__ qpts, const float* __restrict__ rpts,
                               int* __restrict__ nidx)
{
    int blk = blockIdx.x, b = blk / Gg, qc = blk % Gg, t = threadIdx.x;
    __shared__ float dist[Np];
    __shared__ float rv[128]; __shared__ int ri[128];
    const float* Q = qpts + ((size_t)b*Gg + qc)*3;
    float qx=Q[0], qy=Q[1], qz=Q[2], qq = qx*qx+qy*qy+qz*qz;
    const float* R = rpts + (size_t)b*Np*3;
    for (int i = t; i < Np; i += 128) {
        float rx=R[3*i], ry=R[3*i+1], rz=R[3*i+2];
        dist[i] = qq + (rx*rx+ry*ry+rz*rz) - 2.f*(qx*rx+qy*ry+qz*rz);
    }
    __syncthreads();
    for (int kk = 0; kk < Kk; kk++) {
        float bv = 3e38f; int bi = 0x7fffffff;
        for (int i = t; i < Np; i += 128) { float v = dist[i]; if (v < bv) { bv = v; bi = i; } }
        rv[t] = bv; ri[t] = bi; __syncthreads();
        for (int o = 64; o > 0; o >>= 1) {
            if (t < o && (rv[t+o] < rv[t] || (rv[t+o] == rv[t] && ri[t+o] < ri[t]))) { rv[t]=rv[t+o]; ri[t]=ri[t+o]; }
            __syncthreads();
        }
        if (t == 0) { nidx[((size_t)b*Gg + qc)*Kk + kk] = ri[0]; dist[ri[0]] = 3e38f; }
        __syncthreads();
    }
}

__global__ void knn_small_kernel(const float* __restrict__ pts, int S, int* __restrict__ nidx)
{
    int blk = blockIdx.x, b = blk / S, qi = blk % S, t = threadIdx.x;
    __shared__ float dist[128]; __shared__ float rv[128]; __shared__ int ri[128];
    const float* Q = pts + ((size_t)b*S + qi)*3;
    float qx=Q[0], qy=Q[1], qz=Q[2], qq=qx*qx+qy*qy+qz*qz;
    if (t < S) {
        const float* R = pts + ((size_t)b*S + t)*3;
        dist[t] = qq + (R[0]*R[0]+R[1]*R[1]+R[2]*R[2]) - 2.f*(qx*R[0]+qy*R[1]+qz*R[2]);
    } else dist[t] = 3e38f;
    __syncthreads();
    for (int kk = 0; kk < Kk; kk++) {
        rv[t] = dist[t]; ri[t] = t; __syncthreads();
        for (int o = 64; o > 0; o >>= 1) {
            if (t < o && (rv[t+o] < rv[t] || (rv[t+o] == rv[t] && ri[t+o] < ri[t]))) { rv[t]=rv[t+o]; ri[t]=ri[t+o]; }
            __syncthreads();
        }
        if (t == 0) { nidx[((size_t)b*S + qi)*Kk + kk] = ri[0]; dist[ri[0]] = 3e38f; }
        __syncthreads();
    }
}

__global__ void zero_u8_kernel(unsigned char* m, int n)
{ int i = blockIdx.x*blockDim.x + threadIdx.x; if (i < n) m[i] = 0; }

__global__ void scatter_mask_kernel(const int* __restrict__ nidx, unsigned char* __restrict__ m, int S)
{
    int i = blockIdx.x*blockDim.x + threadIdx.x;
    if (i >= Bb*S*Kk) return;
    int b = i / (S*Kk), r = (i / Kk) % S;
    m[((size_t)b*S + r)*S + nidx[i]] = 1;
}

// both sides: rel -> half, padded rows of 32
__global__ void group_rel_kernel(const float* __restrict__ pos0, const float* __restrict__ pos1,
                                 const float* __restrict__ centers, const int* __restrict__ nidx,
                                 __half* __restrict__ rel)
{
    int i = blockIdx.x*blockDim.x + threadIdx.x;
    if (i >= 2*Bb*Gg*Kk) return;
    int side = i / (Bb*Gg*Kk);
    int cb = i / (Gg*Kk);
    int b = cb % Bb;
    int g = (i / Kk) % Gg;
    const float* pos = side ? pos1 : pos0;
    int src = nidx[i];
    const float* P = pos + ((size_t)b*Np + src)*3;
    const float* C = centers + ((size_t)cb*Gg + g)*3;
    __half* rp = rel + (size_t)i*32;
    rp[0] = __float2half(P[0]-C[0]);
    rp[1] = __float2half(P[1]-C[1]);
    rp[2] = __float2half(P[2]-C[2]);
    for (int j = 3; j < 32; j++) rp[j] = __float2half(0.f);
}

__global__ void gmax_h_kernel(const __half* __restrict__ f, __half* __restrict__ g, int C, int tot)
{
    int i = blockIdx.x*blockDim.x + threadIdx.x;
    if (i >= tot) return;
    int bg = i / C, c = i % C;
    const __half* fp = f + (size_t)bg*Kk*C + c;
    float m = __half2float(fp[0]);
    #pragma unroll
    for (int k = 1; k < Kk; k++) m = fmaxf(m, __half2float(fp[(size_t)k*C]));
    g[i] = __float2half(m);
}

__global__ void gmax_f_kernel(const float* __restrict__ f, float* __restrict__ g, int C, int tot)
{
    int i = blockIdx.x*blockDim.x + threadIdx.x;
    if (i >= tot) return;
    int bg = i / C, c = i % C;
    const float* fp = f + (size_t)bg*Kk*C + c;
    float m = fp[0];
    #pragma unroll
    for (int k = 1; k < Kk; k++) m = fmaxf(m, fp[(size_t)k*C]);
    g[i] = m;
}

__global__ void cat_kernel(const __half* __restrict__ g, const __half* __restrict__ f,
                           __half* __restrict__ cat, int tot)
{
    int i = blockIdx.x*blockDim.x + threadIdx.x;
    if (i >= tot) return;
    int c = i % 512, r = i / 512, bg = r / Kk;
    cat[i] = (c < 256) ? g[(size_t)bg*256 + c] : f[(size_t)r*256 + (c - 256)];
}

// fast PE: exp2f + __sinf/__cosf
__global__ void pe_kernel(const float* __restrict__ xyz, float* __restrict__ pe, int rows)
{
    int i = blockIdx.x*blockDim.x + threadIdx.x;
    if (i >= rows*Dd) return;
    int r = i / Dd, j = i % Dd, c = j / 128, jj = j % 128;
    float x = xyz[(size_t)r*3 + c];
    float ex = (float)(2*(jj/2)) * (1.0f/128.0f);
    float p = x * exp2f(-ex * 13.287712379549449f);
    pe[i] = (jj & 1) ? __cosf(p) : __sinf(p);
}

__global__ void gather_kernel(const float* __restrict__ src, const int* __restrict__ idx,
                              float* __restrict__ dst, int outR, int inR, int W)
{
    int row = blockIdx.x, b = row / outR, r = row % outR;
    int s = idx[(size_t)b*outR + r];
    const float* sp = src + ((size_t)b*inR + s)*W;
    float* dp = dst + (size_t)row*W;
    for (int w = threadIdx.x; w < W; w += blockDim.x) dp[w] = sp[w];
}

__global__ void decq_kernel(const float* __restrict__ visout, const float* __restrict__ cpe,
                            const float* __restrict__ mask_token, const int* __restrict__ mskidx,
                            const int* __restrict__ visidx, float* __restrict__ x)
{
    int i = blockIdx.x*blockDim.x + threadIdx.x;
    if (i >= Bb*(Mm+Vv)*Dd) return;
    int d = i % Dd, r = (i / Dd) % (Mm+Vv), b = i / (Dd*(Mm+Vv));
    float base; int pidx;
    if (r < Mm) { base = mask_token[d]; pidx = mskidx[(size_t)b*Mm + r]; }
    else { base = visout[((size_t)b*Vv + (r-Mm))*Dd + d]; pidx = visidx[(size_t)b*Vv + (r-Mm)]; }
    x[i] = base + cpe[((size_t)b*Gg + pidx)*Dd + d];
}

__global__ void add_kernel(const float* __restrict__ a, const float* __restrict__ b,
                           float* __restrict__ c, int n)
{ int i = blockIdx.x*blockDim.x + threadIdx.x; if (i < n) c[i] = a[i] + b[i]; }

__global__ void nn3_kernel(const float* __restrict__ pos, const float* __restrict__ centers,
                           int* __restrict__ oi, float* __restrict__ ow)
{
    int i = blockIdx.x*blockDim.x + threadIdx.x;
    if (i >= Bb*Np) return;
    int b = i / Np;
    const float* P = pos + (size_t)i*3;
    float px=P[0], py=P[1], pz=P[2], qq=px*px+py*py+pz*pz;
    float d0=3e38f, d1=3e38f, d2=3e38f; int i0=-1, i1=-1, i2=-1;
    const float* C = centers + (size_t)b*Gg*3;
    for (int g = 0; g < Gg; g++) {
        float cx=C[3*g], cy=C[3*g+1], cz=C[3*g+2];
        float d = qq + (cx*cx+cy*cy+cz*cz) - 2.f*(px*cx+py*cy+pz*cz);
        if (d < d0) { d2=d1;i2=i1; d1=d0;i1=i0; d0=d;i0=g; }
        else if (d < d1) { d2=d1;i2=i1; d1=d;i1=g; }
        else if (d < d2) { d2=d;i2=g; }
    }
    float w0=1.f/(fmaxf(d0,0.f)+1e-8f), w1=1.f/(fmaxf(d1,0.f)+1e-8f), w2=1.f/(fmaxf(d2,0.f)+1e-8f);
    float s = w0+w1+w2;
    ow[3*i]=w0/s; ow[3*i+1]=w1/s; ow[3*i+2]=w2/s;
    oi[3*i]=i0; oi[3*i+1]=i1; oi[3*i+2]=i2;
}

__global__ void upcat_kernel(const float* __restrict__ feats, const float* __restrict__ pos,
                             const int* __restrict__ oi, const float* __restrict__ ow,
                             __half* __restrict__ cat)
{
    int row = blockIdx.x, b = row / Np, t = threadIdx.x;
    int i0=oi[3*row], i1=oi[3*row+1], i2=oi[3*row+2];
    float w0=ow[3*row], w1=ow[3*row+1], w2=ow[3*row+2];
    const float* F = feats + (size_t)b*Gg*Dd;
    __half* cp = cat + (size_t)row*UPK;
    for (int d = t; d < Dd; d += 128)
        cp[d] = __float2half(w0*F[(size_t)i0*Dd+d] + w1*F[(size_t)i1*Dd+d] + w2*F[(size_t)i2*Dd+d]);
    if (t < 32) cp[Dd + t] = __float2half((t < 3) ? pos[(size_t)row*3 + t] : 0.f);
}

__global__ void loss_kernel(const float* __restrict__ fullout, const int* __restrict__ mskidx,
                            const float* __restrict__ decx, float* __restrict__ partial)
{
    __shared__ float red[256];
    int t = threadIdx.x;
    float acc = 0.f;
    for (int i = blockIdx.x*256 + t; i < Bb*Mm*Dd; i += 64*256) {
        int d = i % Dd, r = (i / Dd) % Mm, b = i / (Dd*Mm);
        int gi = mskidx[(size_t)b*Mm + r];
        float tv = fullout[((size_t)b*Gg + gi)*Dd + d];
        float pv = decx[((size_t)b*(Mm+Vv) + r)*Dd + d];
        float a = fabsf(pv - tv);
        acc += (a < 2.0f) ? 0.25f*a*a : a - 1.0f;
    }
    red[t] = acc; __syncthreads();
    for (int o = 128; o > 0; o >>= 1) { if (t < o) red[t] += red[t+o]; __syncthreads(); }
    if (t == 0) partial[blockIdx.x] = red[0];
}

__global__ void loss_final_kernel(const float* __restrict__ pa, const float* __restrict__ pb,
                                  float* __restrict__ out)
{
    float sa = 0.f, sb = 0.f;
    for (int i = 0; i < 64; i++) { sa += pa[i]; sb += pb[i]; }
    float cnt = (float)(Bb*Mm*Dd);
    out[0] = 0.5f*(sa/cnt) + 0.5f*(sb/cnt);
}

__global__ void copy_kernel(const float* __restrict__ a, float* __restrict__ b, int n)
{ int i = blockIdx.x*blockDim.x + threadIdx.x; if (i < n) b[i] = a[i]; }

// ------------------------------ host side --------------------------------

static __half* WTH;
static float *QB, *SKV;
static __half *CTXH;

static void gemm_h(const __half* A, const __half* Wt, const float* bias,
                   float* Cf, __half* Ch, int rows, int Kd, int Nc, int relu, int accum)
{
    dim3 grid(Nc/128, rows/128);
    gemm_h_kernel<<<grid, 256>>>(A, Wt, bias, Cf, Ch, rows, Kd, Nc, relu, accum);
}

// fused self-attention: one qkv gemm (N=1152)
static void self_attn(float* x, const __half* lnx, long woff, const unsigned char* mask,
                      int S, int nB)
{
    gemm_h(lnx, WTH + woff, nullptr, SKV, nullptr, nB*S, Dd, 3*Dd, 0, 0);
    dim3 g(S, NHh, nB);
    attn_kernel<<<g, 128>>>(SKV, 3*Dd, SKV + Dd, SKV + 2*Dd, 3*Dd, mask, CTXH, S, S, 0);
    gemm_h(CTXH, WTH + woff + 3*MSZ, nullptr, x, nullptr, nB*S, Dd, Dd, 0, 1);
}

// cross-attention: q gemm + fused kv gemm (N=768)
static void cross_attn(float* x, const __half* lnq, const __half* lnkv, long woff,
                       int Sq, int Sk, int nB, int kvxor, int big)
{
    gemm_h(lnq,  WTH + woff,       nullptr, QB, nullptr, nB*Sq, Dd, Dd, 0, 0);
    gemm_h(lnkv, WTH + woff + MSZ, nullptr, SKV, nullptr, nB*Sk, Dd, 2*Dd, 0, 0);
    if (big) {
        dim3 g(Sq/QT, NHh, nB);
        attn_big_kernel<<<g, 128>>>(QB, Dd, SKV, SKV + Dd, 2*Dd, CTXH, Sq);
    } else {
        dim3 g(Sq, NHh, nB);
        attn_kernel<<<g, 128>>>(QB, Dd, SKV, SKV + Dd, 2*Dd, nullptr, CTXH, Sq, Sk, kvxor);
    }
    gemm_h(CTXH, WTH + woff + 3*MSZ, nullptr, x, nullptr, nB*Sq, Dd, Dd, 0, 1);
}

#define GETSYM(var, sym) do { void* _p; cudaGetSymbolAddress(&_p, sym); var = (decltype(var))_p; } while (0)

extern "C" void kernel_launch(void* const* d_in, const int* in_sizes, int n_in,
                              void* d_out_v, int out_size)
{
    (void)in_sizes; (void)n_in; (void)out_size;
    const float* pos[2]    = {(const float*)d_in[0], (const float*)d_in[1]};
    const int*   visidx[2] = {(const int*)d_in[2], (const int*)d_in[4]};
    const int*   mskidx[2] = {(const int*)d_in[3], (const int*)d_in[5]};
    const float* tok_w1 = (const float*)d_in[6];  const float* tok_b1 = (const float*)d_in[7];
    const float* tok_w2 = (const float*)d_in[8];  const float* tok_b2 = (const float*)d_in[9];
    const float* tok_w3 = (const float*)d_in[10]; const float* tok_b3 = (const float*)d_in[11];
    const float* tok_w4 = (const float*)d_in[12]; const float* tok_b4 = (const float*)d_in[13];
    const float* mask_token = (const float*)d_in[14];
    const float* cx_attn = (const float*)d_in[15];
    const float* cx_ff1  = (const float*)d_in[16]; const float* cx_ff2 = (const float*)d_in[17];
    const float* enc_sa  = (const float*)d_in[18]; const float* enc_ca = (const float*)d_in[19];
    const float* enc_ff1 = (const float*)d_in[20]; const float* enc_ff2 = (const float*)d_in[21];
    const float* dec_ca  = (const float*)d_in[22]; const float* dec_ff1 = (const float*)d_in[23];
    const float* dec_ff2 = (const float*)d_in[24];
    const float* up_w1 = (const float*)d_in[25]; const float* up_b1 = (const float*)d_in[26];
    const float* up_w2 = (const float*)d_in[27]; const float* up_b2 = (const float*)d_in[28];
    float* dout = (float*)d_out_v;

    float *centersB, *t2B, *tokensB, *cpeB, *ppeB, *vis3B, *visB, *fullB, *decxB, *mbufB, *nn3wB, *lpartB;
    int *nidxB, *nidxSB, *nn3iB;
    unsigned char *mfullB, *mvisB;
    __half *relH, *f1H, *f2H, *gmaxH, *catH, *t1H, *lnSH, *lnmH, *lnbigH, *hidH, *upcatH;
    GETSYM(centersB, g_centers); GETSYM(nidxB, g_nidx); GETSYM(nidxSB, g_nidxS);
    GETSYM(t2B, g_t2); GETSYM(tokensB, g_tokens);
    GETSYM(cpeB, g_cpe); GETSYM(ppeB, g_ppe); GETSYM(mfullB, g_mfull); GETSYM(mvisB, g_mvis);
    GETSYM(vis3B, g_vis3); GETSYM(visB, g_visbuf); GETSYM(fullB, g_fullbuf); GETSYM(decxB, g_decx);
    GETSYM(mbufB, g_mbuf); GETSYM(QB, g_qbuf); GETSYM(SKV, g_skv);
    GETSYM(nn3iB, g_nn3i); GETSYM(nn3wB, g_nn3w); GETSYM(lpartB, g_lpart);
    GETSYM(relH, g_relh); GETSYM(f1H, g_f1h); GETSYM(f2H, g_f2h); GETSYM(gmaxH, g_gmaxh);
    GETSYM(catH, g_cath); GETSYM(t1H, g_t1h); GETSYM(lnSH, g_lnSh);
    GETSYM(lnmH, g_lnmh); GETSYM(lnbigH, g_lnbigh); GETSYM(hidH, g_hidh);
    GETSYM(CTXH, g_ctxh); GETSYM(upcatH, g_upcath); GETSYM(WTH, g_wth);

    float* centers[2] = {centersB, centersB + Bb*Gg*3};
    float* tokens[2]  = {tokensB,  tokensB  + Bb*Gg*Dd};
    float* cpe[2]     = {cpeB,     cpeB     + Bb*Gg*Dd};
    float* ppe[2]     = {ppeB,     ppeB     + Bb*Np*Dd};
    float* visb[2]    = {visB,     visB     + Bb*Vv*Dd};
    float* fullb[2]   = {fullB,    fullB    + Bb*Gg*Dd};
    float* decx[2]    = {decxB,    decxB    + Bb*(Mm+Vv)*Dd};
    unsigned char* mfull[2] = {mfullB, mfullB + Bb*Gg*Gg};
    unsigned char* mvis[2]  = {mvisB,  mvisB  + Bb*Vv*Vv};

    // Phase 0: fused weight conversion
    {
        WConvArgs wa;
        const float* srcs[16] = {tok_w1, tok_w2, tok_w3, tok_w4, cx_attn, enc_sa, enc_ca,
                                 dec_ca, cx_ff1, cx_ff2, enc_ff1, enc_ff2, dec_ff1, dec_ff2,
                                 up_w1, up_w2};
        long starts[17] = {OFF_W1, OFF_W2, OFF_W3, OFF_W4, OFF_CX, OFF_ENCSA, OFF_ENCCA,
                           OFF_DECCA, OFF_CXFF1, OFF_CXFF2, OFF_EFF1, OFF_EFF2, OFF_DFF1,
                           OFF_DFF2, OFF_UP1, OFF_UP2, WTH_TOT};
        int kds[16]  = {3, 128, 512, 512, Dd, Dd, Dd, Dd, Dd, FFf, Dd, FFf, Dd, FFf, Dd+3, Dd};
        int kps[16]  = {32, 128, 512, 512, Dd, Dd, Dd, Dd, Dd, FFf, Dd, FFf, Dd, FFf, UPK, Dd};
        int ncs[16]  = {128, 256, 512, Dd, Dd, Dd, Dd, Dd, FFf, Dd, FFf, Dd, FFf, Dd, Dd, Dd};
        for (int i = 0; i < 16; i++) { wa.src[i]=srcs[i]; wa.start[i]=starts[i]; wa.Kd[i]=kds[i]; wa.KdPad[i]=kps[i]; wa.Nc[i]=ncs[i]; }
        wa.start[16] = starts[16];
        wtconv_all_kernel<<<(int)(((long)WTH_TOT + 255)/256), 256>>>(wa, WTH);
    }

    // Phase 1: FPS/KNN per side, tokenizer batched over both sides
    for (int s = 0; s < 2; s++) {
        fps_kernel<<<Bb, 512>>>(pos[s], centers[s]);
        knn_big_kernel<<<Bb*Gg, 128>>>(centers[s], pos[s], nidxB + s*Bb*Gg*Kk);
    }
    group_rel_kernel<<<(2*Bb*Gg*Kk + 255)/256, 256>>>(pos[0], pos[1], centersB, nidxB, relH);
    gemm_h(relH, WTH + OFF_W1, tok_b1, nullptr, f1H, 32768, 32, 128, 1, 0);
    gemm_h(f1H, WTH + OFF_W2, tok_b2, nullptr, f2H, 32768, 128, 256, 0, 0);
    gmax_h_kernel<<<(2*Bb*Gg*256 + 255)/256, 256>>>(f2H, gmaxH, 256, 2*Bb*Gg*256);
    cat_kernel<<<(32768*512 + 255)/256, 256>>>(gmaxH, f2H, catH, 32768*512);
    gemm_h(catH, WTH + OFF_W3, tok_b3, nullptr, t1H, 32768, 512, 512, 1, 0);
    gemm_h(t1H, WTH + OFF_W4, tok_b4, t2B, nullptr, 32768, 512, Dd, 0, 0);
    gmax_f_kernel<<<(2*Bb*Gg*Dd + 255)/256, 256>>>(t2B, tokensB, Dd, 2*Bb*Gg*Dd);
    for (int s = 0; s < 2; s++) {
        pe_kernel<<<(Bb*Gg*Dd + 255)/256, 256>>>(centers[s], cpe[s], Bb*Gg);
        pe_kernel<<<(Bb*Np*Dd + 255)/256, 256>>>(pos[s], ppe[s], Bb*Np);
        knn_small_kernel<<<Bb*Gg, 128>>>(centers[s], Gg, nidxSB);
        zero_u8_kernel<<<(Bb*Gg*Gg + 255)/256, 256>>>(mfull[s], Bb*Gg*Gg);
        scatter_mask_kernel<<<(Bb*Gg*Kk + 255)/256, 256>>>(nidxSB, mfull[s], Gg);
        gather_kernel<<<Bb*Vv, 32>>>(centers[s], visidx[s], vis3B, Vv, Gg, 3);
        knn_small_kernel<<<Bb*Vv, 128>>>(vis3B, Vv, nidxSB);
        zero_u8_kernel<<<(Bb*Vv*Vv + 255)/256, 256>>>(mvis[s], Bb*Vv*Vv);
        scatter_mask_kernel<<<(Bb*Vv*Kk + 255)/256, 256>>>(nidxSB, mvis[s], Vv);
        gather_kernel<<<Bb*Vv, 128>>>(tokens[s], visidx[s], visb[s], Vv, Gg, Dd);
        copy_kernel<<<(Bb*Gg*Dd + 255)/256, 256>>>(tokens[s], fullb[s], Bb*Gg*Dd);
    }

    // Phase 2: cross encoders (S and T batched as 16 batches; cross uses kvxor=Bb)
    for (int e = 0; e < 2; e++) {
        int S = e ? Gg : Vv;
        float* ST = e ? fullB : visB;
        const unsigned char* mask = e ? mfullB : mvisB;
        int rows2 = 2*Bb*S;
        ln_kernel<<<rows2, 128>>>(ST, lnSH);
        self_attn(ST, lnSH, OFF_CX, mask, S, 2*Bb);
        ln_kernel<<<rows2, 128>>>(ST, lnSH);
        cross_attn(ST, lnSH, lnSH, OFF_CX + 4*MSZ, S, S, 2*Bb, Bb, 0);
        ln_kernel<<<rows2, 128>>>(ST, lnSH);
        gemm_h(lnSH, WTH + OFF_CXFF1, nullptr, nullptr, hidH, rows2, Dd, FFf, 1, 0);
        gemm_h(hidH, WTH + OFF_CXFF2, nullptr, ST, nullptr, rows2, FFf, Dd, 0, 1);
    }

    // Phase 3: MAE decoder (both sides batched; mem side-swapped at build)
    for (int s = 0; s < 2; s++)
        decq_kernel<<<(Bb*(Mm+Vv)*Dd + 255)/256, 256>>>(visb[s], cpe[s], mask_token,
                                                        mskidx[s], visidx[s], decx[s]);
    add_kernel<<<(Bb*Gg*Dd + 255)/256, 256>>>(fullb[1], cpe[1], mbufB, Bb*Gg*Dd);
    add_kernel<<<(Bb*Gg*Dd + 255)/256, 256>>>(fullb[0], cpe[0], mbufB + Bb*Gg*Dd, Bb*Gg*Dd);
    ln_kernel<<<2*Bb*Gg, 128>>>(mbufB, lnmH);
    for (int l = 0; l < 4; l++) {
        ln_kernel<<<2*Bb*(Mm+Vv), 128>>>(decxB, lnSH);
        self_attn(decxB, lnSH, OFF_ENCSA + (long)l*4*MSZ, nullptr, Mm+Vv, 2*Bb);
        ln_kernel<<<2*Bb*(Mm+Vv), 128>>>(decxB, lnSH);
        cross_attn(decxB, lnSH, lnmH, OFF_ENCCA + (long)l*4*MSZ, Mm+Vv, Gg, 2*Bb, 0, 0);
        ln_kernel<<<2*Bb*(Mm+Vv), 128>>>(decxB, lnSH);
        gemm_h(lnSH, WTH + OFF_EFF1 + (long)l*Dd*FFf, nullptr, nullptr, hidH, 2*Bb*(Mm+Vv), Dd, FFf, 1, 0);
        gemm_h(hidH, WTH + OFF_EFF2 + (long)l*FFf*Dd, nullptr, decxB, nullptr, 2*Bb*(Mm+Vv), FFf, Dd, 0, 1);
    }
    for (int s = 0; s < 2; s++)
        loss_kernel<<<64, 256>>>(fullb[s], mskidx[s], decx[s], lpartB + s*64);

    // Phase 4: upsample + dense decoder (both sides batched, rows=65536)
    for (int s = 0; s < 2; s++) {
        nn3_kernel<<<(Bb*Np + 255)/256, 256>>>(pos[s], centers[s], nn3iB, nn3wB);
        upcat_kernel<<<Bb*Np, 128>>>(fullb[s], pos[s], nn3iB, nn3wB, upcatH + (size_t)s*Bb*Np*UPK);
    }
    gemm_h(upcatH, WTH + OFF_UP1, up_b1, nullptr, hidH, 2*Bb*Np, UPK, Dd, 1, 0);
    gemm_h(hidH, WTH + OFF_UP2, up_b2, QB, nullptr, 2*Bb*Np, Dd, Dd, 1, 0);
    add_kernel<<<(2*Bb*Np*Dd + 255)/256, 256>>>(QB, ppeB, dout, 2*Bb*Np*Dd);
    add_kernel<<<(Bb*Gg*Dd + 255)/256, 256>>>(fullb[0], cpe[0], mbufB, Bb*Gg*Dd);
    add_kernel<<<(Bb*Gg*Dd + 255)/256, 256>>>(fullb[1], cpe[1], mbufB + Bb*Gg*Dd, Bb*Gg*Dd);
    ln_kernel<<<2*Bb*Gg, 128>>>(mbufB, lnmH);
    for (int l = 0; l < 2; l++) {
        ln_kernel<<<2*Bb*Np, 128>>>(dout, lnbigH);
        cross_attn(dout, lnbigH, lnmH, OFF_DECCA + (long)l*4*MSZ, Np, Gg, 2*Bb, 0, 1);
        ln_kernel<<<2*Bb*Np, 128>>>(dout, lnbigH);
        gemm_h(lnbigH, WTH + OFF_DFF1 + (long)l*Dd*FFf, nullptr, nullptr, hidH, 2*Bb*Np, Dd, FFf, 1, 0);
        gemm_h(hidH, WTH + OFF_DFF2 + (long)l*FFf*Dd, nullptr, dout, nullptr, 2*Bb*Np, FFf, Dd, 0, 1);
    }
    loss_final_kernel<<<1, 1>>>(lpartB, lpartB + 64, dout + (size_t)2*Bb*Np*Dd);
}

// round 11
// speedup vs baseline: 5.4867x; 1.0976x over previous
#include <cuda_runtime.h>
#include <cuda_fp16.h>
#include <math.h>
#include <stdint.h>

#define Bb 8
#define Np 4096
#define Gg 128
#define Kk 16
#define Vv 64
#define Mm 64
#define Dd 384
#define NHh 8
#define DHh 48
#define FFf 1536
#define UPK 416

// fp32 buffers
__device__ float g_centers[2*Bb*Gg*3];
__device__ int   g_nidx[2*Bb*Gg*Kk];
__device__ int   g_nidxS[2*Bb*Gg*Kk];
__device__ float g_t2[2*16384*Dd];
__device__ float g_tokens[2*Bb*Gg*Dd];
__device__ float g_cpe[2*Bb*Gg*Dd];
__device__ float g_ppe[2*Bb*Np*Dd];
__device__ unsigned char g_mfull[2*Bb*Gg*Gg];
__device__ unsigned char g_mvis[2*Bb*Vv*Vv];
__device__ float g_vis3[Bb*Vv*3];
__device__ float g_visbuf[2*Bb*Vv*Dd];
__device__ float g_fullbuf[2*Bb*Gg*Dd];
__device__ float g_decx[2*Bb*(Mm+Vv)*Dd];
__device__ float g_mbuf[2*Bb*Gg*Dd];
__device__ float g_qbuf[2*Bb*Np*Dd];
__device__ float g_skv[2048*1152];
__device__ int   g_nn3i[Bb*Np*3];
__device__ float g_nn3w[Bb*Np*3];
__device__ float g_lpart[2*64];

// half buffers
__device__ __align__(16) __half g_relh[32768*32];
__device__ __align__(16) __half g_f1h[32768*128];
__device__ __align__(16) __half g_f2h[32768*256];
__device__ __align__(16) __half g_gmaxh[2*Bb*Gg*256];
__device__ __align__(16) __half g_cath[32768*512];
__device__ __align__(16) __half g_t1h[32768*512];
__device__ __align__(16) __half g_lnSh[2*Bb*Gg*Dd];
__device__ __align__(16) __half g_lnmh[2*Bb*Gg*Dd];
__device__ __align__(16) __half g_lnbigh[2*Bb*Np*Dd];
__device__ __align__(16) __half g_hidh[(size_t)2*Bb*Np*FFf];
__device__ __align__(16) __half g_ctxh[2*Bb*Np*Dd];
__device__ __align__(16) __half g_upcath[2*Bb*Np*UPK];

#define MSZ 147456
#define OFF_W1    0
#define OFF_W2    (OFF_W1 + 32*128)
#define OFF_W3    (OFF_W2 + 128*256)
#define OFF_W4    (OFF_W3 + 512*512)
#define OFF_CX    (OFF_W4 + 512*384)
#define OFF_ENCSA (OFF_CX + 8*MSZ)
#define OFF_ENCCA (OFF_ENCSA + 16*MSZ)
#define OFF_DECCA (OFF_ENCCA + 16*MSZ)
#define OFF_CXFF1 (OFF_DECCA + 8*MSZ)
#define OFF_CXFF2 (OFF_CXFF1 + 384*1536)
#define OFF_EFF1  (OFF_CXFF2 + 1536*384)
#define OFF_EFF2  (OFF_EFF1 + 4*384*1536)
#define OFF_DFF1  (OFF_EFF2 + 4*1536*384)
#define OFF_DFF2  (OFF_DFF1 + 2*384*1536)
#define OFF_UP1   (OFF_DFF2 + 2*1536*384)
#define OFF_UP2   (OFF_UP1 + 416*384)
#define WTH_TOT   (OFF_UP2 + 384*384)
__device__ __align__(16) __half g_wth[WTH_TOT];

struct WConvArgs {
    const float* src[16];
    long start[17];
    int Kd[16], KdPad[16], Nc[16];
};

__global__ void wtconv_all_kernel(WConvArgs A, __half* __restrict__ dst)
{
    long i = (long)blockIdx.x*256 + threadIdx.x;
    if (i >= A.start[16]) return;
    int s = 0;
    while (s < 15 && i >= A.start[s+1]) s++;
    long li = i - A.start[s];
    int Kd = A.Kd[s], Kp = A.KdPad[s], Nc = A.Nc[s];
    long per = (long)Nc*Kp;
    int mt = (int)(li/per);
    long r = li % per;
    int n = (int)(r/Kp), k = (int)(r%Kp);
    float v = (k < Kd) ? A.src[s][(size_t)mt*Kd*Nc + (size_t)k*Nc + n] : 0.f;
    dst[i] = __float2half(v);
}

// fp16 GEMM: 128x128 tile, KT=32, 3-stage cp.async, one barrier/iter, ldmatrix
__global__ __launch_bounds__(256)
void gemm_h_kernel(const __half* __restrict__ A, const __half* __restrict__ Wt,
                   const float* __restrict__ bias, float* __restrict__ Cf,
                   __half* __restrict__ Ch, int rows, int Kd, int Nc, int relu, int accum)
{
    __shared__ __half Ah[3][128][40];
    __shared__ __half Wh[3][128][40];
    int tid = threadIdx.x, wid = tid>>5, lane = tid&31;
    int g = lane>>2, tig = lane&3;
    int wm = (wid>>1)*32, wn = (wid&1)*64;
    int row0 = blockIdx.y*128, col0 = blockIdx.x*128;
    float c[2][8][4] = {};
    int nIter = Kd/32;

    int lr = lane & 7, lj = lane >> 3;
    uint32_t ah0 = (uint32_t)__cvta_generic_to_shared(&Ah[0][0][0]);
    uint32_t wh0 = (uint32_t)__cvta_generic_to_shared(&Wh[0][0][0]);
    uint32_t aAddr[2], wAddr[4];
    #pragma unroll
    for (int mt = 0; mt < 2; mt++)
        aAddr[mt] = ah0 + (uint32_t)((wm + mt*16 + lr + (lj&1)*8)*80 + ((lj>>1)*8)*2);
    #pragma unroll
    for (int p = 0; p < 4; p++)
        wAddr[p] = wh0 + (uint32_t)((wn + p*16 + lr + ((lj>>1)&1)*8)*80 + ((lj&1)*8)*2);

    // prologue: stages 0,1
    #pragma unroll
    for (int st = 0; st < 2; st++) {
        if (st < nIter) {
            int k0 = st*32;
            #pragma unroll
            for (int l = 0; l < 2; l++) {
                int ci = tid + l*256;
                int m = ci>>2, f = ci&3;
                const __half* ga = A + (size_t)(row0+m)*Kd + k0 + f*8;
                uint32_t sa = (uint32_t)__cvta_generic_to_shared(&Ah[st][m][f*8]);
                asm volatile("cp.async.cg.shared.global [%0], [%1], 16;" :: "r"(sa), "l"(ga));
                const __half* gw = Wt + (size_t)(col0+m)*Kd + k0 + f*8;
                uint32_t sw = (uint32_t)__cvta_generic_to_shared(&Wh[st][m][f*8]);
                asm volatile("cp.async.cg.shared.global [%0], [%1], 16;" :: "r"(sw), "l"(gw));
            }
            asm volatile("cp.async.commit_group;");
        }
    }

    for (int it = 0; it < nIter; it++) {
        if (it < nIter-1) asm volatile("cp.async.wait_group 1;");
        else              asm volatile("cp.async.wait_group 0;");
        __syncthreads();
        int cur = it % 3;
        uint32_t stOff = (uint32_t)(cur*10240);
        #pragma unroll
        for (int st = 0; st < 2; st++) {
            uint32_t kOff = stOff + st*32;
            uint32_t a[2][4], b[8][2];
            #pragma unroll
            for (int mt = 0; mt < 2; mt++)
                asm volatile("ldmatrix.sync.aligned.m8n8.x4.shared.b16 {%0,%1,%2,%3}, [%4];"
                    : "=r"(a[mt][0]), "=r"(a[mt][1]), "=r"(a[mt][2]), "=r"(a[mt][3])
                    : "r"(aAddr[mt] + kOff));
            #pragma unroll
            for (int p = 0; p < 4; p++) {
                uint32_t d0, d1, d2, d3;
                asm volatile("ldmatrix.sync.aligned.m8n8.x4.shared.b16 {%0,%1,%2,%3}, [%4];"
                    : "=r"(d0), "=r"(d1), "=r"(d2), "=r"(d3)
                    : "r"(wAddr[p] + kOff));
                b[2*p][0] = d0; b[2*p][1] = d1; b[2*p+1][0] = d2; b[2*p+1][1] = d3;
            }
            #pragma unroll
            for (int mt = 0; mt < 2; mt++)
                #pragma unroll
                for (int nt = 0; nt < 8; nt++)
                    asm volatile(
                        "mma.sync.aligned.m16n8k16.row.col.f32.f16.f16.f32 "
                        "{%0,%1,%2,%3}, {%4,%5,%6,%7}, {%8,%9}, {%0,%1,%2,%3};"
                        : "+f"(c[mt][nt][0]), "+f"(c[mt][nt][1]),
                          "+f"(c[mt][nt][2]), "+f"(c[mt][nt][3])
                        : "r"(a[mt][0]), "r"(a[mt][1]), "r"(a[mt][2]), "r"(a[mt][3]),
                          "r"(b[nt][0]), "r"(b[nt][1]));
        }
        if (it + 2 < nIter) {
            int p = (it+2) % 3;
            int k0 = (it+2)*32;
            #pragma unroll
            for (int l = 0; l < 2; l++) {
                int ci = tid + l*256;
                int m = ci>>2, f = ci&3;
                const __half* ga = A + (size_t)(row0+m)*Kd + k0 + f*8;
                uint32_t sa = (uint32_t)__cvta_generic_to_shared(&Ah[p][m][f*8]);
                asm volatile("cp.async.cg.shared.global [%0], [%1], 16;" :: "r"(sa), "l"(ga));
                const __half* gw = Wt + (size_t)(col0+m)*Kd + k0 + f*8;
                uint32_t sw = (uint32_t)__cvta_generic_to_shared(&Wh[p][m][f*8]);
                asm volatile("cp.async.cg.shared.global [%0], [%1], 16;" :: "r"(sw), "l"(gw));
            }
            asm volatile("cp.async.commit_group;");
        }
    }
    #pragma unroll
    for (int mt = 0; mt < 2; mt++) {
        #pragma unroll
        for (int nt = 0; nt < 8; nt++) {
            int r0 = row0 + wm + mt*16 + g;
            int cc = col0 + wn + nt*8 + 2*tig;
            float v0 = c[mt][nt][0], v1 = c[mt][nt][1];
            float v2 = c[mt][nt][2], v3 = c[mt][nt][3];
            if (bias) { float b0 = bias[cc], b1 = bias[cc+1]; v0 += b0; v1 += b1; v2 += b0; v3 += b1; }
            if (relu) { v0 = fmaxf(v0,0.f); v1 = fmaxf(v1,0.f); v2 = fmaxf(v2,0.f); v3 = fmaxf(v3,0.f); }
            size_t o0 = (size_t)r0*Nc + cc;
            size_t o1 = (size_t)(r0+8)*Nc + cc;
            if (Ch) {
                Ch[o0] = __float2half(v0); Ch[o0+1] = __float2half(v1);
                Ch[o1] = __float2half(v2); Ch[o1+1] = __float2half(v3);
            } else if (accum) {
                Cf[o0] += v0; Cf[o0+1] += v1; Cf[o1] += v2; Cf[o1+1] += v3;
            } else {
                Cf[o0] = v0; Cf[o0+1] = v1; Cf[o1] = v2; Cf[o1+1] = v3;
            }
        }
    }
}

__global__ void ln_kernel(const float* __restrict__ x, __half* __restrict__ y)
{
    int row = blockIdx.x, t = threadIdx.x;
    const float* xr = x + (size_t)row*Dd;
    __shared__ float red[128];
    float a = xr[t], b = xr[t+128], c = xr[t+256];
    red[t] = a + b + c; __syncthreads();
    for (int o = 64; o > 0; o >>= 1) { if (t < o) red[t] += red[t+o]; __syncthreads(); }
    float m = red[0] / (float)Dd; __syncthreads();
    float da=a-m, db=b-m, dc=c-m;
    red[t] = da*da + db*db + dc*dc; __syncthreads();
    for (int o = 64; o > 0; o >>= 1) { if (t < o) red[t] += red[t+o]; __syncthreads(); }
    float inv = rsqrtf(red[0] / (float)Dd + 1e-5f);
    __half* yr = y + (size_t)row*Dd;
    yr[t]=__float2half(da*inv); yr[t+128]=__float2half(db*inv); yr[t+256]=__float2half(dc*inv);
}

// small attention: strided q/k/v; kvxor batch map
__global__ void attn_kernel(const float* __restrict__ q, int qs,
                            const float* __restrict__ kmat, const float* __restrict__ vmat, int kvs,
                            const unsigned char* __restrict__ mask,
                            __half* __restrict__ ctx, int Sq, int Sk, int kvxor)
{
    int qi = blockIdx.x, h = blockIdx.y, b = blockIdx.z, t = threadIdx.x;
    int bk = b ^ kvxor;
    __shared__ float shq[DHh], shp[128], red[128];
    const float* qr = q + (size_t)(b*Sq + qi)*qs + h*DHh;
    if (t < DHh) shq[t] = qr[t];
    __syncthreads();
    float val = -3e38f;
    if (t < Sk) {
        const float* kr = kmat + (size_t)(bk*Sk + t)*kvs + h*DHh;
        float s = 0.f;
        #pragma unroll
        for (int d = 0; d < DHh; d++) s += shq[d]*kr[d];
        s /= sqrtf((float)DHh);
        if (mask && !mask[((size_t)b*Sq + qi)*Sk + t]) s = -1e9f;
        val = s;
    }
    red[t] = val; __syncthreads();
    for (int o = 64; o > 0; o >>= 1) { if (t < o) red[t] = fmaxf(red[t], red[t+o]); __syncthreads(); }
    float mx = red[0]; __syncthreads();
    float e = (t < Sk) ? expf(val - mx) : 0.f;
    shp[t] = e; red[t] = e; __syncthreads();
    for (int o = 64; o > 0; o >>= 1) { if (t < o) red[t] += red[t+o]; __syncthreads(); }
    float inv = 1.f / red[0];
    if (t < DHh) {
        float acc = 0.f;
        const float* vb = vmat + (size_t)(bk*Sk)*kvs + h*DHh + t;
        for (int kk = 0; kk < Sk; kk++) acc += shp[kk]*vb[(size_t)kk*kvs];
        ctx[((size_t)(b*Sq + qi))*Dd + h*DHh + t] = __float2half(acc*inv);
    }
}

// big attention: 32 queries/block, Sk==128
#define QT 32
__global__ __launch_bounds__(128)
void attn_big_kernel(const float* __restrict__ q, int qs,
                     const float* __restrict__ kmat, const float* __restrict__ vmat, int kvs,
                     __half* __restrict__ ctx, int Sq)
{
    int qt = blockIdx.x, h = blockIdx.y, b = blockIdx.z, t = threadIdx.x;
    __shared__ float shq[QT][DHh];
    __shared__ float sc[QT][129];
    __shared__ float Vs[128][DHh];
    for (int i = t; i < QT*DHh; i += 128) {
        int qi = i / DHh, d = i % DHh;
        shq[qi][d] = q[(size_t)(b*Sq + qt*QT + qi)*qs + h*DHh + d];
    }
    for (int i = t; i < 128*DHh; i += 128) {
        int k = i / DHh, d = i % DHh;
        Vs[k][d] = vmat[(size_t)(b*128 + k)*kvs + h*DHh + d];
    }
    __syncthreads();
    float kr[DHh];
    {
        const float* kp = kmat + (size_t)(b*128 + t)*kvs + h*DHh;
        #pragma unroll
        for (int d = 0; d < DHh; d++) kr[d] = kp[d];
    }
    float inv_s = sqrtf((float)DHh);
    #pragma unroll 1
    for (int qi = 0; qi < QT; qi++) {
        float s = 0.f;
        #pragma unroll
        for (int d = 0; d < DHh; d++) s += shq[qi][d]*kr[d];
        sc[qi][t] = s / inv_s;
    }
    __syncthreads();
    int w = t >> 5, lane = t & 31;
    for (int qi = w; qi < QT; qi += 4) {
        float v0 = sc[qi][lane], v1 = sc[qi][lane+32], v2 = sc[qi][lane+64], v3 = sc[qi][lane+96];
        float mx = fmaxf(fmaxf(v0,v1), fmaxf(v2,v3));
        #pragma unroll
        for (int o = 16; o > 0; o >>= 1) mx = fmaxf(mx, __shfl_xor_sync(0xffffffffu, mx, o));
        float e0=expf(v0-mx), e1=expf(v1-mx), e2=expf(v2-mx), e3=expf(v3-mx);
        float sum = e0+e1+e2+e3;
        #pragma unroll
        for (int o = 16; o > 0; o >>= 1) sum += __shfl_xor_sync(0xffffffffu, sum, o);
        float inv = 1.f / sum;
        sc[qi][lane]=e0*inv; sc[qi][lane+32]=e1*inv; sc[qi][lane+64]=e2*inv; sc[qi][lane+96]=e3*inv;
    }
    __syncthreads();
    for (int i = t; i < QT*DHh; i += 128) {
        int qi = i / DHh, d = i % DHh;
        float acc = 0.f;
        #pragma unroll 4
        for (int k = 0; k < 128; k++) acc += sc[qi][k] * Vs[k][d];
        ctx[((size_t)(b*Sq + qt*QT + qi))*Dd + h*DHh + d] = __float2half(acc);
    }
}

// FPS both sides, fused update+argmax pass, shuffle reduce
__global__ void fps_kernel(const float* __restrict__ pos0, const float* __restrict__ pos1,
                           float* __restrict__ centers)
{
    int blk = blockIdx.x, t = threadIdx.x;
    int side = blk >> 3, b = blk & 7;
    const float* P = (side ? pos1 : pos0) + (size_t)b*Np*3;
    float* C = centers + (size_t)blk*Gg*3;
    __shared__ float mind[Np];
    __shared__ float wv[16]; __shared__ int wi[16];
    __shared__ float curp[3];
    int w = t >> 5, lane = t & 31;
    if (t == 0) { curp[0]=P[0]; curp[1]=P[1]; curp[2]=P[2]; C[0]=P[0]; C[1]=P[1]; C[2]=P[2]; }
    for (int i = t; i < Np; i += 512) mind[i] = 3e38f;
    __syncthreads();
    for (int s = 1; s < Gg; s++) {
        float cx = curp[0], cy = curp[1], cz = curp[2];
        float bv = -3e38f; int bi = 0x7fffffff;
        for (int i = t; i < Np; i += 512) {
            float dx=P[3*i]-cx, dy=P[3*i+1]-cy, dz=P[3*i+2]-cz;
            float d = dx*dx + dy*dy + dz*dz;
            float m = fminf(mind[i], d);
            mind[i] = m;
            if (m > bv || (m == bv && i < bi)) { bv = m; bi = i; }
        }
        #pragma unroll
        for (int o = 16; o > 0; o >>= 1) {
            float ov = __shfl_xor_sync(0xffffffffu, bv, o);
            int   oi = __shfl_xor_sync(0xffffffffu, bi, o);
            if (ov > bv || (ov == bv && oi < bi)) { bv = ov; bi = oi; }
        }
        if (lane == 0) { wv[w] = bv; wi[w] = bi; }
        __syncthreads();
        if (w == 0) {
            float v = (lane < 16) ? wv[lane] : -3e38f;
            int  ii = (lane < 16) ? wi[lane] : 0x7fffffff;
            #pragma unroll
            for (int o = 8; o > 0; o >>= 1) {
                float ov = __shfl_xor_sync(0xffffffffu, v, o);
                int   oi = __shfl_xor_sync(0xffffffffu, ii, o);
                if (ov > v || (ov == v && oi < ii)) { v = ov; ii = oi; }
            }
            if (lane == 0) {
                curp[0]=P[3*ii]; curp[1]=P[3*ii+1]; curp[2]=P[3*ii+2];
                C[3*s]=curp[0]; C[3*s+1]=curp[1]; C[3*s+2]=curp[2];
            }
        }
        __syncthreads();
    }
}

// KNN of each center vs all points, both sides in one launch
__global__ void knn_big_kernel(const float* __restrict__ qpts,
                               const float* __restrict__ pos0, const float* __restrict__ pos1,
                               int* __restrict__ nidx)
{
    int blk = blockIdx.x, t = threadIdx.x;
    int side = blk / (Bb*Gg);
    int b = (blk / Gg) % Bb;
    __shared__ float dist[Np];
    __shared__ float rv[128]; __shared__ int ri[128];
    const float* Q = qpts + (size_t)blk*3;
    float qx=Q[0], qy=Q[1], qz=Q[2], qq = qx*qx+qy*qy+qz*qz;
    const float* R = (side ? pos1 : pos0) + (size_t)b*Np*3;
    for (int i = t; i < Np; i += 128) {
        float rx=R[3*i], ry=R[3*i+1], rz=R[3*i+2];
        dist[i] = qq + (rx*rx+ry*ry+rz*rz) - 2.f*(qx*rx+qy*ry+qz*rz);
    }
    __syncthreads();
    for (int kk = 0; kk < Kk; kk++) {
        float bv = 3e38f; int bi = 0x7fffffff;
        for (int i = t; i < Np; i += 128) { float v = dist[i]; if (v < bv) { bv = v; bi = i; } }
        rv[t] = bv; ri[t] = bi; __syncthreads();
        for (int o = 64; o > 0; o >>= 1) {
            if (t < o && (rv[t+o] < rv[t] || (rv[t+o] == rv[t] && ri[t+o] < ri[t]))) { rv[t]=rv[t+o]; ri[t]=ri[t+o]; }
            __syncthreads();
        }
        if (t == 0) { nidx[(size_t)blk*Kk + kk] = ri[0]; dist[ri[0]] = 3e38f; }
        __syncthreads();
    }
}

__global__ void knn_small_kernel(const float* __restrict__ pts, int S, int* __restrict__ nidx)
{
    int blk = blockIdx.x, b = blk / S, qi = blk % S, t = threadIdx.x;
    __shared__ float dist[128]; __shared__ float rv[128]; __shared__ int ri[128];
    const float* Q = pts + ((size_t)b*S + qi)*3;
    float qx=Q[0], qy=Q[1], qz=Q[2], qq=qx*qx+qy*qy+qz*qz;
    if (t < S) {
        const float* R = pts + ((size_t)b*S + t)*3;
        dist[t] = qq + (R[0]*R[0]+R[1]*R[1]+R[2]*R[2]) - 2.f*(qx*R[0]+qy*R[1]+qz*R[2]);
    } else dist[t] = 3e38f;
    __syncthreads();
    for (int kk = 0; kk < Kk; kk++) {
        rv[t] = dist[t]; ri[t] = t; __syncthreads();
        for (int o = 64; o > 0; o >>= 1) {
            if (t < o && (rv[t+o] < rv[t] || (rv[t+o] == rv[t] && ri[t+o] < ri[t]))) { rv[t]=rv[t+o]; ri[t]=ri[t+o]; }
            __syncthreads();
        }
        if (t == 0) { nidx[((size_t)b*S + qi)*Kk + kk] = ri[0]; dist[ri[0]] = 3e38f; }
        __syncthreads();
    }
}

__global__ void zero_u8_kernel(unsigned char* m, int n)
{ int i = blockIdx.x*blockDim.x + threadIdx.x; if (i < n) m[i] = 0; }

__global__ void scatter_mask_kernel(const int* __restrict__ nidx, unsigned char* __restrict__ m,
                                    int S, int tot)
{
    int i = blockIdx.x*blockDim.x + threadIdx.x;
    if (i >= tot) return;
    int b = i / (S*Kk), r = (i / Kk) % S;
    m[((size_t)b*S + r)*S + nidx[i]] = 1;
}

__global__ void group_rel_kernel(const float* __restrict__ pos0, const float* __restrict__ pos1,
                                 const float* __restrict__ centers, const int* __restrict__ nidx,
                                 __half* __restrict__ rel)
{
    int i = blockIdx.x*blockDim.x + threadIdx.x;
    if (i >= 2*Bb*Gg*Kk) return;
    int side = i / (Bb*Gg*Kk);
    int cb = i / (Gg*Kk);
    int b = cb % Bb;
    int g = (i / Kk) % Gg;
    const float* pos = side ? pos1 : pos0;
    int src = nidx[i];
    const float* P = pos + ((size_t)b*Np + src)*3;
    const float* C = centers + ((size_t)cb*Gg + g)*3;
    __half* rp = rel + (size_t)i*32;
    rp[0] = __float2half(P[0]-C[0]);
    rp[1] = __float2half(P[1]-C[1]);
    rp[2] = __float2half(P[2]-C[2]);
    for (int j = 3; j < 32; j++) rp[j] = __float2half(0.f);
}

__global__ void gmax_h_kernel(const __half* __restrict__ f, __half* __restrict__ g, int C, int tot)
{
    int i = blockIdx.x*blockDim.x + threadIdx.x;
    if (i >= tot) return;
    int bg = i / C, c = i % C;
    const __half* fp = f + (size_t)bg*Kk*C + c;
    float m = __half2float(fp[0]);
    #pragma unroll
    for (int k = 1; k < Kk; k++) m = fmaxf(m, __half2float(fp[(size_t)k*C]));
    g[i] = __float2half(m);
}

__global__ void gmax_f_kernel(const float* __restrict__ f, float* __restrict__ g, int C, int tot)
{
    int i = blockIdx.x*blockDim.x + threadIdx.x;
    if (i >= tot) return;
    int bg = i / C, c = i % C;
    const float* fp = f + (size_t)bg*Kk*C + c;
    float m = fp[0];
    #pragma unroll
    for (int k = 1; k < Kk; k++) m = fmaxf(m, fp[(size_t)k*C]);
    g[i] = m;
}

__global__ void cat_kernel(const __half* __restrict__ g, const __half* __restrict__ f,
                           __half* __restrict__ cat, int tot)
{
    int i = blockIdx.x*blockDim.x + threadIdx.x;
    if (i >= tot) return;
    int c = i % 512, r = i / 512, bg = r / Kk;
    cat[i] = (c < 256) ? g[(size_t)bg*256 + c] : f[(size_t)r*256 + (c - 256)];
}

__global__ void pe_kernel(const float* __restrict__ xyz, float* __restrict__ pe, int rows)
{
    int i = blockIdx.x*blockDim.x + threadIdx.x;
    if (i >= rows*Dd) return;
    int r = i / Dd, j = i % Dd, c = j / 128, jj = j % 128;
    float x = xyz[(size_t)r*3 + c];
    float ex = (float)(2*(jj/2)) * (1.0f/128.0f);
    float p = x * exp2f(-ex * 13.287712379549449f);
    pe[i] = (jj & 1) ? __cosf(p) : __sinf(p);
}

__global__ void gather_kernel(const float* __restrict__ src, const int* __restrict__ idx,
                              float* __restrict__ dst, int outR, int inR, int W)
{
    int row = blockIdx.x, b = row / outR, r = row % outR;
    int s = idx[(size_t)b*outR + r];
    const float* sp = src + ((size_t)b*inR + s)*W;
    float* dp = dst + (size_t)row*W;
    for (int w = threadIdx.x; w < W; w += blockDim.x) dp[w] = sp[w];
}

__global__ void decq_kernel(const float* __restrict__ visout, const float* __restrict__ cpe,
                            const float* __restrict__ mask_token, const int* __restrict__ mskidx,
                            const int* __restrict__ visidx, float* __restrict__ x)
{
    int i = blockIdx.x*blockDim.x + threadIdx.x;
    if (i >= Bb*(Mm+Vv)*Dd) return;
    int d = i % Dd, r = (i / Dd) % (Mm+Vv), b = i / (Dd*(Mm+Vv));
    float base; int pidx;
    if (r < Mm) { base = mask_token[d]; pidx = mskidx[(size_t)b*Mm + r]; }
    else { base = visout[((size_t)b*Vv + (r-Mm))*Dd + d]; pidx = visidx[(size_t)b*Vv + (r-Mm)]; }
    x[i] = base + cpe[((size_t)b*Gg + pidx)*Dd + d];
}

__global__ void add_kernel(const float* __restrict__ a, const float* __restrict__ b,
                           float* __restrict__ c, int n)
{ int i = blockIdx.x*blockDim.x + threadIdx.x; if (i < n) c[i] = a[i] + b[i]; }

__global__ void nn3_kernel(const float* __restrict__ pos, const float* __restrict__ centers,
                           int* __restrict__ oi, float* __restrict__ ow)
{
    int i = blockIdx.x*blockDim.x + threadIdx.x;
    if (i >= Bb*Np) return;
    int b = i / Np;
    const float* P = pos + (size_t)i*3;
    float px=P[0], py=P[1], pz=P[2], qq=px*px+py*py+pz*pz;
    float d0=3e38f, d1=3e38f, d2=3e38f; int i0=-1, i1=-1, i2=-1;
    const float* C = centers + (size_t)b*Gg*3;
    for (int g = 0; g < Gg; g++) {
        float cx=C[3*g], cy=C[3*g+1], cz=C[3*g+2];
        float d = qq + (cx*cx+cy*cy+cz*cz) - 2.f*(px*cx+py*cy+pz*cz);
        if (d < d0) { d2=d1;i2=i1; d1=d0;i1=i0; d0=d;i0=g; }
        else if (d < d1) { d2=d1;i2=i1; d1=d;i1=g; }
        else if (d < d2) { d2=d;i2=g; }
    }
    float w0=1.f/(fmaxf(d0,0.f)+1e-8f), w1=1.f/(fmaxf(d1,0.f)+1e-8f), w2=1.f/(fmaxf(d2,0.f)+1e-8f);
    float s = w0+w1+w2;
    ow[3*i]=w0/s; ow[3*i+1]=w1/s; ow[3*i+2]=w2/s;
    oi[3*i]=i0; oi[3*i+1]=i1; oi[3*i+2]=i2;
}

__global__ void upcat_kernel(const float* __restrict__ feats, const float* __restrict__ pos,
                             const int* __restrict__ oi, const float* __restrict__ ow,
                             __half* __restrict__ cat)
{
    int row = blockIdx.x, b = row / Np, t = threadIdx.x;
    int i0=oi[3*row], i1=oi[3*row+1], i2=oi[3*row+2];
    float w0=ow[3*row], w1=ow[3*row+1], w2=ow[3*row+2];
    const float* F = feats + (size_t)b*Gg*Dd;
    __half* cp = cat + (size_t)row*UPK;
    for (int d = t; d < Dd; d += 128)
        cp[d] = __float2half(w0*F[(size_t)i0*Dd+d] + w1*F[(size_t)i1*Dd+d] + w2*F[(size_t)i2*Dd+d]);
    if (t < 32) cp[Dd + t] = __float2half((t < 3) ? pos[(size_t)row*3 + t] : 0.f);
}

__global__ void loss_kernel(const float* __restrict__ fullout, const int* __restrict__ mskidx,
                            const float* __restrict__ decx, float* __restrict__ partial)
{
    __shared__ float red[256];
    int t = threadIdx.x;
    float acc = 0.f;
    for (int i = blockIdx.x*256 + t; i < Bb*Mm*Dd; i += 64*256) {
        int d = i % Dd, r = (i / Dd) % Mm, b = i / (Dd*Mm);
        int gi = mskidx[(size_t)b*Mm + r];
        float tv = fullout[((size_t)b*Gg + gi)*Dd + d];
        float pv = decx[((size_t)b*(Mm+Vv) + r)*Dd + d];
        float a = fabsf(pv - tv);
        acc += (a < 2.0f) ? 0.25f*a*a : a - 1.0f;
    }
    red[t] = acc; __syncthreads();
    for (int o = 128; o > 0; o >>= 1) { if (t < o) red[t] += red[t+o]; __syncthreads(); }
    if (t == 0) partial[blockIdx.x] = red[0];
}

__global__ void loss_final_kernel(const float* __restrict__ pa, const float* __restrict__ pb,
                                  float* __restrict__ out)
{
    float sa = 0.f, sb = 0.f;
    for (int i = 0; i < 64; i++) { sa += pa[i]; sb += pb[i]; }
    float cnt = (float)(Bb*Mm*Dd);
    out[0] = 0.5f*(sa/cnt) + 0.5f*(sb/cnt);
}

__global__ void copy_kernel(const float* __restrict__ a, float* __restrict__ b, int n)
{ int i = blockIdx.x*blockDim.x + threadIdx.x; if (i < n) b[i] = a[i]; }

// ------------------------------ host side --------------------------------

static __half* WTH;
static float *QB, *SKV;
static __half *CTXH;

static void gemm_h(const __half* A, const __half* Wt, const float* bias,
                   float* Cf, __half* Ch, int rows, int Kd, int Nc, int relu, int accum)
{
    dim3 grid(Nc/128, rows/128);
    gemm_h_kernel<<<grid, 256>>>(A, Wt, bias, Cf, Ch, rows, Kd, Nc, relu, accum);
}

static void self_attn(float* x, const __half* lnx, long woff, const unsigned char* mask,
                      int S, int nB)
{
    gemm_h(lnx, WTH + woff, nullptr, SKV, nullptr, nB*S, Dd, 3*Dd, 0, 0);
    dim3 g(S, NHh, nB);
    attn_kernel<<<g, 128>>>(SKV, 3*Dd, SKV + Dd, SKV + 2*Dd, 3*Dd, mask, CTXH, S, S, 0);
    gemm_h(CTXH, WTH + woff + 3*MSZ, nullptr, x, nullptr, nB*S, Dd, Dd, 0, 1);
}

static void cross_attn(float* x, const __half* lnq, const __half* lnkv, long woff,
                       int Sq, int Sk, int nB, int kvxor, int big)
{
    gemm_h(lnq,  WTH + woff,       nullptr, QB, nullptr, nB*Sq, Dd, Dd, 0, 0);
    gemm_h(lnkv, WTH + woff + MSZ, nullptr, SKV, nullptr, nB*Sk, Dd, 2*Dd, 0, 0);
    if (big) {
        dim3 g(Sq/QT, NHh, nB);
        attn_big_kernel<<<g, 128>>>(QB, Dd, SKV, SKV + Dd, 2*Dd, CTXH, Sq);
    } else {
        dim3 g(Sq, NHh, nB);
        attn_kernel<<<g, 128>>>(QB, Dd, SKV, SKV + Dd, 2*Dd, nullptr, CTXH, Sq, Sk, kvxor);
    }
    gemm_h(CTXH, WTH + woff + 3*MSZ, nullptr, x, nullptr, nB*Sq, Dd, Dd, 0, 1);
}

#define GETSYM(var, sym) do { void* _p; cudaGetSymbolAddress(&_p, sym); var = (decltype(var))_p; } while (0)

extern "C" void kernel_launch(void* const* d_in, const int* in_sizes, int n_in,
                              void* d_out_v, int out_size)
{
    (void)in_sizes; (void)n_in; (void)out_size;
    const float* pos[2]    = {(const float*)d_in[0], (const float*)d_in[1]};
    const int*   visidx[2] = {(const int*)d_in[2], (const int*)d_in[4]};
    const int*   mskidx[2] = {(const int*)d_in[3], (const int*)d_in[5]};
    const float* tok_w1 = (const float*)d_in[6];  const float* tok_b1 = (const float*)d_in[7];
    const float* tok_w2 = (const float*)d_in[8];  const float* tok_b2 = (const float*)d_in[9];
    const float* tok_w3 = (const float*)d_in[10]; const float* tok_b3 = (const float*)d_in[11];
    const float* tok_w4 = (const float*)d_in[12]; const float* tok_b4 = (const float*)d_in[13];
    const float* mask_token = (const float*)d_in[14];
    const float* cx_attn = (const float*)d_in[15];
    const float* cx_ff1  = (const float*)d_in[16]; const float* cx_ff2 = (const float*)d_in[17];
    const float* enc_sa  = (const float*)d_in[18]; const float* enc_ca = (const float*)d_in[19];
    const float* enc_ff1 = (const float*)d_in[20]; const float* enc_ff2 = (const float*)d_in[21];
    const float* dec_ca  = (const float*)d_in[22]; const float* dec_ff1 = (const float*)d_in[23];
    const float* dec_ff2 = (const float*)d_in[24];
    const float* up_w1 = (const float*)d_in[25]; const float* up_b1 = (const float*)d_in[26];
    const float* up_w2 = (const float*)d_in[27]; const float* up_b2 = (const float*)d_in[28];
    float* dout = (float*)d_out_v;

    float *centersB, *t2B, *tokensB, *cpeB, *ppeB, *vis3B, *visB, *fullB, *decxB, *mbufB, *nn3wB, *lpartB;
    int *nidxB, *nidxSB, *nn3iB;
    unsigned char *mfullB, *mvisB;
    __half *relH, *f1H, *f2H, *gmaxH, *catH, *t1H, *lnSH, *lnmH, *lnbigH, *hidH, *upcatH;
    GETSYM(centersB, g_centers); GETSYM(nidxB, g_nidx); GETSYM(nidxSB, g_nidxS);
    GETSYM(t2B, g_t2); GETSYM(tokensB, g_tokens);
    GETSYM(cpeB, g_cpe); GETSYM(ppeB, g_ppe); GETSYM(mfullB, g_mfull); GETSYM(mvisB, g_mvis);
    GETSYM(vis3B, g_vis3); GETSYM(visB, g_visbuf); GETSYM(fullB, g_fullbuf); GETSYM(decxB, g_decx);
    GETSYM(mbufB, g_mbuf); GETSYM(QB, g_qbuf); GETSYM(SKV, g_skv);
    GETSYM(nn3iB, g_nn3i); GETSYM(nn3wB, g_nn3w); GETSYM(lpartB, g_lpart);
    GETSYM(relH, g_relh); GETSYM(f1H, g_f1h); GETSYM(f2H, g_f2h); GETSYM(gmaxH, g_gmaxh);
    GETSYM(catH, g_cath); GETSYM(t1H, g_t1h); GETSYM(lnSH, g_lnSh);
    GETSYM(lnmH, g_lnmh); GETSYM(lnbigH, g_lnbigh); GETSYM(hidH, g_hidh);
    GETSYM(CTXH, g_ctxh); GETSYM(upcatH, g_upcath); GETSYM(WTH, g_wth);

    float* centers[2] = {centersB, centersB + Bb*Gg*3};
    float* tokens[2]  = {tokensB,  tokensB  + Bb*Gg*Dd};
    float* cpe[2]     = {cpeB,     cpeB     + Bb*Gg*Dd};
    float* ppe[2]     = {ppeB,     ppeB     + Bb*Np*Dd};
    float* visb[2]    = {visB,     visB     + Bb*Vv*Dd};
    float* fullb[2]   = {fullB,    fullB    + Bb*Gg*Dd};
    float* decx[2]    = {decxB,    decxB    + Bb*(Mm+Vv)*Dd};
    unsigned char* mvis[2]  = {mvisB,  mvisB  + Bb*Vv*Vv};

    // Phase 0: fused weight conversion
    {
        WConvArgs wa;
        const float* srcs[16] = {tok_w1, tok_w2, tok_w3, tok_w4, cx_attn, enc_sa, enc_ca,
                                 dec_ca, cx_ff1, cx_ff2, enc_ff1, enc_ff2, dec_ff1, dec_ff2,
                                 up_w1, up_w2};
        long starts[17] = {OFF_W1, OFF_W2, OFF_W3, OFF_W4, OFF_CX, OFF_ENCSA, OFF_ENCCA,
                           OFF_DECCA, OFF_CXFF1, OFF_CXFF2, OFF_EFF1, OFF_EFF2, OFF_DFF1,
                           OFF_DFF2, OFF_UP1, OFF_UP2, WTH_TOT};
        int kds[16]  = {3, 128, 512, 512, Dd, Dd, Dd, Dd, Dd, FFf, Dd, FFf, Dd, FFf, Dd+3, Dd};
        int kps[16]  = {32, 128, 512, 512, Dd, Dd, Dd, Dd, Dd, FFf, Dd, FFf, Dd, FFf, UPK, Dd};
        int ncs[16]  = {128, 256, 512, Dd, Dd, Dd, Dd, Dd, FFf, Dd, FFf, Dd, FFf, Dd, Dd, Dd};
        for (int i = 0; i < 16; i++) { wa.src[i]=srcs[i]; wa.start[i]=starts[i]; wa.Kd[i]=kds[i]; wa.KdPad[i]=kps[i]; wa.Nc[i]=ncs[i]; }
        wa.start[16] = starts[16];
        wtconv_all_kernel<<<(int)(((long)WTH_TOT + 255)/256), 256>>>(wa, WTH);
    }

    // Phase 1
    fps_kernel<<<16, 512>>>(pos[0], pos[1], centersB);
    knn_big_kernel<<<2*Bb*Gg, 128>>>(centersB, pos[0], pos[1], nidxB);
    group_rel_kernel<<<(2*Bb*Gg*Kk + 255)/256, 256>>>(pos[0], pos[1], centersB, nidxB, relH);
    gemm_h(relH, WTH + OFF_W1, tok_b1, nullptr, f1H, 32768, 32, 128, 1, 0);
    gemm_h(f1H, WTH + OFF_W2, tok_b2, nullptr, f2H, 32768, 128, 256, 0, 0);
    gmax_h_kernel<<<(2*Bb*Gg*256 + 255)/256, 256>>>(f2H, gmaxH, 256, 2*Bb*Gg*256);
    cat_kernel<<<(32768*512 + 255)/256, 256>>>(gmaxH, f2H, catH, 32768*512);
    gemm_h(catH, WTH + OFF_W3, tok_b3, nullptr, t1H, 32768, 512, 512, 1, 0);
    gemm_h(t1H, WTH + OFF_W4, tok_b4, t2B, nullptr, 32768, 512, Dd, 0, 0);
    gmax_f_kernel<<<(2*Bb*Gg*Dd + 255)/256, 256>>>(t2B, tokensB, Dd, 2*Bb*Gg*Dd);
    pe_kernel<<<(2*Bb*Gg*Dd + 255)/256, 256>>>(centersB, cpeB, 2*Bb*Gg);
    pe_kernel<<<(Bb*Np*Dd + 255)/256, 256>>>(pos[0], ppe[0], Bb*Np);
    pe_kernel<<<(Bb*Np*Dd + 255)/256, 256>>>(pos[1], ppe[1], Bb*Np);
    // full masks (both sides batched)
    knn_small_kernel<<<2*Bb*Gg, 128>>>(centersB, Gg, nidxSB);
    zero_u8_kernel<<<(2*Bb*Gg*Gg + 255)/256, 256>>>(mfullB, 2*Bb*Gg*Gg);
    scatter_mask_kernel<<<(2*Bb*Gg*Kk + 255)/256, 256>>>(nidxSB, mfullB, Gg, 2*Bb*Gg*Kk);
    // vis masks per side
    for (int s = 0; s < 2; s++) {
        gather_kernel<<<Bb*Vv, 32>>>(centers[s], visidx[s], vis3B, Vv, Gg, 3);
        knn_small_kernel<<<Bb*Vv, 128>>>(vis3B, Vv, nidxSB);
        zero_u8_kernel<<<(Bb*Vv*Vv + 255)/256, 256>>>(mvis[s], Bb*Vv*Vv);
        scatter_mask_kernel<<<(Bb*Vv*Kk + 255)/256, 256>>>(nidxSB, mvis[s], Vv, Bb*Vv*Kk);
        gather_kernel<<<Bb*Vv, 128>>>(tokens[s], visidx[s], visb[s], Vv, Gg, Dd);
    }
    copy_kernel<<<(2*Bb*Gg*Dd + 255)/256, 256>>>(tokensB, fullB, 2*Bb*Gg*Dd);

    // Phase 2: cross encoders
    for (int e = 0; e < 2; e++) {
        int S = e ? Gg : Vv;
        float* ST = e ? fullB : visB;
        const unsigned char* mask = e ? mfullB : mvisB;
        int rows2 = 2*Bb*S;
        ln_kernel<<<rows2, 128>>>(ST, lnSH);
        self_attn(ST, lnSH, OFF_CX, mask, S, 2*Bb);
        ln_kernel<<<rows2, 128>>>(ST, lnSH);
        cross_attn(ST, lnSH, lnSH, OFF_CX + 4*MSZ, S, S, 2*Bb, Bb, 0);
        ln_kernel<<<rows2, 128>>>(ST, lnSH);
        gemm_h(lnSH, WTH + OFF_CXFF1, nullptr, nullptr, hidH, rows2, Dd, FFf, 1, 0);
        gemm_h(hidH, WTH + OFF_CXFF2, nullptr, ST, nullptr, rows2, FFf, Dd, 0, 1);
    }

    // Phase 3: MAE decoder
    for (int s = 0; s < 2; s++)
        decq_kernel<<<(Bb*(Mm+Vv)*Dd + 255)/256, 256>>>(visb[s], cpe[s], mask_token,
                                                        mskidx[s], visidx[s], decx[s]);
    add_kernel<<<(Bb*Gg*Dd + 255)/256, 256>>>(fullb[1], cpe[1], mbufB, Bb*Gg*Dd);
    add_kernel<<<(Bb*Gg*Dd + 255)/256, 256>>>(fullb[0], cpe[0], mbufB + Bb*Gg*Dd, Bb*Gg*Dd);
    ln_kernel<<<2*Bb*Gg, 128>>>(mbufB, lnmH);
    for (int l = 0; l < 4; l++) {
        ln_kernel<<<2*Bb*(Mm+Vv), 128>>>(decxB, lnSH);
        self_attn(decxB, lnSH, OFF_ENCSA + (long)l*4*MSZ, nullptr, Mm+Vv, 2*Bb);
        ln_kernel<<<2*Bb*(Mm+Vv), 128>>>(decxB, lnSH);
        cross_attn(decxB, lnSH, lnmH, OFF_ENCCA + (long)l*4*MSZ, Mm+Vv, Gg, 2*Bb, 0, 0);
        ln_kernel<<<2*Bb*(Mm+Vv), 128>>>(decxB, lnSH);
        gemm_h(lnSH, WTH + OFF_EFF1 + (long)l*Dd*FFf, nullptr, nullptr, hidH, 2*Bb*(Mm+Vv), Dd, FFf, 1, 0);
        gemm_h(hidH, WTH + OFF_EFF2 + (long)l*FFf*Dd, nullptr, decxB, nullptr, 2*Bb*(Mm+Vv), FFf, Dd, 0, 1);
    }
    for (int s = 0; s < 2; s++)
        loss_kernel<<<64, 256>>>(fullb[s], mskidx[s], decx[s], lpartB + s*64);

    // Phase 4
    for (int s = 0; s < 2; s++) {
        nn3_kernel<<<(Bb*Np + 255)/256, 256>>>(pos[s], centers[s], nn3iB, nn3wB);
        upcat_kernel<<<Bb*Np, 128>>>(fullb[s], pos[s], nn3iB, nn3wB, upcatH + (size_t)s*Bb*Np*UPK);
    }
    gemm_h(upcatH, WTH + OFF_UP1, up_b1, nullptr, hidH, 2*Bb*Np, UPK, Dd, 1, 0);
    gemm_h(hidH, WTH + OFF_UP2, up_b2, QB, nullptr, 2*Bb*Np, Dd, Dd, 1, 0);
    add_kernel<<<(2*Bb*Np*Dd + 255)/256, 256>>>(QB, ppeB, dout, 2*Bb*Np*Dd);
    add_kernel<<<(Bb*Gg*Dd + 255)/256, 256>>>(fullb[0], cpe[0], mbufB, Bb*Gg*Dd);
    add_kernel<<<(Bb*Gg*Dd + 255)/256, 256>>>(fullb[1], cpe[1], mbufB + Bb*Gg*Dd, Bb*Gg*Dd);
    ln_kernel<<<2*Bb*Gg, 128>>>(mbufB, lnmH);
    for (int l = 0; l < 2; l++) {
        ln_kernel<<<2*Bb*Np, 128>>>(dout, lnbigH);
        cross_attn(dout, lnbigH, lnmH, OFF_DECCA + (long)l*4*MSZ, Np, Gg, 2*Bb, 0, 1);
        ln_kernel<<<2*Bb*Np, 128>>>(dout, lnbigH);
        gemm_h(lnbigH, WTH + OFF_DFF1 + (long)l*Dd*FFf, nullptr, nullptr, hidH, 2*Bb*Np, Dd, FFf, 1, 0);
        gemm_h(hidH, WTH + OFF_DFF2 + (long)l*FFf*Dd, nullptr, dout, nullptr, 2*Bb*Np, FFf, Dd, 0, 1);
    }
    loss_final_kernel<<<1, 1>>>(lpartB, lpartB + 64, dout + (size_t)2*Bb*Np*Dd);
}

// round 12
// speedup vs baseline: 6.0420x; 1.1012x over previous
#include <cuda_runtime.h>
#include <cuda_fp16.h>
#include <math.h>
#include <stdint.h>

#define Bb 8
#define Np 4096
#define Gg 128
#define Kk 16
#define Vv 64
#define Mm 64
#define Dd 384
#define NHh 8
#define DHh 48
#define FFf 1536
#define UPK 416

// fp32 buffers
__device__ float g_centers[2*Bb*Gg*3];
__device__ int   g_nidx[2*Bb*Gg*Kk];
__device__ int   g_nidxS[2*Bb*Gg*Kk];
__device__ float g_t2[2*16384*Dd];
__device__ float g_tokens[2*Bb*Gg*Dd];
__device__ float g_cpe[2*Bb*Gg*Dd];
__device__ float g_ppe[2*Bb*Np*Dd];
__device__ unsigned char g_mfull[2*Bb*Gg*Gg];
__device__ unsigned char g_mvis[2*Bb*Vv*Vv];
__device__ float g_vis3[Bb*Vv*3];
__device__ float g_visbuf[2*Bb*Vv*Dd];
__device__ float g_fullbuf[2*Bb*Gg*Dd];
__device__ float g_decx[2*Bb*(Mm+Vv)*Dd];
__device__ float g_qbuf[2*Bb*Np*Dd];
__device__ float g_skv[2048*1152];
__device__ int   g_nn3i[2*Bb*Np*3];
__device__ float g_nn3w[2*Bb*Np*3];
__device__ float g_lpart[2*64];

// half buffers
__device__ __align__(16) __half g_relh[32768*32];
__device__ __align__(16) __half g_f1h[32768*128];
__device__ __align__(16) __half g_f2h[32768*256];
__device__ __align__(16) __half g_gmaxh[2*Bb*Gg*256];
__device__ __align__(16) __half g_cath[32768*512];
__device__ __align__(16) __half g_t1h[32768*512];
__device__ __align__(16) __half g_lnSh[2*Bb*Gg*Dd];
__device__ __align__(16) __half g_lnmh[2*Bb*Gg*Dd];
__device__ __align__(16) __half g_lnbigh[2*Bb*Np*Dd];
__device__ __align__(16) __half g_hidh[(size_t)2*Bb*Np*FFf];
__device__ __align__(16) __half g_ctxh[2*Bb*Np*Dd];
__device__ __align__(16) __half g_upcath[2*Bb*Np*UPK];

#define MSZ 147456
#define OFF_W1    0
#define OFF_W2    (OFF_W1 + 32*128)
#define OFF_W3    (OFF_W2 + 128*256)
#define OFF_W4    (OFF_W3 + 512*512)
#define OFF_CX    (OFF_W4 + 512*384)
#define OFF_ENCSA (OFF_CX + 8*MSZ)
#define OFF_ENCCA (OFF_ENCSA + 16*MSZ)
#define OFF_DECCA (OFF_ENCCA + 16*MSZ)
#define OFF_CXFF1 (OFF_DECCA + 8*MSZ)
#define OFF_CXFF2 (OFF_CXFF1 + 384*1536)
#define OFF_EFF1  (OFF_CXFF2 + 1536*384)
#define OFF_EFF2  (OFF_EFF1 + 4*384*1536)
#define OFF_DFF1  (OFF_EFF2 + 4*1536*384)
#define OFF_DFF2  (OFF_DFF1 + 2*384*1536)
#define OFF_UP1   (OFF_DFF2 + 2*1536*384)
#define OFF_UP2   (OFF_UP1 + 416*384)
#define WTH_TOT   (OFF_UP2 + 384*384)
__device__ __align__(16) __half g_wth[WTH_TOT];

struct WConvArgs {
    const float* src[16];
    long start[17];
    int Kd[16], KdPad[16], Nc[16];
};

__global__ void wtconv_all_kernel(WConvArgs A, __half* __restrict__ dst)
{
    long i = (long)blockIdx.x*256 + threadIdx.x;
    if (i >= A.start[16]) return;
    int s = 0;
    while (s < 15 && i >= A.start[s+1]) s++;
    long li = i - A.start[s];
    int Kd = A.Kd[s], Kp = A.KdPad[s], Nc = A.Nc[s];
    long per = (long)Nc*Kp;
    int mt = (int)(li/per);
    long r = li % per;
    int n = (int)(r/Kp), k = (int)(r%Kp);
    float v = (k < Kd) ? A.src[s][(size_t)mt*Kd*Nc + (size_t)k*Nc + n] : 0.f;
    dst[i] = __float2half(v);
}

// fp16 GEMM: 128x128 tile, KT=32, 3-stage cp.async, one barrier/iter, ldmatrix
__global__ __launch_bounds__(256)
void gemm_h_kernel(const __half* __restrict__ A, const __half* __restrict__ Wt,
                   const float* __restrict__ bias, float* __restrict__ Cf,
                   __half* __restrict__ Ch, int rows, int Kd, int Nc, int relu, int accum)
{
    __shared__ __half Ah[3][128][40];
    __shared__ __half Wh[3][128][40];
    int tid = threadIdx.x, wid = tid>>5, lane = tid&31;
    int g = lane>>2, tig = lane&3;
    int wm = (wid>>1)*32, wn = (wid&1)*64;
    int row0 = blockIdx.y*128, col0 = blockIdx.x*128;
    float c[2][8][4] = {};
    int nIter = Kd/32;

    int lr = lane & 7, lj = lane >> 3;
    uint32_t ah0 = (uint32_t)__cvta_generic_to_shared(&Ah[0][0][0]);
    uint32_t wh0 = (uint32_t)__cvta_generic_to_shared(&Wh[0][0][0]);
    uint32_t aAddr[2], wAddr[4];
    #pragma unroll
    for (int mt = 0; mt < 2; mt++)
        aAddr[mt] = ah0 + (uint32_t)((wm + mt*16 + lr + (lj&1)*8)*80 + ((lj>>1)*8)*2);
    #pragma unroll
    for (int p = 0; p < 4; p++)
        wAddr[p] = wh0 + (uint32_t)((wn + p*16 + lr + ((lj>>1)&1)*8)*80 + ((lj&1)*8)*2);

    #pragma unroll
    for (int st = 0; st < 2; st++) {
        if (st < nIter) {
            int k0 = st*32;
            #pragma unroll
            for (int l = 0; l < 2; l++) {
                int ci = tid + l*256;
                int m = ci>>2, f = ci&3;
                const __half* ga = A + (size_t)(row0+m)*Kd + k0 + f*8;
                uint32_t sa = (uint32_t)__cvta_generic_to_shared(&Ah[st][m][f*8]);
                asm volatile("cp.async.cg.shared.global [%0], [%1], 16;" :: "r"(sa), "l"(ga));
                const __half* gw = Wt + (size_t)(col0+m)*Kd + k0 + f*8;
                uint32_t sw = (uint32_t)__cvta_generic_to_shared(&Wh[st][m][f*8]);
                asm volatile("cp.async.cg.shared.global [%0], [%1], 16;" :: "r"(sw), "l"(gw));
            }
            asm volatile("cp.async.commit_group;");
        }
    }

    for (int it = 0; it < nIter; it++) {
        if (it < nIter-1) asm volatile("cp.async.wait_group 1;");
        else              asm volatile("cp.async.wait_group 0;");
        __syncthreads();
        int cur = it % 3;
        uint32_t stOff = (uint32_t)(cur*10240);
        #pragma unroll
        for (int st = 0; st < 2; st++) {
            uint32_t kOff = stOff + st*32;
            uint32_t a[2][4], b[8][2];
            #pragma unroll
            for (int mt = 0; mt < 2; mt++)
                asm volatile("ldmatrix.sync.aligned.m8n8.x4.shared.b16 {%0,%1,%2,%3}, [%4];"
                    : "=r"(a[mt][0]), "=r"(a[mt][1]), "=r"(a[mt][2]), "=r"(a[mt][3])
                    : "r"(aAddr[mt] + kOff));
            #pragma unroll
            for (int p = 0; p < 4; p++) {
                uint32_t d0, d1, d2, d3;
                asm volatile("ldmatrix.sync.aligned.m8n8.x4.shared.b16 {%0,%1,%2,%3}, [%4];"
                    : "=r"(d0), "=r"(d1), "=r"(d2), "=r"(d3)
                    : "r"(wAddr[p] + kOff));
                b[2*p][0] = d0; b[2*p][1] = d1; b[2*p+1][0] = d2; b[2*p+1][1] = d3;
            }
            #pragma unroll
            for (int mt = 0; mt < 2; mt++)
                #pragma unroll
                for (int nt = 0; nt < 8; nt++)
                    asm volatile(
                        "mma.sync.aligned.m16n8k16.row.col.f32.f16.f16.f32 "
                        "{%0,%1,%2,%3}, {%4,%5,%6,%7}, {%8,%9}, {%0,%1,%2,%3};"
                        : "+f"(c[mt][nt][0]), "+f"(c[mt][nt][1]),
                          "+f"(c[mt][nt][2]), "+f"(c[mt][nt][3])
                        : "r"(a[mt][0]), "r"(a[mt][1]), "r"(a[mt][2]), "r"(a[mt][3]),
                          "r"(b[nt][0]), "r"(b[nt][1]));
        }
        if (it + 2 < nIter) {
            int p = (it+2) % 3;
            int k0 = (it+2)*32;
            #pragma unroll
            for (int l = 0; l < 2; l++) {
                int ci = tid + l*256;
                int m = ci>>2, f = ci&3;
                const __half* ga = A + (size_t)(row0+m)*Kd + k0 + f*8;
                uint32_t sa = (uint32_t)__cvta_generic_to_shared(&Ah[p][m][f*8]);
                asm volatile("cp.async.cg.shared.global [%0], [%1], 16;" :: "r"(sa), "l"(ga));
                const __half* gw = Wt + (size_t)(col0+m)*Kd + k0 + f*8;
                uint32_t sw = (uint32_t)__cvta_generic_to_shared(&Wh[p][m][f*8]);
                asm volatile("cp.async.cg.shared.global [%0], [%1], 16;" :: "r"(sw), "l"(gw));
            }
            asm volatile("cp.async.commit_group;");
        }
    }
    #pragma unroll
    for (int mt = 0; mt < 2; mt++) {
        #pragma unroll
        for (int nt = 0; nt < 8; nt++) {
            int r0 = row0 + wm + mt*16 + g;
            int cc = col0 + wn + nt*8 + 2*tig;
            float v0 = c[mt][nt][0], v1 = c[mt][nt][1];
            float v2 = c[mt][nt][2], v3 = c[mt][nt][3];
            if (bias) { float b0 = bias[cc], b1 = bias[cc+1]; v0 += b0; v1 += b1; v2 += b0; v3 += b1; }
            if (relu) { v0 = fmaxf(v0,0.f); v1 = fmaxf(v1,0.f); v2 = fmaxf(v2,0.f); v3 = fmaxf(v3,0.f); }
            size_t o0 = (size_t)r0*Nc + cc;
            size_t o1 = (size_t)(r0+8)*Nc + cc;
            if (Ch) {
                Ch[o0] = __float2half(v0); Ch[o0+1] = __float2half(v1);
                Ch[o1] = __float2half(v2); Ch[o1+1] = __float2half(v3);
            } else if (accum) {
                Cf[o0] += v0; Cf[o0+1] += v1; Cf[o1] += v2; Cf[o1+1] += v3;
            } else {
                Cf[o0] = v0; Cf[o0+1] = v1; Cf[o1] = v2; Cf[o1+1] = v3;
            }
        }
    }
}

// LayerNorm, warp-per-row (8 rows/block), fp32 -> fp16
__global__ __launch_bounds__(256)
void ln_kernel(const float* __restrict__ x, __half* __restrict__ y, int rows)
{
    int w = threadIdx.x >> 5, lane = threadIdx.x & 31;
    int row = blockIdx.x*8 + w;
    if (row >= rows) return;
    const float* xr = x + (size_t)row*Dd;
    float e[12]; float s = 0.f;
    #pragma unroll
    for (int j = 0; j < 12; j++) { e[j] = xr[lane + j*32]; s += e[j]; }
    #pragma unroll
    for (int o = 16; o > 0; o >>= 1) s += __shfl_xor_sync(0xffffffffu, s, o);
    float m = s * (1.0f/384.0f);
    float v = 0.f;
    #pragma unroll
    for (int j = 0; j < 12; j++) { e[j] -= m; v += e[j]*e[j]; }
    #pragma unroll
    for (int o = 16; o > 0; o >>= 1) v += __shfl_xor_sync(0xffffffffu, v, o);
    float inv = rsqrtf(v * (1.0f/384.0f) + 1e-5f);
    __half* yr = y + (size_t)row*Dd;
    #pragma unroll
    for (int j = 0; j < 12; j++) yr[lane + j*32] = __float2half(e[j]*inv);
}

// Fused residual+LN: y = LN(a+b), two side segments concatenated
__global__ __launch_bounds__(256)
void ln2res_kernel(const float* __restrict__ a0, const float* __restrict__ b0,
                   const float* __restrict__ a1, const float* __restrict__ b1,
                   __half* __restrict__ y, int rowsHalf)
{
    int w = threadIdx.x >> 5, lane = threadIdx.x & 31;
    int row = blockIdx.x*8 + w;
    const float* a; const float* b; int lr;
    if (row < rowsHalf) { a = a0; b = b0; lr = row; }
    else { a = a1; b = b1; lr = row - rowsHalf; }
    float e[12]; float s = 0.f;
    #pragma unroll
    for (int j = 0; j < 12; j++) {
        size_t idx = (size_t)lr*Dd + lane + j*32;
        e[j] = a[idx] + b[idx]; s += e[j];
    }
    #pragma unroll
    for (int o = 16; o > 0; o >>= 1) s += __shfl_xor_sync(0xffffffffu, s, o);
    float m = s * (1.0f/384.0f);
    float v = 0.f;
    #pragma unroll
    for (int j = 0; j < 12; j++) { e[j] -= m; v += e[j]*e[j]; }
    #pragma unroll
    for (int o = 16; o > 0; o >>= 1) v += __shfl_xor_sync(0xffffffffu, v, o);
    float inv = rsqrtf(v * (1.0f/384.0f) + 1e-5f);
    __half* yr = y + (size_t)row*Dd;
    #pragma unroll
    for (int j = 0; j < 12; j++) yr[lane + j*32] = __float2half(e[j]*inv);
}

// small attention: strided q/k/v; kvxor batch map
__global__ void attn_kernel(const float* __restrict__ q, int qs,
                            const float* __restrict__ kmat, const float* __restrict__ vmat, int kvs,
                            const unsigned char* __restrict__ mask,
                            __half* __restrict__ ctx, int Sq, int Sk, int kvxor)
{
    int qi = blockIdx.x, h = blockIdx.y, b = blockIdx.z, t = threadIdx.x;
    int bk = b ^ kvxor;
    __shared__ float shq[DHh], shp[128], red[128];
    const float* qr = q + (size_t)(b*Sq + qi)*qs + h*DHh;
    if (t < DHh) shq[t] = qr[t];
    __syncthreads();
    float val = -3e38f;
    if (t < Sk) {
        const float* kr = kmat + (size_t)(bk*Sk + t)*kvs + h*DHh;
        float s = 0.f;
        #pragma unroll
        for (int d = 0; d < DHh; d++) s += shq[d]*kr[d];
        s /= sqrtf((float)DHh);
        if (mask && !mask[((size_t)b*Sq + qi)*Sk + t]) s = -1e9f;
        val = s;
    }
    red[t] = val; __syncthreads();
    for (int o = 64; o > 0; o >>= 1) { if (t < o) red[t] = fmaxf(red[t], red[t+o]); __syncthreads(); }
    float mx = red[0]; __syncthreads();
    float e = (t < Sk) ? expf(val - mx) : 0.f;
    shp[t] = e; red[t] = e; __syncthreads();
    for (int o = 64; o > 0; o >>= 1) { if (t < o) red[t] += red[t+o]; __syncthreads(); }
    float inv = 1.f / red[0];
    if (t < DHh) {
        float acc = 0.f;
        const float* vb = vmat + (size_t)(bk*Sk)*kvs + h*DHh + t;
        for (int kk = 0; kk < Sk; kk++) acc += shp[kk]*vb[(size_t)kk*kvs];
        ctx[((size_t)(b*Sq + qi))*Dd + h*DHh + t] = __float2half(acc*inv);
    }
}

// big attention: 32 queries/block, Sk==128, register-blocked output
#define QT 32
__global__ __launch_bounds__(128)
void attn_big_kernel(const float* __restrict__ q, int qs,
                     const float* __restrict__ kmat, const float* __restrict__ vmat, int kvs,
                     __half* __restrict__ ctx, int Sq)
{
    int qt = blockIdx.x, h = blockIdx.y, b = blockIdx.z, t = threadIdx.x;
    __shared__ float shq[QT][DHh];
    __shared__ float sc[QT][129];
    __shared__ float Vs[128][DHh];
    for (int i = t; i < QT*DHh; i += 128) {
        int qi = i / DHh, d = i % DHh;
        shq[qi][d] = q[(size_t)(b*Sq + qt*QT + qi)*qs + h*DHh + d];
    }
    for (int i = t; i < 128*DHh; i += 128) {
        int k = i / DHh, d = i % DHh;
        Vs[k][d] = vmat[(size_t)(b*128 + k)*kvs + h*DHh + d];
    }
    __syncthreads();
    float kr[DHh];
    {
        const float* kp = kmat + (size_t)(b*128 + t)*kvs + h*DHh;
        #pragma unroll
        for (int d = 0; d < DHh; d++) kr[d] = kp[d];
    }
    float inv_s = rsqrtf((float)DHh);
    #pragma unroll 1
    for (int qi = 0; qi < QT; qi++) {
        float s = 0.f;
        #pragma unroll
        for (int d = 0; d < DHh; d++) s += shq[qi][d]*kr[d];
        sc[qi][t] = s * inv_s;
    }
    __syncthreads();
    int w = t >> 5, lane = t & 31;
    for (int qi = w; qi < QT; qi += 4) {
        float v0 = sc[qi][lane], v1 = sc[qi][lane+32], v2 = sc[qi][lane+64], v3 = sc[qi][lane+96];
        float mx = fmaxf(fmaxf(v0,v1), fmaxf(v2,v3));
        #pragma unroll
        for (int o = 16; o > 0; o >>= 1) mx = fmaxf(mx, __shfl_xor_sync(0xffffffffu, mx, o));
        float e0=expf(v0-mx), e1=expf(v1-mx), e2=expf(v2-mx), e3=expf(v3-mx);
        float sum = e0+e1+e2+e3;
        #pragma unroll
        for (int o = 16; o > 0; o >>= 1) sum += __shfl_xor_sync(0xffffffffu, sum, o);
        float inv = 1.f / sum;
        sc[qi][lane]=e0*inv; sc[qi][lane+32]=e1*inv; sc[qi][lane+64]=e2*inv; sc[qi][lane+96]=e3*inv;
    }
    __syncthreads();
    // output: 4 threads per query, 12 d each, float4 V loads
    {
        int qi = t >> 2;
        int d0 = (t & 3) * 12;
        float acc[12];
        #pragma unroll
        for (int j = 0; j < 12; j++) acc[j] = 0.f;
        #pragma unroll 4
        for (int k = 0; k < 128; k++) {
            float p = sc[qi][k];
            float4 va = *(const float4*)&Vs[k][d0];
            float4 vb = *(const float4*)&Vs[k][d0+4];
            float4 vc = *(const float4*)&Vs[k][d0+8];
            acc[0]+=p*va.x; acc[1]+=p*va.y; acc[2]+=p*va.z; acc[3]+=p*va.w;
            acc[4]+=p*vb.x; acc[5]+=p*vb.y; acc[6]+=p*vb.z; acc[7]+=p*vb.w;
            acc[8]+=p*vc.x; acc[9]+=p*vc.y; acc[10]+=p*vc.z; acc[11]+=p*vc.w;
        }
        __half2* cp = (__half2*)(ctx + ((size_t)(b*Sq + qt*QT + qi))*Dd + h*DHh + d0);
        #pragma unroll
        for (int j = 0; j < 6; j++)
            cp[j] = __floats2half2_rn(acc[2*j], acc[2*j+1]);
    }
}

// FPS both sides, fused update+argmax, shuffle reduce
__global__ void fps_kernel(const float* __restrict__ pos0, const float* __restrict__ pos1,
                           float* __restrict__ centers)
{
    int blk = blockIdx.x, t = threadIdx.x;
    int side = blk >> 3, b = blk & 7;
    const float* P = (side ? pos1 : pos0) + (size_t)b*Np*3;
    float* C = centers + (size_t)blk*Gg*3;
    __shared__ float mind[Np];
    __shared__ float wv[16]; __shared__ int wi[16];
    __shared__ float curp[3];
    int w = t >> 5, lane = t & 31;
    if (t == 0) { curp[0]=P[0]; curp[1]=P[1]; curp[2]=P[2]; C[0]=P[0]; C[1]=P[1]; C[2]=P[2]; }
    for (int i = t; i < Np; i += 512) mind[i] = 3e38f;
    __syncthreads();
    for (int s = 1; s < Gg; s++) {
        float cx = curp[0], cy = curp[1], cz = curp[2];
        float bv = -3e38f; int bi = 0x7fffffff;
        for (int i = t; i < Np; i += 512) {
            float dx=P[3*i]-cx, dy=P[3*i+1]-cy, dz=P[3*i+2]-cz;
            float d = dx*dx + dy*dy + dz*dz;
            float m = fminf(mind[i], d);
            mind[i] = m;
            if (m > bv || (m == bv && i < bi)) { bv = m; bi = i; }
        }
        #pragma unroll
        for (int o = 16; o > 0; o >>= 1) {
            float ov = __shfl_xor_sync(0xffffffffu, bv, o);
            int   oi = __shfl_xor_sync(0xffffffffu, bi, o);
            if (ov > bv || (ov == bv && oi < bi)) { bv = ov; bi = oi; }
        }
        if (lane == 0) { wv[w] = bv; wi[w] = bi; }
        __syncthreads();
        if (w == 0) {
            float v = (lane < 16) ? wv[lane] : -3e38f;
            int  ii = (lane < 16) ? wi[lane] : 0x7fffffff;
            #pragma unroll
            for (int o = 8; o > 0; o >>= 1) {
                float ov = __shfl_xor_sync(0xffffffffu, v, o);
                int   oi = __shfl_xor_sync(0xffffffffu, ii, o);
                if (ov > v || (ov == v && oi < ii)) { v = ov; ii = oi; }
            }
            if (lane == 0) {
                curp[0]=P[3*ii]; curp[1]=P[3*ii+1]; curp[2]=P[3*ii+2];
                C[3*s]=curp[0]; C[3*s+1]=curp[1]; C[3*s+2]=curp[2];
            }
        }
        __syncthreads();
    }
}

__global__ void knn_big_kernel(const float* __restrict__ qpts,
                               const float* __restrict__ pos0, const float* __restrict__ pos1,
                               int* __restrict__ nidx)
{
    int blk = blockIdx.x, t = threadIdx.x;
    int side = blk / (Bb*Gg);
    int b = (blk / Gg) % Bb;
    __shared__ float dist[Np];
    __shared__ float rv[128]; __shared__ int ri[128];
    const float* Q = qpts + (size_t)blk*3;
    float qx=Q[0], qy=Q[1], qz=Q[2], qq = qx*qx+qy*qy+qz*qz;
    const float* R = (side ? pos1 : pos0) + (size_t)b*Np*3;
    for (int i = t; i < Np; i += 128) {
        float rx=R[3*i], ry=R[3*i+1], rz=R[3*i+2];
        dist[i] = qq + (rx*rx+ry*ry+rz*rz) - 2.f*(qx*rx+qy*ry+qz*rz);
    }
    __syncthreads();
    for (int kk = 0; kk < Kk; kk++) {
        float bv = 3e38f; int bi = 0x7fffffff;
        for (int i = t; i < Np; i += 128) { float v = dist[i]; if (v < bv) { bv = v; bi = i; } }
        rv[t] = bv; ri[t] = bi; __syncthreads();
        for (int o = 64; o > 0; o >>= 1) {
            if (t < o && (rv[t+o] < rv[t] || (rv[t+o] == rv[t] && ri[t+o] < ri[t]))) { rv[t]=rv[t+o]; ri[t]=ri[t+o]; }
            __syncthreads();
        }
        if (t == 0) { nidx[(size_t)blk*Kk + kk] = ri[0]; dist[ri[0]] = 3e38f; }
        __syncthreads();
    }
}

__global__ void knn_small_kernel(const float* __restrict__ pts, int S, int* __restrict__ nidx)
{
    int blk = blockIdx.x, b = blk / S, qi = blk % S, t = threadIdx.x;
    __shared__ float dist[128]; __shared__ float rv[128]; __shared__ int ri[128];
    const float* Q = pts + ((size_t)b*S + qi)*3;
    float qx=Q[0], qy=Q[1], qz=Q[2], qq=qx*qx+qy*qy+qz*qz;
    if (t < S) {
        const float* R = pts + ((size_t)b*S + t)*3;
        dist[t] = qq + (R[0]*R[0]+R[1]*R[1]+R[2]*R[2]) - 2.f*(qx*R[0]+qy*R[1]+qz*R[2]);
    } else dist[t] = 3e38f;
    __syncthreads();
    for (int kk = 0; kk < Kk; kk++) {
        rv[t] = dist[t]; ri[t] = t; __syncthreads();
        for (int o = 64; o > 0; o >>= 1) {
            if (t < o && (rv[t+o] < rv[t] || (rv[t+o] == rv[t] && ri[t+o] < ri[t]))) { rv[t]=rv[t+o]; ri[t]=ri[t+o]; }
            __syncthreads();
        }
        if (t == 0) { nidx[((size_t)b*S + qi)*Kk + kk] = ri[0]; dist[ri[0]] = 3e38f; }
        __syncthreads();
    }
}

__global__ void zero_u8_kernel(unsigned char* m, int n)
{ int i = blockIdx.x*blockDim.x + threadIdx.x; if (i < n) m[i] = 0; }

__global__ void scatter_mask_kernel(const int* __restrict__ nidx, unsigned char* __restrict__ m,
                                    int S, int tot)
{
    int i = blockIdx.x*blockDim.x + threadIdx.x;
    if (i >= tot) return;
    int b = i / (S*Kk), r = (i / Kk) % S;
    m[((size_t)b*S + r)*S + nidx[i]] = 1;
}

__global__ void group_rel_kernel(const float* __restrict__ pos0, const float* __restrict__ pos1,
                                 const float* __restrict__ centers, const int* __restrict__ nidx,
                                 __half* __restrict__ rel)
{
    int i = blockIdx.x*blockDim.x + threadIdx.x;
    if (i >= 2*Bb*Gg*Kk) return;
    int side = i / (Bb*Gg*Kk);
    int cb = i / (Gg*Kk);
    int b = cb % Bb;
    int g = (i / Kk) % Gg;
    const float* pos = side ? pos1 : pos0;
    int src = nidx[i];
    const float* P = pos + ((size_t)b*Np + src)*3;
    const float* C = centers + ((size_t)cb*Gg + g)*3;
    __half* rp = rel + (size_t)i*32;
    rp[0] = __float2half(P[0]-C[0]);
    rp[1] = __float2half(P[1]-C[1]);
    rp[2] = __float2half(P[2]-C[2]);
    for (int j = 3; j < 32; j++) rp[j] = __float2half(0.f);
}

__global__ void gmax_h_kernel(const __half* __restrict__ f, __half* __restrict__ g, int C, int tot)
{
    int i = blockIdx.x*blockDim.x + threadIdx.x;
    if (i >= tot) return;
    int bg = i / C, c = i % C;
    const __half* fp = f + (size_t)bg*Kk*C + c;
    float m = __half2float(fp[0]);
    #pragma unroll
    for (int k = 1; k < Kk; k++) m = fmaxf(m, __half2float(fp[(size_t)k*C]));
    g[i] = __float2half(m);
}

__global__ void gmax_f_kernel(const float* __restrict__ f, float* __restrict__ g, int C, int tot)
{
    int i = blockIdx.x*blockDim.x + threadIdx.x;
    if (i >= tot) return;
    int bg = i / C, c = i % C;
    const float* fp = f + (size_t)bg*Kk*C + c;
    float m = fp[0];
    #pragma unroll
    for (int k = 1; k < Kk; k++) m = fmaxf(m, fp[(size_t)k*C]);
    g[i] = m;
}

__global__ void cat_kernel(const __half* __restrict__ g, const __half* __restrict__ f,
                           __half* __restrict__ cat, int tot)
{
    int i = blockIdx.x*blockDim.x + threadIdx.x;
    if (i >= tot) return;
    int c = i % 512, r = i / 512, bg = r / Kk;
    cat[i] = (c < 256) ? g[(size_t)bg*256 + c] : f[(size_t)r*256 + (c - 256)];
}

// PE for both ppe sides in one launch
__global__ void pe2_kernel(const float* __restrict__ p0, const float* __restrict__ p1,
                           float* __restrict__ pe, int rowsHalf)
{
    int i = blockIdx.x*blockDim.x + threadIdx.x;
    if (i >= 2*rowsHalf*Dd) return;
    int r = i / Dd, j = i % Dd, c = j / 128, jj = j % 128;
    const float* xyz = (r < rowsHalf) ? p0 : p1;
    int lr = (r < rowsHalf) ? r : r - rowsHalf;
    float x = xyz[(size_t)lr*3 + c];
    float ex = (float)(2*(jj/2)) * (1.0f/128.0f);
    float p = x * exp2f(-ex * 13.287712379549449f);
    pe[i] = (jj & 1) ? __cosf(p) : __sinf(p);
}

__global__ void pe_kernel(const float* __restrict__ xyz, float* __restrict__ pe, int rows)
{
    int i = blockIdx.x*blockDim.x + threadIdx.x;
    if (i >= rows*Dd) return;
    int r = i / Dd, j = i % Dd, c = j / 128, jj = j % 128;
    float x = xyz[(size_t)r*3 + c];
    float ex = (float)(2*(jj/2)) * (1.0f/128.0f);
    float p = x * exp2f(-ex * 13.287712379549449f);
    pe[i] = (jj & 1) ? __cosf(p) : __sinf(p);
}

__global__ void gather_kernel(const float* __restrict__ src, const int* __restrict__ idx,
                              float* __restrict__ dst, int outR, int inR, int W)
{
    int row = blockIdx.x, b = row / outR, r = row % outR;
    int s = idx[(size_t)b*outR + r];
    const float* sp = src + ((size_t)b*inR + s)*W;
    float* dp = dst + (size_t)row*W;
    for (int w = threadIdx.x; w < W; w += blockDim.x) dp[w] = sp[w];
}

__global__ void decq_kernel(const float* __restrict__ visout, const float* __restrict__ cpe,
                            const float* __restrict__ mask_token, const int* __restrict__ mskidx,
                            const int* __restrict__ visidx, float* __restrict__ x)
{
    int i = blockIdx.x*blockDim.x + threadIdx.x;
    if (i >= Bb*(Mm+Vv)*Dd) return;
    int d = i % Dd, r = (i / Dd) % (Mm+Vv), b = i / (Dd*(Mm+Vv));
    float base; int pidx;
    if (r < Mm) { base = mask_token[d]; pidx = mskidx[(size_t)b*Mm + r]; }
    else { base = visout[((size_t)b*Vv + (r-Mm))*Dd + d]; pidx = visidx[(size_t)b*Vv + (r-Mm)]; }
    x[i] = base + cpe[((size_t)b*Gg + pidx)*Dd + d];
}

__global__ void add_kernel(const float* __restrict__ a, const float* __restrict__ b,
                           float* __restrict__ c, int n)
{ int i = blockIdx.x*blockDim.x + threadIdx.x; if (i < n) c[i] = a[i] + b[i]; }

// nn3 both sides in one launch
__global__ void nn3_kernel(const float* __restrict__ pos0, const float* __restrict__ pos1,
                           const float* __restrict__ centers,
                           int* __restrict__ oi, float* __restrict__ ow)
{
    int i = blockIdx.x*blockDim.x + threadIdx.x;
    if (i >= 2*Bb*Np) return;
    int side = i / (Bb*Np);
    int li = i % (Bb*Np);
    int b = li / Np;
    const float* P = (side ? pos1 : pos0) + (size_t)li*3;
    float px=P[0], py=P[1], pz=P[2], qq=px*px+py*py+pz*pz;
    float d0=3e38f, d1=3e38f, d2=3e38f; int i0=-1, i1=-1, i2=-1;
    const float* C = centers + ((size_t)side*Bb + b)*Gg*3;
    for (int g = 0; g < Gg; g++) {
        float cx=C[3*g], cy=C[3*g+1], cz=C[3*g+2];
        float d = qq + (cx*cx+cy*cy+cz*cz) - 2.f*(px*cx+py*cy+pz*cz);
        if (d < d0) { d2=d1;i2=i1; d1=d0;i1=i0; d0=d;i0=g; }
        else if (d < d1) { d2=d1;i2=i1; d1=d;i1=g; }
        else if (d < d2) { d2=d;i2=g; }
    }
    float w0=1.f/(fmaxf(d0,0.f)+1e-8f), w1=1.f/(fmaxf(d1,0.f)+1e-8f), w2=1.f/(fmaxf(d2,0.f)+1e-8f);
    float s = w0+w1+w2;
    ow[3*i]=w0/s; ow[3*i+1]=w1/s; ow[3*i+2]=w2/s;
    oi[3*i]=i0; oi[3*i+1]=i1; oi[3*i+2]=i2;
}

// upcat both sides in one launch
__global__ void upcat_kernel(const float* __restrict__ feats, const float* __restrict__ pos0,
                             const float* __restrict__ pos1,
                             const int* __restrict__ oi, const float* __restrict__ ow,
                             __half* __restrict__ cat)
{
    int row = blockIdx.x, t = threadIdx.x;
    int side = row / (Bb*Np);
    int li = row % (Bb*Np);
    int b = li / Np;
    int i0=oi[3*row], i1=oi[3*row+1], i2=oi[3*row+2];
    float w0=ow[3*row], w1=ow[3*row+1], w2=ow[3*row+2];
    const float* F = feats + ((size_t)side*Bb + b)*Gg*Dd;
    const float* pos = side ? pos1 : pos0;
    __half* cp = cat + (size_t)row*UPK;
    for (int d = t; d < Dd; d += 128)
        cp[d] = __float2half(w0*F[(size_t)i0*Dd+d] + w1*F[(size_t)i1*Dd+d] + w2*F[(size_t)i2*Dd+d]);
    if (t < 32) cp[Dd + t] = __float2half((t < 3) ? pos[(size_t)li*3 + t] : 0.f);
}

__global__ void loss_kernel(const float* __restrict__ fullout, const int* __restrict__ mskidx,
                            const float* __restrict__ decx, float* __restrict__ partial)
{
    __shared__ float red[256];
    int t = threadIdx.x;
    float acc = 0.f;
    for (int i = blockIdx.x*256 + t; i < Bb*Mm*Dd; i += 64*256) {
        int d = i % Dd, r = (i / Dd) % Mm, b = i / (Dd*Mm);
        int gi = mskidx[(size_t)b*Mm + r];
        float tv = fullout[((size_t)b*Gg + gi)*Dd + d];
        float pv = decx[((size_t)b*(Mm+Vv) + r)*Dd + d];
        float a = fabsf(pv - tv);
        acc += (a < 2.0f) ? 0.25f*a*a : a - 1.0f;
    }
    red[t] = acc; __syncthreads();
    for (int o = 128; o > 0; o >>= 1) { if (t < o) red[t] += red[t+o]; __syncthreads(); }
    if (t == 0) partial[blockIdx.x] = red[0];
}

__global__ void loss_final_kernel(const float* __restrict__ pa, const float* __restrict__ pb,
                                  float* __restrict__ out)
{
    float sa = 0.f, sb = 0.f;
    for (int i = 0; i < 64; i++) { sa += pa[i]; sb += pb[i]; }
    float cnt = (float)(Bb*Mm*Dd);
    out[0] = 0.5f*(sa/cnt) + 0.5f*(sb/cnt);
}

__global__ void copy_kernel(const float* __restrict__ a, float* __restrict__ b, int n)
{ int i = blockIdx.x*blockDim.x + threadIdx.x; if (i < n) b[i] = a[i]; }

// ------------------------------ host side --------------------------------

static __half* WTH;
static float *QB, *SKV;
static __half *CTXH;

static void gemm_h(const __half* A, const __half* Wt, const float* bias,
                   float* Cf, __half* Ch, int rows, int Kd, int Nc, int relu, int accum)
{
    dim3 grid(Nc/128, rows/128);
    gemm_h_kernel<<<grid, 256>>>(A, Wt, bias, Cf, Ch, rows, Kd, Nc, relu, accum);
}

static void self_attn(float* x, const __half* lnx, long woff, const unsigned char* mask,
                      int S, int nB)
{
    gemm_h(lnx, WTH + woff, nullptr, SKV, nullptr, nB*S, Dd, 3*Dd, 0, 0);
    dim3 g(S, NHh, nB);
    attn_kernel<<<g, 128>>>(SKV, 3*Dd, SKV + Dd, SKV + 2*Dd, 3*Dd, mask, CTXH, S, S, 0);
    gemm_h(CTXH, WTH + woff + 3*MSZ, nullptr, x, nullptr, nB*S, Dd, Dd, 0, 1);
}

static void cross_attn(float* x, const __half* lnq, const __half* lnkv, long woff,
                       int Sq, int Sk, int nB, int kvxor, int big)
{
    gemm_h(lnq,  WTH + woff,       nullptr, QB, nullptr, nB*Sq, Dd, Dd, 0, 0);
    gemm_h(lnkv, WTH + woff + MSZ, nullptr, SKV, nullptr, nB*Sk, Dd, 2*Dd, 0, 0);
    if (big) {
        dim3 g(Sq/QT, NHh, nB);
        attn_big_kernel<<<g, 128>>>(QB, Dd, SKV, SKV + Dd, 2*Dd, CTXH, Sq);
    } else {
        dim3 g(Sq, NHh, nB);
        attn_kernel<<<g, 128>>>(QB, Dd, SKV, SKV + Dd, 2*Dd, nullptr, CTXH, Sq, Sk, kvxor);
    }
    gemm_h(CTXH, WTH + woff + 3*MSZ, nullptr, x, nullptr, nB*Sq, Dd, Dd, 0, 1);
}

#define GETSYM(var, sym) do { void* _p; cudaGetSymbolAddress(&_p, sym); var = (decltype(var))_p; } while (0)

extern "C" void kernel_launch(void* const* d_in, const int* in_sizes, int n_in,
                              void* d_out_v, int out_size)
{
    (void)in_sizes; (void)n_in; (void)out_size;
    const float* pos[2]    = {(const float*)d_in[0], (const float*)d_in[1]};
    const int*   visidx[2] = {(const int*)d_in[2], (const int*)d_in[4]};
    const int*   mskidx[2] = {(const int*)d_in[3], (const int*)d_in[5]};
    const float* tok_w1 = (const float*)d_in[6];  const float* tok_b1 = (const float*)d_in[7];
    const float* tok_w2 = (const float*)d_in[8];  const float* tok_b2 = (const float*)d_in[9];
    const float* tok_w3 = (const float*)d_in[10]; const float* tok_b3 = (const float*)d_in[11];
    const float* tok_w4 = (const float*)d_in[12]; const float* tok_b4 = (const float*)d_in[13];
    const float* mask_token = (const float*)d_in[14];
    const float* cx_attn = (const float*)d_in[15];
    const float* cx_ff1  = (const float*)d_in[16]; const float* cx_ff2 = (const float*)d_in[17];
    const float* enc_sa  = (const float*)d_in[18]; const float* enc_ca = (const float*)d_in[19];
    const float* enc_ff1 = (const float*)d_in[20]; const float* enc_ff2 = (const float*)d_in[21];
    const float* dec_ca  = (const float*)d_in[22]; const float* dec_ff1 = (const float*)d_in[23];
    const float* dec_ff2 = (const float*)d_in[24];
    const float* up_w1 = (const float*)d_in[25]; const float* up_b1 = (const float*)d_in[26];
    const float* up_w2 = (const float*)d_in[27]; const float* up_b2 = (const float*)d_in[28];
    float* dout = (float*)d_out_v;

    float *centersB, *t2B, *tokensB, *cpeB, *ppeB, *vis3B, *visB, *fullB, *decxB, *nn3wB, *lpartB;
    int *nidxB, *nidxSB, *nn3iB;
    unsigned char *mfullB, *mvisB;
    __half *relH, *f1H, *f2H, *gmaxH, *catH, *t1H, *lnSH, *lnmH, *lnbigH, *hidH, *upcatH;
    GETSYM(centersB, g_centers); GETSYM(nidxB, g_nidx); GETSYM(nidxSB, g_nidxS);
    GETSYM(t2B, g_t2); GETSYM(tokensB, g_tokens);
    GETSYM(cpeB, g_cpe); GETSYM(ppeB, g_ppe); GETSYM(mfullB, g_mfull); GETSYM(mvisB, g_mvis);
    GETSYM(vis3B, g_vis3); GETSYM(visB, g_visbuf); GETSYM(fullB, g_fullbuf); GETSYM(decxB, g_decx);
    GETSYM(QB, g_qbuf); GETSYM(SKV, g_skv);
    GETSYM(nn3iB, g_nn3i); GETSYM(nn3wB, g_nn3w); GETSYM(lpartB, g_lpart);
    GETSYM(relH, g_relh); GETSYM(f1H, g_f1h); GETSYM(f2H, g_f2h); GETSYM(gmaxH, g_gmaxh);
    GETSYM(catH, g_cath); GETSYM(t1H, g_t1h); GETSYM(lnSH, g_lnSh);
    GETSYM(lnmH, g_lnmh); GETSYM(lnbigH, g_lnbigh); GETSYM(hidH, g_hidh);
    GETSYM(CTXH, g_ctxh); GETSYM(upcatH, g_upcath); GETSYM(WTH, g_wth);

    float* centers[2] = {centersB, centersB + Bb*Gg*3};
    float* tokens[2]  = {tokensB,  tokensB  + Bb*Gg*Dd};
    float* cpe[2]     = {cpeB,     cpeB     + Bb*Gg*Dd};
    float* visb[2]    = {visB,     visB     + Bb*Vv*Dd};
    float* fullb[2]   = {fullB,    fullB    + Bb*Gg*Dd};
    float* decx[2]    = {decxB,    decxB    + Bb*(Mm+Vv)*Dd};
    unsigned char* mvis[2]  = {mvisB,  mvisB  + Bb*Vv*Vv};

    // Phase 0: fused weight conversion
    {
        WConvArgs wa;
        const float* srcs[16] = {tok_w1, tok_w2, tok_w3, tok_w4, cx_attn, enc_sa, enc_ca,
                                 dec_ca, cx_ff1, cx_ff2, enc_ff1, enc_ff2, dec_ff1, dec_ff2,
                                 up_w1, up_w2};
        long starts[17] = {OFF_W1, OFF_W2, OFF_W3, OFF_W4, OFF_CX, OFF_ENCSA, OFF_ENCCA,
                           OFF_DECCA, OFF_CXFF1, OFF_CXFF2, OFF_EFF1, OFF_EFF2, OFF_DFF1,
                           OFF_DFF2, OFF_UP1, OFF_UP2, WTH_TOT};
        int kds[16]  = {3, 128, 512, 512, Dd, Dd, Dd, Dd, Dd, FFf, Dd, FFf, Dd, FFf, Dd+3, Dd};
        int kps[16]  = {32, 128, 512, 512, Dd, Dd, Dd, Dd, Dd, FFf, Dd, FFf, Dd, FFf, UPK, Dd};
        int ncs[16]  = {128, 256, 512, Dd, Dd, Dd, Dd, Dd, FFf, Dd, FFf, Dd, FFf, Dd, Dd, Dd};
        for (int i = 0; i < 16; i++) { wa.src[i]=srcs[i]; wa.start[i]=starts[i]; wa.Kd[i]=kds[i]; wa.KdPad[i]=kps[i]; wa.Nc[i]=ncs[i]; }
        wa.start[16] = starts[16];
        wtconv_all_kernel<<<(int)(((long)WTH_TOT + 255)/256), 256>>>(wa, WTH);
    }

    // Phase 1
    fps_kernel<<<16, 512>>>(pos[0], pos[1], centersB);
    knn_big_kernel<<<2*Bb*Gg, 128>>>(centersB, pos[0], pos[1], nidxB);
    group_rel_kernel<<<(2*Bb*Gg*Kk + 255)/256, 256>>>(pos[0], pos[1], centersB, nidxB, relH);
    gemm_h(relH, WTH + OFF_W1, tok_b1, nullptr, f1H, 32768, 32, 128, 1, 0);
    gemm_h(f1H, WTH + OFF_W2, tok_b2, nullptr, f2H, 32768, 128, 256, 0, 0);
    gmax_h_kernel<<<(2*Bb*Gg*256 + 255)/256, 256>>>(f2H, gmaxH, 256, 2*Bb*Gg*256);
    cat_kernel<<<(32768*512 + 255)/256, 256>>>(gmaxH, f2H, catH, 32768*512);
    gemm_h(catH, WTH + OFF_W3, tok_b3, nullptr, t1H, 32768, 512, 512, 1, 0);
    gemm_h(t1H, WTH + OFF_W4, tok_b4, t2B, nullptr, 32768, 512, Dd, 0, 0);
    gmax_f_kernel<<<(2*Bb*Gg*Dd + 255)/256, 256>>>(t2B, tokensB, Dd, 2*Bb*Gg*Dd);
    pe_kernel<<<(2*Bb*Gg*Dd + 255)/256, 256>>>(centersB, cpeB, 2*Bb*Gg);
    pe2_kernel<<<(2*Bb*Np*Dd + 255)/256, 256>>>(pos[0], pos[1], ppeB, Bb*Np);
    knn_small_kernel<<<2*Bb*Gg, 128>>>(centersB, Gg, nidxSB);
    zero_u8_kernel<<<(2*Bb*Gg*Gg + 255)/256, 256>>>(mfullB, 2*Bb*Gg*Gg);
    scatter_mask_kernel<<<(2*Bb*Gg*Kk + 255)/256, 256>>>(nidxSB, mfullB, Gg, 2*Bb*Gg*Kk);
    for (int s = 0; s < 2; s++) {
        gather_kernel<<<Bb*Vv, 32>>>(centers[s], visidx[s], vis3B, Vv, Gg, 3);
        knn_small_kernel<<<Bb*Vv, 128>>>(vis3B, Vv, nidxSB);
        zero_u8_kernel<<<(Bb*Vv*Vv + 255)/256, 256>>>(mvis[s], Bb*Vv*Vv);
        scatter_mask_kernel<<<(Bb*Vv*Kk + 255)/256, 256>>>(nidxSB, mvis[s], Vv, Bb*Vv*Kk);
        gather_kernel<<<Bb*Vv, 128>>>(tokens[s], visidx[s], visb[s], Vv, Gg, Dd);
    }
    copy_kernel<<<(2*Bb*Gg*Dd + 255)/256, 256>>>(tokensB, fullB, 2*Bb*Gg*Dd);

    // Phase 2: cross encoders
    for (int e = 0; e < 2; e++) {
        int S = e ? Gg : Vv;
        float* ST = e ? fullB : visB;
        const unsigned char* mask = e ? mfullB : mvisB;
        int rows2 = 2*Bb*S;
        ln_kernel<<<rows2/8, 256>>>(ST, lnSH, rows2);
        self_attn(ST, lnSH, OFF_CX, mask, S, 2*Bb);
        ln_kernel<<<rows2/8, 256>>>(ST, lnSH, rows2);
        cross_attn(ST, lnSH, lnSH, OFF_CX + 4*MSZ, S, S, 2*Bb, Bb, 0);
        ln_kernel<<<rows2/8, 256>>>(ST, lnSH, rows2);
        gemm_h(lnSH, WTH + OFF_CXFF1, nullptr, nullptr, hidH, rows2, Dd, FFf, 1, 0);
        gemm_h(hidH, WTH + OFF_CXFF2, nullptr, ST, nullptr, rows2, FFf, Dd, 0, 1);
    }

    // Phase 3: MAE decoder
    for (int s = 0; s < 2; s++)
        decq_kernel<<<(Bb*(Mm+Vv)*Dd + 255)/256, 256>>>(visb[s], cpe[s], mask_token,
                                                        mskidx[s], visidx[s], decx[s]);
    ln2res_kernel<<<(2*Bb*Gg)/8, 256>>>(fullb[1], cpe[1], fullb[0], cpe[0], lnmH, Bb*Gg);
    for (int l = 0; l < 4; l++) {
        ln_kernel<<<(2*Bb*(Mm+Vv))/8, 256>>>(decxB, lnSH, 2*Bb*(Mm+Vv));
        self_attn(decxB, lnSH, OFF_ENCSA + (long)l*4*MSZ, nullptr, Mm+Vv, 2*Bb);
        ln_kernel<<<(2*Bb*(Mm+Vv))/8, 256>>>(decxB, lnSH, 2*Bb*(Mm+Vv));
        cross_attn(decxB, lnSH, lnmH, OFF_ENCCA + (long)l*4*MSZ, Mm+Vv, Gg, 2*Bb, 0, 0);
        ln_kernel<<<(2*Bb*(Mm+Vv))/8, 256>>>(decxB, lnSH, 2*Bb*(Mm+Vv));
        gemm_h(lnSH, WTH + OFF_EFF1 + (long)l*Dd*FFf, nullptr, nullptr, hidH, 2*Bb*(Mm+Vv), Dd, FFf, 1, 0);
        gemm_h(hidH, WTH + OFF_EFF2 + (long)l*FFf*Dd, nullptr, decxB, nullptr, 2*Bb*(Mm+Vv), FFf, Dd, 0, 1);
    }
    for (int s = 0; s < 2; s++)
        loss_kernel<<<64, 256>>>(fullb[s], mskidx[s], decx[s], lpartB + s*64);

    // Phase 4
    nn3_kernel<<<(2*Bb*Np + 255)/256, 256>>>(pos[0], pos[1], centersB, nn3iB, nn3wB);
    upcat_kernel<<<2*Bb*Np, 128>>>(fullB, pos[0], pos[1], nn3iB, nn3wB, upcatH);
    gemm_h(upcatH, WTH + OFF_UP1, up_b1, nullptr, hidH, 2*Bb*Np, UPK, Dd, 1, 0);
    gemm_h(hidH, WTH + OFF_UP2, up_b2, QB, nullptr, 2*Bb*Np, Dd, Dd, 1, 0);
    add_kernel<<<(2*Bb*Np*Dd + 255)/256, 256>>>(QB, ppeB, dout, 2*Bb*Np*Dd);
    ln2res_kernel<<<(2*Bb*Gg)/8, 256>>>(fullb[0], cpe[0], fullb[1], cpe[1], lnmH, Bb*Gg);
    for (int l = 0; l < 2; l++) {
        ln_kernel<<<(2*Bb*Np)/8, 256>>>(dout, lnbigH, 2*Bb*Np);
        cross_attn(dout, lnbigH, lnmH, OFF_DECCA + (long)l*4*MSZ, Np, Gg, 2*Bb, 0, 1);
        ln_kernel<<<(2*Bb*Np)/8, 256>>>(dout, lnbigH, 2*Bb*Np);
        gemm_h(lnbigH, WTH + OFF_DFF1 + (long)l*Dd*FFf, nullptr, nullptr, hidH, 2*Bb*Np, Dd, FFf, 1, 0);
        gemm_h(hidH, WTH + OFF_DFF2 + (long)l*FFf*Dd, nullptr, dout, nullptr, 2*Bb*Np, FFf, Dd, 0, 1);
    }
    loss_final_kernel<<<1, 1>>>(lpartB, lpartB + 64, dout + (size_t)2*Bb*Np*Dd);
}

// round 13
// speedup vs baseline: 8.7567x; 1.4493x over previous
#include <cuda_runtime.h>
#include <cuda_fp16.h>
#include <math.h>
#include <stdint.h>

#define Bb 8
#define Np 4096
#define Gg 128
#define Kk 16
#define Vv 64
#define Mm 64
#define Dd 384
#define NHh 8
#define DHh 48
#define FFf 1536
#define UPK 416

// fp32 buffers
__device__ float g_centers[2*Bb*Gg*3];
__device__ int   g_nidx[2*Bb*Gg*Kk];
__device__ int   g_nidxS[2*Bb*Gg*Kk];
__device__ float g_t2[2*16384*Dd];
__device__ float g_tokens[2*Bb*Gg*Dd];
__device__ float g_cpe[2*Bb*Gg*Dd];
__device__ float g_ppe[2*Bb*Np*Dd];
__device__ unsigned char g_mfull[2*Bb*Gg*Gg];
__device__ unsigned char g_mvis[2*Bb*Vv*Vv];
__device__ float g_vis3[Bb*Vv*3];
__device__ float g_visbuf[2*Bb*Vv*Dd];
__device__ float g_fullbuf[2*Bb*Gg*Dd];
__device__ float g_decx[2*Bb*(Mm+Vv)*Dd];
__device__ float g_qbuf[2*Bb*Np*Dd];
__device__ float g_skv[2048*1152];
__device__ int   g_nn3i[2*Bb*Np*3];
__device__ float g_nn3w[2*Bb*Np*3];
__device__ float g_lpart[2*64];

// half buffers
__device__ __align__(16) __half g_relh[32768*32];
__device__ __align__(16) __half g_f1h[32768*128];
__device__ __align__(16) __half g_f2h[32768*256];
__device__ __align__(16) __half g_gmaxh[2*Bb*Gg*256];
__device__ __align__(16) __half g_cath[32768*512];
__device__ __align__(16) __half g_t1h[32768*512];
__device__ __align__(16) __half g_lnSh[2*Bb*Gg*Dd];
__device__ __align__(16) __half g_lnmh[2*Bb*Gg*Dd];
__device__ __align__(16) __half g_lnbigh[2*Bb*Np*Dd];
__device__ __align__(16) __half g_hidh[(size_t)2*Bb*Np*FFf];
__device__ __align__(16) __half g_ctxh[2*Bb*Np*Dd];
__device__ __align__(16) __half g_upcath[2*Bb*Np*UPK];

#define MSZ 147456
#define OFF_W1    0
#define OFF_W2    (OFF_W1 + 32*128)
#define OFF_W3    (OFF_W2 + 128*256)
#define OFF_W4    (OFF_W3 + 512*512)
#define OFF_CX    (OFF_W4 + 512*384)
#define OFF_ENCSA (OFF_CX + 8*MSZ)
#define OFF_ENCCA (OFF_ENCSA + 16*MSZ)
#define OFF_DECCA (OFF_ENCCA + 16*MSZ)
#define OFF_CXFF1 (OFF_DECCA + 8*MSZ)
#define OFF_CXFF2 (OFF_CXFF1 + 384*1536)
#define OFF_EFF1  (OFF_CXFF2 + 1536*384)
#define OFF_EFF2  (OFF_EFF1 + 4*384*1536)
#define OFF_DFF1  (OFF_EFF2 + 4*1536*384)
#define OFF_DFF2  (OFF_DFF1 + 2*384*1536)
#define OFF_UP1   (OFF_DFF2 + 2*1536*384)
#define OFF_UP2   (OFF_UP1 + 416*384)
#define WTH_TOT   (OFF_UP2 + 384*384)
__device__ __align__(16) __half g_wth[WTH_TOT];

struct WConvArgs {
    const float* src[16];
    long start[17];
    int Kd[16], KdPad[16], Nc[16];
};

__global__ void wtconv_all_kernel(WConvArgs A, __half* __restrict__ dst)
{
    long i = (long)blockIdx.x*256 + threadIdx.x;
    if (i >= A.start[16]) return;
    int s = 0;
    while (s < 15 && i >= A.start[s+1]) s++;
    long li = i - A.start[s];
    int Kd = A.Kd[s], Kp = A.KdPad[s], Nc = A.Nc[s];
    long per = (long)Nc*Kp;
    int mt = (int)(li/per);
    long r = li % per;
    int n = (int)(r/Kp), k = (int)(r%Kp);
    float v = (k < Kd) ? A.src[s][(size_t)mt*Kd*Nc + (size_t)k*Nc + n] : 0.f;
    dst[i] = __float2half(v);
}

// fp16 GEMM: 128x128 tile, KT=32, 3-stage cp.async, one barrier/iter, ldmatrix
__global__ __launch_bounds__(256)
void gemm_h_kernel(const __half* __restrict__ A, const __half* __restrict__ Wt,
                   const float* __restrict__ bias, float* __restrict__ Cf,
                   __half* __restrict__ Ch, int rows, int Kd, int Nc, int relu, int accum)
{
    __shared__ __half Ah[3][128][40];
    __shared__ __half Wh[3][128][40];
    int tid = threadIdx.x, wid = tid>>5, lane = tid&31;
    int g = lane>>2, tig = lane&3;
    int wm = (wid>>1)*32, wn = (wid&1)*64;
    int row0 = blockIdx.y*128, col0 = blockIdx.x*128;
    float c[2][8][4] = {};
    int nIter = Kd/32;

    int lr = lane & 7, lj = lane >> 3;
    uint32_t ah0 = (uint32_t)__cvta_generic_to_shared(&Ah[0][0][0]);
    uint32_t wh0 = (uint32_t)__cvta_generic_to_shared(&Wh[0][0][0]);
    uint32_t aAddr[2], wAddr[4];
    #pragma unroll
    for (int mt = 0; mt < 2; mt++)
        aAddr[mt] = ah0 + (uint32_t)((wm + mt*16 + lr + (lj&1)*8)*80 + ((lj>>1)*8)*2);
    #pragma unroll
    for (int p = 0; p < 4; p++)
        wAddr[p] = wh0 + (uint32_t)((wn + p*16 + lr + ((lj>>1)&1)*8)*80 + ((lj&1)*8)*2);

    #pragma unroll
    for (int st = 0; st < 2; st++) {
        if (st < nIter) {
            int k0 = st*32;
            #pragma unroll
            for (int l = 0; l < 2; l++) {
                int ci = tid + l*256;
                int m = ci>>2, f = ci&3;
                const __half* ga = A + (size_t)(row0+m)*Kd + k0 + f*8;
                uint32_t sa = (uint32_t)__cvta_generic_to_shared(&Ah[st][m][f*8]);
                asm volatile("cp.async.cg.shared.global [%0], [%1], 16;" :: "r"(sa), "l"(ga));
                const __half* gw = Wt + (size_t)(col0+m)*Kd + k0 + f*8;
                uint32_t sw = (uint32_t)__cvta_generic_to_shared(&Wh[st][m][f*8]);
                asm volatile("cp.async.cg.shared.global [%0], [%1], 16;" :: "r"(sw), "l"(gw));
            }
            asm volatile("cp.async.commit_group;");
        }
    }

    for (int it = 0; it < nIter; it++) {
        if (it < nIter-1) asm volatile("cp.async.wait_group 1;");
        else              asm volatile("cp.async.wait_group 0;");
        __syncthreads();
        int cur = it % 3;
        uint32_t stOff = (uint32_t)(cur*10240);
        #pragma unroll
        for (int st = 0; st < 2; st++) {
            uint32_t kOff = stOff + st*32;
            uint32_t a[2][4], b[8][2];
            #pragma unroll
            for (int mt = 0; mt < 2; mt++)
                asm volatile("ldmatrix.sync.aligned.m8n8.x4.shared.b16 {%0,%1,%2,%3}, [%4];"
                    : "=r"(a[mt][0]), "=r"(a[mt][1]), "=r"(a[mt][2]), "=r"(a[mt][3])
                    : "r"(aAddr[mt] + kOff));
            #pragma unroll
            for (int p = 0; p < 4; p++) {
                uint32_t d0, d1, d2, d3;
                asm volatile("ldmatrix.sync.aligned.m8n8.x4.shared.b16 {%0,%1,%2,%3}, [%4];"
                    : "=r"(d0), "=r"(d1), "=r"(d2), "=r"(d3)
                    : "r"(wAddr[p] + kOff));
                b[2*p][0] = d0; b[2*p][1] = d1; b[2*p+1][0] = d2; b[2*p+1][1] = d3;
            }
            #pragma unroll
            for (int mt = 0; mt < 2; mt++)
                #pragma unroll
                for (int nt = 0; nt < 8; nt++)
                    asm volatile(
                        "mma.sync.aligned.m16n8k16.row.col.f32.f16.f16.f32 "
                        "{%0,%1,%2,%3}, {%4,%5,%6,%7}, {%8,%9}, {%0,%1,%2,%3};"
                        : "+f"(c[mt][nt][0]), "+f"(c[mt][nt][1]),
                          "+f"(c[mt][nt][2]), "+f"(c[mt][nt][3])
                        : "r"(a[mt][0]), "r"(a[mt][1]), "r"(a[mt][2]), "r"(a[mt][3]),
                          "r"(b[nt][0]), "r"(b[nt][1]));
        }
        if (it + 2 < nIter) {
            int p = (it+2) % 3;
            int k0 = (it+2)*32;
            #pragma unroll
            for (int l = 0; l < 2; l++) {
                int ci = tid + l*256;
                int m = ci>>2, f = ci&3;
                const __half* ga = A + (size_t)(row0+m)*Kd + k0 + f*8;
                uint32_t sa = (uint32_t)__cvta_generic_to_shared(&Ah[p][m][f*8]);
                asm volatile("cp.async.cg.shared.global [%0], [%1], 16;" :: "r"(sa), "l"(ga));
                const __half* gw = Wt + (size_t)(col0+m)*Kd + k0 + f*8;
                uint32_t sw = (uint32_t)__cvta_generic_to_shared(&Wh[p][m][f*8]);
                asm volatile("cp.async.cg.shared.global [%0], [%1], 16;" :: "r"(sw), "l"(gw));
            }
            asm volatile("cp.async.commit_group;");
        }
    }
    #pragma unroll
    for (int mt = 0; mt < 2; mt++) {
        #pragma unroll
        for (int nt = 0; nt < 8; nt++) {
            int r0 = row0 + wm + mt*16 + g;
            int cc = col0 + wn + nt*8 + 2*tig;
            float v0 = c[mt][nt][0], v1 = c[mt][nt][1];
            float v2 = c[mt][nt][2], v3 = c[mt][nt][3];
            if (bias) { float b0 = bias[cc], b1 = bias[cc+1]; v0 += b0; v1 += b1; v2 += b0; v3 += b1; }
            if (relu) { v0 = fmaxf(v0,0.f); v1 = fmaxf(v1,0.f); v2 = fmaxf(v2,0.f); v3 = fmaxf(v3,0.f); }
            size_t o0 = (size_t)r0*Nc + cc;
            size_t o1 = (size_t)(r0+8)*Nc + cc;
            if (Ch) {
                Ch[o0] = __float2half(v0); Ch[o0+1] = __float2half(v1);
                Ch[o1] = __float2half(v2); Ch[o1+1] = __float2half(v3);
            } else if (accum) {
                Cf[o0] += v0; Cf[o0+1] += v1; Cf[o1] += v2; Cf[o1+1] += v3;
            } else {
                Cf[o0] = v0; Cf[o0+1] = v1; Cf[o1] = v2; Cf[o1+1] = v3;
            }
        }
    }
}

// LayerNorm, warp-per-row
__global__ __launch_bounds__(256)
void ln_kernel(const float* __restrict__ x, __half* __restrict__ y, int rows)
{
    int w = threadIdx.x >> 5, lane = threadIdx.x & 31;
    int row = blockIdx.x*8 + w;
    if (row >= rows) return;
    const float* xr = x + (size_t)row*Dd;
    float e[12]; float s = 0.f;
    #pragma unroll
    for (int j = 0; j < 12; j++) { e[j] = xr[lane + j*32]; s += e[j]; }
    #pragma unroll
    for (int o = 16; o > 0; o >>= 1) s += __shfl_xor_sync(0xffffffffu, s, o);
    float m = s * (1.0f/384.0f);
    float v = 0.f;
    #pragma unroll
    for (int j = 0; j < 12; j++) { e[j] -= m; v += e[j]*e[j]; }
    #pragma unroll
    for (int o = 16; o > 0; o >>= 1) v += __shfl_xor_sync(0xffffffffu, v, o);
    float inv = rsqrtf(v * (1.0f/384.0f) + 1e-5f);
    __half* yr = y + (size_t)row*Dd;
    #pragma unroll
    for (int j = 0; j < 12; j++) yr[lane + j*32] = __float2half(e[j]*inv);
}

// Fused residual+LN
__global__ __launch_bounds__(256)
void ln2res_kernel(const float* __restrict__ a0, const float* __restrict__ b0,
                   const float* __restrict__ a1, const float* __restrict__ b1,
                   __half* __restrict__ y, int rowsHalf)
{
    int w = threadIdx.x >> 5, lane = threadIdx.x & 31;
    int row = blockIdx.x*8 + w;
    const float* a; const float* b; int lr;
    if (row < rowsHalf) { a = a0; b = b0; lr = row; }
    else { a = a1; b = b1; lr = row - rowsHalf; }
    float e[12]; float s = 0.f;
    #pragma unroll
    for (int j = 0; j < 12; j++) {
        size_t idx = (size_t)lr*Dd + lane + j*32;
        e[j] = a[idx] + b[idx]; s += e[j];
    }
    #pragma unroll
    for (int o = 16; o > 0; o >>= 1) s += __shfl_xor_sync(0xffffffffu, s, o);
    float m = s * (1.0f/384.0f);
    float v = 0.f;
    #pragma unroll
    for (int j = 0; j < 12; j++) { e[j] -= m; v += e[j]*e[j]; }
    #pragma unroll
    for (int o = 16; o > 0; o >>= 1) v += __shfl_xor_sync(0xffffffffu, v, o);
    float inv = rsqrtf(v * (1.0f/384.0f) + 1e-5f);
    __half* yr = y + (size_t)row*Dd;
    #pragma unroll
    for (int j = 0; j < 12; j++) yr[lane + j*32] = __float2half(e[j]*inv);
}

// small attention: strided q/k/v; kvxor batch map
__global__ void attn_kernel(const float* __restrict__ q, int qs,
                            const float* __restrict__ kmat, const float* __restrict__ vmat, int kvs,
                            const unsigned char* __restrict__ mask,
                            __half* __restrict__ ctx, int Sq, int Sk, int kvxor)
{
    int qi = blockIdx.x, h = blockIdx.y, b = blockIdx.z, t = threadIdx.x;
    int bk = b ^ kvxor;
    __shared__ float shq[DHh], shp[128], red[128];
    const float* qr = q + (size_t)(b*Sq + qi)*qs + h*DHh;
    if (t < DHh) shq[t] = qr[t];
    __syncthreads();
    float val = -3e38f;
    if (t < Sk) {
        const float* kr = kmat + (size_t)(bk*Sk + t)*kvs + h*DHh;
        float s = 0.f;
        #pragma unroll
        for (int d = 0; d < DHh; d++) s += shq[d]*kr[d];
        s /= sqrtf((float)DHh);
        if (mask && !mask[((size_t)b*Sq + qi)*Sk + t]) s = -1e9f;
        val = s;
    }
    red[t] = val; __syncthreads();
    for (int o = 64; o > 0; o >>= 1) { if (t < o) red[t] = fmaxf(red[t], red[t+o]); __syncthreads(); }
    float mx = red[0]; __syncthreads();
    float e = (t < Sk) ? expf(val - mx) : 0.f;
    shp[t] = e; red[t] = e; __syncthreads();
    for (int o = 64; o > 0; o >>= 1) { if (t < o) red[t] += red[t+o]; __syncthreads(); }
    float inv = 1.f / red[0];
    if (t < DHh) {
        float acc = 0.f;
        const float* vb = vmat + (size_t)(bk*Sk)*kvs + h*DHh + t;
        for (int kk = 0; kk < Sk; kk++) acc += shp[kk]*vb[(size_t)kk*kvs];
        ctx[((size_t)(b*Sq + qi))*Dd + h*DHh + t] = __float2half(acc*inv);
    }
}

// big attention: 32 queries/block, Sk==128, kvxor, register-blocked output
#define QT 32
__global__ __launch_bounds__(128)
void attn_big_kernel(const float* __restrict__ q, int qs,
                     const float* __restrict__ kmat, const float* __restrict__ vmat, int kvs,
                     __half* __restrict__ ctx, int Sq, int kvxor)
{
    int qt = blockIdx.x, h = blockIdx.y, b = blockIdx.z, t = threadIdx.x;
    int bk = b ^ kvxor;
    __shared__ float shq[QT][DHh];
    __shared__ float sc[QT][129];
    __shared__ float Vs[128][DHh];
    for (int i = t; i < QT*DHh; i += 128) {
        int qi = i / DHh, d = i % DHh;
        shq[qi][d] = q[(size_t)(b*Sq + qt*QT + qi)*qs + h*DHh + d];
    }
    for (int i = t; i < 128*DHh; i += 128) {
        int k = i / DHh, d = i % DHh;
        Vs[k][d] = vmat[(size_t)(bk*128 + k)*kvs + h*DHh + d];
    }
    __syncthreads();
    float kr[DHh];
    {
        const float* kp = kmat + (size_t)(bk*128 + t)*kvs + h*DHh;
        #pragma unroll
        for (int d = 0; d < DHh; d++) kr[d] = kp[d];
    }
    float inv_s = rsqrtf((float)DHh);
    #pragma unroll 1
    for (int qi = 0; qi < QT; qi++) {
        float s = 0.f;
        #pragma unroll
        for (int d = 0; d < DHh; d++) s += shq[qi][d]*kr[d];
        sc[qi][t] = s * inv_s;
    }
    __syncthreads();
    int w = t >> 5, lane = t & 31;
    for (int qi = w; qi < QT; qi += 4) {
        float v0 = sc[qi][lane], v1 = sc[qi][lane+32], v2 = sc[qi][lane+64], v3 = sc[qi][lane+96];
        float mx = fmaxf(fmaxf(v0,v1), fmaxf(v2,v3));
        #pragma unroll
        for (int o = 16; o > 0; o >>= 1) mx = fmaxf(mx, __shfl_xor_sync(0xffffffffu, mx, o));
        float e0=expf(v0-mx), e1=expf(v1-mx), e2=expf(v2-mx), e3=expf(v3-mx);
        float sum = e0+e1+e2+e3;
        #pragma unroll
        for (int o = 16; o > 0; o >>= 1) sum += __shfl_xor_sync(0xffffffffu, sum, o);
        float inv = 1.f / sum;
        sc[qi][lane]=e0*inv; sc[qi][lane+32]=e1*inv; sc[qi][lane+64]=e2*inv; sc[qi][lane+96]=e3*inv;
    }
    __syncthreads();
    {
        int qi = t >> 2;
        int d0 = (t & 3) * 12;
        float acc[12];
        #pragma unroll
        for (int j = 0; j < 12; j++) acc[j] = 0.f;
        #pragma unroll 4
        for (int k = 0; k < 128; k++) {
            float p = sc[qi][k];
            float4 va = *(const float4*)&Vs[k][d0];
            float4 vb = *(const float4*)&Vs[k][d0+4];
            float4 vc = *(const float4*)&Vs[k][d0+8];
            acc[0]+=p*va.x; acc[1]+=p*va.y; acc[2]+=p*va.z; acc[3]+=p*va.w;
            acc[4]+=p*vb.x; acc[5]+=p*vb.y; acc[6]+=p*vb.z; acc[7]+=p*vb.w;
            acc[8]+=p*vc.x; acc[9]+=p*vc.y; acc[10]+=p*vc.z; acc[11]+=p*vc.w;
        }
        __half2* cp = (__half2*)(ctx + ((size_t)(b*Sq + qt*QT + qi))*Dd + h*DHh + d0);
        #pragma unroll
        for (int j = 0; j < 6; j++)
            cp[j] = __floats2half2_rn(acc[2*j], acc[2*j+1]);
    }
}

// FPS both sides, fused update+argmax, shuffle reduce
__global__ void fps_kernel(const float* __restrict__ pos0, const float* __restrict__ pos1,
                           float* __restrict__ centers)
{
    int blk = blockIdx.x, t = threadIdx.x;
    int side = blk >> 3, b = blk & 7;
    const float* P = (side ? pos1 : pos0) + (size_t)b*Np*3;
    float* C = centers + (size_t)blk*Gg*3;
    __shared__ float mind[Np];
    __shared__ float wv[16]; __shared__ int wi[16];
    __shared__ float curp[3];
    int w = t >> 5, lane = t & 31;
    if (t == 0) { curp[0]=P[0]; curp[1]=P[1]; curp[2]=P[2]; C[0]=P[0]; C[1]=P[1]; C[2]=P[2]; }
    for (int i = t; i < Np; i += 512) mind[i] = 3e38f;
    __syncthreads();
    for (int s = 1; s < Gg; s++) {
        float cx = curp[0], cy = curp[1], cz = curp[2];
        float bv = -3e38f; int bi = 0x7fffffff;
        for (int i = t; i < Np; i += 512) {
            float dx=P[3*i]-cx, dy=P[3*i+1]-cy, dz=P[3*i+2]-cz;
            float d = dx*dx + dy*dy + dz*dz;
            float m = fminf(mind[i], d);
            mind[i] = m;
            if (m > bv || (m == bv && i < bi)) { bv = m; bi = i; }
        }
        #pragma unroll
        for (int o = 16; o > 0; o >>= 1) {
            float ov = __shfl_xor_sync(0xffffffffu, bv, o);
            int   oi = __shfl_xor_sync(0xffffffffu, bi, o);
            if (ov > bv || (ov == bv && oi < bi)) { bv = ov; bi = oi; }
        }
        if (lane == 0) { wv[w] = bv; wi[w] = bi; }
        __syncthreads();
        if (w == 0) {
            float v = (lane < 16) ? wv[lane] : -3e38f;
            int  ii = (lane < 16) ? wi[lane] : 0x7fffffff;
            #pragma unroll
            for (int o = 8; o > 0; o >>= 1) {
                float ov = __shfl_xor_sync(0xffffffffu, v, o);
                int   oi = __shfl_xor_sync(0xffffffffu, ii, o);
                if (ov > v || (ov == v && oi < ii)) { v = ov; ii = oi; }
            }
            if (lane == 0) {
                curp[0]=P[3*ii]; curp[1]=P[3*ii+1]; curp[2]=P[3*ii+2];
                C[3*s]=curp[0]; C[3*s+1]=curp[1]; C[3*s+2]=curp[2];
            }
        }
        __syncthreads();
    }
}

// KNN big: shuffle-reduced selection
__global__ void knn_big_kernel(const float* __restrict__ qpts,
                               const float* __restrict__ pos0, const float* __restrict__ pos1,
                               int* __restrict__ nidx)
{
    int blk = blockIdx.x, t = threadIdx.x;
    int side = blk / (Bb*Gg);
    int b = (blk / Gg) % Bb;
    __shared__ float dist[Np];
    __shared__ float wv[4]; __shared__ int wi[4];
    __shared__ int selS;
    int w = t >> 5, lane = t & 31;
    const float* Q = qpts + (size_t)blk*3;
    float qx=Q[0], qy=Q[1], qz=Q[2], qq = qx*qx+qy*qy+qz*qz;
    const float* R = (side ? pos1 : pos0) + (size_t)b*Np*3;
    for (int i = t; i < Np; i += 128) {
        float rx=R[3*i], ry=R[3*i+1], rz=R[3*i+2];
        dist[i] = qq + (rx*rx+ry*ry+rz*rz) - 2.f*(qx*rx+qy*ry+qz*rz);
    }
    __syncthreads();
    for (int kk = 0; kk < Kk; kk++) {
        float bv = 3e38f; int bi = 0x7fffffff;
        for (int i = t; i < Np; i += 128) {
            float v = dist[i];
            if (v < bv || (v == bv && i < bi)) { bv = v; bi = i; }
        }
        #pragma unroll
        for (int o = 16; o > 0; o >>= 1) {
            float ov = __shfl_xor_sync(0xffffffffu, bv, o);
            int   oi = __shfl_xor_sync(0xffffffffu, bi, o);
            if (ov < bv || (ov == bv && oi < bi)) { bv = ov; bi = oi; }
        }
        if (lane == 0) { wv[w] = bv; wi[w] = bi; }
        __syncthreads();
        if (t == 0) {
            float v = wv[0]; int ii = wi[0];
            #pragma unroll
            for (int j = 1; j < 4; j++)
                if (wv[j] < v || (wv[j] == v && wi[j] < ii)) { v = wv[j]; ii = wi[j]; }
            nidx[(size_t)blk*Kk + kk] = ii;
            dist[ii] = 3e38f;
            selS = ii;
        }
        __syncthreads();
        (void)selS;
    }
}

// KNN small: shuffle-reduced selection
__global__ void knn_small_kernel(const float* __restrict__ pts, int S, int* __restrict__ nidx)
{
    int blk = blockIdx.x, b = blk / S, qi = blk % S, t = threadIdx.x;
    __shared__ float dist[128];
    __shared__ float wv[4]; __shared__ int wi[4];
    int w = t >> 5, lane = t & 31;
    const float* Q = pts + ((size_t)b*S + qi)*3;
    float qx=Q[0], qy=Q[1], qz=Q[2], qq=qx*qx+qy*qy+qz*qz;
    if (t < S) {
        const float* R = pts + ((size_t)b*S + t)*3;
        dist[t] = qq + (R[0]*R[0]+R[1]*R[1]+R[2]*R[2]) - 2.f*(qx*R[0]+qy*R[1]+qz*R[2]);
    } else dist[t] = 3e38f;
    __syncthreads();
    for (int kk = 0; kk < Kk; kk++) {
        float bv = dist[t]; int bi = t;
        #pragma unroll
        for (int o = 16; o > 0; o >>= 1) {
            float ov = __shfl_xor_sync(0xffffffffu, bv, o);
            int   oi = __shfl_xor_sync(0xffffffffu, bi, o);
            if (ov < bv || (ov == bv && oi < bi)) { bv = ov; bi = oi; }
        }
        if (lane == 0) { wv[w] = bv; wi[w] = bi; }
        __syncthreads();
        if (t == 0) {
            float v = wv[0]; int ii = wi[0];
            #pragma unroll
            for (int j = 1; j < 4; j++)
                if (wv[j] < v || (wv[j] == v && wi[j] < ii)) { v = wv[j]; ii = wi[j]; }
            nidx[((size_t)b*S + qi)*Kk + kk] = ii;
            dist[ii] = 3e38f;
        }
        __syncthreads();
    }
}

__global__ void zero_u8_kernel(unsigned char* m, int n)
{ int i = blockIdx.x*blockDim.x + threadIdx.x; if (i < n) m[i] = 0; }

__global__ void scatter_mask_kernel(const int* __restrict__ nidx, unsigned char* __restrict__ m,
                                    int S, int tot)
{
    int i = blockIdx.x*blockDim.x + threadIdx.x;
    if (i >= tot) return;
    int b = i / (S*Kk), r = (i / Kk) % S;
    m[((size_t)b*S + r)*S + nidx[i]] = 1;
}

__global__ void group_rel_kernel(const float* __restrict__ pos0, const float* __restrict__ pos1,
                                 const float* __restrict__ centers, const int* __restrict__ nidx,
                                 __half* __restrict__ rel)
{
    int i = blockIdx.x*blockDim.x + threadIdx.x;
    if (i >= 2*Bb*Gg*Kk) return;
    int side = i / (Bb*Gg*Kk);
    int cb = i / (Gg*Kk);
    int b = cb % Bb;
    int g = (i / Kk) % Gg;
    const float* pos = side ? pos1 : pos0;
    int src = nidx[i];
    const float* P = pos + ((size_t)b*Np + src)*3;
    const float* C = centers + ((size_t)cb*Gg + g)*3;
    __half* rp = rel + (size_t)i*32;
    rp[0] = __float2half(P[0]-C[0]);
    rp[1] = __float2half(P[1]-C[1]);
    rp[2] = __float2half(P[2]-C[2]);
    for (int j = 3; j < 32; j++) rp[j] = __float2half(0.f);
}

__global__ void gmax_h_kernel(const __half* __restrict__ f, __half* __restrict__ g, int C, int tot)
{
    int i = blockIdx.x*blockDim.x + threadIdx.x;
    if (i >= tot) return;
    int bg = i / C, c = i % C;
    const __half* fp = f + (size_t)bg*Kk*C + c;
    float m = __half2float(fp[0]);
    #pragma unroll
    for (int k = 1; k < Kk; k++) m = fmaxf(m, __half2float(fp[(size_t)k*C]));
    g[i] = __float2half(m);
}

__global__ void gmax_f_kernel(const float* __restrict__ f, float* __restrict__ g, int C, int tot)
{
    int i = blockIdx.x*blockDim.x + threadIdx.x;
    if (i >= tot) return;
    int bg = i / C, c = i % C;
    const float* fp = f + (size_t)bg*Kk*C + c;
    float m = fp[0];
    #pragma unroll
    for (int k = 1; k < Kk; k++) m = fmaxf(m, fp[(size_t)k*C]);
    g[i] = m;
}

__global__ void cat_kernel(const __half* __restrict__ g, const __half* __restrict__ f,
                           __half* __restrict__ cat, int tot)
{
    int i = blockIdx.x*blockDim.x + threadIdx.x;
    if (i >= tot) return;
    int c = i % 512, r = i / 512, bg = r / Kk;
    cat[i] = (c < 256) ? g[(size_t)bg*256 + c] : f[(size_t)r*256 + (c - 256)];
}

__global__ void pe2_kernel(const float* __restrict__ p0, const float* __restrict__ p1,
                           float* __restrict__ pe, int rowsHalf)
{
    int i = blockIdx.x*blockDim.x + threadIdx.x;
    if (i >= 2*rowsHalf*Dd) return;
    int r = i / Dd, j = i % Dd, c = j / 128, jj = j % 128;
    const float* xyz = (r < rowsHalf) ? p0 : p1;
    int lr = (r < rowsHalf) ? r : r - rowsHalf;
    float x = xyz[(size_t)lr*3 + c];
    float ex = (float)(2*(jj/2)) * (1.0f/128.0f);
    float p = x * exp2f(-ex * 13.287712379549449f);
    pe[i] = (jj & 1) ? __cosf(p) : __sinf(p);
}

__global__ void pe_kernel(const float* __restrict__ xyz, float* __restrict__ pe, int rows)
{
    int i = blockIdx.x*blockDim.x + threadIdx.x;
    if (i >= rows*Dd) return;
    int r = i / Dd, j = i % Dd, c = j / 128, jj = j % 128;
    float x = xyz[(size_t)r*3 + c];
    float ex = (float)(2*(jj/2)) * (1.0f/128.0f);
    float p = x * exp2f(-ex * 13.287712379549449f);
    pe[i] = (jj & 1) ? __cosf(p) : __sinf(p);
}

__global__ void gather_kernel(const float* __restrict__ src, const int* __restrict__ idx,
                              float* __restrict__ dst, int outR, int inR, int W)
{
    int row = blockIdx.x, b = row / outR, r = row % outR;
    int s = idx[(size_t)b*outR + r];
    const float* sp = src + ((size_t)b*inR + s)*W;
    float* dp = dst + (size_t)row*W;
    for (int w = threadIdx.x; w < W; w += blockDim.x) dp[w] = sp[w];
}

__global__ void decq_kernel(const float* __restrict__ visout, const float* __restrict__ cpe,
                            const float* __restrict__ mask_token, const int* __restrict__ mskidx,
                            const int* __restrict__ visidx, float* __restrict__ x)
{
    int i = blockIdx.x*blockDim.x + threadIdx.x;
    if (i >= Bb*(Mm+Vv)*Dd) return;
    int d = i % Dd, r = (i / Dd) % (Mm+Vv), b = i / (Dd*(Mm+Vv));
    float base; int pidx;
    if (r < Mm) { base = mask_token[d]; pidx = mskidx[(size_t)b*Mm + r]; }
    else { base = visout[((size_t)b*Vv + (r-Mm))*Dd + d]; pidx = visidx[(size_t)b*Vv + (r-Mm)]; }
    x[i] = base + cpe[((size_t)b*Gg + pidx)*Dd + d];
}

__global__ void add_kernel(const float* __restrict__ a, const float* __restrict__ b,
                           float* __restrict__ c, int n)
{ int i = blockIdx.x*blockDim.x + threadIdx.x; if (i < n) c[i] = a[i] + b[i]; }

__global__ void nn3_kernel(const float* __restrict__ pos0, const float* __restrict__ pos1,
                           const float* __restrict__ centers,
                           int* __restrict__ oi, float* __restrict__ ow)
{
    int i = blockIdx.x*blockDim.x + threadIdx.x;
    if (i >= 2*Bb*Np) return;
    int side = i / (Bb*Np);
    int li = i % (Bb*Np);
    int b = li / Np;
    const float* P = (side ? pos1 : pos0) + (size_t)li*3;
    float px=P[0], py=P[1], pz=P[2], qq=px*px+py*py+pz*pz;
    float d0=3e38f, d1=3e38f, d2=3e38f; int i0=-1, i1=-1, i2=-1;
    const float* C = centers + ((size_t)side*Bb + b)*Gg*3;
    for (int g = 0; g < Gg; g++) {
        float cx=C[3*g], cy=C[3*g+1], cz=C[3*g+2];
        float d = qq + (cx*cx+cy*cy+cz*cz) - 2.f*(px*cx+py*cy+pz*cz);
        if (d < d0) { d2=d1;i2=i1; d1=d0;i1=i0; d0=d;i0=g; }
        else if (d < d1) { d2=d1;i2=i1; d1=d;i1=g; }
        else if (d < d2) { d2=d;i2=g; }
    }
    float w0=1.f/(fmaxf(d0,0.f)+1e-8f), w1=1.f/(fmaxf(d1,0.f)+1e-8f), w2=1.f/(fmaxf(d2,0.f)+1e-8f);
    float s = w0+w1+w2;
    ow[3*i]=w0/s; ow[3*i+1]=w1/s; ow[3*i+2]=w2/s;
    oi[3*i]=i0; oi[3*i+1]=i1; oi[3*i+2]=i2;
}

__global__ void upcat_kernel(const float* __restrict__ feats, const float* __restrict__ pos0,
                             const float* __restrict__ pos1,
                             const int* __restrict__ oi, const float* __restrict__ ow,
                             __half* __restrict__ cat)
{
    int row = blockIdx.x, t = threadIdx.x;
    int side = row / (Bb*Np);
    int li = row % (Bb*Np);
    int b = li / Np;
    int i0=oi[3*row], i1=oi[3*row+1], i2=oi[3*row+2];
    float w0=ow[3*row], w1=ow[3*row+1], w2=ow[3*row+2];
    const float* F = feats + ((size_t)side*Bb + b)*Gg*Dd;
    const float* pos = side ? pos1 : pos0;
    __half* cp = cat + (size_t)row*UPK;
    for (int d = t; d < Dd; d += 128)
        cp[d] = __float2half(w0*F[(size_t)i0*Dd+d] + w1*F[(size_t)i1*Dd+d] + w2*F[(size_t)i2*Dd+d]);
    if (t < 32) cp[Dd + t] = __float2half((t < 3) ? pos[(size_t)li*3 + t] : 0.f);
}

__global__ void loss_kernel(const float* __restrict__ fullout, const int* __restrict__ mskidx,
                            const float* __restrict__ decx, float* __restrict__ partial)
{
    __shared__ float red[256];
    int t = threadIdx.x;
    float acc = 0.f;
    for (int i = blockIdx.x*256 + t; i < Bb*Mm*Dd; i += 64*256) {
        int d = i % Dd, r = (i / Dd) % Mm, b = i / (Dd*Mm);
        int gi = mskidx[(size_t)b*Mm + r];
        float tv = fullout[((size_t)b*Gg + gi)*Dd + d];
        float pv = decx[((size_t)b*(Mm+Vv) + r)*Dd + d];
        float a = fabsf(pv - tv);
        acc += (a < 2.0f) ? 0.25f*a*a : a - 1.0f;
    }
    red[t] = acc; __syncthreads();
    for (int o = 128; o > 0; o >>= 1) { if (t < o) red[t] += red[t+o]; __syncthreads(); }
    if (t == 0) partial[blockIdx.x] = red[0];
}

__global__ void loss_final_kernel(const float* __restrict__ pa, const float* __restrict__ pb,
                                  float* __restrict__ out)
{
    float sa = 0.f, sb = 0.f;
    for (int i = 0; i < 64; i++) { sa += pa[i]; sb += pb[i]; }
    float cnt = (float)(Bb*Mm*Dd);
    out[0] = 0.5f*(sa/cnt) + 0.5f*(sb/cnt);
}

__global__ void copy_kernel(const float* __restrict__ a, float* __restrict__ b, int n)
{ int i = blockIdx.x*blockDim.x + threadIdx.x; if (i < n) b[i] = a[i]; }

// ------------------------------ host side --------------------------------

static __half* WTH;
static float *QB, *SKV;
static __half *CTXH;

static void gemm_h(const __half* A, const __half* Wt, const float* bias,
                   float* Cf, __half* Ch, int rows, int Kd, int Nc, int relu, int accum)
{
    dim3 grid(Nc/128, rows/128);
    gemm_h_kernel<<<grid, 256>>>(A, Wt, bias, Cf, Ch, rows, Kd, Nc, relu, accum);
}

static void self_attn(float* x, const __half* lnx, long woff, const unsigned char* mask,
                      int S, int nB)
{
    gemm_h(lnx, WTH + woff, nullptr, SKV, nullptr, nB*S, Dd, 3*Dd, 0, 0);
    if (mask == nullptr && S == 128) {
        dim3 g(S/QT, NHh, nB);
        attn_big_kernel<<<g, 128>>>(SKV, 3*Dd, SKV + Dd, SKV + 2*Dd, 3*Dd, CTXH, S, 0);
    } else {
        dim3 g(S, NHh, nB);
        attn_kernel<<<g, 128>>>(SKV, 3*Dd, SKV + Dd, SKV + 2*Dd, 3*Dd, mask, CTXH, S, S, 0);
    }
    gemm_h(CTXH, WTH + woff + 3*MSZ, nullptr, x, nullptr, nB*S, Dd, Dd, 0, 1);
}

static void cross_attn(float* x, const __half* lnq, const __half* lnkv, long woff,
                       int Sq, int Sk, int nB, int kvxor)
{
    gemm_h(lnq,  WTH + woff,       nullptr, QB, nullptr, nB*Sq, Dd, Dd, 0, 0);
    gemm_h(lnkv, WTH + woff + MSZ, nullptr, SKV, nullptr, nB*Sk, Dd, 2*Dd, 0, 0);
    if (Sk == 128 && (Sq % QT) == 0) {
        dim3 g(Sq/QT, NHh, nB);
        attn_big_kernel<<<g, 128>>>(QB, Dd, SKV, SKV + Dd, 2*Dd, CTXH, Sq, kvxor);
    } else {
        dim3 g(Sq, NHh, nB);
        attn_kernel<<<g, 128>>>(QB, Dd, SKV, SKV + Dd, 2*Dd, nullptr, CTXH, Sq, Sk, kvxor);
    }
    gemm_h(CTXH, WTH + woff + 3*MSZ, nullptr, x, nullptr, nB*Sq, Dd, Dd, 0, 1);
}

#define GETSYM(var, sym) do { void* _p; cudaGetSymbolAddress(&_p, sym); var = (decltype(var))_p; } while (0)

extern "C" void kernel_launch(void* const* d_in, const int* in_sizes, int n_in,
                              void* d_out_v, int out_size)
{
    (void)in_sizes; (void)n_in; (void)out_size;
    const float* pos[2]    = {(const float*)d_in[0], (const float*)d_in[1]};
    const int*   visidx[2] = {(const int*)d_in[2], (const int*)d_in[4]};
    const int*   mskidx[2] = {(const int*)d_in[3], (const int*)d_in[5]};
    const float* tok_w1 = (const float*)d_in[6];  const float* tok_b1 = (const float*)d_in[7];
    const float* tok_w2 = (const float*)d_in[8];  const float* tok_b2 = (const float*)d_in[9];
    const float* tok_w3 = (const float*)d_in[10]; const float* tok_b3 = (const float*)d_in[11];
    const float* tok_w4 = (const float*)d_in[12]; const float* tok_b4 = (const float*)d_in[13];
    const float* mask_token = (const float*)d_in[14];
    const float* cx_attn = (const float*)d_in[15];
    const float* cx_ff1  = (const float*)d_in[16]; const float* cx_ff2 = (const float*)d_in[17];
    const float* enc_sa  = (const float*)d_in[18]; const float* enc_ca = (const float*)d_in[19];
    const float* enc_ff1 = (const float*)d_in[20]; const float* enc_ff2 = (const float*)d_in[21];
    const float* dec_ca  = (const float*)d_in[22]; const float* dec_ff1 = (const float*)d_in[23];
    const float* dec_ff2 = (const float*)d_in[24];
    const float* up_w1 = (const float*)d_in[25]; const float* up_b1 = (const float*)d_in[26];
    const float* up_w2 = (const float*)d_in[27]; const float* up_b2 = (const float*)d_in[28];
    float* dout = (float*)d_out_v;

    float *centersB, *t2B, *tokensB, *cpeB, *ppeB, *vis3B, *visB, *fullB, *decxB, *nn3wB, *lpartB;
    int *nidxB, *nidxSB, *nn3iB;
    unsigned char *mfullB, *mvisB;
    __half *relH, *f1H, *f2H, *gmaxH, *catH, *t1H, *lnSH, *lnmH, *lnbigH, *hidH, *upcatH;
    GETSYM(centersB, g_centers); GETSYM(nidxB, g_nidx); GETSYM(nidxSB, g_nidxS);
    GETSYM(t2B, g_t2); GETSYM(tokensB, g_tokens);
    GETSYM(cpeB, g_cpe); GETSYM(ppeB, g_ppe); GETSYM(mfullB, g_mfull); GETSYM(mvisB, g_mvis);
    GETSYM(vis3B, g_vis3); GETSYM(visB, g_visbuf); GETSYM(fullB, g_fullbuf); GETSYM(decxB, g_decx);
    GETSYM(QB, g_qbuf); GETSYM(SKV, g_skv);
    GETSYM(nn3iB, g_nn3i); GETSYM(nn3wB, g_nn3w); GETSYM(lpartB, g_lpart);
    GETSYM(relH, g_relh); GETSYM(f1H, g_f1h); GETSYM(f2H, g_f2h); GETSYM(gmaxH, g_gmaxh);
    GETSYM(catH, g_cath); GETSYM(t1H, g_t1h); GETSYM(lnSH, g_lnSh);
    GETSYM(lnmH, g_lnmh); GETSYM(lnbigH, g_lnbigh); GETSYM(hidH, g_hidh);
    GETSYM(CTXH, g_ctxh); GETSYM(upcatH, g_upcath); GETSYM(WTH, g_wth);

    float* centers[2] = {centersB, centersB + Bb*Gg*3};
    float* tokens[2]  = {tokensB,  tokensB  + Bb*Gg*Dd};
    float* cpe[2]     = {cpeB,     cpeB     + Bb*Gg*Dd};
    float* visb[2]    = {visB,     visB     + Bb*Vv*Dd};
    float* fullb[2]   = {fullB,    fullB    + Bb*Gg*Dd};
    float* decx[2]    = {decxB,    decxB    + Bb*(Mm+Vv)*Dd};
    unsigned char* mvis[2]  = {mvisB,  mvisB  + Bb*Vv*Vv};

    // Phase 0: fused weight conversion
    {
        WConvArgs wa;
        const float* srcs[16] = {tok_w1, tok_w2, tok_w3, tok_w4, cx_attn, enc_sa, enc_ca,
                                 dec_ca, cx_ff1, cx_ff2, enc_ff1, enc_ff2, dec_ff1, dec_ff2,
                                 up_w1, up_w2};
        long starts[17] = {OFF_W1, OFF_W2, OFF_W3, OFF_W4, OFF_CX, OFF_ENCSA, OFF_ENCCA,
                           OFF_DECCA, OFF_CXFF1, OFF_CXFF2, OFF_EFF1, OFF_EFF2, OFF_DFF1,
                           OFF_DFF2, OFF_UP1, OFF_UP2, WTH_TOT};
        int kds[16]  = {3, 128, 512, 512, Dd, Dd, Dd, Dd, Dd, FFf, Dd, FFf, Dd, FFf, Dd+3, Dd};
        int kps[16]  = {32, 128, 512, 512, Dd, Dd, Dd, Dd, Dd, FFf, Dd, FFf, Dd, FFf, UPK, Dd};
        int ncs[16]  = {128, 256, 512, Dd, Dd, Dd, Dd, Dd, FFf, Dd, FFf, Dd, FFf, Dd, Dd, Dd};
        for (int i = 0; i < 16; i++) { wa.src[i]=srcs[i]; wa.start[i]=starts[i]; wa.Kd[i]=kds[i]; wa.KdPad[i]=kps[i]; wa.Nc[i]=ncs[i]; }
        wa.start[16] = starts[16];
        wtconv_all_kernel<<<(int)(((long)WTH_TOT + 255)/256), 256>>>(wa, WTH);
    }

    // Phase 1
    fps_kernel<<<16, 512>>>(pos[0], pos[1], centersB);
    knn_big_kernel<<<2*Bb*Gg, 128>>>(centersB, pos[0], pos[1], nidxB);
    group_rel_kernel<<<(2*Bb*Gg*Kk + 255)/256, 256>>>(pos[0], pos[1], centersB, nidxB, relH);
    gemm_h(relH, WTH + OFF_W1, tok_b1, nullptr, f1H, 32768, 32, 128, 1, 0);
    gemm_h(f1H, WTH + OFF_W2, tok_b2, nullptr, f2H, 32768, 128, 256, 0, 0);
    gmax_h_kernel<<<(2*Bb*Gg*256 + 255)/256, 256>>>(f2H, gmaxH, 256, 2*Bb*Gg*256);
    cat_kernel<<<(32768*512 + 255)/256, 256>>>(gmaxH, f2H, catH, 32768*512);
    gemm_h(catH, WTH + OFF_W3, tok_b3, nullptr, t1H, 32768, 512, 512, 1, 0);
    gemm_h(t1H, WTH + OFF_W4, tok_b4, t2B, nullptr, 32768, 512, Dd, 0, 0);
    gmax_f_kernel<<<(2*Bb*Gg*Dd + 255)/256, 256>>>(t2B, tokensB, Dd, 2*Bb*Gg*Dd);
    pe_kernel<<<(2*Bb*Gg*Dd + 255)/256, 256>>>(centersB, cpeB, 2*Bb*Gg);
    pe2_kernel<<<(2*Bb*Np*Dd + 255)/256, 256>>>(pos[0], pos[1], ppeB, Bb*Np);
    knn_small_kernel<<<2*Bb*Gg, 128>>>(centersB, Gg, nidxSB);
    zero_u8_kernel<<<(2*Bb*Gg*Gg + 255)/256, 256>>>(mfullB, 2*Bb*Gg*Gg);
    scatter_mask_kernel<<<(2*Bb*Gg*Kk + 255)/256, 256>>>(nidxSB, mfullB, Gg, 2*Bb*Gg*Kk);
    for (int s = 0; s < 2; s++) {
        gather_kernel<<<Bb*Vv, 32>>>(centers[s], visidx[s], vis3B, Vv, Gg, 3);
        knn_small_kernel<<<Bb*Vv, 128>>>(vis3B, Vv, nidxSB);
        zero_u8_kernel<<<(Bb*Vv*Vv + 255)/256, 256>>>(mvis[s], Bb*Vv*Vv);
        scatter_mask_kernel<<<(Bb*Vv*Kk + 255)/256, 256>>>(nidxSB, mvis[s], Vv, Bb*Vv*Kk);
        gather_kernel<<<Bb*Vv, 128>>>(tokens[s], visidx[s], visb[s], Vv, Gg, Dd);
    }
    copy_kernel<<<(2*Bb*Gg*Dd + 255)/256, 256>>>(tokensB, fullB, 2*Bb*Gg*Dd);

    // Phase 2: cross encoders
    for (int e = 0; e < 2; e++) {
        int S = e ? Gg : Vv;
        float* ST = e ? fullB : visB;
        const unsigned char* mask = e ? mfullB : mvisB;
        int rows2 = 2*Bb*S;
        ln_kernel<<<rows2/8, 256>>>(ST, lnSH, rows2);
        self_attn(ST, lnSH, OFF_CX, mask, S, 2*Bb);
        ln_kernel<<<rows2/8, 256>>>(ST, lnSH, rows2);
        cross_attn(ST, lnSH, lnSH, OFF_CX + 4*MSZ, S, S, 2*Bb, Bb);
        ln_kernel<<<rows2/8, 256>>>(ST, lnSH, rows2);
        gemm_h(lnSH, WTH + OFF_CXFF1, nullptr, nullptr, hidH, rows2, Dd, FFf, 1, 0);
        gemm_h(hidH, WTH + OFF_CXFF2, nullptr, ST, nullptr, rows2, FFf, Dd, 0, 1);
    }

    // Phase 3: MAE decoder
    for (int s = 0; s < 2; s++)
        decq_kernel<<<(Bb*(Mm+Vv)*Dd + 255)/256, 256>>>(visb[s], cpe[s], mask_token,
                                                        mskidx[s], visidx[s], decx[s]);
    ln2res_kernel<<<(2*Bb*Gg)/8, 256>>>(fullb[1], cpe[1], fullb[0], cpe[0], lnmH, Bb*Gg);
    for (int l = 0; l < 4; l++) {
        ln_kernel<<<(2*Bb*(Mm+Vv))/8, 256>>>(decxB, lnSH, 2*Bb*(Mm+Vv));
        self_attn(decxB, lnSH, OFF_ENCSA + (long)l*4*MSZ, nullptr, Mm+Vv, 2*Bb);
        ln_kernel<<<(2*Bb*(Mm+Vv))/8, 256>>>(decxB, lnSH, 2*Bb*(Mm+Vv));
        cross_attn(decxB, lnSH, lnmH, OFF_ENCCA + (long)l*4*MSZ, Mm+Vv, Gg, 2*Bb, 0);
        ln_kernel<<<(2*Bb*(Mm+Vv))/8, 256>>>(decxB, lnSH, 2*Bb*(Mm+Vv));
        gemm_h(lnSH, WTH + OFF_EFF1 + (long)l*Dd*FFf, nullptr, nullptr, hidH, 2*Bb*(Mm+Vv), Dd, FFf, 1, 0);
        gemm_h(hidH, WTH + OFF_EFF2 + (long)l*FFf*Dd, nullptr, decxB, nullptr, 2*Bb*(Mm+Vv), FFf, Dd, 0, 1);
    }
    for (int s = 0; s < 2; s++)
        loss_kernel<<<64, 256>>>(fullb[s], mskidx[s], decx[s], lpartB + s*64);

    // Phase 4
    nn3_kernel<<<(2*Bb*Np + 255)/256, 256>>>(pos[0], pos[1], centersB, nn3iB, nn3wB);
    upcat_kernel<<<2*Bb*Np, 128>>>(fullB, pos[0], pos[1], nn3iB, nn3wB, upcatH);
    gemm_h(upcatH, WTH + OFF_UP1, up_b1, nullptr, hidH, 2*Bb*Np, UPK, Dd, 1, 0);
    gemm_h(hidH, WTH + OFF_UP2, up_b2, QB, nullptr, 2*Bb*Np, Dd, Dd, 1, 0);
    add_kernel<<<(2*Bb*Np*Dd + 255)/256, 256>>>(QB, ppeB, dout, 2*Bb*Np*Dd);
    ln2res_kernel<<<(2*Bb*Gg)/8, 256>>>(fullb[0], cpe[0], fullb[1], cpe[1], lnmH, Bb*Gg);
    for (int l = 0; l < 2; l++) {
        ln_kernel<<<(2*Bb*Np)/8, 256>>>(dout, lnbigH, 2*Bb*Np);
        cross_attn(dout, lnbigH, lnmH, OFF_DECCA + (long)l*4*MSZ, Np, Gg, 2*Bb, 0);
        ln_kernel<<<(2*Bb*Np)/8, 256>>>(dout, lnbigH, 2*Bb*Np);
        gemm_h(lnbigH, WTH + OFF_DFF1 + (long)l*Dd*FFf, nullptr, nullptr, hidH, 2*Bb*Np, Dd, FFf, 1, 0);
        gemm_h(hidH, WTH + OFF_DFF2 + (long)l*FFf*Dd, nullptr, dout, nullptr, 2*Bb*Np, FFf, Dd, 0, 1);
    }
    loss_final_kernel<<<1, 1>>>(lpartB, lpartB + 64, dout + (size_t)2*Bb*Np*Dd);
}